// round 2
// baseline (speedup 1.0000x reference)
#include <cuda_runtime.h>
#include <cuda_bf16.h>

#define S_LEN 2048
#define D_DIM 1024
#define H_N 16
#define DHALF 32
#define FF_IN 4096
#define FUSEDW 8192

// ---------------- scratch (static device globals; no allocs) ----------------
__device__ float g_x  [S_LEN * D_DIM];   // rmsnorm output
__device__ float g_q  [S_LEN * D_DIM];
__device__ float g_k  [S_LEN * D_DIM];
__device__ float g_v  [S_LEN * D_DIM];
__device__ float g_qb [S_LEN * D_DIM];
__device__ float g_kb [S_LEN * D_DIM];
__device__ float g_pkb[S_LEN * D_DIM];   // prefix-summed kb
__device__ float g_y  [S_LEN * D_DIM];   // attention output (s, h*64+d)
__device__ float g_ao [S_LEN * D_DIM];   // attn_out = y@Wo + bo
__device__ float g_u  [S_LEN * FUSEDW];  // x@W1 + b1
__device__ float g_fm [S_LEN * FF_IN];   // silu(gate)*xp

// ---------------- RMSNorm ----------------
__global__ void __launch_bounds__(256) rmsnorm_kernel(const float* __restrict__ h,
                                                      float* __restrict__ x) {
    int row = blockIdx.x;
    int t = threadIdx.x;
    const float4* hr = reinterpret_cast<const float4*>(h + (size_t)row * D_DIM);
    float4 a = hr[t];
    float ss = a.x * a.x + a.y * a.y + a.z * a.z + a.w * a.w;
    __shared__ float red[8];
    #pragma unroll
    for (int off = 16; off; off >>= 1) ss += __shfl_xor_sync(0xffffffffu, ss, off);
    if ((t & 31) == 0) red[t >> 5] = ss;
    __syncthreads();
    float tot = red[0] + red[1] + red[2] + red[3] + red[4] + red[5] + red[6] + red[7];
    float r = rsqrtf(tot * (1.0f / 1024.0f) + 1.1920929e-7f);
    float4 o = make_float4(a.x * r, a.y * r, a.z * r, a.w * r);
    reinterpret_cast<float4*>(x + (size_t)row * D_DIM)[t] = o;
}

// ---------------- generic SGEMM: C = A[MxK] @ B[KxN] (+bias +add0 +lam*add1) ----------------
#define BM 128
#define BN 128
#define BKT 8
#define TM 8
#define TN 8
__global__ void __launch_bounds__(256) sgemm_kernel(
    const float* __restrict__ A, const float* __restrict__ B, float* __restrict__ C,
    int M, int N, int K,
    const float* __restrict__ bias,
    const float* __restrict__ add0,
    const float* __restrict__ add1,
    const float* __restrict__ lamPtr)
{
    __shared__ float As[BKT][BM];
    __shared__ float Bs[BKT][BN];
    int tid = threadIdx.x;
    int bm = blockIdx.y * BM;
    int bn = blockIdx.x * BN;
    int arow = tid >> 1;
    int acol = (tid & 1) * 4;
    int brow = tid >> 5;
    int bcol = (tid & 31) * 4;
    int tx = (tid & 15) * TN;
    int ty = (tid >> 4) * TM;

    float acc[TM][TN];
    #pragma unroll
    for (int i = 0; i < TM; i++)
        #pragma unroll
        for (int j = 0; j < TN; j++) acc[i][j] = 0.f;

    const float* Aptr = A + (size_t)(bm + arow) * K + acol;
    const float* Bptr = B + (size_t)brow * N + bn + bcol;

    for (int k0 = 0; k0 < K; k0 += BKT) {
        float4 a4 = *reinterpret_cast<const float4*>(Aptr + k0);
        As[acol + 0][arow] = a4.x;
        As[acol + 1][arow] = a4.y;
        As[acol + 2][arow] = a4.z;
        As[acol + 3][arow] = a4.w;
        float4 b4 = *reinterpret_cast<const float4*>(Bptr + (size_t)k0 * N);
        *reinterpret_cast<float4*>(&Bs[brow][bcol]) = b4;
        __syncthreads();
        #pragma unroll
        for (int kk = 0; kk < BKT; kk++) {
            float ar[TM], br[TN];
            *reinterpret_cast<float4*>(&ar[0]) = *reinterpret_cast<const float4*>(&As[kk][ty]);
            *reinterpret_cast<float4*>(&ar[4]) = *reinterpret_cast<const float4*>(&As[kk][ty + 4]);
            *reinterpret_cast<float4*>(&br[0]) = *reinterpret_cast<const float4*>(&Bs[kk][tx]);
            *reinterpret_cast<float4*>(&br[4]) = *reinterpret_cast<const float4*>(&Bs[kk][tx + 4]);
            #pragma unroll
            for (int i = 0; i < TM; i++)
                #pragma unroll
                for (int j = 0; j < TN; j++) acc[i][j] += ar[i] * br[j];
        }
        __syncthreads();
    }

    float lam = lamPtr ? lamPtr[0] : 0.f;
    #pragma unroll
    for (int i = 0; i < TM; i++) {
        int r = bm + ty + i;
        #pragma unroll
        for (int j = 0; j < TN; j++) {
            int c = bn + tx + j;
            float val = acc[i][j];
            if (bias) val += bias[c];
            size_t idx = (size_t)r * N + c;
            if (add0) val += add0[idx];
            if (add1) val += lam * add1[idx];
            C[idx] = val;
        }
    }
}

// ---------------- l2norm + RoPE (in-place, per (s, h, array)) ----------------
__global__ void ropenorm_kernel(float* q, float* k, float* qb, float* kb) {
    int s = blockIdx.x;
    int h = blockIdx.y;
    int a = blockIdx.z;
    int lane = threadIdx.x;
    float* arr = (a == 0) ? q : (a == 1) ? k : (a == 2) ? qb : kb;
    float* p = arr + (size_t)s * D_DIM + h * 64;
    float x1 = p[lane];
    float x2 = p[lane + DHALF];
    float ss = x1 * x1 + x2 * x2;
    #pragma unroll
    for (int off = 16; off; off >>= 1) ss += __shfl_xor_sync(0xffffffffu, ss, off);
    float n = fmaxf(sqrtf(ss), 1e-12f);
    float inv = 1.f / n;
    x1 *= inv;
    x2 *= inv;
    // inv_freq = 1000^(-lane/32); tables quantized to bf16 like the reference
    float invfreq = powf(1000.0f, -(float)lane * (1.0f / 32.0f));
    float fr = (float)s * invfreq;
    float c  = __bfloat162float(__float2bfloat16(cosf(fr)));
    float sn = __bfloat162float(__float2bfloat16(sinf(fr)));
    p[lane]         = x1 * c + x2 * sn;
    p[lane + DHALF] = -x1 * sn + x2 * c;
}

// ---------------- prefix-sum of (roped) kb along sequence ----------------
__global__ void prefix_kernel(const float* __restrict__ kb, float* __restrict__ pkb) {
    int col = blockIdx.x * 64 + threadIdx.x;  // 16 blocks * 64 threads = 1024 cols
    float acc = 0.f;
    #pragma unroll 8
    for (int s = 0; s < S_LEN; s++) {
        acc += kb[(size_t)s * D_DIM + col];
        pkb[(size_t)s * D_DIM + col] = acc;
    }
}

// ---------------- flash attention: warp per q-row, 8 rows/block ----------------
__global__ void __launch_bounds__(256) attn_kernel(
    const float* __restrict__ q, const float* __restrict__ k, const float* __restrict__ v,
    const float* __restrict__ qb, const float* __restrict__ pkb,
    const float* __restrict__ l2sp, float* __restrict__ y)
{
    __shared__ float Ks[64][64];
    __shared__ float Vs[64][64];
    int h = blockIdx.y;
    int q0 = blockIdx.x * 8;
    int tid = threadIdx.x;
    int w = tid >> 5, lane = tid & 31;
    int qi = q0 + w;
    size_t qoff = (size_t)qi * D_DIM + h * 64;
    float q0r = q[qoff + lane];
    float q1r = q[qoff + lane + DHALF];
    float m = -1e30f, l = 0.f, a0 = 0.f, a1 = 0.f;
    int nt = q0 / 64 + 1;  // same for all 8 rows in this block
    for (int kt = 0; kt < nt; kt++) {
        int kbase = kt * 64;
        __syncthreads();
        #pragma unroll
        for (int i = 0; i < 4; i++) {
            int idx = tid + i * 256;
            int kk = idx >> 4;
            int d4 = (idx & 15) << 2;
            size_t g = (size_t)(kbase + kk) * D_DIM + h * 64 + d4;
            *reinterpret_cast<float4*>(&Ks[kk][d4]) = *reinterpret_cast<const float4*>(&k[g]);
            *reinterpret_cast<float4*>(&Vs[kk][d4]) = *reinterpret_cast<const float4*>(&v[g]);
        }
        __syncthreads();
        int kend = qi - kbase + 1;
        if (kend > 64) kend = 64;
        for (int kk = 0; kk < kend; kk++) {
            float s = q0r * Ks[kk][lane] + q1r * Ks[kk][lane + DHALF];
            #pragma unroll
            for (int off = 16; off; off >>= 1) s += __shfl_xor_sync(0xffffffffu, s, off);
            float mn = fmaxf(m, s);
            float corr = __expf(m - mn);
            float p = __expf(s - mn);
            l = l * corr + p;
            a0 = a0 * corr + p * Vs[kk][lane];
            a1 = a1 * corr + p * Vs[kk][lane + DHALF];
            m = mn;
        }
    }
    float inv = 1.f / l;
    float l2s = l2sp[0];
    // linear bonus term: scale * qb . prefix(kb), scale = DH^-0.5 = 1/8
    float sb = qb[qoff + lane] * pkb[qoff + lane] +
               qb[qoff + lane + DHALF] * pkb[qoff + lane + DHALF];
    #pragma unroll
    for (int off = 16; off; off >>= 1) sb += __shfl_xor_sync(0xffffffffu, sb, off);
    sb *= 0.125f;
    y[qoff + lane]         = l2s * a0 * inv + sb;
    y[qoff + lane + DHALF] = l2s * a1 * inv + sb;
}

// ---------------- SwiGLU: fm = silu(u[:,4096:]) * u[:,:4096] ----------------
__global__ void __launch_bounds__(256) swiglu_kernel(const float* __restrict__ u,
                                                     float* __restrict__ fm) {
    int i = blockIdx.x * blockDim.x + threadIdx.x;  // over (2048*4096)/4 float4s
    int e = i * 4;
    int row = e >> 12;          // / 4096
    int col = e & 4095;
    float4 xp = *reinterpret_cast<const float4*>(&u[(size_t)row * FUSEDW + col]);
    float4 g  = *reinterpret_cast<const float4*>(&u[(size_t)row * FUSEDW + FF_IN + col]);
    float4 o;
    o.x = (g.x / (1.f + __expf(-g.x))) * xp.x;
    o.y = (g.y / (1.f + __expf(-g.y))) * xp.y;
    o.z = (g.z / (1.f + __expf(-g.z))) * xp.z;
    o.w = (g.w / (1.f + __expf(-g.w))) * xp.w;
    *reinterpret_cast<float4*>(&fm[(size_t)row * FF_IN + col]) = o;
}

// ---------------- launch ----------------
extern "C" void kernel_launch(void* const* d_in, const int* in_sizes, int n_in,
                              void* d_out, int out_size) {
    const float* h_states = (const float*)d_in[0];
    const float* Wq  = (const float*)d_in[1];
    const float* Wk  = (const float*)d_in[2];
    const float* Wv  = (const float*)d_in[3];
    const float* Wqb = (const float*)d_in[4];
    const float* Wkb = (const float*)d_in[5];
    const float* Wo  = (const float*)d_in[6];
    const float* bo  = (const float*)d_in[7];
    const float* W1  = (const float*)d_in[8];
    const float* b1  = (const float*)d_in[9];
    const float* W2  = (const float*)d_in[10];
    const float* b2  = (const float*)d_in[11];
    const float* lam = (const float*)d_in[12];
    const float* l2s = (const float*)d_in[13];
    float* out = (float*)d_out;

    float *x, *q, *k, *v, *qb, *kb, *pkb, *y, *ao, *u, *fm;
    cudaGetSymbolAddress((void**)&x,  g_x);
    cudaGetSymbolAddress((void**)&q,  g_q);
    cudaGetSymbolAddress((void**)&k,  g_k);
    cudaGetSymbolAddress((void**)&v,  g_v);
    cudaGetSymbolAddress((void**)&qb, g_qb);
    cudaGetSymbolAddress((void**)&kb, g_kb);
    cudaGetSymbolAddress((void**)&pkb, g_pkb);
    cudaGetSymbolAddress((void**)&y,  g_y);
    cudaGetSymbolAddress((void**)&ao, g_ao);
    cudaGetSymbolAddress((void**)&u,  g_u);
    cudaGetSymbolAddress((void**)&fm, g_fm);

    // 1. RMSNorm
    rmsnorm_kernel<<<S_LEN, 256>>>(h_states, x);

    // 2. five projections: [2048x1024] @ [1024x1024]
    dim3 gP(D_DIM / BN, S_LEN / BM);
    sgemm_kernel<<<gP, 256>>>(x, Wq,  q,  S_LEN, D_DIM, D_DIM, nullptr, nullptr, nullptr, nullptr);
    sgemm_kernel<<<gP, 256>>>(x, Wk,  k,  S_LEN, D_DIM, D_DIM, nullptr, nullptr, nullptr, nullptr);
    sgemm_kernel<<<gP, 256>>>(x, Wv,  v,  S_LEN, D_DIM, D_DIM, nullptr, nullptr, nullptr, nullptr);
    sgemm_kernel<<<gP, 256>>>(x, Wqb, qb, S_LEN, D_DIM, D_DIM, nullptr, nullptr, nullptr, nullptr);
    sgemm_kernel<<<gP, 256>>>(x, Wkb, kb, S_LEN, D_DIM, D_DIM, nullptr, nullptr, nullptr, nullptr);

    // 3. l2norm + RoPE in-place on q, k, qb, kb
    ropenorm_kernel<<<dim3(S_LEN, H_N, 4), 32>>>(q, k, qb, kb);

    // 4. prefix sum of kb over sequence (for the linear sb term)
    prefix_kernel<<<H_N, 64>>>(kb, pkb);

    // 5. causal flash attention + sb epilogue -> y [s, h*64+d]
    attn_kernel<<<dim3(S_LEN / 8, H_N), 256>>>(q, k, v, qb, pkb, l2s, y);

    // 6. attn_out = y @ Wo + bo
    sgemm_kernel<<<gP, 256>>>(y, Wo, ao, S_LEN, D_DIM, D_DIM, bo, nullptr, nullptr, nullptr);

    // 7. u = x @ W1 + b1  [2048 x 8192]
    dim3 g1(FUSEDW / BN, S_LEN / BM);
    sgemm_kernel<<<g1, 256>>>(x, W1, u, S_LEN, FUSEDW, D_DIM, b1, nullptr, nullptr, nullptr);

    // 8. SwiGLU
    swiglu_kernel<<<(S_LEN * FF_IN / 4) / 256, 256>>>(u, fm);

    // 9. out = fm @ W2 + b2 + attn_out + lambda * h_states
    sgemm_kernel<<<gP, 256>>>(fm, W2, out, S_LEN, D_DIM, FF_IN, b2, ao, h_states, lam);
}

// round 3
// speedup vs baseline: 1.8574x; 1.8574x over previous
#include <cuda_runtime.h>
#include <cuda_bf16.h>
#include <cstdint>

#define S_LEN 2048
#define D_DIM 1024
#define H_N 16
#define DHALF 32
#define FF_IN 4096
#define FUSEDW 8192

// ---------------- scratch (static device globals; no allocs) ----------------
__device__ float g_x  [S_LEN * D_DIM];   // rmsnorm output
__device__ float g_q  [S_LEN * D_DIM];
__device__ float g_k  [S_LEN * D_DIM];
__device__ float g_v  [S_LEN * D_DIM];
__device__ float g_qb [S_LEN * D_DIM];
__device__ float g_kb [S_LEN * D_DIM];
__device__ float g_pkb[S_LEN * D_DIM];   // prefix-summed kb
__device__ float g_y  [S_LEN * D_DIM];   // attention output (s, h*64+d)
__device__ float g_ao [S_LEN * D_DIM];   // attn_out = y@Wo + bo
__device__ float g_u  [S_LEN * FUSEDW];  // x@W1 + b1
__device__ float g_fm [S_LEN * FF_IN];   // silu(gate)*xp

// ---------------- RMSNorm ----------------
__global__ void __launch_bounds__(256) rmsnorm_kernel(const float* __restrict__ h,
                                                      float* __restrict__ x) {
    int row = blockIdx.x;
    int t = threadIdx.x;
    const float4* hr = reinterpret_cast<const float4*>(h + (size_t)row * D_DIM);
    float4 a = hr[t];
    float ss = a.x * a.x + a.y * a.y + a.z * a.z + a.w * a.w;
    __shared__ float red[8];
    #pragma unroll
    for (int off = 16; off; off >>= 1) ss += __shfl_xor_sync(0xffffffffu, ss, off);
    if ((t & 31) == 0) red[t >> 5] = ss;
    __syncthreads();
    float tot = red[0] + red[1] + red[2] + red[3] + red[4] + red[5] + red[6] + red[7];
    float r = rsqrtf(tot * (1.0f / 1024.0f) + 1.1920929e-7f);
    float4 o = make_float4(a.x * r, a.y * r, a.z * r, a.w * r);
    reinterpret_cast<float4*>(x + (size_t)row * D_DIM)[t] = o;
}

// ---------------- TF32 tensor-core GEMM ----------------
// C = A[MxK] @ B[KxN] (+bias +add0 +lam*add1). Block tile 128x128, BK=16.
// 8 warps, warp tile 32x64 (2x8 m16n8k8 mma tiles). blockIdx.z selects one of
// up to 5 (B, C) pairs so the 5 projections go out in a single launch.

__device__ __forceinline__ uint32_t f2tf(float f) {
    uint32_t u;
    asm("cvt.rna.tf32.f32 %0, %1;" : "=r"(u) : "f"(f));
    return u;
}

#define MMA_TF32(d, a, b)                                                     \
    asm volatile(                                                             \
        "mma.sync.aligned.m16n8k8.row.col.f32.tf32.tf32.f32 "                 \
        "{%0,%1,%2,%3}, {%4,%5,%6,%7}, {%8,%9}, {%0,%1,%2,%3};"               \
        : "+f"(d[0]), "+f"(d[1]), "+f"(d[2]), "+f"(d[3])                      \
        : "r"(a[0]), "r"(a[1]), "r"(a[2]), "r"(a[3]), "r"(b[0]), "r"(b[1]))

#define ASTRIDE 20
#define BSTRIDE 136

__global__ void __launch_bounds__(256) gemm_tf32_kernel(
    const float* __restrict__ A,
    const float* __restrict__ B0, const float* __restrict__ B1,
    const float* __restrict__ B2, const float* __restrict__ B3,
    const float* __restrict__ B4,
    float* __restrict__ C0, float* __restrict__ C1,
    float* __restrict__ C2, float* __restrict__ C3,
    float* __restrict__ C4,
    int M, int N, int K,
    const float* __restrict__ bias,
    const float* __restrict__ add0,
    const float* __restrict__ add1,
    const float* __restrict__ lamPtr)
{
    int z = blockIdx.z;
    const float* B = (z == 0) ? B0 : (z == 1) ? B1 : (z == 2) ? B2 : (z == 3) ? B3 : B4;
    float* C = (z == 0) ? C0 : (z == 1) ? C1 : (z == 2) ? C2 : (z == 3) ? C3 : C4;

    __shared__ uint32_t As[2][128][ASTRIDE];
    __shared__ uint32_t Bs[2][16][BSTRIDE];

    int tid = threadIdx.x;
    int lane = tid & 31;
    int warp = tid >> 5;
    int warpM = warp >> 1;   // 0..3  -> 32-row slice
    int warpN = warp & 1;    // 0..1  -> 64-col slice
    int bm = blockIdx.y * 128;
    int bn = blockIdx.x * 128;

    // global staging indices
    int ar = tid >> 2;          // 0..63  (A rows, +64 for second)
    int ac = (tid & 3) * 4;     // 0,4,8,12
    int br = tid >> 5;          // 0..7   (B rows, +8 for second)
    int bc = (tid & 31) * 4;

    const float* Ap0 = A + (size_t)(bm + ar) * K + ac;
    const float* Ap1 = A + (size_t)(bm + ar + 64) * K + ac;
    const float* Bp0 = B + (size_t)br * N + bn + bc;
    const float* Bp1 = B + (size_t)(br + 8) * N + bn + bc;

    float acc[2][8][4];
    #pragma unroll
    for (int mi = 0; mi < 2; mi++)
        #pragma unroll
        for (int ni = 0; ni < 8; ni++)
            #pragma unroll
            for (int r = 0; r < 4; r++) acc[mi][ni][r] = 0.f;

    int NT = K / 16;
    // prologue: stage tile 0
    float4 av0 = *reinterpret_cast<const float4*>(Ap0);
    float4 av1 = *reinterpret_cast<const float4*>(Ap1);
    float4 bv0 = *reinterpret_cast<const float4*>(Bp0);
    float4 bv1 = *reinterpret_cast<const float4*>(Bp1);
    {
        uint4 pa0 = make_uint4(f2tf(av0.x), f2tf(av0.y), f2tf(av0.z), f2tf(av0.w));
        uint4 pa1 = make_uint4(f2tf(av1.x), f2tf(av1.y), f2tf(av1.z), f2tf(av1.w));
        uint4 pb0 = make_uint4(f2tf(bv0.x), f2tf(bv0.y), f2tf(bv0.z), f2tf(bv0.w));
        uint4 pb1 = make_uint4(f2tf(bv1.x), f2tf(bv1.y), f2tf(bv1.z), f2tf(bv1.w));
        *reinterpret_cast<uint4*>(&As[0][ar][ac])      = pa0;
        *reinterpret_cast<uint4*>(&As[0][ar + 64][ac]) = pa1;
        *reinterpret_cast<uint4*>(&Bs[0][br][bc])      = pb0;
        *reinterpret_cast<uint4*>(&Bs[0][br + 8][bc])  = pb1;
    }
    __syncthreads();

    int buf = 0;
    for (int t = 0; t < NT; t++) {
        if (t + 1 < NT) {
            size_t k0 = (size_t)(t + 1) * 16;
            av0 = *reinterpret_cast<const float4*>(Ap0 + k0);
            av1 = *reinterpret_cast<const float4*>(Ap1 + k0);
            bv0 = *reinterpret_cast<const float4*>(Bp0 + k0 * N);
            bv1 = *reinterpret_cast<const float4*>(Bp1 + k0 * N);
        }
        // compute on buf
        #pragma unroll
        for (int ks = 0; ks < 2; ks++) {
            uint32_t af[2][4], bf[8][2];
            int kc = ks * 8 + (lane & 3);
            #pragma unroll
            for (int mi = 0; mi < 2; mi++) {
                int r = warpM * 32 + mi * 16 + (lane >> 2);
                af[mi][0] = As[buf][r][kc];
                af[mi][1] = As[buf][r + 8][kc];
                af[mi][2] = As[buf][r][kc + 4];
                af[mi][3] = As[buf][r + 8][kc + 4];
            }
            #pragma unroll
            for (int ni = 0; ni < 8; ni++) {
                int c = warpN * 64 + ni * 8 + (lane >> 2);
                bf[ni][0] = Bs[buf][kc][c];
                bf[ni][1] = Bs[buf][ks * 8 + 4 + (lane & 3)][c];
            }
            #pragma unroll
            for (int mi = 0; mi < 2; mi++)
                #pragma unroll
                for (int ni = 0; ni < 8; ni++)
                    MMA_TF32(acc[mi][ni], af[mi], bf[ni]);
        }
        if (t + 1 < NT) {
            int nb = buf ^ 1;
            uint4 pa0 = make_uint4(f2tf(av0.x), f2tf(av0.y), f2tf(av0.z), f2tf(av0.w));
            uint4 pa1 = make_uint4(f2tf(av1.x), f2tf(av1.y), f2tf(av1.z), f2tf(av1.w));
            uint4 pb0 = make_uint4(f2tf(bv0.x), f2tf(bv0.y), f2tf(bv0.z), f2tf(bv0.w));
            uint4 pb1 = make_uint4(f2tf(bv1.x), f2tf(bv1.y), f2tf(bv1.z), f2tf(bv1.w));
            *reinterpret_cast<uint4*>(&As[nb][ar][ac])      = pa0;
            *reinterpret_cast<uint4*>(&As[nb][ar + 64][ac]) = pa1;
            *reinterpret_cast<uint4*>(&Bs[nb][br][bc])      = pb0;
            *reinterpret_cast<uint4*>(&Bs[nb][br + 8][bc])  = pb1;
            __syncthreads();
            buf = nb;
        }
    }

    // epilogue
    float lam = lamPtr ? lamPtr[0] : 0.f;
    #pragma unroll
    for (int mi = 0; mi < 2; mi++) {
        int r0 = bm + warpM * 32 + mi * 16 + (lane >> 2);
        #pragma unroll
        for (int ni = 0; ni < 8; ni++) {
            int c0 = bn + warpN * 64 + ni * 8 + (lane & 3) * 2;
            #pragma unroll
            for (int half = 0; half < 2; half++) {
                int r = r0 + half * 8;
                float v0 = acc[mi][ni][half * 2 + 0];
                float v1 = acc[mi][ni][half * 2 + 1];
                if (bias) { v0 += bias[c0]; v1 += bias[c0 + 1]; }
                size_t idx = (size_t)r * N + c0;
                if (add0) { v0 += add0[idx]; v1 += add0[idx + 1]; }
                if (add1) { v0 += lam * add1[idx]; v1 += lam * add1[idx + 1]; }
                C[idx]     = v0;
                C[idx + 1] = v1;
            }
        }
    }
}

// ---------------- l2norm + RoPE (in-place, per (s, h, array)) ----------------
__global__ void ropenorm_kernel(float* q, float* k, float* qb, float* kb) {
    int s = blockIdx.x;
    int h = blockIdx.y;
    int a = blockIdx.z;
    int lane = threadIdx.x;
    float* arr = (a == 0) ? q : (a == 1) ? k : (a == 2) ? qb : kb;
    float* p = arr + (size_t)s * D_DIM + h * 64;
    float x1 = p[lane];
    float x2 = p[lane + DHALF];
    float ss = x1 * x1 + x2 * x2;
    #pragma unroll
    for (int off = 16; off; off >>= 1) ss += __shfl_xor_sync(0xffffffffu, ss, off);
    float n = fmaxf(sqrtf(ss), 1e-12f);
    float inv = 1.f / n;
    x1 *= inv;
    x2 *= inv;
    float invfreq = powf(1000.0f, -(float)lane * (1.0f / 32.0f));
    float fr = (float)s * invfreq;
    float c  = __bfloat162float(__float2bfloat16(cosf(fr)));
    float sn = __bfloat162float(__float2bfloat16(sinf(fr)));
    p[lane]         = x1 * c + x2 * sn;
    p[lane + DHALF] = -x1 * sn + x2 * c;
}

// ---------------- prefix-sum of (roped) kb along sequence ----------------
__global__ void prefix_kernel(const float* __restrict__ kb, float* __restrict__ pkb) {
    int col = blockIdx.x * 64 + threadIdx.x;
    float acc = 0.f;
    #pragma unroll 8
    for (int s = 0; s < S_LEN; s++) {
        acc += kb[(size_t)s * D_DIM + col];
        pkb[(size_t)s * D_DIM + col] = acc;
    }
}

// ---------------- flash attention: warp per q-row, 8 rows/block ----------------
__global__ void __launch_bounds__(256) attn_kernel(
    const float* __restrict__ q, const float* __restrict__ k, const float* __restrict__ v,
    const float* __restrict__ qb, const float* __restrict__ pkb,
    const float* __restrict__ l2sp, float* __restrict__ y)
{
    __shared__ float Ks[64][64];
    __shared__ float Vs[64][64];
    int h = blockIdx.y;
    int q0 = blockIdx.x * 8;
    int tid = threadIdx.x;
    int w = tid >> 5, lane = tid & 31;
    int qi = q0 + w;
    size_t qoff = (size_t)qi * D_DIM + h * 64;
    float q0r = q[qoff + lane];
    float q1r = q[qoff + lane + DHALF];
    float m = -1e30f, l = 0.f, a0 = 0.f, a1 = 0.f;
    int nt = q0 / 64 + 1;
    for (int kt = 0; kt < nt; kt++) {
        int kbase = kt * 64;
        __syncthreads();
        #pragma unroll
        for (int i = 0; i < 4; i++) {
            int idx = tid + i * 256;
            int kk = idx >> 4;
            int d4 = (idx & 15) << 2;
            size_t g = (size_t)(kbase + kk) * D_DIM + h * 64 + d4;
            *reinterpret_cast<float4*>(&Ks[kk][d4]) = *reinterpret_cast<const float4*>(&k[g]);
            *reinterpret_cast<float4*>(&Vs[kk][d4]) = *reinterpret_cast<const float4*>(&v[g]);
        }
        __syncthreads();
        int kend = qi - kbase + 1;
        if (kend > 64) kend = 64;
        for (int kk = 0; kk < kend; kk++) {
            float s = q0r * Ks[kk][lane] + q1r * Ks[kk][lane + DHALF];
            #pragma unroll
            for (int off = 16; off; off >>= 1) s += __shfl_xor_sync(0xffffffffu, s, off);
            float mn = fmaxf(m, s);
            float corr = __expf(m - mn);
            float p = __expf(s - mn);
            l = l * corr + p;
            a0 = a0 * corr + p * Vs[kk][lane];
            a1 = a1 * corr + p * Vs[kk][lane + DHALF];
            m = mn;
        }
    }
    float inv = 1.f / l;
    float l2s = l2sp[0];
    float sb = qb[qoff + lane] * pkb[qoff + lane] +
               qb[qoff + lane + DHALF] * pkb[qoff + lane + DHALF];
    #pragma unroll
    for (int off = 16; off; off >>= 1) sb += __shfl_xor_sync(0xffffffffu, sb, off);
    sb *= 0.125f;
    y[qoff + lane]         = l2s * a0 * inv + sb;
    y[qoff + lane + DHALF] = l2s * a1 * inv + sb;
}

// ---------------- SwiGLU: fm = silu(u[:,4096:]) * u[:,:4096] ----------------
__global__ void __launch_bounds__(256) swiglu_kernel(const float* __restrict__ u,
                                                     float* __restrict__ fm) {
    int i = blockIdx.x * blockDim.x + threadIdx.x;
    int e = i * 4;
    int row = e >> 12;
    int col = e & 4095;
    float4 xp = *reinterpret_cast<const float4*>(&u[(size_t)row * FUSEDW + col]);
    float4 g  = *reinterpret_cast<const float4*>(&u[(size_t)row * FUSEDW + FF_IN + col]);
    float4 o;
    o.x = (g.x / (1.f + __expf(-g.x))) * xp.x;
    o.y = (g.y / (1.f + __expf(-g.y))) * xp.y;
    o.z = (g.z / (1.f + __expf(-g.z))) * xp.z;
    o.w = (g.w / (1.f + __expf(-g.w))) * xp.w;
    *reinterpret_cast<float4*>(&fm[(size_t)row * FF_IN + col]) = o;
}

// ---------------- launch ----------------
extern "C" void kernel_launch(void* const* d_in, const int* in_sizes, int n_in,
                              void* d_out, int out_size) {
    const float* h_states = (const float*)d_in[0];
    const float* Wq  = (const float*)d_in[1];
    const float* Wk  = (const float*)d_in[2];
    const float* Wv  = (const float*)d_in[3];
    const float* Wqb = (const float*)d_in[4];
    const float* Wkb = (const float*)d_in[5];
    const float* Wo  = (const float*)d_in[6];
    const float* bo  = (const float*)d_in[7];
    const float* W1  = (const float*)d_in[8];
    const float* b1  = (const float*)d_in[9];
    const float* W2  = (const float*)d_in[10];
    const float* b2  = (const float*)d_in[11];
    const float* lam = (const float*)d_in[12];
    const float* l2s = (const float*)d_in[13];
    float* out = (float*)d_out;

    float *x, *q, *k, *v, *qb, *kb, *pkb, *y, *ao, *u, *fm;
    cudaGetSymbolAddress((void**)&x,  g_x);
    cudaGetSymbolAddress((void**)&q,  g_q);
    cudaGetSymbolAddress((void**)&k,  g_k);
    cudaGetSymbolAddress((void**)&v,  g_v);
    cudaGetSymbolAddress((void**)&qb, g_qb);
    cudaGetSymbolAddress((void**)&kb, g_kb);
    cudaGetSymbolAddress((void**)&pkb, g_pkb);
    cudaGetSymbolAddress((void**)&y,  g_y);
    cudaGetSymbolAddress((void**)&ao, g_ao);
    cudaGetSymbolAddress((void**)&u,  g_u);
    cudaGetSymbolAddress((void**)&fm, g_fm);

    // 1. RMSNorm
    rmsnorm_kernel<<<S_LEN, 256>>>(h_states, x);

    // 2. five projections in ONE launch (blockIdx.z selects weight/output)
    dim3 gP(D_DIM / 128, S_LEN / 128, 5);
    gemm_tf32_kernel<<<gP, 256>>>(x, Wq, Wk, Wv, Wqb, Wkb, q, k, v, qb, kb,
                                  S_LEN, D_DIM, D_DIM,
                                  nullptr, nullptr, nullptr, nullptr);

    // 3. l2norm + RoPE in-place on q, k, qb, kb
    ropenorm_kernel<<<dim3(S_LEN, H_N, 4), 32>>>(q, k, qb, kb);

    // 4. prefix sum of kb over sequence (linear sb term)
    prefix_kernel<<<H_N, 64>>>(kb, pkb);

    // 5. causal flash attention + sb epilogue -> y
    attn_kernel<<<dim3(S_LEN / 8, H_N), 256>>>(q, k, v, qb, pkb, l2s, y);

    // 6. attn_out = y @ Wo + bo
    dim3 g1(D_DIM / 128, S_LEN / 128, 1);
    gemm_tf32_kernel<<<g1, 256>>>(y, Wo, nullptr, nullptr, nullptr, nullptr,
                                  ao, nullptr, nullptr, nullptr, nullptr,
                                  S_LEN, D_DIM, D_DIM,
                                  bo, nullptr, nullptr, nullptr);

    // 7. u = x @ W1 + b1  [2048 x 8192]
    dim3 g2(FUSEDW / 128, S_LEN / 128, 1);
    gemm_tf32_kernel<<<g2, 256>>>(x, W1, nullptr, nullptr, nullptr, nullptr,
                                  u, nullptr, nullptr, nullptr, nullptr,
                                  S_LEN, FUSEDW, D_DIM,
                                  b1, nullptr, nullptr, nullptr);

    // 8. SwiGLU
    swiglu_kernel<<<(S_LEN * FF_IN / 4) / 256, 256>>>(u, fm);

    // 9. out = fm @ W2 + b2 + attn_out + lambda * h_states
    gemm_tf32_kernel<<<g1, 256>>>(fm, W2, nullptr, nullptr, nullptr, nullptr,
                                  out, nullptr, nullptr, nullptr, nullptr,
                                  S_LEN, D_DIM, FF_IN,
                                  b2, ao, h_states, lam);
}

// round 4
// speedup vs baseline: 4.5055x; 2.4257x over previous
#include <cuda_runtime.h>
#include <cuda_bf16.h>
#include <cstdint>

#define S_LEN 2048
#define D_DIM 1024
#define H_N 16
#define DHALF 32
#define FF_IN 4096
#define FUSEDW 8192

// ---------------- scratch (static device globals; no allocs) ----------------
__device__ float g_x  [S_LEN * D_DIM];   // rmsnorm output
__device__ float g_q  [S_LEN * D_DIM];
__device__ float g_k  [S_LEN * D_DIM];
__device__ float g_v  [S_LEN * D_DIM];
__device__ float g_qb [S_LEN * D_DIM];
__device__ float g_kb [S_LEN * D_DIM];
__device__ float g_pkb[S_LEN * D_DIM];   // prefix-summed kb
__device__ float g_cs [64 * D_DIM];      // chunk sums for prefix scan
__device__ float g_sb [S_LEN * H_N];     // per-(s,h) linear bonus value
__device__ float g_y  [S_LEN * D_DIM];   // attention output (s, h*64+d)
__device__ float g_ao [S_LEN * D_DIM];   // attn_out = y@Wo + bo
__device__ float g_u  [S_LEN * FUSEDW];  // x@W1 + b1
__device__ float g_fm [S_LEN * FF_IN];   // silu(gate)*xp

// ---------------- RMSNorm ----------------
__global__ void __launch_bounds__(256) rmsnorm_kernel(const float* __restrict__ h,
                                                      float* __restrict__ x) {
    int row = blockIdx.x;
    int t = threadIdx.x;
    const float4* hr = reinterpret_cast<const float4*>(h + (size_t)row * D_DIM);
    float4 a = hr[t];
    float ss = a.x * a.x + a.y * a.y + a.z * a.z + a.w * a.w;
    __shared__ float red[8];
    #pragma unroll
    for (int off = 16; off; off >>= 1) ss += __shfl_xor_sync(0xffffffffu, ss, off);
    if ((t & 31) == 0) red[t >> 5] = ss;
    __syncthreads();
    float tot = red[0] + red[1] + red[2] + red[3] + red[4] + red[5] + red[6] + red[7];
    float r = rsqrtf(tot * (1.0f / 1024.0f) + 1.1920929e-7f);
    float4 o = make_float4(a.x * r, a.y * r, a.z * r, a.w * r);
    reinterpret_cast<float4*>(x + (size_t)row * D_DIM)[t] = o;
}

// ---------------- TF32 helpers ----------------
__device__ __forceinline__ uint32_t f2tf(float f) {
    uint32_t u;
    asm("cvt.rna.tf32.f32 %0, %1;" : "=r"(u) : "f"(f));
    return u;
}

#define MMA_TF32(d, a, b)                                                     \
    asm volatile(                                                             \
        "mma.sync.aligned.m16n8k8.row.col.f32.tf32.tf32.f32 "                 \
        "{%0,%1,%2,%3}, {%4,%5,%6,%7}, {%8,%9}, {%0,%1,%2,%3};"               \
        : "+f"(d[0]), "+f"(d[1]), "+f"(d[2]), "+f"(d[3])                      \
        : "r"(a[0]), "r"(a[1]), "r"(a[2]), "r"(a[3]), "r"(b[0]), "r"(b[1]))

// ---------------- TF32 tensor-core GEMM (same as R2; proven) ----------------
#define ASTRIDE 20
#define BSTRIDE 136

__global__ void __launch_bounds__(256) gemm_tf32_kernel(
    const float* __restrict__ A,
    const float* __restrict__ B0, const float* __restrict__ B1,
    const float* __restrict__ B2, const float* __restrict__ B3,
    const float* __restrict__ B4,
    float* __restrict__ C0, float* __restrict__ C1,
    float* __restrict__ C2, float* __restrict__ C3,
    float* __restrict__ C4,
    int M, int N, int K,
    const float* __restrict__ bias,
    const float* __restrict__ add0,
    const float* __restrict__ add1,
    const float* __restrict__ lamPtr)
{
    int z = blockIdx.z;
    const float* B = (z == 0) ? B0 : (z == 1) ? B1 : (z == 2) ? B2 : (z == 3) ? B3 : B4;
    float* C = (z == 0) ? C0 : (z == 1) ? C1 : (z == 2) ? C2 : (z == 3) ? C3 : C4;

    __shared__ uint32_t As[2][128][ASTRIDE];
    __shared__ uint32_t Bs[2][16][BSTRIDE];

    int tid = threadIdx.x;
    int lane = tid & 31;
    int warp = tid >> 5;
    int warpM = warp >> 1;
    int warpN = warp & 1;
    int bm = blockIdx.y * 128;
    int bn = blockIdx.x * 128;

    int ar = tid >> 2;
    int ac = (tid & 3) * 4;
    int br = tid >> 5;
    int bc = (tid & 31) * 4;

    const float* Ap0 = A + (size_t)(bm + ar) * K + ac;
    const float* Ap1 = A + (size_t)(bm + ar + 64) * K + ac;
    const float* Bp0 = B + (size_t)br * N + bn + bc;
    const float* Bp1 = B + (size_t)(br + 8) * N + bn + bc;

    float acc[2][8][4];
    #pragma unroll
    for (int mi = 0; mi < 2; mi++)
        #pragma unroll
        for (int ni = 0; ni < 8; ni++)
            #pragma unroll
            for (int r = 0; r < 4; r++) acc[mi][ni][r] = 0.f;

    int NT = K / 16;
    float4 av0 = *reinterpret_cast<const float4*>(Ap0);
    float4 av1 = *reinterpret_cast<const float4*>(Ap1);
    float4 bv0 = *reinterpret_cast<const float4*>(Bp0);
    float4 bv1 = *reinterpret_cast<const float4*>(Bp1);
    {
        uint4 pa0 = make_uint4(f2tf(av0.x), f2tf(av0.y), f2tf(av0.z), f2tf(av0.w));
        uint4 pa1 = make_uint4(f2tf(av1.x), f2tf(av1.y), f2tf(av1.z), f2tf(av1.w));
        uint4 pb0 = make_uint4(f2tf(bv0.x), f2tf(bv0.y), f2tf(bv0.z), f2tf(bv0.w));
        uint4 pb1 = make_uint4(f2tf(bv1.x), f2tf(bv1.y), f2tf(bv1.z), f2tf(bv1.w));
        *reinterpret_cast<uint4*>(&As[0][ar][ac])      = pa0;
        *reinterpret_cast<uint4*>(&As[0][ar + 64][ac]) = pa1;
        *reinterpret_cast<uint4*>(&Bs[0][br][bc])      = pb0;
        *reinterpret_cast<uint4*>(&Bs[0][br + 8][bc])  = pb1;
    }
    __syncthreads();

    int buf = 0;
    for (int t = 0; t < NT; t++) {
        if (t + 1 < NT) {
            size_t k0 = (size_t)(t + 1) * 16;
            av0 = *reinterpret_cast<const float4*>(Ap0 + k0);
            av1 = *reinterpret_cast<const float4*>(Ap1 + k0);
            bv0 = *reinterpret_cast<const float4*>(Bp0 + k0 * N);
            bv1 = *reinterpret_cast<const float4*>(Bp1 + k0 * N);
        }
        #pragma unroll
        for (int ks = 0; ks < 2; ks++) {
            uint32_t af[2][4], bf[8][2];
            int kc = ks * 8 + (lane & 3);
            #pragma unroll
            for (int mi = 0; mi < 2; mi++) {
                int r = warpM * 32 + mi * 16 + (lane >> 2);
                af[mi][0] = As[buf][r][kc];
                af[mi][1] = As[buf][r + 8][kc];
                af[mi][2] = As[buf][r][kc + 4];
                af[mi][3] = As[buf][r + 8][kc + 4];
            }
            #pragma unroll
            for (int ni = 0; ni < 8; ni++) {
                int c = warpN * 64 + ni * 8 + (lane >> 2);
                bf[ni][0] = Bs[buf][kc][c];
                bf[ni][1] = Bs[buf][ks * 8 + 4 + (lane & 3)][c];
            }
            #pragma unroll
            for (int mi = 0; mi < 2; mi++)
                #pragma unroll
                for (int ni = 0; ni < 8; ni++)
                    MMA_TF32(acc[mi][ni], af[mi], bf[ni]);
        }
        if (t + 1 < NT) {
            int nb = buf ^ 1;
            uint4 pa0 = make_uint4(f2tf(av0.x), f2tf(av0.y), f2tf(av0.z), f2tf(av0.w));
            uint4 pa1 = make_uint4(f2tf(av1.x), f2tf(av1.y), f2tf(av1.z), f2tf(av1.w));
            uint4 pb0 = make_uint4(f2tf(bv0.x), f2tf(bv0.y), f2tf(bv0.z), f2tf(bv0.w));
            uint4 pb1 = make_uint4(f2tf(bv1.x), f2tf(bv1.y), f2tf(bv1.z), f2tf(bv1.w));
            *reinterpret_cast<uint4*>(&As[nb][ar][ac])      = pa0;
            *reinterpret_cast<uint4*>(&As[nb][ar + 64][ac]) = pa1;
            *reinterpret_cast<uint4*>(&Bs[nb][br][bc])      = pb0;
            *reinterpret_cast<uint4*>(&Bs[nb][br + 8][bc])  = pb1;
            __syncthreads();
            buf = nb;
        }
    }

    float lam = lamPtr ? lamPtr[0] : 0.f;
    #pragma unroll
    for (int mi = 0; mi < 2; mi++) {
        int r0 = bm + warpM * 32 + mi * 16 + (lane >> 2);
        #pragma unroll
        for (int ni = 0; ni < 8; ni++) {
            int c0 = bn + warpN * 64 + ni * 8 + (lane & 3) * 2;
            #pragma unroll
            for (int half = 0; half < 2; half++) {
                int r = r0 + half * 8;
                float v0 = acc[mi][ni][half * 2 + 0];
                float v1 = acc[mi][ni][half * 2 + 1];
                if (bias) { v0 += bias[c0]; v1 += bias[c0 + 1]; }
                size_t idx = (size_t)r * N + c0;
                if (add0) { v0 += add0[idx]; v1 += add0[idx + 1]; }
                if (add1) { v0 += lam * add1[idx]; v1 += lam * add1[idx + 1]; }
                C[idx]     = v0;
                C[idx + 1] = v1;
            }
        }
    }
}

// ---------------- l2norm + RoPE: 8 warps/block, warp -> (h, array) ----------------
__global__ void __launch_bounds__(256) ropenorm_kernel(float* q, float* k, float* qb, float* kb) {
    int s = blockIdx.x;
    int warp = threadIdx.x >> 5;
    int lane = threadIdx.x & 31;
    int idx = blockIdx.y * 8 + warp;       // 0..63
    int h = idx & 15;
    int a = idx >> 4;
    float* arr = (a == 0) ? q : (a == 1) ? k : (a == 2) ? qb : kb;
    float* p = arr + (size_t)s * D_DIM + h * 64;
    float x1 = p[lane];
    float x2 = p[lane + DHALF];
    float ss = x1 * x1 + x2 * x2;
    #pragma unroll
    for (int off = 16; off; off >>= 1) ss += __shfl_xor_sync(0xffffffffu, ss, off);
    float n = fmaxf(sqrtf(ss), 1e-12f);
    float inv = 1.f / n;
    x1 *= inv;
    x2 *= inv;
    float invfreq = powf(1000.0f, -(float)lane * (1.0f / 32.0f));
    float fr = (float)s * invfreq;
    float c  = __bfloat162float(__float2bfloat16(cosf(fr)));
    float sn = __bfloat162float(__float2bfloat16(sinf(fr)));
    p[lane]         = x1 * c + x2 * sn;
    p[lane + DHALF] = -x1 * sn + x2 * c;
}

// ---------------- parallel prefix sum of kb (3 phases, 64 chunks of 32) ---------
__global__ void __launch_bounds__(256) prefix_p1(const float* __restrict__ kb,
                                                 float* __restrict__ cs) {
    int ch = blockIdx.x;
    int col = blockIdx.y * 256 + threadIdx.x;
    const float* p = kb + (size_t)(ch * 32) * D_DIM + col;
    float acc = 0.f;
    #pragma unroll
    for (int r = 0; r < 32; r++) acc += p[(size_t)r * D_DIM];
    cs[(size_t)ch * D_DIM + col] = acc;
}
__global__ void __launch_bounds__(1024) prefix_p2(float* __restrict__ cs) {
    int col = threadIdx.x;  // 1024 cols
    float run = 0.f;
    #pragma unroll 8
    for (int ch = 0; ch < 64; ch++) {
        size_t i = (size_t)ch * D_DIM + col;
        float t = cs[i];
        cs[i] = run;        // exclusive
        run += t;
    }
}
__global__ void __launch_bounds__(256) prefix_p3(const float* __restrict__ kb,
                                                 const float* __restrict__ cs,
                                                 float* __restrict__ pkb) {
    int ch = blockIdx.x;
    int col = blockIdx.y * 256 + threadIdx.x;
    float acc = cs[(size_t)ch * D_DIM + col];
    const float* p = kb + (size_t)(ch * 32) * D_DIM + col;
    float* o = pkb + (size_t)(ch * 32) * D_DIM + col;
    #pragma unroll
    for (int r = 0; r < 32; r++) {
        acc += p[(size_t)r * D_DIM];
        o[(size_t)r * D_DIM] = acc;
    }
}

// ---------------- sb values: sbv[s,h] = 0.125 * qb[s,h,:] . pkb[s,h,:] ----------
__global__ void __launch_bounds__(512) sb_kernel(const float* __restrict__ qb,
                                                 const float* __restrict__ pkb,
                                                 float* __restrict__ sbv) {
    int s = blockIdx.x;
    int h = threadIdx.x >> 5;
    int lane = threadIdx.x & 31;
    size_t off = (size_t)s * D_DIM + h * 64;
    float v = qb[off + lane] * pkb[off + lane] +
              qb[off + lane + DHALF] * pkb[off + lane + DHALF];
    #pragma unroll
    for (int o = 16; o; o >>= 1) v += __shfl_xor_sync(0xffffffffu, v, o);
    if (lane == 0) sbv[s * H_N + h] = 0.125f * v;
}

// ---------------- MMA flash attention: 64 q-rows/block, 8 warps ----------------
// Smem (dynamic): Qs/Ks/Ps [64][68] tf32, Vs [64][72] tf32, red_m/red_l [2][64].
#define QSTR 68
#define VSTR 72
#define ATT_SMEM ((3 * 64 * QSTR + 64 * VSTR + 256) * 4)

__global__ void __launch_bounds__(256) attn_mma_kernel(
    const float* __restrict__ q, const float* __restrict__ k, const float* __restrict__ v,
    const float* __restrict__ sbv, const float* __restrict__ l2sp, float* __restrict__ y)
{
    extern __shared__ uint32_t sm[];
    uint32_t (*Qs)[QSTR] = reinterpret_cast<uint32_t(*)[QSTR]>(sm);
    uint32_t (*Ks)[QSTR] = reinterpret_cast<uint32_t(*)[QSTR]>(sm + 64 * QSTR);
    uint32_t (*Ps)[QSTR] = reinterpret_cast<uint32_t(*)[QSTR]>(sm + 2 * 64 * QSTR);
    uint32_t (*Vs)[VSTR] = reinterpret_cast<uint32_t(*)[VSTR]>(sm + 3 * 64 * QSTR);
    float* red_m = reinterpret_cast<float*>(sm + 3 * 64 * QSTR + 64 * VSTR);  // [2][64]
    float* red_l = red_m + 128;                                               // [2][64]

    int h = blockIdx.y;
    int q0 = blockIdx.x * 64;
    int tid = threadIdx.x;
    int lane = tid & 31, warp = tid >> 5;
    int wm = warp >> 1;        // 0..3 : 16-row slice
    int wn = warp & 1;         // 0..1 : 32-col slice
    int lr = lane >> 2;        // 0..7
    int lc = lane & 3;         // 0..3

    // stage Q tile (tf32)
    {
        int r = tid >> 2, c0 = (tid & 3) * 16;
        const float* src = q + (size_t)(q0 + r) * D_DIM + h * 64 + c0;
        #pragma unroll
        for (int j = 0; j < 4; j++) {
            float4 f = *reinterpret_cast<const float4*>(src + j * 4);
            Qs[r][c0 + j * 4 + 0] = f2tf(f.x);
            Qs[r][c0 + j * 4 + 1] = f2tf(f.y);
            Qs[r][c0 + j * 4 + 2] = f2tf(f.z);
            Qs[r][c0 + j * 4 + 3] = f2tf(f.w);
        }
    }

    float m0 = -1e30f, m1 = -1e30f, l0 = 0.f, l1 = 0.f;
    float o[4][4];
    #pragma unroll
    for (int ni = 0; ni < 4; ni++)
        #pragma unroll
        for (int j = 0; j < 4; j++) o[ni][j] = 0.f;

    int row0 = wm * 16 + lr;       // local row (0..63)
    int row1 = row0 + 8;
    int nt = blockIdx.x + 1;

    for (int kt = 0; kt < nt; kt++) {
        int kbase = kt * 64;
        __syncthreads();   // prev tile's phase-2 reads done (and Q staged, 1st iter)
        {
            int r = tid >> 2, c0 = (tid & 3) * 16;
            const float* ksrc = k + (size_t)(kbase + r) * D_DIM + h * 64 + c0;
            const float* vsrc = v + (size_t)(kbase + r) * D_DIM + h * 64 + c0;
            #pragma unroll
            for (int j = 0; j < 4; j++) {
                float4 f = *reinterpret_cast<const float4*>(ksrc + j * 4);
                Ks[r][c0 + j * 4 + 0] = f2tf(f.x);
                Ks[r][c0 + j * 4 + 1] = f2tf(f.y);
                Ks[r][c0 + j * 4 + 2] = f2tf(f.z);
                Ks[r][c0 + j * 4 + 3] = f2tf(f.w);
                float4 g = *reinterpret_cast<const float4*>(vsrc + j * 4);
                Vs[r][c0 + j * 4 + 0] = f2tf(g.x);
                Vs[r][c0 + j * 4 + 1] = f2tf(g.y);
                Vs[r][c0 + j * 4 + 2] = f2tf(g.z);
                Vs[r][c0 + j * 4 + 3] = f2tf(g.w);
            }
        }
        __syncthreads();

        // phase 1: S = Q . K^T   (warp: rows wm*16+16, cols wn*32+32)
        float s[4][4];
        #pragma unroll
        for (int ni = 0; ni < 4; ni++)
            #pragma unroll
            for (int j = 0; j < 4; j++) s[ni][j] = 0.f;
        #pragma unroll
        for (int ks = 0; ks < 8; ks++) {
            int kc = ks * 8 + lc;
            uint32_t af[4];
            af[0] = Qs[row0][kc];
            af[1] = Qs[row1][kc];
            af[2] = Qs[row0][kc + 4];
            af[3] = Qs[row1][kc + 4];
            #pragma unroll
            for (int ni = 0; ni < 4; ni++) {
                int c = wn * 32 + ni * 8 + lr;     // k-position (B stored [n][k])
                uint32_t bf[2];
                bf[0] = Ks[c][kc];
                bf[1] = Ks[c][kc + 4];
                MMA_TF32(s[ni], af, bf);
            }
        }
        // causal mask (diagonal tile only: kbase == q0)
        if (kt == nt - 1) {
            #pragma unroll
            for (int ni = 0; ni < 4; ni++) {
                int cbase = wn * 32 + ni * 8 + lc * 2;
                #pragma unroll
                for (int j = 0; j < 4; j++) {
                    int row = (j < 2) ? row0 : row1;
                    int col = cbase + (j & 1);
                    if (col > row) s[ni][j] = -1e30f;
                }
            }
        }
        // row max over this warp's 32 cols
        float mx0 = -1e30f, mx1 = -1e30f;
        #pragma unroll
        for (int ni = 0; ni < 4; ni++) {
            mx0 = fmaxf(mx0, fmaxf(s[ni][0], s[ni][1]));
            mx1 = fmaxf(mx1, fmaxf(s[ni][2], s[ni][3]));
        }
        mx0 = fmaxf(mx0, __shfl_xor_sync(0xffffffffu, mx0, 1));
        mx0 = fmaxf(mx0, __shfl_xor_sync(0xffffffffu, mx0, 2));
        mx1 = fmaxf(mx1, __shfl_xor_sync(0xffffffffu, mx1, 1));
        mx1 = fmaxf(mx1, __shfl_xor_sync(0xffffffffu, mx1, 2));
        if (lc == 0) {
            red_m[wn * 64 + row0] = mx0;
            red_m[wn * 64 + row1] = mx1;
        }
        __syncthreads();
        float mn0 = fmaxf(m0, fmaxf(red_m[row0], red_m[64 + row0]));
        float mn1 = fmaxf(m1, fmaxf(red_m[row1], red_m[64 + row1]));
        float corr0 = __expf(m0 - mn0);
        float corr1 = __expf(m1 - mn1);
        // p = exp(s - m); partial row sums; stage P (tf32)
        float ls0 = 0.f, ls1 = 0.f;
        #pragma unroll
        for (int ni = 0; ni < 4; ni++) {
            int cbase = wn * 32 + ni * 8 + lc * 2;
            float p0 = __expf(s[ni][0] - mn0);
            float p1 = __expf(s[ni][1] - mn0);
            float p2 = __expf(s[ni][2] - mn1);
            float p3 = __expf(s[ni][3] - mn1);
            ls0 += p0 + p1;
            ls1 += p2 + p3;
            Ps[row0][cbase]     = f2tf(p0);
            Ps[row0][cbase + 1] = f2tf(p1);
            Ps[row1][cbase]     = f2tf(p2);
            Ps[row1][cbase + 1] = f2tf(p3);
        }
        ls0 += __shfl_xor_sync(0xffffffffu, ls0, 1);
        ls0 += __shfl_xor_sync(0xffffffffu, ls0, 2);
        ls1 += __shfl_xor_sync(0xffffffffu, ls1, 1);
        ls1 += __shfl_xor_sync(0xffffffffu, ls1, 2);
        if (lc == 0) {
            red_l[wn * 64 + row0] = ls0;
            red_l[wn * 64 + row1] = ls1;
        }
        __syncthreads();
        l0 = l0 * corr0 + red_l[row0] + red_l[64 + row0];
        l1 = l1 * corr1 + red_l[row1] + red_l[64 + row1];
        m0 = mn0;
        m1 = mn1;
        // rescale running O, then O += P . V
        #pragma unroll
        for (int ni = 0; ni < 4; ni++) {
            o[ni][0] *= corr0;
            o[ni][1] *= corr0;
            o[ni][2] *= corr1;
            o[ni][3] *= corr1;
        }
        #pragma unroll
        for (int ks = 0; ks < 8; ks++) {
            int kc = ks * 8 + lc;
            uint32_t af[4];
            af[0] = Ps[row0][kc];
            af[1] = Ps[row1][kc];
            af[2] = Ps[row0][kc + 4];
            af[3] = Ps[row1][kc + 4];
            #pragma unroll
            for (int ni = 0; ni < 4; ni++) {
                int cd = wn * 32 + ni * 8 + lr;    // output dim (B = V stored [k][n])
                uint32_t bf[2];
                bf[0] = Vs[kc][cd];
                bf[1] = Vs[kc + 4][cd];
                MMA_TF32(o[ni], af, bf);
            }
        }
    }

    // epilogue: y = l2s * O / l + sb(row)
    float l2sv = l2sp[0];
    float inv0 = l2sv / l0;
    float inv1 = l2sv / l1;
    int g0 = q0 + row0, g1 = q0 + row1;
    float sb0 = sbv[g0 * H_N + h];
    float sb1 = sbv[g1 * H_N + h];
    #pragma unroll
    for (int ni = 0; ni < 4; ni++) {
        int col = h * 64 + wn * 32 + ni * 8 + lc * 2;
        float2 r0v = make_float2(o[ni][0] * inv0 + sb0, o[ni][1] * inv0 + sb0);
        float2 r1v = make_float2(o[ni][2] * inv1 + sb1, o[ni][3] * inv1 + sb1);
        *reinterpret_cast<float2*>(&y[(size_t)g0 * D_DIM + col]) = r0v;
        *reinterpret_cast<float2*>(&y[(size_t)g1 * D_DIM + col]) = r1v;
    }
}

// ---------------- SwiGLU ----------------
__global__ void __launch_bounds__(256) swiglu_kernel(const float* __restrict__ u,
                                                     float* __restrict__ fm) {
    int i = blockIdx.x * blockDim.x + threadIdx.x;
    int e = i * 4;
    int row = e >> 12;
    int col = e & 4095;
    float4 xp = *reinterpret_cast<const float4*>(&u[(size_t)row * FUSEDW + col]);
    float4 g  = *reinterpret_cast<const float4*>(&u[(size_t)row * FUSEDW + FF_IN + col]);
    float4 o;
    o.x = (g.x / (1.f + __expf(-g.x))) * xp.x;
    o.y = (g.y / (1.f + __expf(-g.y))) * xp.y;
    o.z = (g.z / (1.f + __expf(-g.z))) * xp.z;
    o.w = (g.w / (1.f + __expf(-g.w))) * xp.w;
    *reinterpret_cast<float4*>(&fm[(size_t)row * FF_IN + col]) = o;
}

// ---------------- launch ----------------
extern "C" void kernel_launch(void* const* d_in, const int* in_sizes, int n_in,
                              void* d_out, int out_size) {
    const float* h_states = (const float*)d_in[0];
    const float* Wq  = (const float*)d_in[1];
    const float* Wk  = (const float*)d_in[2];
    const float* Wv  = (const float*)d_in[3];
    const float* Wqb = (const float*)d_in[4];
    const float* Wkb = (const float*)d_in[5];
    const float* Wo  = (const float*)d_in[6];
    const float* bo  = (const float*)d_in[7];
    const float* W1  = (const float*)d_in[8];
    const float* b1  = (const float*)d_in[9];
    const float* W2  = (const float*)d_in[10];
    const float* b2  = (const float*)d_in[11];
    const float* lam = (const float*)d_in[12];
    const float* l2s = (const float*)d_in[13];
    float* out = (float*)d_out;

    float *x, *q, *k, *v, *qb, *kb, *pkb, *cs, *sbv, *y, *ao, *u, *fm;
    cudaGetSymbolAddress((void**)&x,  g_x);
    cudaGetSymbolAddress((void**)&q,  g_q);
    cudaGetSymbolAddress((void**)&k,  g_k);
    cudaGetSymbolAddress((void**)&v,  g_v);
    cudaGetSymbolAddress((void**)&qb, g_qb);
    cudaGetSymbolAddress((void**)&kb, g_kb);
    cudaGetSymbolAddress((void**)&pkb, g_pkb);
    cudaGetSymbolAddress((void**)&cs, g_cs);
    cudaGetSymbolAddress((void**)&sbv, g_sb);
    cudaGetSymbolAddress((void**)&y,  g_y);
    cudaGetSymbolAddress((void**)&ao, g_ao);
    cudaGetSymbolAddress((void**)&u,  g_u);
    cudaGetSymbolAddress((void**)&fm, g_fm);

    cudaFuncSetAttribute(attn_mma_kernel,
                         cudaFuncAttributeMaxDynamicSharedMemorySize, ATT_SMEM);

    // 1. RMSNorm
    rmsnorm_kernel<<<S_LEN, 256>>>(h_states, x);

    // 2. five projections in one launch
    dim3 gP(D_DIM / 128, S_LEN / 128, 5);
    gemm_tf32_kernel<<<gP, 256>>>(x, Wq, Wk, Wv, Wqb, Wkb, q, k, v, qb, kb,
                                  S_LEN, D_DIM, D_DIM,
                                  nullptr, nullptr, nullptr, nullptr);

    // 3. l2norm + RoPE in-place
    ropenorm_kernel<<<dim3(S_LEN, 8), 256>>>(q, k, qb, kb);

    // 4. parallel prefix of kb; 5. sb values
    prefix_p1<<<dim3(64, 4), 256>>>(kb, cs);
    prefix_p2<<<1, 1024>>>(cs);
    prefix_p3<<<dim3(64, 4), 256>>>(kb, cs, pkb);
    sb_kernel<<<S_LEN, 512>>>(qb, pkb, sbv);

    // 6. MMA flash attention
    attn_mma_kernel<<<dim3(S_LEN / 64, H_N), 256, ATT_SMEM>>>(q, k, v, sbv, l2s, y);

    // 7. attn_out = y @ Wo + bo
    dim3 g1(D_DIM / 128, S_LEN / 128, 1);
    gemm_tf32_kernel<<<g1, 256>>>(y, Wo, nullptr, nullptr, nullptr, nullptr,
                                  ao, nullptr, nullptr, nullptr, nullptr,
                                  S_LEN, D_DIM, D_DIM,
                                  bo, nullptr, nullptr, nullptr);

    // 8. u = x @ W1 + b1
    dim3 g2(FUSEDW / 128, S_LEN / 128, 1);
    gemm_tf32_kernel<<<g2, 256>>>(x, W1, nullptr, nullptr, nullptr, nullptr,
                                  u, nullptr, nullptr, nullptr, nullptr,
                                  S_LEN, FUSEDW, D_DIM,
                                  b1, nullptr, nullptr, nullptr);

    // 9. SwiGLU
    swiglu_kernel<<<(S_LEN * FF_IN / 4) / 256, 256>>>(u, fm);

    // 10. out = fm @ W2 + b2 + attn_out + lambda * h_states
    gemm_tf32_kernel<<<g1, 256>>>(fm, W2, nullptr, nullptr, nullptr, nullptr,
                                  out, nullptr, nullptr, nullptr, nullptr,
                                  S_LEN, D_DIM, FF_IN,
                                  b2, ao, h_states, lam);
}

// round 6
// speedup vs baseline: 5.0917x; 1.1301x over previous
#include <cuda_runtime.h>
#include <cuda_bf16.h>
#include <cstdint>

#define S_LEN 2048
#define D_DIM 1024
#define H_N 16
#define DHALF 32
#define FF_IN 4096
#define FUSEDW 8192

// ---------------- scratch (static device globals; no allocs) ----------------
__device__ float g_x  [S_LEN * D_DIM];
__device__ float g_q  [S_LEN * D_DIM];
__device__ float g_k  [S_LEN * D_DIM];
__device__ float g_v  [S_LEN * D_DIM];
__device__ float g_qb [S_LEN * D_DIM];
__device__ float g_kb [S_LEN * D_DIM];
__device__ float g_pkb[S_LEN * D_DIM];
__device__ float g_cs [64 * D_DIM];
__device__ float g_sb [S_LEN * H_N];
__device__ float g_y  [S_LEN * D_DIM];
__device__ float g_ao [S_LEN * D_DIM];
__device__ float g_u  [S_LEN * FUSEDW];
__device__ float g_fm [S_LEN * FF_IN];
// tf32-rounded weight copies
__device__ float g_wq [D_DIM * D_DIM];
__device__ float g_wk [D_DIM * D_DIM];
__device__ float g_wv [D_DIM * D_DIM];
__device__ float g_wqb[D_DIM * D_DIM];
__device__ float g_wkb[D_DIM * D_DIM];
__device__ float g_wo [D_DIM * D_DIM];
__device__ float g_w1 [D_DIM * FUSEDW];
__device__ float g_w2 [FF_IN * D_DIM];

// ---------------- helpers ----------------
__device__ __forceinline__ uint32_t f2tf(float f) {
    uint32_t u;
    asm("cvt.rna.tf32.f32 %0, %1;" : "=r"(u) : "f"(f));
    return u;
}
__device__ __forceinline__ float tfround(float f) { return __uint_as_float(f2tf(f)); }
__device__ __forceinline__ uint32_t smem_u32(const void* p) {
    uint32_t a;
    asm("{ .reg .u64 t; cvta.to.shared.u64 t, %1; cvt.u32.u64 %0, t; }" : "=r"(a) : "l"(p));
    return a;
}

#define MMA_TF32(d, a, b)                                                     \
    asm volatile(                                                             \
        "mma.sync.aligned.m16n8k8.row.col.f32.tf32.tf32.f32 "                 \
        "{%0,%1,%2,%3}, {%4,%5,%6,%7}, {%8,%9}, {%0,%1,%2,%3};"               \
        : "+f"(d[0]), "+f"(d[1]), "+f"(d[2]), "+f"(d[3])                      \
        : "r"(a[0]), "r"(a[1]), "r"(a[2]), "r"(a[3]), "r"(b[0]), "r"(b[1]))

// ---------------- weight tf32 pre-round ----------------
__global__ void __launch_bounds__(256) cvt_tf32_kernel(const float* __restrict__ src,
                                                       float* __restrict__ dst, int n4) {
    int i = blockIdx.x * 256 + threadIdx.x;
    if (i >= n4) return;
    float4 v = reinterpret_cast<const float4*>(src)[i];
    v.x = tfround(v.x); v.y = tfround(v.y); v.z = tfround(v.z); v.w = tfround(v.w);
    reinterpret_cast<float4*>(dst)[i] = v;
}

// ---------------- RMSNorm (emits tf32-rounded x) ----------------
__global__ void __launch_bounds__(256) rmsnorm_kernel(const float* __restrict__ h,
                                                      float* __restrict__ x) {
    int row = blockIdx.x;
    int t = threadIdx.x;
    const float4* hr = reinterpret_cast<const float4*>(h + (size_t)row * D_DIM);
    float4 a = hr[t];
    float ss = a.x * a.x + a.y * a.y + a.z * a.z + a.w * a.w;
    __shared__ float red[8];
    #pragma unroll
    for (int off = 16; off; off >>= 1) ss += __shfl_xor_sync(0xffffffffu, ss, off);
    if ((t & 31) == 0) red[t >> 5] = ss;
    __syncthreads();
    float tot = red[0] + red[1] + red[2] + red[3] + red[4] + red[5] + red[6] + red[7];
    float r = rsqrtf(tot * (1.0f / 1024.0f) + 1.1920929e-7f);
    float4 o = make_float4(tfround(a.x * r), tfround(a.y * r),
                           tfround(a.z * r), tfround(a.w * r));
    reinterpret_cast<float4*>(x + (size_t)row * D_DIM)[t] = o;
}

// ---------------- cp.async tf32 GEMM ----------------
// C[M,N] = A@B (+bias +add0 +lam*add1). Tile 128x128, BK=32, 256 thr, 8 warps
// (warp tile 32x64). Inputs pre-rounded to tf32. 2-stage cp.async pipeline.
#define A_STR 36
#define B_STR 136
#define GEMM_SMEM ((2 * 128 * A_STR + 2 * 32 * B_STR) * 4)

__global__ void __launch_bounds__(256) gemm_mma_kernel(
    const float* __restrict__ A,
    const float* __restrict__ B0, const float* __restrict__ B1,
    const float* __restrict__ B2, const float* __restrict__ B3,
    const float* __restrict__ B4,
    float* __restrict__ C0, float* __restrict__ C1,
    float* __restrict__ C2, float* __restrict__ C3,
    float* __restrict__ C4,
    int M, int N, int K,
    const float* __restrict__ bias,
    const float* __restrict__ add0,
    const float* __restrict__ add1,
    const float* __restrict__ lamPtr)
{
    int z = blockIdx.z;
    const float* B = (z == 0) ? B0 : (z == 1) ? B1 : (z == 2) ? B2 : (z == 3) ? B3 : B4;
    float* C = (z == 0) ? C0 : (z == 1) ? C1 : (z == 2) ? C2 : (z == 3) ? C3 : C4;

    extern __shared__ float sm[];
    float (*As)[128][A_STR] = reinterpret_cast<float(*)[128][A_STR]>(sm);
    float (*Bs)[32][B_STR]  = reinterpret_cast<float(*)[32][B_STR]>(sm + 2 * 128 * A_STR);

    int tid = threadIdx.x;
    int lane = tid & 31;
    int warp = tid >> 5;
    int warpM = warp >> 1;
    int warpN = warp & 1;
    int lr = lane >> 2;
    int lc = lane & 3;
    int bm = blockIdx.y * 128;
    int bn = blockIdx.x * 128;

    // copy index precompute
    int car = (tid >> 3);            // A row  (0..31 step over i)
    int cac = (tid & 7) * 4;         // A col
    int cbr = (tid >> 5);            // B row
    int cbc = (tid & 31) * 4;        // B col

    float acc[2][8][4];
    #pragma unroll
    for (int mi = 0; mi < 2; mi++)
        #pragma unroll
        for (int ni = 0; ni < 8; ni++)
            #pragma unroll
            for (int r = 0; r < 4; r++) acc[mi][ni][r] = 0.f;

    int NT = K / 32;

    auto issue = [&](int buf, int t) {
        #pragma unroll
        for (int i = 0; i < 4; i++) {
            int r = car + i * 32;
            const float* g = A + (size_t)(bm + r) * K + t * 32 + cac;
            uint32_t s = smem_u32(&As[buf][r][cac]);
            asm volatile("cp.async.ca.shared.global [%0], [%1], 16;" :: "r"(s), "l"(g));
        }
        #pragma unroll
        for (int i = 0; i < 4; i++) {
            int r = cbr + i * 8;
            const float* g = B + (size_t)(t * 32 + r) * N + bn + cbc;
            uint32_t s = smem_u32(&Bs[buf][r][cbc]);
            asm volatile("cp.async.ca.shared.global [%0], [%1], 16;" :: "r"(s), "l"(g));
        }
        asm volatile("cp.async.commit_group;" ::: "memory");
    };

    issue(0, 0);
    for (int t = 0; t < NT; t++) {
        int buf = t & 1;
        if (t + 1 < NT) {
            issue(buf ^ 1, t + 1);
            asm volatile("cp.async.wait_group 1;" ::: "memory");
        } else {
            asm volatile("cp.async.wait_group 0;" ::: "memory");
        }
        __syncthreads();
        #pragma unroll
        for (int ks = 0; ks < 4; ks++) {
            int kc = ks * 8 + lc;
            uint32_t af[2][4], bf[8][2];
            #pragma unroll
            for (int mi = 0; mi < 2; mi++) {
                int r = warpM * 32 + mi * 16 + lr;
                af[mi][0] = __float_as_uint(As[buf][r][kc]);
                af[mi][1] = __float_as_uint(As[buf][r + 8][kc]);
                af[mi][2] = __float_as_uint(As[buf][r][kc + 4]);
                af[mi][3] = __float_as_uint(As[buf][r + 8][kc + 4]);
            }
            #pragma unroll
            for (int ni = 0; ni < 8; ni++) {
                int c = warpN * 64 + ni * 8 + lr;
                bf[ni][0] = __float_as_uint(Bs[buf][kc][c]);
                bf[ni][1] = __float_as_uint(Bs[buf][kc + 4][c]);
            }
            #pragma unroll
            for (int mi = 0; mi < 2; mi++)
                #pragma unroll
                for (int ni = 0; ni < 8; ni++)
                    MMA_TF32(acc[mi][ni], af[mi], bf[ni]);
        }
        __syncthreads();
    }

    float lam = lamPtr ? lamPtr[0] : 0.f;
    #pragma unroll
    for (int mi = 0; mi < 2; mi++) {
        int r0 = bm + warpM * 32 + mi * 16 + lr;
        #pragma unroll
        for (int ni = 0; ni < 8; ni++) {
            int c0 = bn + warpN * 64 + ni * 8 + lc * 2;
            #pragma unroll
            for (int half = 0; half < 2; half++) {
                int r = r0 + half * 8;
                float v0 = acc[mi][ni][half * 2 + 0];
                float v1 = acc[mi][ni][half * 2 + 1];
                if (bias) { v0 += bias[c0]; v1 += bias[c0 + 1]; }
                size_t idx = (size_t)r * N + c0;
                if (add0) { v0 += add0[idx]; v1 += add0[idx + 1]; }
                if (add1) { v0 += lam * add1[idx]; v1 += lam * add1[idx + 1]; }
                C[idx]     = v0;
                C[idx + 1] = v1;
            }
        }
    }
}

// ---------------- l2norm + RoPE ----------------
__global__ void __launch_bounds__(256) ropenorm_kernel(float* q, float* k, float* qb, float* kb) {
    int s = blockIdx.x;
    int warp = threadIdx.x >> 5;
    int lane = threadIdx.x & 31;
    int idx = blockIdx.y * 8 + warp;
    int h = idx & 15;
    int a = idx >> 4;
    float* arr = (a == 0) ? q : (a == 1) ? k : (a == 2) ? qb : kb;
    float* p = arr + (size_t)s * D_DIM + h * 64;
    float x1 = p[lane];
    float x2 = p[lane + DHALF];
    float ss = x1 * x1 + x2 * x2;
    #pragma unroll
    for (int off = 16; off; off >>= 1) ss += __shfl_xor_sync(0xffffffffu, ss, off);
    float n = fmaxf(sqrtf(ss), 1e-12f);
    float inv = 1.f / n;
    x1 *= inv;
    x2 *= inv;
    float invfreq = powf(1000.0f, -(float)lane * (1.0f / 32.0f));
    float fr = (float)s * invfreq;
    float c  = __bfloat162float(__float2bfloat16(cosf(fr)));
    float sn = __bfloat162float(__float2bfloat16(sinf(fr)));
    p[lane]         = x1 * c + x2 * sn;
    p[lane + DHALF] = -x1 * sn + x2 * c;
}

// ---------------- parallel prefix sum of kb ----------------
__global__ void __launch_bounds__(256) prefix_p1(const float* __restrict__ kb,
                                                 float* __restrict__ cs) {
    int ch = blockIdx.x;
    int col = blockIdx.y * 256 + threadIdx.x;
    const float* p = kb + (size_t)(ch * 32) * D_DIM + col;
    float acc = 0.f;
    #pragma unroll
    for (int r = 0; r < 32; r++) acc += p[(size_t)r * D_DIM];
    cs[(size_t)ch * D_DIM + col] = acc;
}
__global__ void __launch_bounds__(1024) prefix_p2(float* __restrict__ cs) {
    int col = threadIdx.x;
    float run = 0.f;
    #pragma unroll 8
    for (int ch = 0; ch < 64; ch++) {
        size_t i = (size_t)ch * D_DIM + col;
        float t = cs[i];
        cs[i] = run;
        run += t;
    }
}
__global__ void __launch_bounds__(256) prefix_p3(const float* __restrict__ kb,
                                                 const float* __restrict__ cs,
                                                 float* __restrict__ pkb) {
    int ch = blockIdx.x;
    int col = blockIdx.y * 256 + threadIdx.x;
    float acc = cs[(size_t)ch * D_DIM + col];
    const float* p = kb + (size_t)(ch * 32) * D_DIM + col;
    float* o = pkb + (size_t)(ch * 32) * D_DIM + col;
    #pragma unroll
    for (int r = 0; r < 32; r++) {
        acc += p[(size_t)r * D_DIM];
        o[(size_t)r * D_DIM] = acc;
    }
}

// ---------------- sb values ----------------
__global__ void __launch_bounds__(512) sb_kernel(const float* __restrict__ qb,
                                                 const float* __restrict__ pkb,
                                                 float* __restrict__ sbv) {
    int s = blockIdx.x;
    int h = threadIdx.x >> 5;
    int lane = threadIdx.x & 31;
    size_t off = (size_t)s * D_DIM + h * 64;
    float v = qb[off + lane] * pkb[off + lane] +
              qb[off + lane + DHALF] * pkb[off + lane + DHALF];
    #pragma unroll
    for (int o = 16; o; o >>= 1) v += __shfl_xor_sync(0xffffffffu, v, o);
    if (lane == 0) sbv[s * H_N + h] = 0.125f * v;
}

// ---------------- MMA flash attention (proven; y emitted tf32-rounded) --------
#define QSTR 68
#define VSTR 72
#define ATT_SMEM ((3 * 64 * QSTR + 64 * VSTR + 256) * 4)

__global__ void __launch_bounds__(256) attn_mma_kernel(
    const float* __restrict__ q, const float* __restrict__ k, const float* __restrict__ v,
    const float* __restrict__ sbv, const float* __restrict__ l2sp, float* __restrict__ y)
{
    extern __shared__ uint32_t sma[];
    uint32_t (*Qs)[QSTR] = reinterpret_cast<uint32_t(*)[QSTR]>(sma);
    uint32_t (*Ks)[QSTR] = reinterpret_cast<uint32_t(*)[QSTR]>(sma + 64 * QSTR);
    uint32_t (*Ps)[QSTR] = reinterpret_cast<uint32_t(*)[QSTR]>(sma + 2 * 64 * QSTR);
    uint32_t (*Vs)[VSTR] = reinterpret_cast<uint32_t(*)[VSTR]>(sma + 3 * 64 * QSTR);
    float* red_m = reinterpret_cast<float*>(sma + 3 * 64 * QSTR + 64 * VSTR);
    float* red_l = red_m + 128;

    int h = blockIdx.y;
    int q0 = blockIdx.x * 64;
    int tid = threadIdx.x;
    int lane = tid & 31, warp = tid >> 5;
    int wm = warp >> 1;
    int wn = warp & 1;
    int lr = lane >> 2;
    int lc = lane & 3;

    {
        int r = tid >> 2, c0 = (tid & 3) * 16;
        const float* src = q + (size_t)(q0 + r) * D_DIM + h * 64 + c0;
        #pragma unroll
        for (int j = 0; j < 4; j++) {
            float4 f = *reinterpret_cast<const float4*>(src + j * 4);
            Qs[r][c0 + j * 4 + 0] = f2tf(f.x);
            Qs[r][c0 + j * 4 + 1] = f2tf(f.y);
            Qs[r][c0 + j * 4 + 2] = f2tf(f.z);
            Qs[r][c0 + j * 4 + 3] = f2tf(f.w);
        }
    }

    float m0 = -1e30f, m1 = -1e30f, l0 = 0.f, l1 = 0.f;
    float o[4][4];
    #pragma unroll
    for (int ni = 0; ni < 4; ni++)
        #pragma unroll
        for (int j = 0; j < 4; j++) o[ni][j] = 0.f;

    int row0 = wm * 16 + lr;
    int row1 = row0 + 8;
    int nt = blockIdx.x + 1;

    for (int kt = 0; kt < nt; kt++) {
        int kbase = kt * 64;
        __syncthreads();
        {
            int r = tid >> 2, c0 = (tid & 3) * 16;
            const float* ksrc = k + (size_t)(kbase + r) * D_DIM + h * 64 + c0;
            const float* vsrc = v + (size_t)(kbase + r) * D_DIM + h * 64 + c0;
            #pragma unroll
            for (int j = 0; j < 4; j++) {
                float4 f = *reinterpret_cast<const float4*>(ksrc + j * 4);
                Ks[r][c0 + j * 4 + 0] = f2tf(f.x);
                Ks[r][c0 + j * 4 + 1] = f2tf(f.y);
                Ks[r][c0 + j * 4 + 2] = f2tf(f.z);
                Ks[r][c0 + j * 4 + 3] = f2tf(f.w);
                float4 g = *reinterpret_cast<const float4*>(vsrc + j * 4);
                Vs[r][c0 + j * 4 + 0] = f2tf(g.x);
                Vs[r][c0 + j * 4 + 1] = f2tf(g.y);
                Vs[r][c0 + j * 4 + 2] = f2tf(g.z);
                Vs[r][c0 + j * 4 + 3] = f2tf(g.w);
            }
        }
        __syncthreads();

        float s[4][4];
        #pragma unroll
        for (int ni = 0; ni < 4; ni++)
            #pragma unroll
            for (int j = 0; j < 4; j++) s[ni][j] = 0.f;
        #pragma unroll
        for (int ks = 0; ks < 8; ks++) {
            int kc = ks * 8 + lc;
            uint32_t af[4];
            af[0] = Qs[row0][kc];
            af[1] = Qs[row1][kc];
            af[2] = Qs[row0][kc + 4];
            af[3] = Qs[row1][kc + 4];
            #pragma unroll
            for (int ni = 0; ni < 4; ni++) {
                int c = wn * 32 + ni * 8 + lr;
                uint32_t bf[2];
                bf[0] = Ks[c][kc];
                bf[1] = Ks[c][kc + 4];
                MMA_TF32(s[ni], af, bf);
            }
        }
        if (kt == nt - 1) {
            #pragma unroll
            for (int ni = 0; ni < 4; ni++) {
                int cbase = wn * 32 + ni * 8 + lc * 2;
                #pragma unroll
                for (int j = 0; j < 4; j++) {
                    int row = (j < 2) ? row0 : row1;
                    int col = cbase + (j & 1);
                    if (col > row) s[ni][j] = -1e30f;
                }
            }
        }
        float mx0 = -1e30f, mx1 = -1e30f;
        #pragma unroll
        for (int ni = 0; ni < 4; ni++) {
            mx0 = fmaxf(mx0, fmaxf(s[ni][0], s[ni][1]));
            mx1 = fmaxf(mx1, fmaxf(s[ni][2], s[ni][3]));
        }
        mx0 = fmaxf(mx0, __shfl_xor_sync(0xffffffffu, mx0, 1));
        mx0 = fmaxf(mx0, __shfl_xor_sync(0xffffffffu, mx0, 2));
        mx1 = fmaxf(mx1, __shfl_xor_sync(0xffffffffu, mx1, 1));
        mx1 = fmaxf(mx1, __shfl_xor_sync(0xffffffffu, mx1, 2));
        if (lc == 0) {
            red_m[wn * 64 + row0] = mx0;
            red_m[wn * 64 + row1] = mx1;
        }
        __syncthreads();
        float mn0 = fmaxf(m0, fmaxf(red_m[row0], red_m[64 + row0]));
        float mn1 = fmaxf(m1, fmaxf(red_m[row1], red_m[64 + row1]));
        float corr0 = __expf(m0 - mn0);
        float corr1 = __expf(m1 - mn1);
        float ls0 = 0.f, ls1 = 0.f;
        #pragma unroll
        for (int ni = 0; ni < 4; ni++) {
            int cbase = wn * 32 + ni * 8 + lc * 2;
            float p0 = __expf(s[ni][0] - mn0);
            float p1 = __expf(s[ni][1] - mn0);
            float p2 = __expf(s[ni][2] - mn1);
            float p3 = __expf(s[ni][3] - mn1);
            ls0 += p0 + p1;
            ls1 += p2 + p3;
            Ps[row0][cbase]     = f2tf(p0);
            Ps[row0][cbase + 1] = f2tf(p1);
            Ps[row1][cbase]     = f2tf(p2);
            Ps[row1][cbase + 1] = f2tf(p3);
        }
        ls0 += __shfl_xor_sync(0xffffffffu, ls0, 1);
        ls0 += __shfl_xor_sync(0xffffffffu, ls0, 2);
        ls1 += __shfl_xor_sync(0xffffffffu, ls1, 1);
        ls1 += __shfl_xor_sync(0xffffffffu, ls1, 2);
        if (lc == 0) {
            red_l[wn * 64 + row0] = ls0;
            red_l[wn * 64 + row1] = ls1;
        }
        __syncthreads();
        l0 = l0 * corr0 + red_l[row0] + red_l[64 + row0];
        l1 = l1 * corr1 + red_l[row1] + red_l[64 + row1];
        m0 = mn0;
        m1 = mn1;
        #pragma unroll
        for (int ni = 0; ni < 4; ni++) {
            o[ni][0] *= corr0;
            o[ni][1] *= corr0;
            o[ni][2] *= corr1;
            o[ni][3] *= corr1;
        }
        #pragma unroll
        for (int ks = 0; ks < 8; ks++) {
            int kc = ks * 8 + lc;
            uint32_t af[4];
            af[0] = Ps[row0][kc];
            af[1] = Ps[row1][kc];
            af[2] = Ps[row0][kc + 4];
            af[3] = Ps[row1][kc + 4];
            #pragma unroll
            for (int ni = 0; ni < 4; ni++) {
                int cd = wn * 32 + ni * 8 + lr;
                uint32_t bf[2];
                bf[0] = Vs[kc][cd];
                bf[1] = Vs[kc + 4][cd];
                MMA_TF32(o[ni], af, bf);
            }
        }
    }

    float l2sv = l2sp[0];
    float inv0 = l2sv / l0;
    float inv1 = l2sv / l1;
    int g0 = q0 + row0, g1 = q0 + row1;
    float sb0 = sbv[g0 * H_N + h];
    float sb1 = sbv[g1 * H_N + h];
    #pragma unroll
    for (int ni = 0; ni < 4; ni++) {
        int col = h * 64 + wn * 32 + ni * 8 + lc * 2;
        float2 r0v = make_float2(tfround(o[ni][0] * inv0 + sb0),
                                 tfround(o[ni][1] * inv0 + sb0));
        float2 r1v = make_float2(tfround(o[ni][2] * inv1 + sb1),
                                 tfround(o[ni][3] * inv1 + sb1));
        *reinterpret_cast<float2*>(&y[(size_t)g0 * D_DIM + col]) = r0v;
        *reinterpret_cast<float2*>(&y[(size_t)g1 * D_DIM + col]) = r1v;
    }
}

// ---------------- SwiGLU (emits tf32-rounded fm) ----------------
__global__ void __launch_bounds__(256) swiglu_kernel(const float* __restrict__ u,
                                                     float* __restrict__ fm) {
    int i = blockIdx.x * blockDim.x + threadIdx.x;
    int e = i * 4;
    int row = e >> 12;
    int col = e & 4095;
    float4 xp = *reinterpret_cast<const float4*>(&u[(size_t)row * FUSEDW + col]);
    float4 g  = *reinterpret_cast<const float4*>(&u[(size_t)row * FUSEDW + FF_IN + col]);
    float4 o;
    o.x = tfround((g.x / (1.f + __expf(-g.x))) * xp.x);
    o.y = tfround((g.y / (1.f + __expf(-g.y))) * xp.y);
    o.z = tfround((g.z / (1.f + __expf(-g.z))) * xp.z);
    o.w = tfround((g.w / (1.f + __expf(-g.w))) * xp.w);
    *reinterpret_cast<float4*>(&fm[(size_t)row * FF_IN + col]) = o;
}

// ---------------- launch ----------------
extern "C" void kernel_launch(void* const* d_in, const int* in_sizes, int n_in,
                              void* d_out, int out_size) {
    const float* h_states = (const float*)d_in[0];
    const float* Wq  = (const float*)d_in[1];
    const float* Wk  = (const float*)d_in[2];
    const float* Wv  = (const float*)d_in[3];
    const float* Wqb = (const float*)d_in[4];
    const float* Wkb = (const float*)d_in[5];
    const float* Wo  = (const float*)d_in[6];
    const float* bo  = (const float*)d_in[7];
    const float* W1  = (const float*)d_in[8];
    const float* b1  = (const float*)d_in[9];
    const float* W2  = (const float*)d_in[10];
    const float* b2  = (const float*)d_in[11];
    const float* lam = (const float*)d_in[12];
    const float* l2s = (const float*)d_in[13];
    float* out = (float*)d_out;

    float *x, *q, *k, *v, *qb, *kb, *pkb, *cs, *sbv, *y, *ao, *u, *fm;
    float *wq, *wk, *wv, *wqb, *wkb, *wo, *w1, *w2;
    cudaGetSymbolAddress((void**)&x,  g_x);
    cudaGetSymbolAddress((void**)&q,  g_q);
    cudaGetSymbolAddress((void**)&k,  g_k);
    cudaGetSymbolAddress((void**)&v,  g_v);
    cudaGetSymbolAddress((void**)&qb, g_qb);
    cudaGetSymbolAddress((void**)&kb, g_kb);
    cudaGetSymbolAddress((void**)&pkb, g_pkb);
    cudaGetSymbolAddress((void**)&cs, g_cs);
    cudaGetSymbolAddress((void**)&sbv, g_sb);
    cudaGetSymbolAddress((void**)&y,  g_y);
    cudaGetSymbolAddress((void**)&ao, g_ao);
    cudaGetSymbolAddress((void**)&u,  g_u);
    cudaGetSymbolAddress((void**)&fm, g_fm);
    cudaGetSymbolAddress((void**)&wq, g_wq);
    cudaGetSymbolAddress((void**)&wk, g_wk);
    cudaGetSymbolAddress((void**)&wv, g_wv);
    cudaGetSymbolAddress((void**)&wqb, g_wqb);
    cudaGetSymbolAddress((void**)&wkb, g_wkb);
    cudaGetSymbolAddress((void**)&wo, g_wo);
    cudaGetSymbolAddress((void**)&w1, g_w1);
    cudaGetSymbolAddress((void**)&w2, g_w2);

    cudaFuncSetAttribute(attn_mma_kernel,
                         cudaFuncAttributeMaxDynamicSharedMemorySize, ATT_SMEM);
    cudaFuncSetAttribute(gemm_mma_kernel,
                         cudaFuncAttributeMaxDynamicSharedMemorySize, GEMM_SMEM);

    // 0. pre-round all weights to tf32 (numerics identical to in-loop cvt)
    const int DD4 = D_DIM * D_DIM / 4;
    cvt_tf32_kernel<<<(DD4 + 255) / 256, 256>>>(Wq,  wq,  DD4);
    cvt_tf32_kernel<<<(DD4 + 255) / 256, 256>>>(Wk,  wk,  DD4);
    cvt_tf32_kernel<<<(DD4 + 255) / 256, 256>>>(Wv,  wv,  DD4);
    cvt_tf32_kernel<<<(DD4 + 255) / 256, 256>>>(Wqb, wqb, DD4);
    cvt_tf32_kernel<<<(DD4 + 255) / 256, 256>>>(Wkb, wkb, DD4);
    cvt_tf32_kernel<<<(DD4 + 255) / 256, 256>>>(Wo,  wo,  DD4);
    const int W14 = D_DIM * FUSEDW / 4;
    cvt_tf32_kernel<<<(W14 + 255) / 256, 256>>>(W1, w1, W14);
    const int W24 = FF_IN * D_DIM / 4;
    cvt_tf32_kernel<<<(W24 + 255) / 256, 256>>>(W2, w2, W24);

    // 1. RMSNorm (tf32-rounded x)
    rmsnorm_kernel<<<S_LEN, 256>>>(h_states, x);

    // 2. five projections in one launch
    gemm_mma_kernel<<<dim3(D_DIM / 128, S_LEN / 128, 5), 256, GEMM_SMEM>>>(
        x, wq, wk, wv, wqb, wkb, q, k, v, qb, kb,
        S_LEN, D_DIM, D_DIM, nullptr, nullptr, nullptr, nullptr);

    // 3. l2norm + RoPE
    ropenorm_kernel<<<dim3(S_LEN, 8), 256>>>(q, k, qb, kb);

    // 4. prefix of kb; 5. sb values
    prefix_p1<<<dim3(64, 4), 256>>>(kb, cs);
    prefix_p2<<<1, 1024>>>(cs);
    prefix_p3<<<dim3(64, 4), 256>>>(kb, cs, pkb);
    sb_kernel<<<S_LEN, 512>>>(qb, pkb, sbv);

    // 6. MMA flash attention (tf32-rounded y)
    attn_mma_kernel<<<dim3(S_LEN / 64, H_N), 256, ATT_SMEM>>>(q, k, v, sbv, l2s, y);

    // 7. attn_out = y @ Wo + bo
    gemm_mma_kernel<<<dim3(D_DIM / 128, S_LEN / 128, 1), 256, GEMM_SMEM>>>(
        y, wo, nullptr, nullptr, nullptr, nullptr,
        ao, nullptr, nullptr, nullptr, nullptr,
        S_LEN, D_DIM, D_DIM, bo, nullptr, nullptr, nullptr);

    // 8. u = x @ W1 + b1
    gemm_mma_kernel<<<dim3(FUSEDW / 128, S_LEN / 128, 1), 256, GEMM_SMEM>>>(
        x, w1, nullptr, nullptr, nullptr, nullptr,
        u, nullptr, nullptr, nullptr, nullptr,
        S_LEN, FUSEDW, D_DIM, b1, nullptr, nullptr, nullptr);

    // 9. SwiGLU (tf32-rounded fm)
    swiglu_kernel<<<(S_LEN * FF_IN / 4) / 256, 256>>>(u, fm);

    // 10. out = fm @ W2 + b2 + attn_out + lambda * h_states
    gemm_mma_kernel<<<dim3(D_DIM / 128, S_LEN / 128, 1), 256, GEMM_SMEM>>>(
        fm, w2, nullptr, nullptr, nullptr, nullptr,
        out, nullptr, nullptr, nullptr, nullptr,
        S_LEN, D_DIM, FF_IN, b2, ao, h_states, lam);
}

// round 7
// speedup vs baseline: 5.9842x; 1.1753x over previous
#include <cuda_runtime.h>
#include <cuda_bf16.h>
#include <cuda_fp16.h>
#include <cstdint>

#define S_LEN 2048
#define D_DIM 1024
#define H_N 16
#define DHALF 32
#define FF_IN 4096
#define FUSEDW 8192

// ---------------- scratch (static device globals; no allocs) ----------------
__device__ float  g_q  [S_LEN * D_DIM];
__device__ float  g_k  [S_LEN * D_DIM];
__device__ float  g_v  [S_LEN * D_DIM];
__device__ float  g_qb [S_LEN * D_DIM];
__device__ float  g_kb [S_LEN * D_DIM];
__device__ float  g_pkb[S_LEN * D_DIM];
__device__ float  g_cs [64 * D_DIM];
__device__ float  g_sb [S_LEN * H_N];
__device__ float  g_ao [S_LEN * D_DIM];
__device__ float  g_u  [S_LEN * FUSEDW];
// fp16 GEMM operands
__device__ __half g_xh [S_LEN * D_DIM];
__device__ __half g_yh [S_LEN * D_DIM];
__device__ __half g_fmh[S_LEN * FF_IN];
__device__ __half g_wqh [D_DIM * D_DIM];   // transposed [N][K]
__device__ __half g_wkh [D_DIM * D_DIM];
__device__ __half g_wvh [D_DIM * D_DIM];
__device__ __half g_wqbh[D_DIM * D_DIM];
__device__ __half g_wkbh[D_DIM * D_DIM];
__device__ __half g_woh [D_DIM * D_DIM];
__device__ __half g_w1h [FUSEDW * D_DIM];  // [N=8192][K=1024]
__device__ __half g_w2h [D_DIM * FF_IN];   // [N=1024][K=4096]

// ---------------- helpers ----------------
__device__ __forceinline__ uint32_t f2tf(float f) {
    uint32_t u;
    asm("cvt.rna.tf32.f32 %0, %1;" : "=r"(u) : "f"(f));
    return u;
}
__device__ __forceinline__ uint32_t smem_u32(const void* p) {
    uint32_t a;
    asm("{ .reg .u64 t; cvta.to.shared.u64 t, %1; cvt.u32.u64 %0, t; }" : "=r"(a) : "l"(p));
    return a;
}

#define MMA_TF32(d, a, b)                                                     \
    asm volatile(                                                             \
        "mma.sync.aligned.m16n8k8.row.col.f32.tf32.tf32.f32 "                 \
        "{%0,%1,%2,%3}, {%4,%5,%6,%7}, {%8,%9}, {%0,%1,%2,%3};"               \
        : "+f"(d[0]), "+f"(d[1]), "+f"(d[2]), "+f"(d[3])                      \
        : "r"(a[0]), "r"(a[1]), "r"(a[2]), "r"(a[3]), "r"(b[0]), "r"(b[1]))

#define MMA_F16(d, a, b)                                                      \
    asm volatile(                                                             \
        "mma.sync.aligned.m16n8k16.row.col.f32.f16.f16.f32 "                  \
        "{%0,%1,%2,%3}, {%4,%5,%6,%7}, {%8,%9}, {%0,%1,%2,%3};"               \
        : "+f"(d[0]), "+f"(d[1]), "+f"(d[2]), "+f"(d[3])                      \
        : "r"(a[0]), "r"(a[1]), "r"(a[2]), "r"(a[3]), "r"(b[0]), "r"(b[1]))

// ---------------- weight fp16 convert + transpose ----------------
// W [K][N] fp32 -> Wt [N][K] fp16
__global__ void __launch_bounds__(256) cvtT_kernel(const float* __restrict__ W,
                                                   __half* __restrict__ Wt,
                                                   int K, int N) {
    __shared__ float t[32][33];
    int n0 = blockIdx.x * 32, k0 = blockIdx.y * 32;
    int tx = threadIdx.x & 31, ty = threadIdx.x >> 5;
    #pragma unroll
    for (int i = 0; i < 32; i += 8)
        t[ty + i][tx] = W[(size_t)(k0 + ty + i) * N + n0 + tx];
    __syncthreads();
    #pragma unroll
    for (int i = 0; i < 32; i += 8)
        Wt[(size_t)(n0 + ty + i) * K + k0 + tx] = __float2half(t[tx][ty + i]);
}

// ---------------- RMSNorm -> fp16 x ----------------
__global__ void __launch_bounds__(256) rmsnorm_kernel(const float* __restrict__ h,
                                                      __half* __restrict__ xh) {
    int row = blockIdx.x;
    int t = threadIdx.x;
    const float4* hr = reinterpret_cast<const float4*>(h + (size_t)row * D_DIM);
    float4 a = hr[t];
    float ss = a.x * a.x + a.y * a.y + a.z * a.z + a.w * a.w;
    __shared__ float red[8];
    #pragma unroll
    for (int off = 16; off; off >>= 1) ss += __shfl_xor_sync(0xffffffffu, ss, off);
    if ((t & 31) == 0) red[t >> 5] = ss;
    __syncthreads();
    float tot = red[0] + red[1] + red[2] + red[3] + red[4] + red[5] + red[6] + red[7];
    float r = rsqrtf(tot * (1.0f / 1024.0f) + 1.1920929e-7f);
    __half2 h0 = __floats2half2_rn(a.x * r, a.y * r);
    __half2 h1 = __floats2half2_rn(a.z * r, a.w * r);
    uint2 packed = make_uint2(*reinterpret_cast<uint32_t*>(&h0),
                              *reinterpret_cast<uint32_t*>(&h1));
    *reinterpret_cast<uint2*>(xh + (size_t)row * D_DIM + t * 4) = packed;
}

// ---------------- fp16 cp.async GEMM ----------------
// C[M,N] = A[M,K] @ Bt[N,K]^T (+bias +add0 +lam*add1). Tile 128x128, BK=32,
// 8 warps (warp tile 32x64), mma m16n8k16. A and Bt are fp16, K-contiguous.
#define HSTR 40
#define GEMM_SMEM (4 * 128 * HSTR * 2)   // 2 bufs x (A+B) x 128 x 40 halfs

__global__ void __launch_bounds__(256) gemm_f16_kernel(
    const __half* __restrict__ A,
    const __half* __restrict__ B0, const __half* __restrict__ B1,
    const __half* __restrict__ B2, const __half* __restrict__ B3,
    const __half* __restrict__ B4,
    float* __restrict__ C0, float* __restrict__ C1,
    float* __restrict__ C2, float* __restrict__ C3,
    float* __restrict__ C4,
    int M, int N, int K,
    const float* __restrict__ bias,
    const float* __restrict__ add0,
    const float* __restrict__ add1,
    const float* __restrict__ lamPtr)
{
    int z = blockIdx.z;
    const __half* B = (z == 0) ? B0 : (z == 1) ? B1 : (z == 2) ? B2 : (z == 3) ? B3 : B4;
    float* C = (z == 0) ? C0 : (z == 1) ? C1 : (z == 2) ? C2 : (z == 3) ? C3 : C4;

    extern __shared__ __half smh[];
    __half (*As)[128][HSTR] = reinterpret_cast<__half(*)[128][HSTR]>(smh);
    __half (*Bs)[128][HSTR] = reinterpret_cast<__half(*)[128][HSTR]>(smh + 2 * 128 * HSTR);

    int tid = threadIdx.x;
    int lane = tid & 31;
    int warp = tid >> 5;
    int warpM = warp >> 1;    // 0..3 -> 32-row slice
    int warpN = warp & 1;     // 0..1 -> 64-col slice
    int lr = lane >> 2;
    int lc = lane & 3;
    int bm = blockIdx.y * 128;
    int bn = blockIdx.x * 128;

    // staging: thread -> row tid>>1 of both tiles, 32B at half-offset (tid&1)*16
    int sr = tid >> 1;
    int sc = (tid & 1) * 16;
    const __half* Ap = A + (size_t)(bm + sr) * K + sc;
    const __half* Bp = B + (size_t)(bn + sr) * K + sc;

    float acc[2][8][4];
    #pragma unroll
    for (int mi = 0; mi < 2; mi++)
        #pragma unroll
        for (int ni = 0; ni < 8; ni++)
            #pragma unroll
            for (int r = 0; r < 4; r++) acc[mi][ni][r] = 0.f;

    int NT = K / 32;

    auto issue = [&](int buf, int t) {
        const __half* ga = Ap + t * 32;
        const __half* gb = Bp + t * 32;
        uint32_t da = smem_u32(&As[buf][sr][sc]);
        uint32_t db = smem_u32(&Bs[buf][sr][sc]);
        asm volatile("cp.async.ca.shared.global [%0], [%1], 16;" :: "r"(da), "l"(ga));
        asm volatile("cp.async.ca.shared.global [%0], [%1], 16;" :: "r"(da + 16), "l"(ga + 8));
        asm volatile("cp.async.ca.shared.global [%0], [%1], 16;" :: "r"(db), "l"(gb));
        asm volatile("cp.async.ca.shared.global [%0], [%1], 16;" :: "r"(db + 16), "l"(gb + 8));
        asm volatile("cp.async.commit_group;" ::: "memory");
    };

    issue(0, 0);
    for (int t = 0; t < NT; t++) {
        int buf = t & 1;
        if (t + 1 < NT) {
            issue(buf ^ 1, t + 1);
            asm volatile("cp.async.wait_group 1;" ::: "memory");
        } else {
            asm volatile("cp.async.wait_group 0;" ::: "memory");
        }
        __syncthreads();
        #pragma unroll
        for (int ks = 0; ks < 2; ks++) {
            int kb = ks * 16 + lc * 2;
            uint32_t af[2][4], bf[8][2];
            #pragma unroll
            for (int mi = 0; mi < 2; mi++) {
                int r = warpM * 32 + mi * 16 + lr;
                af[mi][0] = *reinterpret_cast<const uint32_t*>(&As[buf][r][kb]);
                af[mi][1] = *reinterpret_cast<const uint32_t*>(&As[buf][r + 8][kb]);
                af[mi][2] = *reinterpret_cast<const uint32_t*>(&As[buf][r][kb + 8]);
                af[mi][3] = *reinterpret_cast<const uint32_t*>(&As[buf][r + 8][kb + 8]);
            }
            #pragma unroll
            for (int ni = 0; ni < 8; ni++) {
                int c = warpN * 64 + ni * 8 + lr;
                bf[ni][0] = *reinterpret_cast<const uint32_t*>(&Bs[buf][c][kb]);
                bf[ni][1] = *reinterpret_cast<const uint32_t*>(&Bs[buf][c][kb + 8]);
            }
            #pragma unroll
            for (int mi = 0; mi < 2; mi++)
                #pragma unroll
                for (int ni = 0; ni < 8; ni++)
                    MMA_F16(acc[mi][ni], af[mi], bf[ni]);
        }
        __syncthreads();
    }

    float lam = lamPtr ? lamPtr[0] : 0.f;
    #pragma unroll
    for (int mi = 0; mi < 2; mi++) {
        int r0 = bm + warpM * 32 + mi * 16 + lr;
        #pragma unroll
        for (int ni = 0; ni < 8; ni++) {
            int c0 = bn + warpN * 64 + ni * 8 + lc * 2;
            #pragma unroll
            for (int half_ = 0; half_ < 2; half_++) {
                int r = r0 + half_ * 8;
                float v0 = acc[mi][ni][half_ * 2 + 0];
                float v1 = acc[mi][ni][half_ * 2 + 1];
                if (bias) { v0 += bias[c0]; v1 += bias[c0 + 1]; }
                size_t idx = (size_t)r * N + c0;
                if (add0) { v0 += add0[idx]; v1 += add0[idx + 1]; }
                if (add1) { v0 += lam * add1[idx]; v1 += lam * add1[idx + 1]; }
                C[idx]     = v0;
                C[idx + 1] = v1;
            }
        }
    }
}

// ---------------- l2norm + RoPE ----------------
__global__ void __launch_bounds__(256) ropenorm_kernel(float* q, float* k, float* qb, float* kb) {
    int s = blockIdx.x;
    int warp = threadIdx.x >> 5;
    int lane = threadIdx.x & 31;
    int idx = blockIdx.y * 8 + warp;
    int h = idx & 15;
    int a = idx >> 4;
    float* arr = (a == 0) ? q : (a == 1) ? k : (a == 2) ? qb : kb;
    float* p = arr + (size_t)s * D_DIM + h * 64;
    float x1 = p[lane];
    float x2 = p[lane + DHALF];
    float ss = x1 * x1 + x2 * x2;
    #pragma unroll
    for (int off = 16; off; off >>= 1) ss += __shfl_xor_sync(0xffffffffu, ss, off);
    float n = fmaxf(sqrtf(ss), 1e-12f);
    float inv = 1.f / n;
    x1 *= inv;
    x2 *= inv;
    float invfreq = powf(1000.0f, -(float)lane * (1.0f / 32.0f));
    float fr = (float)s * invfreq;
    float c  = __bfloat162float(__float2bfloat16(cosf(fr)));
    float sn = __bfloat162float(__float2bfloat16(sinf(fr)));
    p[lane]         = x1 * c + x2 * sn;
    p[lane + DHALF] = -x1 * sn + x2 * c;
}

// ---------------- parallel prefix sum of kb ----------------
__global__ void __launch_bounds__(256) prefix_p1(const float* __restrict__ kb,
                                                 float* __restrict__ cs) {
    int ch = blockIdx.x;
    int col = blockIdx.y * 256 + threadIdx.x;
    const float* p = kb + (size_t)(ch * 32) * D_DIM + col;
    float acc = 0.f;
    #pragma unroll
    for (int r = 0; r < 32; r++) acc += p[(size_t)r * D_DIM];
    cs[(size_t)ch * D_DIM + col] = acc;
}
__global__ void __launch_bounds__(1024) prefix_p2(float* __restrict__ cs) {
    int col = threadIdx.x;
    float run = 0.f;
    #pragma unroll 8
    for (int ch = 0; ch < 64; ch++) {
        size_t i = (size_t)ch * D_DIM + col;
        float t = cs[i];
        cs[i] = run;
        run += t;
    }
}
__global__ void __launch_bounds__(256) prefix_p3(const float* __restrict__ kb,
                                                 const float* __restrict__ cs,
                                                 float* __restrict__ pkb) {
    int ch = blockIdx.x;
    int col = blockIdx.y * 256 + threadIdx.x;
    float acc = cs[(size_t)ch * D_DIM + col];
    const float* p = kb + (size_t)(ch * 32) * D_DIM + col;
    float* o = pkb + (size_t)(ch * 32) * D_DIM + col;
    #pragma unroll
    for (int r = 0; r < 32; r++) {
        acc += p[(size_t)r * D_DIM];
        o[(size_t)r * D_DIM] = acc;
    }
}

// ---------------- sb values ----------------
__global__ void __launch_bounds__(512) sb_kernel(const float* __restrict__ qb,
                                                 const float* __restrict__ pkb,
                                                 float* __restrict__ sbv) {
    int s = blockIdx.x;
    int h = threadIdx.x >> 5;
    int lane = threadIdx.x & 31;
    size_t off = (size_t)s * D_DIM + h * 64;
    float v = qb[off + lane] * pkb[off + lane] +
              qb[off + lane + DHALF] * pkb[off + lane + DHALF];
    #pragma unroll
    for (int o = 16; o; o >>= 1) v += __shfl_xor_sync(0xffffffffu, v, o);
    if (lane == 0) sbv[s * H_N + h] = 0.125f * v;
}

// ---------------- MMA flash attention (tf32; y emitted fp16) ----------------
#define QSTR 68
#define VSTR 72
#define ATT_SMEM ((3 * 64 * QSTR + 64 * VSTR + 256) * 4)

__global__ void __launch_bounds__(256) attn_mma_kernel(
    const float* __restrict__ q, const float* __restrict__ k, const float* __restrict__ v,
    const float* __restrict__ sbv, const float* __restrict__ l2sp,
    __half* __restrict__ yh)
{
    extern __shared__ uint32_t sma[];
    uint32_t (*Qs)[QSTR] = reinterpret_cast<uint32_t(*)[QSTR]>(sma);
    uint32_t (*Ks)[QSTR] = reinterpret_cast<uint32_t(*)[QSTR]>(sma + 64 * QSTR);
    uint32_t (*Ps)[QSTR] = reinterpret_cast<uint32_t(*)[QSTR]>(sma + 2 * 64 * QSTR);
    uint32_t (*Vs)[VSTR] = reinterpret_cast<uint32_t(*)[VSTR]>(sma + 3 * 64 * QSTR);
    float* red_m = reinterpret_cast<float*>(sma + 3 * 64 * QSTR + 64 * VSTR);
    float* red_l = red_m + 128;

    int h = blockIdx.y;
    int q0 = blockIdx.x * 64;
    int tid = threadIdx.x;
    int lane = tid & 31, warp = tid >> 5;
    int wm = warp >> 1;
    int wn = warp & 1;
    int lr = lane >> 2;
    int lc = lane & 3;

    {
        int r = tid >> 2, c0 = (tid & 3) * 16;
        const float* src = q + (size_t)(q0 + r) * D_DIM + h * 64 + c0;
        #pragma unroll
        for (int j = 0; j < 4; j++) {
            float4 f = *reinterpret_cast<const float4*>(src + j * 4);
            Qs[r][c0 + j * 4 + 0] = f2tf(f.x);
            Qs[r][c0 + j * 4 + 1] = f2tf(f.y);
            Qs[r][c0 + j * 4 + 2] = f2tf(f.z);
            Qs[r][c0 + j * 4 + 3] = f2tf(f.w);
        }
    }

    float m0 = -1e30f, m1 = -1e30f, l0 = 0.f, l1 = 0.f;
    float o[4][4];
    #pragma unroll
    for (int ni = 0; ni < 4; ni++)
        #pragma unroll
        for (int j = 0; j < 4; j++) o[ni][j] = 0.f;

    int row0 = wm * 16 + lr;
    int row1 = row0 + 8;
    int nt = blockIdx.x + 1;

    for (int kt = 0; kt < nt; kt++) {
        int kbase = kt * 64;
        __syncthreads();
        {
            int r = tid >> 2, c0 = (tid & 3) * 16;
            const float* ksrc = k + (size_t)(kbase + r) * D_DIM + h * 64 + c0;
            const float* vsrc = v + (size_t)(kbase + r) * D_DIM + h * 64 + c0;
            #pragma unroll
            for (int j = 0; j < 4; j++) {
                float4 f = *reinterpret_cast<const float4*>(ksrc + j * 4);
                Ks[r][c0 + j * 4 + 0] = f2tf(f.x);
                Ks[r][c0 + j * 4 + 1] = f2tf(f.y);
                Ks[r][c0 + j * 4 + 2] = f2tf(f.z);
                Ks[r][c0 + j * 4 + 3] = f2tf(f.w);
                float4 g = *reinterpret_cast<const float4*>(vsrc + j * 4);
                Vs[r][c0 + j * 4 + 0] = f2tf(g.x);
                Vs[r][c0 + j * 4 + 1] = f2tf(g.y);
                Vs[r][c0 + j * 4 + 2] = f2tf(g.z);
                Vs[r][c0 + j * 4 + 3] = f2tf(g.w);
            }
        }
        __syncthreads();

        float s[4][4];
        #pragma unroll
        for (int ni = 0; ni < 4; ni++)
            #pragma unroll
            for (int j = 0; j < 4; j++) s[ni][j] = 0.f;
        #pragma unroll
        for (int ks = 0; ks < 8; ks++) {
            int kc = ks * 8 + lc;
            uint32_t af[4];
            af[0] = Qs[row0][kc];
            af[1] = Qs[row1][kc];
            af[2] = Qs[row0][kc + 4];
            af[3] = Qs[row1][kc + 4];
            #pragma unroll
            for (int ni = 0; ni < 4; ni++) {
                int c = wn * 32 + ni * 8 + lr;
                uint32_t bf[2];
                bf[0] = Ks[c][kc];
                bf[1] = Ks[c][kc + 4];
                MMA_TF32(s[ni], af, bf);
            }
        }
        if (kt == nt - 1) {
            #pragma unroll
            for (int ni = 0; ni < 4; ni++) {
                int cbase = wn * 32 + ni * 8 + lc * 2;
                #pragma unroll
                for (int j = 0; j < 4; j++) {
                    int row = (j < 2) ? row0 : row1;
                    int col = cbase + (j & 1);
                    if (col > row) s[ni][j] = -1e30f;
                }
            }
        }
        float mx0 = -1e30f, mx1 = -1e30f;
        #pragma unroll
        for (int ni = 0; ni < 4; ni++) {
            mx0 = fmaxf(mx0, fmaxf(s[ni][0], s[ni][1]));
            mx1 = fmaxf(mx1, fmaxf(s[ni][2], s[ni][3]));
        }
        mx0 = fmaxf(mx0, __shfl_xor_sync(0xffffffffu, mx0, 1));
        mx0 = fmaxf(mx0, __shfl_xor_sync(0xffffffffu, mx0, 2));
        mx1 = fmaxf(mx1, __shfl_xor_sync(0xffffffffu, mx1, 1));
        mx1 = fmaxf(mx1, __shfl_xor_sync(0xffffffffu, mx1, 2));
        if (lc == 0) {
            red_m[wn * 64 + row0] = mx0;
            red_m[wn * 64 + row1] = mx1;
        }
        __syncthreads();
        float mn0 = fmaxf(m0, fmaxf(red_m[row0], red_m[64 + row0]));
        float mn1 = fmaxf(m1, fmaxf(red_m[row1], red_m[64 + row1]));
        float corr0 = __expf(m0 - mn0);
        float corr1 = __expf(m1 - mn1);
        float ls0 = 0.f, ls1 = 0.f;
        #pragma unroll
        for (int ni = 0; ni < 4; ni++) {
            int cbase = wn * 32 + ni * 8 + lc * 2;
            float p0 = __expf(s[ni][0] - mn0);
            float p1 = __expf(s[ni][1] - mn0);
            float p2 = __expf(s[ni][2] - mn1);
            float p3 = __expf(s[ni][3] - mn1);
            ls0 += p0 + p1;
            ls1 += p2 + p3;
            Ps[row0][cbase]     = f2tf(p0);
            Ps[row0][cbase + 1] = f2tf(p1);
            Ps[row1][cbase]     = f2tf(p2);
            Ps[row1][cbase + 1] = f2tf(p3);
        }
        ls0 += __shfl_xor_sync(0xffffffffu, ls0, 1);
        ls0 += __shfl_xor_sync(0xffffffffu, ls0, 2);
        ls1 += __shfl_xor_sync(0xffffffffu, ls1, 1);
        ls1 += __shfl_xor_sync(0xffffffffu, ls1, 2);
        if (lc == 0) {
            red_l[wn * 64 + row0] = ls0;
            red_l[wn * 64 + row1] = ls1;
        }
        __syncthreads();
        l0 = l0 * corr0 + red_l[row0] + red_l[64 + row0];
        l1 = l1 * corr1 + red_l[row1] + red_l[64 + row1];
        m0 = mn0;
        m1 = mn1;
        #pragma unroll
        for (int ni = 0; ni < 4; ni++) {
            o[ni][0] *= corr0;
            o[ni][1] *= corr0;
            o[ni][2] *= corr1;
            o[ni][3] *= corr1;
        }
        #pragma unroll
        for (int ks = 0; ks < 8; ks++) {
            int kc = ks * 8 + lc;
            uint32_t af[4];
            af[0] = Ps[row0][kc];
            af[1] = Ps[row1][kc];
            af[2] = Ps[row0][kc + 4];
            af[3] = Ps[row1][kc + 4];
            #pragma unroll
            for (int ni = 0; ni < 4; ni++) {
                int cd = wn * 32 + ni * 8 + lr;
                uint32_t bf[2];
                bf[0] = Vs[kc][cd];
                bf[1] = Vs[kc + 4][cd];
                MMA_TF32(o[ni], af, bf);
            }
        }
    }

    float l2sv = l2sp[0];
    float inv0 = l2sv / l0;
    float inv1 = l2sv / l1;
    int g0 = q0 + row0, g1 = q0 + row1;
    float sb0 = sbv[g0 * H_N + h];
    float sb1 = sbv[g1 * H_N + h];
    #pragma unroll
    for (int ni = 0; ni < 4; ni++) {
        int col = h * 64 + wn * 32 + ni * 8 + lc * 2;
        __half2 r0v = __floats2half2_rn(o[ni][0] * inv0 + sb0, o[ni][1] * inv0 + sb0);
        __half2 r1v = __floats2half2_rn(o[ni][2] * inv1 + sb1, o[ni][3] * inv1 + sb1);
        *reinterpret_cast<__half2*>(&yh[(size_t)g0 * D_DIM + col]) = r0v;
        *reinterpret_cast<__half2*>(&yh[(size_t)g1 * D_DIM + col]) = r1v;
    }
}

// ---------------- SwiGLU -> fp16 fm ----------------
__global__ void __launch_bounds__(256) swiglu_kernel(const float* __restrict__ u,
                                                     __half* __restrict__ fmh) {
    int i = blockIdx.x * blockDim.x + threadIdx.x;
    int e = i * 4;
    int row = e >> 12;
    int col = e & 4095;
    float4 xp = *reinterpret_cast<const float4*>(&u[(size_t)row * FUSEDW + col]);
    float4 g  = *reinterpret_cast<const float4*>(&u[(size_t)row * FUSEDW + FF_IN + col]);
    __half2 h0 = __floats2half2_rn((g.x / (1.f + __expf(-g.x))) * xp.x,
                                   (g.y / (1.f + __expf(-g.y))) * xp.y);
    __half2 h1 = __floats2half2_rn((g.z / (1.f + __expf(-g.z))) * xp.z,
                                   (g.w / (1.f + __expf(-g.w))) * xp.w);
    uint2 packed = make_uint2(*reinterpret_cast<uint32_t*>(&h0),
                              *reinterpret_cast<uint32_t*>(&h1));
    *reinterpret_cast<uint2*>(fmh + (size_t)row * FF_IN + col) = packed;
}

// ---------------- launch ----------------
extern "C" void kernel_launch(void* const* d_in, const int* in_sizes, int n_in,
                              void* d_out, int out_size) {
    const float* h_states = (const float*)d_in[0];
    const float* Wq  = (const float*)d_in[1];
    const float* Wk  = (const float*)d_in[2];
    const float* Wv  = (const float*)d_in[3];
    const float* Wqb = (const float*)d_in[4];
    const float* Wkb = (const float*)d_in[5];
    const float* Wo  = (const float*)d_in[6];
    const float* bo  = (const float*)d_in[7];
    const float* W1  = (const float*)d_in[8];
    const float* b1  = (const float*)d_in[9];
    const float* W2  = (const float*)d_in[10];
    const float* b2  = (const float*)d_in[11];
    const float* lam = (const float*)d_in[12];
    const float* l2s = (const float*)d_in[13];
    float* out = (float*)d_out;

    float *q, *k, *v, *qb, *kb, *pkb, *cs, *sbv, *ao, *u;
    __half *xh, *yh, *fmh, *wqh, *wkh, *wvh, *wqbh, *wkbh, *woh, *w1h, *w2h;
    cudaGetSymbolAddress((void**)&q,  g_q);
    cudaGetSymbolAddress((void**)&k,  g_k);
    cudaGetSymbolAddress((void**)&v,  g_v);
    cudaGetSymbolAddress((void**)&qb, g_qb);
    cudaGetSymbolAddress((void**)&kb, g_kb);
    cudaGetSymbolAddress((void**)&pkb, g_pkb);
    cudaGetSymbolAddress((void**)&cs, g_cs);
    cudaGetSymbolAddress((void**)&sbv, g_sb);
    cudaGetSymbolAddress((void**)&ao, g_ao);
    cudaGetSymbolAddress((void**)&u,  g_u);
    cudaGetSymbolAddress((void**)&xh,  g_xh);
    cudaGetSymbolAddress((void**)&yh,  g_yh);
    cudaGetSymbolAddress((void**)&fmh, g_fmh);
    cudaGetSymbolAddress((void**)&wqh,  g_wqh);
    cudaGetSymbolAddress((void**)&wkh,  g_wkh);
    cudaGetSymbolAddress((void**)&wvh,  g_wvh);
    cudaGetSymbolAddress((void**)&wqbh, g_wqbh);
    cudaGetSymbolAddress((void**)&wkbh, g_wkbh);
    cudaGetSymbolAddress((void**)&woh,  g_woh);
    cudaGetSymbolAddress((void**)&w1h,  g_w1h);
    cudaGetSymbolAddress((void**)&w2h,  g_w2h);

    cudaFuncSetAttribute(attn_mma_kernel,
                         cudaFuncAttributeMaxDynamicSharedMemorySize, ATT_SMEM);
    cudaFuncSetAttribute(gemm_f16_kernel,
                         cudaFuncAttributeMaxDynamicSharedMemorySize, GEMM_SMEM);

    // 0. convert + transpose weights to fp16 [N][K]
    cvtT_kernel<<<dim3(32, 32), 256>>>(Wq,  wqh,  D_DIM, D_DIM);
    cvtT_kernel<<<dim3(32, 32), 256>>>(Wk,  wkh,  D_DIM, D_DIM);
    cvtT_kernel<<<dim3(32, 32), 256>>>(Wv,  wvh,  D_DIM, D_DIM);
    cvtT_kernel<<<dim3(32, 32), 256>>>(Wqb, wqbh, D_DIM, D_DIM);
    cvtT_kernel<<<dim3(32, 32), 256>>>(Wkb, wkbh, D_DIM, D_DIM);
    cvtT_kernel<<<dim3(32, 32), 256>>>(Wo,  woh,  D_DIM, D_DIM);
    cvtT_kernel<<<dim3(FUSEDW / 32, 32), 256>>>(W1, w1h, D_DIM, FUSEDW);
    cvtT_kernel<<<dim3(32, FF_IN / 32), 256>>>(W2, w2h, FF_IN, D_DIM);

    // 1. RMSNorm -> fp16 x
    rmsnorm_kernel<<<S_LEN, 256>>>(h_states, xh);

    // 2. five projections in one launch
    gemm_f16_kernel<<<dim3(D_DIM / 128, S_LEN / 128, 5), 256, GEMM_SMEM>>>(
        xh, wqh, wkh, wvh, wqbh, wkbh, q, k, v, qb, kb,
        S_LEN, D_DIM, D_DIM, nullptr, nullptr, nullptr, nullptr);

    // 3. l2norm + RoPE
    ropenorm_kernel<<<dim3(S_LEN, 8), 256>>>(q, k, qb, kb);

    // 4. prefix of kb; 5. sb values
    prefix_p1<<<dim3(64, 4), 256>>>(kb, cs);
    prefix_p2<<<1, 1024>>>(cs);
    prefix_p3<<<dim3(64, 4), 256>>>(kb, cs, pkb);
    sb_kernel<<<S_LEN, 512>>>(qb, pkb, sbv);

    // 6. MMA flash attention -> fp16 y
    attn_mma_kernel<<<dim3(S_LEN / 64, H_N), 256, ATT_SMEM>>>(q, k, v, sbv, l2s, yh);

    // 7. attn_out = y @ Wo + bo
    gemm_f16_kernel<<<dim3(D_DIM / 128, S_LEN / 128, 1), 256, GEMM_SMEM>>>(
        yh, woh, nullptr, nullptr, nullptr, nullptr,
        ao, nullptr, nullptr, nullptr, nullptr,
        S_LEN, D_DIM, D_DIM, bo, nullptr, nullptr, nullptr);

    // 8. u = x @ W1 + b1
    gemm_f16_kernel<<<dim3(FUSEDW / 128, S_LEN / 128, 1), 256, GEMM_SMEM>>>(
        xh, w1h, nullptr, nullptr, nullptr, nullptr,
        u, nullptr, nullptr, nullptr, nullptr,
        S_LEN, FUSEDW, D_DIM, b1, nullptr, nullptr, nullptr);

    // 9. SwiGLU -> fp16 fm
    swiglu_kernel<<<(S_LEN * FF_IN / 4) / 256, 256>>>(u, fmh);

    // 10. out = fm @ W2 + b2 + attn_out + lambda * h_states
    gemm_f16_kernel<<<dim3(D_DIM / 128, S_LEN / 128, 1), 256, GEMM_SMEM>>>(
        fmh, w2h, nullptr, nullptr, nullptr, nullptr,
        out, nullptr, nullptr, nullptr, nullptr,
        S_LEN, D_DIM, FF_IN, b2, ao, h_states, lam);
}

// round 8
// speedup vs baseline: 6.5581x; 1.0959x over previous
#include <cuda_runtime.h>
#include <cuda_bf16.h>
#include <cuda_fp16.h>
#include <cstdint>

#define S_LEN 2048
#define D_DIM 1024
#define H_N 16
#define DHALF 32
#define FF_IN 4096
#define FUSEDW 8192

// ---------------- scratch (static device globals; no allocs) ----------------
__device__ float  g_q  [S_LEN * D_DIM];
__device__ float  g_k  [S_LEN * D_DIM];
__device__ float  g_v  [S_LEN * D_DIM];
__device__ float  g_qb [S_LEN * D_DIM];
__device__ float  g_kb [S_LEN * D_DIM];
__device__ float  g_pkb[S_LEN * D_DIM];
__device__ float  g_cs [64 * D_DIM];
__device__ float  g_sb [S_LEN * H_N];
__device__ float  g_ao [S_LEN * D_DIM];
__device__ float  g_u  [S_LEN * FUSEDW];
// fp16 GEMM operands
__device__ __half g_xh [S_LEN * D_DIM];
__device__ __half g_yh [S_LEN * D_DIM];
__device__ __half g_fmh[S_LEN * FF_IN];
__device__ __half g_wqh [D_DIM * D_DIM];   // transposed [N][K]
__device__ __half g_wkh [D_DIM * D_DIM];
__device__ __half g_wvh [D_DIM * D_DIM];
__device__ __half g_wqbh[D_DIM * D_DIM];
__device__ __half g_wkbh[D_DIM * D_DIM];
__device__ __half g_woh [D_DIM * D_DIM];
__device__ __half g_w1h [FUSEDW * D_DIM];  // [N=8192][K=1024]
__device__ __half g_w2h [D_DIM * FF_IN];   // [N=1024][K=4096]

// ---------------- helpers ----------------
__device__ __forceinline__ uint32_t smem_u32(const void* p) {
    uint32_t a;
    asm("{ .reg .u64 t; cvta.to.shared.u64 t, %1; cvt.u32.u64 %0, t; }" : "=r"(a) : "l"(p));
    return a;
}

#define MMA_F16(d, a, b)                                                      \
    asm volatile(                                                             \
        "mma.sync.aligned.m16n8k16.row.col.f32.f16.f16.f32 "                  \
        "{%0,%1,%2,%3}, {%4,%5,%6,%7}, {%8,%9}, {%0,%1,%2,%3};"               \
        : "+f"(d[0]), "+f"(d[1]), "+f"(d[2]), "+f"(d[3])                      \
        : "r"(a[0]), "r"(a[1]), "r"(a[2]), "r"(a[3]), "r"(b[0]), "r"(b[1]))

// ---------------- weight fp16 convert + transpose ----------------
// W [K][N] fp32 -> Wt [N][K] fp16; batched x6 via blockIdx.z
__global__ void __launch_bounds__(256) cvtT6_kernel(
    const float* __restrict__ W0, const float* __restrict__ W1,
    const float* __restrict__ W2, const float* __restrict__ W3,
    const float* __restrict__ W4, const float* __restrict__ W5,
    __half* __restrict__ O0, __half* __restrict__ O1,
    __half* __restrict__ O2, __half* __restrict__ O3,
    __half* __restrict__ O4, __half* __restrict__ O5) {
    int z = blockIdx.z;
    const float* W = (z == 0) ? W0 : (z == 1) ? W1 : (z == 2) ? W2
                   : (z == 3) ? W3 : (z == 4) ? W4 : W5;
    __half* Wt = (z == 0) ? O0 : (z == 1) ? O1 : (z == 2) ? O2
               : (z == 3) ? O3 : (z == 4) ? O4 : O5;
    __shared__ float t[32][33];
    int n0 = blockIdx.x * 32, k0 = blockIdx.y * 32;
    int tx = threadIdx.x & 31, ty = threadIdx.x >> 5;
    #pragma unroll
    for (int i = 0; i < 32; i += 8)
        t[ty + i][tx] = W[(size_t)(k0 + ty + i) * D_DIM + n0 + tx];
    __syncthreads();
    #pragma unroll
    for (int i = 0; i < 32; i += 8)
        Wt[(size_t)(n0 + ty + i) * D_DIM + k0 + tx] = __float2half(t[tx][ty + i]);
}

__global__ void __launch_bounds__(256) cvtT_kernel(const float* __restrict__ W,
                                                   __half* __restrict__ Wt,
                                                   int K, int N) {
    __shared__ float t[32][33];
    int n0 = blockIdx.x * 32, k0 = blockIdx.y * 32;
    int tx = threadIdx.x & 31, ty = threadIdx.x >> 5;
    #pragma unroll
    for (int i = 0; i < 32; i += 8)
        t[ty + i][tx] = W[(size_t)(k0 + ty + i) * N + n0 + tx];
    __syncthreads();
    #pragma unroll
    for (int i = 0; i < 32; i += 8)
        Wt[(size_t)(n0 + ty + i) * K + k0 + tx] = __float2half(t[tx][ty + i]);
}

// ---------------- RMSNorm -> fp16 x ----------------
__global__ void __launch_bounds__(256) rmsnorm_kernel(const float* __restrict__ h,
                                                      __half* __restrict__ xh) {
    int row = blockIdx.x;
    int t = threadIdx.x;
    const float4* hr = reinterpret_cast<const float4*>(h + (size_t)row * D_DIM);
    float4 a = hr[t];
    float ss = a.x * a.x + a.y * a.y + a.z * a.z + a.w * a.w;
    __shared__ float red[8];
    #pragma unroll
    for (int off = 16; off; off >>= 1) ss += __shfl_xor_sync(0xffffffffu, ss, off);
    if ((t & 31) == 0) red[t >> 5] = ss;
    __syncthreads();
    float tot = red[0] + red[1] + red[2] + red[3] + red[4] + red[5] + red[6] + red[7];
    float r = rsqrtf(tot * (1.0f / 1024.0f) + 1.1920929e-7f);
    __half2 h0 = __floats2half2_rn(a.x * r, a.y * r);
    __half2 h1 = __floats2half2_rn(a.z * r, a.w * r);
    uint2 packed = make_uint2(*reinterpret_cast<uint32_t*>(&h0),
                              *reinterpret_cast<uint32_t*>(&h1));
    *reinterpret_cast<uint2*>(xh + (size_t)row * D_DIM + t * 4) = packed;
}

// ---------------- fp16 cp.async GEMM (proven R6) ----------------
#define HSTR 40
#define GEMM_SMEM (4 * 128 * HSTR * 2)

__global__ void __launch_bounds__(256) gemm_f16_kernel(
    const __half* __restrict__ A,
    const __half* __restrict__ B0, const __half* __restrict__ B1,
    const __half* __restrict__ B2, const __half* __restrict__ B3,
    const __half* __restrict__ B4,
    float* __restrict__ C0, float* __restrict__ C1,
    float* __restrict__ C2, float* __restrict__ C3,
    float* __restrict__ C4,
    int M, int N, int K,
    const float* __restrict__ bias,
    const float* __restrict__ add0,
    const float* __restrict__ add1,
    const float* __restrict__ lamPtr)
{
    int z = blockIdx.z;
    const __half* B = (z == 0) ? B0 : (z == 1) ? B1 : (z == 2) ? B2 : (z == 3) ? B3 : B4;
    float* C = (z == 0) ? C0 : (z == 1) ? C1 : (z == 2) ? C2 : (z == 3) ? C3 : C4;

    extern __shared__ __half smh[];
    __half (*As)[128][HSTR] = reinterpret_cast<__half(*)[128][HSTR]>(smh);
    __half (*Bs)[128][HSTR] = reinterpret_cast<__half(*)[128][HSTR]>(smh + 2 * 128 * HSTR);

    int tid = threadIdx.x;
    int lane = tid & 31;
    int warp = tid >> 5;
    int warpM = warp >> 1;
    int warpN = warp & 1;
    int lr = lane >> 2;
    int lc = lane & 3;
    int bm = blockIdx.y * 128;
    int bn = blockIdx.x * 128;

    int sr = tid >> 1;
    int sc = (tid & 1) * 16;
    const __half* Ap = A + (size_t)(bm + sr) * K + sc;
    const __half* Bp = B + (size_t)(bn + sr) * K + sc;

    float acc[2][8][4];
    #pragma unroll
    for (int mi = 0; mi < 2; mi++)
        #pragma unroll
        for (int ni = 0; ni < 8; ni++)
            #pragma unroll
            for (int r = 0; r < 4; r++) acc[mi][ni][r] = 0.f;

    int NT = K / 32;

    auto issue = [&](int buf, int t) {
        const __half* ga = Ap + t * 32;
        const __half* gb = Bp + t * 32;
        uint32_t da = smem_u32(&As[buf][sr][sc]);
        uint32_t db = smem_u32(&Bs[buf][sr][sc]);
        asm volatile("cp.async.ca.shared.global [%0], [%1], 16;" :: "r"(da), "l"(ga));
        asm volatile("cp.async.ca.shared.global [%0], [%1], 16;" :: "r"(da + 16), "l"(ga + 8));
        asm volatile("cp.async.ca.shared.global [%0], [%1], 16;" :: "r"(db), "l"(gb));
        asm volatile("cp.async.ca.shared.global [%0], [%1], 16;" :: "r"(db + 16), "l"(gb + 8));
        asm volatile("cp.async.commit_group;" ::: "memory");
    };

    issue(0, 0);
    for (int t = 0; t < NT; t++) {
        int buf = t & 1;
        if (t + 1 < NT) {
            issue(buf ^ 1, t + 1);
            asm volatile("cp.async.wait_group 1;" ::: "memory");
        } else {
            asm volatile("cp.async.wait_group 0;" ::: "memory");
        }
        __syncthreads();
        #pragma unroll
        for (int ks = 0; ks < 2; ks++) {
            int kb = ks * 16 + lc * 2;
            uint32_t af[2][4], bf[8][2];
            #pragma unroll
            for (int mi = 0; mi < 2; mi++) {
                int r = warpM * 32 + mi * 16 + lr;
                af[mi][0] = *reinterpret_cast<const uint32_t*>(&As[buf][r][kb]);
                af[mi][1] = *reinterpret_cast<const uint32_t*>(&As[buf][r + 8][kb]);
                af[mi][2] = *reinterpret_cast<const uint32_t*>(&As[buf][r][kb + 8]);
                af[mi][3] = *reinterpret_cast<const uint32_t*>(&As[buf][r + 8][kb + 8]);
            }
            #pragma unroll
            for (int ni = 0; ni < 8; ni++) {
                int c = warpN * 64 + ni * 8 + lr;
                bf[ni][0] = *reinterpret_cast<const uint32_t*>(&Bs[buf][c][kb]);
                bf[ni][1] = *reinterpret_cast<const uint32_t*>(&Bs[buf][c][kb + 8]);
            }
            #pragma unroll
            for (int mi = 0; mi < 2; mi++)
                #pragma unroll
                for (int ni = 0; ni < 8; ni++)
                    MMA_F16(acc[mi][ni], af[mi], bf[ni]);
        }
        __syncthreads();
    }

    float lam = lamPtr ? lamPtr[0] : 0.f;
    #pragma unroll
    for (int mi = 0; mi < 2; mi++) {
        int r0 = bm + warpM * 32 + mi * 16 + lr;
        #pragma unroll
        for (int ni = 0; ni < 8; ni++) {
            int c0 = bn + warpN * 64 + ni * 8 + lc * 2;
            #pragma unroll
            for (int half_ = 0; half_ < 2; half_++) {
                int r = r0 + half_ * 8;
                float v0 = acc[mi][ni][half_ * 2 + 0];
                float v1 = acc[mi][ni][half_ * 2 + 1];
                if (bias) { v0 += bias[c0]; v1 += bias[c0 + 1]; }
                size_t idx = (size_t)r * N + c0;
                if (add0) { v0 += add0[idx]; v1 += add0[idx + 1]; }
                if (add1) { v0 += lam * add1[idx]; v1 += lam * add1[idx + 1]; }
                C[idx]     = v0;
                C[idx + 1] = v1;
            }
        }
    }
}

// ---------------- l2norm + RoPE ----------------
__global__ void __launch_bounds__(256) ropenorm_kernel(float* q, float* k, float* qb, float* kb) {
    int s = blockIdx.x;
    int warp = threadIdx.x >> 5;
    int lane = threadIdx.x & 31;
    int idx = blockIdx.y * 8 + warp;
    int h = idx & 15;
    int a = idx >> 4;
    float* arr = (a == 0) ? q : (a == 1) ? k : (a == 2) ? qb : kb;
    float* p = arr + (size_t)s * D_DIM + h * 64;
    float x1 = p[lane];
    float x2 = p[lane + DHALF];
    float ss = x1 * x1 + x2 * x2;
    #pragma unroll
    for (int off = 16; off; off >>= 1) ss += __shfl_xor_sync(0xffffffffu, ss, off);
    float n = fmaxf(sqrtf(ss), 1e-12f);
    float inv = 1.f / n;
    x1 *= inv;
    x2 *= inv;
    float invfreq = powf(1000.0f, -(float)lane * (1.0f / 32.0f));
    float fr = (float)s * invfreq;
    float c  = __bfloat162float(__float2bfloat16(cosf(fr)));
    float sn = __bfloat162float(__float2bfloat16(sinf(fr)));
    p[lane]         = x1 * c + x2 * sn;
    p[lane + DHALF] = -x1 * sn + x2 * c;
}

// ---------------- parallel prefix sum of kb ----------------
__global__ void __launch_bounds__(256) prefix_p1(const float* __restrict__ kb,
                                                 float* __restrict__ cs) {
    int ch = blockIdx.x;
    int col = blockIdx.y * 256 + threadIdx.x;
    const float* p = kb + (size_t)(ch * 32) * D_DIM + col;
    float acc = 0.f;
    #pragma unroll
    for (int r = 0; r < 32; r++) acc += p[(size_t)r * D_DIM];
    cs[(size_t)ch * D_DIM + col] = acc;
}
__global__ void __launch_bounds__(1024) prefix_p2(float* __restrict__ cs) {
    int col = threadIdx.x;
    float run = 0.f;
    #pragma unroll 8
    for (int ch = 0; ch < 64; ch++) {
        size_t i = (size_t)ch * D_DIM + col;
        float t = cs[i];
        cs[i] = run;
        run += t;
    }
}
__global__ void __launch_bounds__(256) prefix_p3(const float* __restrict__ kb,
                                                 const float* __restrict__ cs,
                                                 float* __restrict__ pkb) {
    int ch = blockIdx.x;
    int col = blockIdx.y * 256 + threadIdx.x;
    float acc = cs[(size_t)ch * D_DIM + col];
    const float* p = kb + (size_t)(ch * 32) * D_DIM + col;
    float* o = pkb + (size_t)(ch * 32) * D_DIM + col;
    #pragma unroll
    for (int r = 0; r < 32; r++) {
        acc += p[(size_t)r * D_DIM];
        o[(size_t)r * D_DIM] = acc;
    }
}

// ---------------- sb values ----------------
__global__ void __launch_bounds__(512) sb_kernel(const float* __restrict__ qb,
                                                 const float* __restrict__ pkb,
                                                 float* __restrict__ sbv) {
    int s = blockIdx.x;
    int h = threadIdx.x >> 5;
    int lane = threadIdx.x & 31;
    size_t off = (size_t)s * D_DIM + h * 64;
    float v = qb[off + lane] * pkb[off + lane] +
              qb[off + lane + DHALF] * pkb[off + lane + DHALF];
    #pragma unroll
    for (int o = 16; o; o >>= 1) v += __shfl_xor_sync(0xffffffffu, v, o);
    if (lane == 0) sbv[s * H_N + h] = 0.125f * v;
}

// ---------------- fp16 MMA flash attention ----------------
// 64 q-rows/block, 8 warps (wm 0..3 x wn 0..1), mma m16n8k16.
// Qs/Ks/Ps [64][QSH] half (k-contig), Vs [64][QSH] half TRANSPOSED (Vs[d][kpos]).
#define QSH 72
#define ATT_SMEM (4 * 64 * QSH * 2 + 256 * 4)

__global__ void __launch_bounds__(256) attn_mma_kernel(
    const float* __restrict__ q, const float* __restrict__ k, const float* __restrict__ v,
    const float* __restrict__ sbv, const float* __restrict__ l2sp,
    __half* __restrict__ yh)
{
    extern __shared__ __half smah[];
    __half (*Qs)[QSH] = reinterpret_cast<__half(*)[QSH]>(smah);
    __half (*Ks)[QSH] = reinterpret_cast<__half(*)[QSH]>(smah + 64 * QSH);
    __half (*Ps)[QSH] = reinterpret_cast<__half(*)[QSH]>(smah + 2 * 64 * QSH);
    __half (*Vs)[QSH] = reinterpret_cast<__half(*)[QSH]>(smah + 3 * 64 * QSH);
    float* red_m = reinterpret_cast<float*>(smah + 4 * 64 * QSH);  // [2][64]
    float* red_l = red_m + 128;

    int h = blockIdx.y;
    int q0 = blockIdx.x * 64;
    int tid = threadIdx.x;
    int lane = tid & 31, warp = tid >> 5;
    int wm = warp >> 1;
    int wn = warp & 1;
    int lr = lane >> 2;
    int lc = lane & 3;

    // stage Q (fp16, k-contig)
    {
        int r = tid >> 2, c0 = (tid & 3) * 16;
        const float* src = q + (size_t)(q0 + r) * D_DIM + h * 64 + c0;
        #pragma unroll
        for (int j = 0; j < 4; j++) {
            float4 f = *reinterpret_cast<const float4*>(src + j * 4);
            __half2 p0 = __floats2half2_rn(f.x, f.y);
            __half2 p1 = __floats2half2_rn(f.z, f.w);
            *reinterpret_cast<uint2*>(&Qs[r][c0 + j * 4]) =
                make_uint2(*reinterpret_cast<uint32_t*>(&p0),
                           *reinterpret_cast<uint32_t*>(&p1));
        }
    }

    float m0 = -1e30f, m1 = -1e30f, l0 = 0.f, l1 = 0.f;
    float o[4][4];
    #pragma unroll
    for (int ni = 0; ni < 4; ni++)
        #pragma unroll
        for (int j = 0; j < 4; j++) o[ni][j] = 0.f;

    int row0 = wm * 16 + lr;
    int row1 = row0 + 8;
    int nt = blockIdx.x + 1;

    for (int kt = 0; kt < nt; kt++) {
        int kbase = kt * 64;
        __syncthreads();
        {
            int r = tid >> 2, c0 = (tid & 3) * 16;
            const float* ksrc = k + (size_t)(kbase + r) * D_DIM + h * 64 + c0;
            const float* vsrc = v + (size_t)(kbase + r) * D_DIM + h * 64 + c0;
            #pragma unroll
            for (int j = 0; j < 4; j++) {
                float4 f = *reinterpret_cast<const float4*>(ksrc + j * 4);
                __half2 p0 = __floats2half2_rn(f.x, f.y);
                __half2 p1 = __floats2half2_rn(f.z, f.w);
                *reinterpret_cast<uint2*>(&Ks[r][c0 + j * 4]) =
                    make_uint2(*reinterpret_cast<uint32_t*>(&p0),
                               *reinterpret_cast<uint32_t*>(&p1));
                float4 g = *reinterpret_cast<const float4*>(vsrc + j * 4);
                // transposed: Vs[d][kpos]
                Vs[c0 + j * 4 + 0][r] = __float2half(g.x);
                Vs[c0 + j * 4 + 1][r] = __float2half(g.y);
                Vs[c0 + j * 4 + 2][r] = __float2half(g.z);
                Vs[c0 + j * 4 + 3][r] = __float2half(g.w);
            }
        }
        __syncthreads();

        // S = Q . K^T  (fp16 mma, 4 k-steps of 16)
        float s[4][4];
        #pragma unroll
        for (int ni = 0; ni < 4; ni++)
            #pragma unroll
            for (int j = 0; j < 4; j++) s[ni][j] = 0.f;
        #pragma unroll
        for (int ks = 0; ks < 4; ks++) {
            int kb = ks * 16 + lc * 2;
            uint32_t af[4];
            af[0] = *reinterpret_cast<const uint32_t*>(&Qs[row0][kb]);
            af[1] = *reinterpret_cast<const uint32_t*>(&Qs[row1][kb]);
            af[2] = *reinterpret_cast<const uint32_t*>(&Qs[row0][kb + 8]);
            af[3] = *reinterpret_cast<const uint32_t*>(&Qs[row1][kb + 8]);
            #pragma unroll
            for (int ni = 0; ni < 4; ni++) {
                int c = wn * 32 + ni * 8 + lr;
                uint32_t bf[2];
                bf[0] = *reinterpret_cast<const uint32_t*>(&Ks[c][kb]);
                bf[1] = *reinterpret_cast<const uint32_t*>(&Ks[c][kb + 8]);
                MMA_F16(s[ni], af, bf);
            }
        }
        if (kt == nt - 1) {
            #pragma unroll
            for (int ni = 0; ni < 4; ni++) {
                int cbase = wn * 32 + ni * 8 + lc * 2;
                #pragma unroll
                for (int j = 0; j < 4; j++) {
                    int row = (j < 2) ? row0 : row1;
                    int col = cbase + (j & 1);
                    if (col > row) s[ni][j] = -1e30f;
                }
            }
        }
        float mx0 = -1e30f, mx1 = -1e30f;
        #pragma unroll
        for (int ni = 0; ni < 4; ni++) {
            mx0 = fmaxf(mx0, fmaxf(s[ni][0], s[ni][1]));
            mx1 = fmaxf(mx1, fmaxf(s[ni][2], s[ni][3]));
        }
        mx0 = fmaxf(mx0, __shfl_xor_sync(0xffffffffu, mx0, 1));
        mx0 = fmaxf(mx0, __shfl_xor_sync(0xffffffffu, mx0, 2));
        mx1 = fmaxf(mx1, __shfl_xor_sync(0xffffffffu, mx1, 1));
        mx1 = fmaxf(mx1, __shfl_xor_sync(0xffffffffu, mx1, 2));
        if (lc == 0) {
            red_m[wn * 64 + row0] = mx0;
            red_m[wn * 64 + row1] = mx1;
        }
        __syncthreads();
        float mn0 = fmaxf(m0, fmaxf(red_m[row0], red_m[64 + row0]));
        float mn1 = fmaxf(m1, fmaxf(red_m[row1], red_m[64 + row1]));
        float corr0 = __expf(m0 - mn0);
        float corr1 = __expf(m1 - mn1);
        float ls0 = 0.f, ls1 = 0.f;
        #pragma unroll
        for (int ni = 0; ni < 4; ni++) {
            int cbase = wn * 32 + ni * 8 + lc * 2;
            float p0 = __expf(s[ni][0] - mn0);
            float p1 = __expf(s[ni][1] - mn0);
            float p2 = __expf(s[ni][2] - mn1);
            float p3 = __expf(s[ni][3] - mn1);
            ls0 += p0 + p1;
            ls1 += p2 + p3;
            __half2 hp0 = __floats2half2_rn(p0, p1);
            __half2 hp1 = __floats2half2_rn(p2, p3);
            *reinterpret_cast<uint32_t*>(&Ps[row0][cbase]) =
                *reinterpret_cast<uint32_t*>(&hp0);
            *reinterpret_cast<uint32_t*>(&Ps[row1][cbase]) =
                *reinterpret_cast<uint32_t*>(&hp1);
        }
        ls0 += __shfl_xor_sync(0xffffffffu, ls0, 1);
        ls0 += __shfl_xor_sync(0xffffffffu, ls0, 2);
        ls1 += __shfl_xor_sync(0xffffffffu, ls1, 1);
        ls1 += __shfl_xor_sync(0xffffffffu, ls1, 2);
        if (lc == 0) {
            red_l[wn * 64 + row0] = ls0;
            red_l[wn * 64 + row1] = ls1;
        }
        __syncthreads();
        l0 = l0 * corr0 + red_l[row0] + red_l[64 + row0];
        l1 = l1 * corr1 + red_l[row1] + red_l[64 + row1];
        m0 = mn0;
        m1 = mn1;
        #pragma unroll
        for (int ni = 0; ni < 4; ni++) {
            o[ni][0] *= corr0;
            o[ni][1] *= corr0;
            o[ni][2] *= corr1;
            o[ni][3] *= corr1;
        }
        // O += P . V  (A=Ps rows, k=kpos; B=Vs[d][kpos] k-contig)
        #pragma unroll
        for (int ks = 0; ks < 4; ks++) {
            int kb = ks * 16 + lc * 2;
            uint32_t af[4];
            af[0] = *reinterpret_cast<const uint32_t*>(&Ps[row0][kb]);
            af[1] = *reinterpret_cast<const uint32_t*>(&Ps[row1][kb]);
            af[2] = *reinterpret_cast<const uint32_t*>(&Ps[row0][kb + 8]);
            af[3] = *reinterpret_cast<const uint32_t*>(&Ps[row1][kb + 8]);
            #pragma unroll
            for (int ni = 0; ni < 4; ni++) {
                int cd = wn * 32 + ni * 8 + lr;
                uint32_t bf[2];
                bf[0] = *reinterpret_cast<const uint32_t*>(&Vs[cd][kb]);
                bf[1] = *reinterpret_cast<const uint32_t*>(&Vs[cd][kb + 8]);
                MMA_F16(o[ni], af, bf);
            }
        }
    }

    float l2sv = l2sp[0];
    float inv0 = l2sv / l0;
    float inv1 = l2sv / l1;
    int g0 = q0 + row0, g1 = q0 + row1;
    float sb0 = sbv[g0 * H_N + h];
    float sb1 = sbv[g1 * H_N + h];
    #pragma unroll
    for (int ni = 0; ni < 4; ni++) {
        int col = h * 64 + wn * 32 + ni * 8 + lc * 2;
        __half2 r0v = __floats2half2_rn(o[ni][0] * inv0 + sb0, o[ni][1] * inv0 + sb0);
        __half2 r1v = __floats2half2_rn(o[ni][2] * inv1 + sb1, o[ni][3] * inv1 + sb1);
        *reinterpret_cast<__half2*>(&yh[(size_t)g0 * D_DIM + col]) = r0v;
        *reinterpret_cast<__half2*>(&yh[(size_t)g1 * D_DIM + col]) = r1v;
    }
}

// ---------------- SwiGLU -> fp16 fm ----------------
__global__ void __launch_bounds__(256) swiglu_kernel(const float* __restrict__ u,
                                                     __half* __restrict__ fmh) {
    int i = blockIdx.x * blockDim.x + threadIdx.x;
    int e = i * 4;
    int row = e >> 12;
    int col = e & 4095;
    float4 xp = *reinterpret_cast<const float4*>(&u[(size_t)row * FUSEDW + col]);
    float4 g  = *reinterpret_cast<const float4*>(&u[(size_t)row * FUSEDW + FF_IN + col]);
    __half2 h0 = __floats2half2_rn((g.x / (1.f + __expf(-g.x))) * xp.x,
                                   (g.y / (1.f + __expf(-g.y))) * xp.y);
    __half2 h1 = __floats2half2_rn((g.z / (1.f + __expf(-g.z))) * xp.z,
                                   (g.w / (1.f + __expf(-g.w))) * xp.w);
    uint2 packed = make_uint2(*reinterpret_cast<uint32_t*>(&h0),
                              *reinterpret_cast<uint32_t*>(&h1));
    *reinterpret_cast<uint2*>(fmh + (size_t)row * FF_IN + col) = packed;
}

// ---------------- launch ----------------
extern "C" void kernel_launch(void* const* d_in, const int* in_sizes, int n_in,
                              void* d_out, int out_size) {
    const float* h_states = (const float*)d_in[0];
    const float* Wq  = (const float*)d_in[1];
    const float* Wk  = (const float*)d_in[2];
    const float* Wv  = (const float*)d_in[3];
    const float* Wqb = (const float*)d_in[4];
    const float* Wkb = (const float*)d_in[5];
    const float* Wo  = (const float*)d_in[6];
    const float* bo  = (const float*)d_in[7];
    const float* W1  = (const float*)d_in[8];
    const float* b1  = (const float*)d_in[9];
    const float* W2  = (const float*)d_in[10];
    const float* b2  = (const float*)d_in[11];
    const float* lam = (const float*)d_in[12];
    const float* l2s = (const float*)d_in[13];
    float* out = (float*)d_out;

    float *q, *k, *v, *qb, *kb, *pkb, *cs, *sbv, *ao, *u;
    __half *xh, *yh, *fmh, *wqh, *wkh, *wvh, *wqbh, *wkbh, *woh, *w1h, *w2h;
    cudaGetSymbolAddress((void**)&q,  g_q);
    cudaGetSymbolAddress((void**)&k,  g_k);
    cudaGetSymbolAddress((void**)&v,  g_v);
    cudaGetSymbolAddress((void**)&qb, g_qb);
    cudaGetSymbolAddress((void**)&kb, g_kb);
    cudaGetSymbolAddress((void**)&pkb, g_pkb);
    cudaGetSymbolAddress((void**)&cs, g_cs);
    cudaGetSymbolAddress((void**)&sbv, g_sb);
    cudaGetSymbolAddress((void**)&ao, g_ao);
    cudaGetSymbolAddress((void**)&u,  g_u);
    cudaGetSymbolAddress((void**)&xh,  g_xh);
    cudaGetSymbolAddress((void**)&yh,  g_yh);
    cudaGetSymbolAddress((void**)&fmh, g_fmh);
    cudaGetSymbolAddress((void**)&wqh,  g_wqh);
    cudaGetSymbolAddress((void**)&wkh,  g_wkh);
    cudaGetSymbolAddress((void**)&wvh,  g_wvh);
    cudaGetSymbolAddress((void**)&wqbh, g_wqbh);
    cudaGetSymbolAddress((void**)&wkbh, g_wkbh);
    cudaGetSymbolAddress((void**)&woh,  g_woh);
    cudaGetSymbolAddress((void**)&w1h,  g_w1h);
    cudaGetSymbolAddress((void**)&w2h,  g_w2h);

    cudaFuncSetAttribute(attn_mma_kernel,
                         cudaFuncAttributeMaxDynamicSharedMemorySize, ATT_SMEM);
    cudaFuncSetAttribute(gemm_f16_kernel,
                         cudaFuncAttributeMaxDynamicSharedMemorySize, GEMM_SMEM);

    // 0. convert + transpose weights to fp16 [N][K] (six 1024^2 in one launch)
    cvtT6_kernel<<<dim3(32, 32, 6), 256>>>(Wq, Wk, Wv, Wqb, Wkb, Wo,
                                           wqh, wkh, wvh, wqbh, wkbh, woh);
    cvtT_kernel<<<dim3(FUSEDW / 32, 32), 256>>>(W1, w1h, D_DIM, FUSEDW);
    cvtT_kernel<<<dim3(32, FF_IN / 32), 256>>>(W2, w2h, FF_IN, D_DIM);

    // 1. RMSNorm -> fp16 x
    rmsnorm_kernel<<<S_LEN, 256>>>(h_states, xh);

    // 2. five projections in one launch
    gemm_f16_kernel<<<dim3(D_DIM / 128, S_LEN / 128, 5), 256, GEMM_SMEM>>>(
        xh, wqh, wkh, wvh, wqbh, wkbh, q, k, v, qb, kb,
        S_LEN, D_DIM, D_DIM, nullptr, nullptr, nullptr, nullptr);

    // 3. l2norm + RoPE
    ropenorm_kernel<<<dim3(S_LEN, 8), 256>>>(q, k, qb, kb);

    // 4. prefix of kb; 5. sb values
    prefix_p1<<<dim3(64, 4), 256>>>(kb, cs);
    prefix_p2<<<1, 1024>>>(cs);
    prefix_p3<<<dim3(64, 4), 256>>>(kb, cs, pkb);
    sb_kernel<<<S_LEN, 512>>>(qb, pkb, sbv);

    // 6. fp16 MMA flash attention -> fp16 y
    attn_mma_kernel<<<dim3(S_LEN / 64, H_N), 256, ATT_SMEM>>>(q, k, v, sbv, l2s, yh);

    // 7. attn_out = y @ Wo + bo
    gemm_f16_kernel<<<dim3(D_DIM / 128, S_LEN / 128, 1), 256, GEMM_SMEM>>>(
        yh, woh, nullptr, nullptr, nullptr, nullptr,
        ao, nullptr, nullptr, nullptr, nullptr,
        S_LEN, D_DIM, D_DIM, bo, nullptr, nullptr, nullptr);

    // 8. u = x @ W1 + b1
    gemm_f16_kernel<<<dim3(FUSEDW / 128, S_LEN / 128, 1), 256, GEMM_SMEM>>>(
        xh, w1h, nullptr, nullptr, nullptr, nullptr,
        u, nullptr, nullptr, nullptr, nullptr,
        S_LEN, FUSEDW, D_DIM, b1, nullptr, nullptr, nullptr);

    // 9. SwiGLU -> fp16 fm
    swiglu_kernel<<<(S_LEN * FF_IN / 4) / 256, 256>>>(u, fmh);

    // 10. out = fm @ W2 + b2 + attn_out + lambda * h_states
    gemm_f16_kernel<<<dim3(D_DIM / 128, S_LEN / 128, 1), 256, GEMM_SMEM>>>(
        fmh, w2h, nullptr, nullptr, nullptr, nullptr,
        out, nullptr, nullptr, nullptr, nullptr,
        S_LEN, D_DIM, FF_IN, b2, ao, h_states, lam);
}

// round 9
// speedup vs baseline: 7.6884x; 1.1724x over previous
#include <cuda_runtime.h>
#include <cuda_bf16.h>
#include <cuda_fp16.h>
#include <cstdint>

#define S_LEN 2048
#define D_DIM 1024
#define H_N 16
#define DHALF 32
#define FF_IN 4096
#define FUSEDW 8192

// ---------------- scratch ----------------
__device__ float  g_q  [S_LEN * D_DIM];
__device__ float  g_k  [S_LEN * D_DIM];
__device__ float  g_v  [S_LEN * D_DIM];
__device__ float  g_qb [S_LEN * D_DIM];
__device__ float  g_kb [S_LEN * D_DIM];
__device__ float  g_pkb[S_LEN * D_DIM];
__device__ float  g_cs [64 * D_DIM];
__device__ float  g_sb [S_LEN * H_N];
__device__ float  g_ao [S_LEN * D_DIM];
__device__ __half g_uh [S_LEN * FUSEDW];
__device__ __half g_xh [S_LEN * D_DIM];
__device__ __half g_yh [S_LEN * D_DIM];
__device__ __half g_fmh[S_LEN * FF_IN];
__device__ __half g_wqh [D_DIM * D_DIM];   // transposed [N][K]
__device__ __half g_wkh [D_DIM * D_DIM];
__device__ __half g_wvh [D_DIM * D_DIM];
__device__ __half g_wqbh[D_DIM * D_DIM];
__device__ __half g_wkbh[D_DIM * D_DIM];
__device__ __half g_woh [D_DIM * D_DIM];
__device__ __half g_w1h [FUSEDW * D_DIM];
__device__ __half g_w2h [D_DIM * FF_IN];

// ---------------- helpers ----------------
__device__ __forceinline__ uint32_t smem_u32(const void* p) {
    uint32_t a;
    asm("{ .reg .u64 t; cvta.to.shared.u64 t, %1; cvt.u32.u64 %0, t; }" : "=r"(a) : "l"(p));
    return a;
}

#define MMA_F16(d, a, b)                                                      \
    asm volatile(                                                             \
        "mma.sync.aligned.m16n8k16.row.col.f32.f16.f16.f32 "                  \
        "{%0,%1,%2,%3}, {%4,%5,%6,%7}, {%8,%9}, {%0,%1,%2,%3};"               \
        : "+f"(d[0]), "+f"(d[1]), "+f"(d[2]), "+f"(d[3])                      \
        : "r"(a[0]), "r"(a[1]), "r"(a[2]), "r"(a[3]), "r"(b[0]), "r"(b[1]))

#define LDSM_X4(r0, r1, r2, r3, a)                                            \
    asm volatile("ldmatrix.sync.aligned.m8n8.x4.shared.b16 {%0,%1,%2,%3}, [%4];" \
                 : "=r"(r0), "=r"(r1), "=r"(r2), "=r"(r3) : "r"(a))

#define LDSM_X4T(r0, r1, r2, r3, a)                                           \
    asm volatile("ldmatrix.sync.aligned.m8n8.x4.trans.shared.b16 {%0,%1,%2,%3}, [%4];" \
                 : "=r"(r0), "=r"(r1), "=r"(r2), "=r"(r3) : "r"(a))

// ---------------- weight fp16 convert + transpose ----------------
__global__ void __launch_bounds__(256) cvtT6_kernel(
    const float* __restrict__ W0, const float* __restrict__ W1,
    const float* __restrict__ W2, const float* __restrict__ W3,
    const float* __restrict__ W4, const float* __restrict__ W5,
    __half* __restrict__ O0, __half* __restrict__ O1,
    __half* __restrict__ O2, __half* __restrict__ O3,
    __half* __restrict__ O4, __half* __restrict__ O5) {
    int z = blockIdx.z;
    const float* W = (z == 0) ? W0 : (z == 1) ? W1 : (z == 2) ? W2
                   : (z == 3) ? W3 : (z == 4) ? W4 : W5;
    __half* Wt = (z == 0) ? O0 : (z == 1) ? O1 : (z == 2) ? O2
               : (z == 3) ? O3 : (z == 4) ? O4 : O5;
    __shared__ float t[32][33];
    int n0 = blockIdx.x * 32, k0 = blockIdx.y * 32;
    int tx = threadIdx.x & 31, ty = threadIdx.x >> 5;
    #pragma unroll
    for (int i = 0; i < 32; i += 8)
        t[ty + i][tx] = W[(size_t)(k0 + ty + i) * D_DIM + n0 + tx];
    __syncthreads();
    #pragma unroll
    for (int i = 0; i < 32; i += 8)
        Wt[(size_t)(n0 + ty + i) * D_DIM + k0 + tx] = __float2half(t[tx][ty + i]);
}

__global__ void __launch_bounds__(256) cvtT_kernel(const float* __restrict__ W,
                                                   __half* __restrict__ Wt,
                                                   int K, int N) {
    __shared__ float t[32][33];
    int n0 = blockIdx.x * 32, k0 = blockIdx.y * 32;
    int tx = threadIdx.x & 31, ty = threadIdx.x >> 5;
    #pragma unroll
    for (int i = 0; i < 32; i += 8)
        t[ty + i][tx] = W[(size_t)(k0 + ty + i) * N + n0 + tx];
    __syncthreads();
    #pragma unroll
    for (int i = 0; i < 32; i += 8)
        Wt[(size_t)(n0 + ty + i) * K + k0 + tx] = __float2half(t[tx][ty + i]);
}

// ---------------- RMSNorm -> fp16 x ----------------
__global__ void __launch_bounds__(256) rmsnorm_kernel(const float* __restrict__ h,
                                                      __half* __restrict__ xh) {
    int row = blockIdx.x;
    int t = threadIdx.x;
    const float4* hr = reinterpret_cast<const float4*>(h + (size_t)row * D_DIM);
    float4 a = hr[t];
    float ss = a.x * a.x + a.y * a.y + a.z * a.z + a.w * a.w;
    __shared__ float red[8];
    #pragma unroll
    for (int off = 16; off; off >>= 1) ss += __shfl_xor_sync(0xffffffffu, ss, off);
    if ((t & 31) == 0) red[t >> 5] = ss;
    __syncthreads();
    float tot = red[0] + red[1] + red[2] + red[3] + red[4] + red[5] + red[6] + red[7];
    float r = rsqrtf(tot * (1.0f / 1024.0f) + 1.1920929e-7f);
    __half2 h0 = __floats2half2_rn(a.x * r, a.y * r);
    __half2 h1 = __floats2half2_rn(a.z * r, a.w * r);
    uint2 packed = make_uint2(*reinterpret_cast<uint32_t*>(&h0),
                              *reinterpret_cast<uint32_t*>(&h1));
    *reinterpret_cast<uint2*>(xh + (size_t)row * D_DIM + t * 4) = packed;
}

// ---------------- fp16 cp.async GEMM with ldmatrix fragments ----------------
#define HSTR 40
#define GEMM_SMEM (4 * 128 * HSTR * 2)

__global__ void __launch_bounds__(256) gemm_f16_kernel(
    const __half* __restrict__ A,
    const __half* __restrict__ B0, const __half* __restrict__ B1,
    const __half* __restrict__ B2, const __half* __restrict__ B3,
    const __half* __restrict__ B4,
    float* __restrict__ C0, float* __restrict__ C1,
    float* __restrict__ C2, float* __restrict__ C3,
    float* __restrict__ C4,
    __half* __restrict__ Ch,
    int M, int N, int K,
    const float* __restrict__ bias,
    const float* __restrict__ add0,
    const float* __restrict__ add1,
    const float* __restrict__ lamPtr)
{
    int z = blockIdx.z;
    const __half* B = (z == 0) ? B0 : (z == 1) ? B1 : (z == 2) ? B2 : (z == 3) ? B3 : B4;
    float* C = (z == 0) ? C0 : (z == 1) ? C1 : (z == 2) ? C2 : (z == 3) ? C3 : C4;

    extern __shared__ __half smh[];
    __half (*As)[128][HSTR] = reinterpret_cast<__half(*)[128][HSTR]>(smh);
    __half (*Bs)[128][HSTR] = reinterpret_cast<__half(*)[128][HSTR]>(smh + 2 * 128 * HSTR);

    int tid = threadIdx.x;
    int lane = tid & 31;
    int warp = tid >> 5;
    int warpM = warp >> 1;
    int warpN = warp & 1;
    int lr = lane >> 2;
    int lc = lane & 3;
    int bm = blockIdx.y * 128;
    int bn = blockIdx.x * 128;

    int sr = tid >> 1;
    int sc = (tid & 1) * 16;
    const __half* Ap = A + (size_t)(bm + sr) * K + sc;
    const __half* Bp = B + (size_t)(bn + sr) * K + sc;

    // ldmatrix per-thread offsets (halfs)
    int aRow = lane & 15, aCol = (lane >> 4) * 8;
    int bRow = ((lane & 16) ? 8 : 0) + (lane & 7);
    int bCol = ((lane & 8) ? 8 : 0);
    uint32_t aOff[2], bOff[4];
    #pragma unroll
    for (int mi = 0; mi < 2; mi++)
        aOff[mi] = ((warpM * 32 + mi * 16 + aRow) * HSTR + aCol) * 2;
    #pragma unroll
    for (int nip = 0; nip < 4; nip++)
        bOff[nip] = ((warpN * 64 + nip * 16 + bRow) * HSTR + bCol) * 2;

    float acc[2][8][4];
    #pragma unroll
    for (int mi = 0; mi < 2; mi++)
        #pragma unroll
        for (int ni = 0; ni < 8; ni++)
            #pragma unroll
            for (int r = 0; r < 4; r++) acc[mi][ni][r] = 0.f;

    int NT = K / 32;

    auto issue = [&](int buf, int t) {
        const __half* ga = Ap + t * 32;
        const __half* gb = Bp + t * 32;
        uint32_t da = smem_u32(&As[buf][sr][sc]);
        uint32_t db = smem_u32(&Bs[buf][sr][sc]);
        asm volatile("cp.async.ca.shared.global [%0], [%1], 16;" :: "r"(da), "l"(ga));
        asm volatile("cp.async.ca.shared.global [%0], [%1], 16;" :: "r"(da + 16), "l"(ga + 8));
        asm volatile("cp.async.ca.shared.global [%0], [%1], 16;" :: "r"(db), "l"(gb));
        asm volatile("cp.async.ca.shared.global [%0], [%1], 16;" :: "r"(db + 16), "l"(gb + 8));
        asm volatile("cp.async.commit_group;" ::: "memory");
    };

    issue(0, 0);
    for (int t = 0; t < NT; t++) {
        int buf = t & 1;
        if (t + 1 < NT) {
            issue(buf ^ 1, t + 1);
            asm volatile("cp.async.wait_group 1;" ::: "memory");
        } else {
            asm volatile("cp.async.wait_group 0;" ::: "memory");
        }
        __syncthreads();
        uint32_t aBase = smem_u32(&As[buf][0][0]);
        uint32_t bBase = smem_u32(&Bs[buf][0][0]);
        #pragma unroll
        for (int ks = 0; ks < 2; ks++) {
            uint32_t koff = ks * 32;   // 16 halfs
            uint32_t af[2][4], bf[8][2];
            #pragma unroll
            for (int mi = 0; mi < 2; mi++)
                LDSM_X4(af[mi][0], af[mi][1], af[mi][2], af[mi][3],
                        aBase + aOff[mi] + koff);
            #pragma unroll
            for (int nip = 0; nip < 4; nip++)
                LDSM_X4(bf[2 * nip][0], bf[2 * nip][1],
                        bf[2 * nip + 1][0], bf[2 * nip + 1][1],
                        bBase + bOff[nip] + koff);
            #pragma unroll
            for (int mi = 0; mi < 2; mi++)
                #pragma unroll
                for (int ni = 0; ni < 8; ni++)
                    MMA_F16(acc[mi][ni], af[mi], bf[ni]);
        }
        __syncthreads();
    }

    float lam = lamPtr ? lamPtr[0] : 0.f;
    #pragma unroll
    for (int mi = 0; mi < 2; mi++) {
        int r0 = bm + warpM * 32 + mi * 16 + lr;
        #pragma unroll
        for (int ni = 0; ni < 8; ni++) {
            int c0 = bn + warpN * 64 + ni * 8 + lc * 2;
            #pragma unroll
            for (int half_ = 0; half_ < 2; half_++) {
                int r = r0 + half_ * 8;
                float v0 = acc[mi][ni][half_ * 2 + 0];
                float v1 = acc[mi][ni][half_ * 2 + 1];
                if (bias) { v0 += bias[c0]; v1 += bias[c0 + 1]; }
                size_t idx = (size_t)r * N + c0;
                if (Ch) {
                    __half2 hv = __floats2half2_rn(v0, v1);
                    *reinterpret_cast<__half2*>(Ch + idx) = hv;
                } else {
                    if (add0) { v0 += add0[idx]; v1 += add0[idx + 1]; }
                    if (add1) { v0 += lam * add1[idx]; v1 += lam * add1[idx + 1]; }
                    C[idx]     = v0;
                    C[idx + 1] = v1;
                }
            }
        }
    }
}

// ---------------- l2norm + RoPE ----------------
__global__ void __launch_bounds__(256) ropenorm_kernel(float* q, float* k, float* qb, float* kb) {
    int s = blockIdx.x;
    int warp = threadIdx.x >> 5;
    int lane = threadIdx.x & 31;
    int idx = blockIdx.y * 8 + warp;
    int h = idx & 15;
    int a = idx >> 4;
    float* arr = (a == 0) ? q : (a == 1) ? k : (a == 2) ? qb : kb;
    float* p = arr + (size_t)s * D_DIM + h * 64;
    float x1 = p[lane];
    float x2 = p[lane + DHALF];
    float ss = x1 * x1 + x2 * x2;
    #pragma unroll
    for (int off = 16; off; off >>= 1) ss += __shfl_xor_sync(0xffffffffu, ss, off);
    float n = fmaxf(sqrtf(ss), 1e-12f);
    float inv = 1.f / n;
    x1 *= inv;
    x2 *= inv;
    float invfreq = powf(1000.0f, -(float)lane * (1.0f / 32.0f));
    float fr = (float)s * invfreq;
    float c  = __bfloat162float(__float2bfloat16(cosf(fr)));
    float sn = __bfloat162float(__float2bfloat16(sinf(fr)));
    p[lane]         = x1 * c + x2 * sn;
    p[lane + DHALF] = -x1 * sn + x2 * c;
}

// ---------------- parallel prefix sum of kb ----------------
__global__ void __launch_bounds__(256) prefix_p1(const float* __restrict__ kb,
                                                 float* __restrict__ cs) {
    int ch = blockIdx.x;
    int col = blockIdx.y * 256 + threadIdx.x;
    const float* p = kb + (size_t)(ch * 32) * D_DIM + col;
    float acc = 0.f;
    #pragma unroll
    for (int r = 0; r < 32; r++) acc += p[(size_t)r * D_DIM];
    cs[(size_t)ch * D_DIM + col] = acc;
}
__global__ void __launch_bounds__(1024) prefix_p2(float* __restrict__ cs) {
    int col = threadIdx.x;
    float run = 0.f;
    #pragma unroll 8
    for (int ch = 0; ch < 64; ch++) {
        size_t i = (size_t)ch * D_DIM + col;
        float t = cs[i];
        cs[i] = run;
        run += t;
    }
}
__global__ void __launch_bounds__(256) prefix_p3(const float* __restrict__ kb,
                                                 const float* __restrict__ cs,
                                                 float* __restrict__ pkb) {
    int ch = blockIdx.x;
    int col = blockIdx.y * 256 + threadIdx.x;
    float acc = cs[(size_t)ch * D_DIM + col];
    const float* p = kb + (size_t)(ch * 32) * D_DIM + col;
    float* o = pkb + (size_t)(ch * 32) * D_DIM + col;
    #pragma unroll
    for (int r = 0; r < 32; r++) {
        acc += p[(size_t)r * D_DIM];
        o[(size_t)r * D_DIM] = acc;
    }
}

// ---------------- sb values ----------------
__global__ void __launch_bounds__(512) sb_kernel(const float* __restrict__ qb,
                                                 const float* __restrict__ pkb,
                                                 float* __restrict__ sbv) {
    int s = blockIdx.x;
    int h = threadIdx.x >> 5;
    int lane = threadIdx.x & 31;
    size_t off = (size_t)s * D_DIM + h * 64;
    float v = qb[off + lane] * pkb[off + lane] +
              qb[off + lane + DHALF] * pkb[off + lane + DHALF];
    #pragma unroll
    for (int o = 16; o; o >>= 1) v += __shfl_xor_sync(0xffffffffu, v, o);
    if (lane == 0) sbv[s * H_N + h] = 0.125f * v;
}

// ---------------- fp16 MMA flash attention with ldmatrix ----------------
// Qs/Ks/Ps/Vs all [64][QSH] half, row-major k-contig (Vs rows = kpos).
#define QSH 72
#define ATT_SMEM (4 * 64 * QSH * 2 + 256 * 4)

__global__ void __launch_bounds__(256) attn_mma_kernel(
    const float* __restrict__ q, const float* __restrict__ k, const float* __restrict__ v,
    const float* __restrict__ sbv, const float* __restrict__ l2sp,
    __half* __restrict__ yh)
{
    extern __shared__ __half smah[];
    __half (*Qs)[QSH] = reinterpret_cast<__half(*)[QSH]>(smah);
    __half (*Ks)[QSH] = reinterpret_cast<__half(*)[QSH]>(smah + 64 * QSH);
    __half (*Ps)[QSH] = reinterpret_cast<__half(*)[QSH]>(smah + 2 * 64 * QSH);
    __half (*Vs)[QSH] = reinterpret_cast<__half(*)[QSH]>(smah + 3 * 64 * QSH);
    float* red_m = reinterpret_cast<float*>(smah + 4 * 64 * QSH);
    float* red_l = red_m + 128;

    int h = blockIdx.y;
    int q0 = blockIdx.x * 64;
    int tid = threadIdx.x;
    int lane = tid & 31, warp = tid >> 5;
    int wm = warp >> 1;
    int wn = warp & 1;
    int lr = lane >> 2;
    int lc = lane & 3;

    // ldmatrix offsets (halfs*2 = bytes)
    int aRow = lane & 15, aCol = (lane >> 4) * 8;
    uint32_t qOff = ((wm * 16 + aRow) * QSH + aCol) * 2;          // A for QK & PV
    int bRow = ((lane & 16) ? 8 : 0) + (lane & 7);
    int bCol = ((lane & 8) ? 8 : 0);
    uint32_t kOff[2];
    #pragma unroll
    for (int nip = 0; nip < 2; nip++)
        kOff[nip] = ((wn * 32 + nip * 16 + bRow) * QSH + bCol) * 2;
    // PV B (trans): row = kpos, col = d
    int tRow = ((lane & 8) ? 8 : 0) + (lane & 7);
    int tCol = ((lane & 16) ? 8 : 0);
    uint32_t vOff[2];
    #pragma unroll
    for (int nip = 0; nip < 2; nip++)
        vOff[nip] = (tRow * QSH + wn * 32 + nip * 16 + tCol) * 2;

    uint32_t qBase = smem_u32(&Qs[0][0]);
    uint32_t kBase = smem_u32(&Ks[0][0]);
    uint32_t pBase = smem_u32(&Ps[0][0]);
    uint32_t vBase = smem_u32(&Vs[0][0]);

    // stage Q
    {
        int r = tid >> 2, c0 = (tid & 3) * 16;
        const float* src = q + (size_t)(q0 + r) * D_DIM + h * 64 + c0;
        #pragma unroll
        for (int j = 0; j < 4; j++) {
            float4 f = *reinterpret_cast<const float4*>(src + j * 4);
            __half2 p0 = __floats2half2_rn(f.x, f.y);
            __half2 p1 = __floats2half2_rn(f.z, f.w);
            *reinterpret_cast<uint2*>(&Qs[r][c0 + j * 4]) =
                make_uint2(*reinterpret_cast<uint32_t*>(&p0),
                           *reinterpret_cast<uint32_t*>(&p1));
        }
    }

    float m0 = -1e30f, m1 = -1e30f, l0 = 0.f, l1 = 0.f;
    float o[4][4];
    #pragma unroll
    for (int ni = 0; ni < 4; ni++)
        #pragma unroll
        for (int j = 0; j < 4; j++) o[ni][j] = 0.f;

    int row0 = wm * 16 + lr;
    int row1 = row0 + 8;
    int nt = blockIdx.x + 1;

    for (int kt = 0; kt < nt; kt++) {
        int kbase = kt * 64;
        __syncthreads();
        {
            int r = tid >> 2, c0 = (tid & 3) * 16;
            const float* ksrc = k + (size_t)(kbase + r) * D_DIM + h * 64 + c0;
            const float* vsrc = v + (size_t)(kbase + r) * D_DIM + h * 64 + c0;
            #pragma unroll
            for (int j = 0; j < 4; j++) {
                float4 f = *reinterpret_cast<const float4*>(ksrc + j * 4);
                __half2 p0 = __floats2half2_rn(f.x, f.y);
                __half2 p1 = __floats2half2_rn(f.z, f.w);
                *reinterpret_cast<uint2*>(&Ks[r][c0 + j * 4]) =
                    make_uint2(*reinterpret_cast<uint32_t*>(&p0),
                               *reinterpret_cast<uint32_t*>(&p1));
                float4 g = *reinterpret_cast<const float4*>(vsrc + j * 4);
                __half2 q0h = __floats2half2_rn(g.x, g.y);
                __half2 q1h = __floats2half2_rn(g.z, g.w);
                *reinterpret_cast<uint2*>(&Vs[r][c0 + j * 4]) =
                    make_uint2(*reinterpret_cast<uint32_t*>(&q0h),
                               *reinterpret_cast<uint32_t*>(&q1h));
            }
        }
        __syncthreads();

        // S = Q . K^T (ldmatrix frags)
        float s[4][4];
        #pragma unroll
        for (int ni = 0; ni < 4; ni++)
            #pragma unroll
            for (int j = 0; j < 4; j++) s[ni][j] = 0.f;
        #pragma unroll
        for (int ks = 0; ks < 4; ks++) {
            uint32_t kbyte = ks * 32;
            uint32_t af[4], bf[4][2];
            LDSM_X4(af[0], af[1], af[2], af[3], qBase + qOff + kbyte);
            #pragma unroll
            for (int nip = 0; nip < 2; nip++)
                LDSM_X4(bf[2 * nip][0], bf[2 * nip][1],
                        bf[2 * nip + 1][0], bf[2 * nip + 1][1],
                        kBase + kOff[nip] + kbyte);
            #pragma unroll
            for (int ni = 0; ni < 4; ni++)
                MMA_F16(s[ni], af, bf[ni]);
        }
        if (kt == nt - 1) {
            #pragma unroll
            for (int ni = 0; ni < 4; ni++) {
                int cbase = wn * 32 + ni * 8 + lc * 2;
                #pragma unroll
                for (int j = 0; j < 4; j++) {
                    int row = (j < 2) ? row0 : row1;
                    int col = cbase + (j & 1);
                    if (col > row) s[ni][j] = -1e30f;
                }
            }
        }
        float mx0 = -1e30f, mx1 = -1e30f;
        #pragma unroll
        for (int ni = 0; ni < 4; ni++) {
            mx0 = fmaxf(mx0, fmaxf(s[ni][0], s[ni][1]));
            mx1 = fmaxf(mx1, fmaxf(s[ni][2], s[ni][3]));
        }
        mx0 = fmaxf(mx0, __shfl_xor_sync(0xffffffffu, mx0, 1));
        mx0 = fmaxf(mx0, __shfl_xor_sync(0xffffffffu, mx0, 2));
        mx1 = fmaxf(mx1, __shfl_xor_sync(0xffffffffu, mx1, 1));
        mx1 = fmaxf(mx1, __shfl_xor_sync(0xffffffffu, mx1, 2));
        if (lc == 0) {
            red_m[wn * 64 + row0] = mx0;
            red_m[wn * 64 + row1] = mx1;
        }
        __syncthreads();
        float mn0 = fmaxf(m0, fmaxf(red_m[row0], red_m[64 + row0]));
        float mn1 = fmaxf(m1, fmaxf(red_m[row1], red_m[64 + row1]));
        float corr0 = __expf(m0 - mn0);
        float corr1 = __expf(m1 - mn1);
        float ls0 = 0.f, ls1 = 0.f;
        #pragma unroll
        for (int ni = 0; ni < 4; ni++) {
            int cbase = wn * 32 + ni * 8 + lc * 2;
            float p0 = __expf(s[ni][0] - mn0);
            float p1 = __expf(s[ni][1] - mn0);
            float p2 = __expf(s[ni][2] - mn1);
            float p3 = __expf(s[ni][3] - mn1);
            ls0 += p0 + p1;
            ls1 += p2 + p3;
            __half2 hp0 = __floats2half2_rn(p0, p1);
            __half2 hp1 = __floats2half2_rn(p2, p3);
            *reinterpret_cast<uint32_t*>(&Ps[row0][cbase]) =
                *reinterpret_cast<uint32_t*>(&hp0);
            *reinterpret_cast<uint32_t*>(&Ps[row1][cbase]) =
                *reinterpret_cast<uint32_t*>(&hp1);
        }
        ls0 += __shfl_xor_sync(0xffffffffu, ls0, 1);
        ls0 += __shfl_xor_sync(0xffffffffu, ls0, 2);
        ls1 += __shfl_xor_sync(0xffffffffu, ls1, 1);
        ls1 += __shfl_xor_sync(0xffffffffu, ls1, 2);
        if (lc == 0) {
            red_l[wn * 64 + row0] = ls0;
            red_l[wn * 64 + row1] = ls1;
        }
        __syncthreads();
        l0 = l0 * corr0 + red_l[row0] + red_l[64 + row0];
        l1 = l1 * corr1 + red_l[row1] + red_l[64 + row1];
        m0 = mn0;
        m1 = mn1;
        #pragma unroll
        for (int ni = 0; ni < 4; ni++) {
            o[ni][0] *= corr0;
            o[ni][1] *= corr0;
            o[ni][2] *= corr1;
            o[ni][3] *= corr1;
        }
        // O += P . V  (A = Ps via ldmatrix; B = Vs via ldmatrix.trans)
        #pragma unroll
        for (int ks = 0; ks < 4; ks++) {
            uint32_t af[4], bf[4][2];
            LDSM_X4(af[0], af[1], af[2], af[3], pBase + qOff + ks * 32);
            #pragma unroll
            for (int nip = 0; nip < 2; nip++)
                LDSM_X4T(bf[2 * nip][0], bf[2 * nip][1],
                         bf[2 * nip + 1][0], bf[2 * nip + 1][1],
                         vBase + vOff[nip] + ks * 16 * QSH * 2);
            #pragma unroll
            for (int ni = 0; ni < 4; ni++)
                MMA_F16(o[ni], af, bf[ni]);
        }
    }

    float l2sv = l2sp[0];
    float inv0 = l2sv / l0;
    float inv1 = l2sv / l1;
    int g0 = q0 + row0, g1 = q0 + row1;
    float sb0 = sbv[g0 * H_N + h];
    float sb1 = sbv[g1 * H_N + h];
    #pragma unroll
    for (int ni = 0; ni < 4; ni++) {
        int col = h * 64 + wn * 32 + ni * 8 + lc * 2;
        __half2 r0v = __floats2half2_rn(o[ni][0] * inv0 + sb0, o[ni][1] * inv0 + sb0);
        __half2 r1v = __floats2half2_rn(o[ni][2] * inv1 + sb1, o[ni][3] * inv1 + sb1);
        *reinterpret_cast<__half2*>(&yh[(size_t)g0 * D_DIM + col]) = r0v;
        *reinterpret_cast<__half2*>(&yh[(size_t)g1 * D_DIM + col]) = r1v;
    }
}

// ---------------- SwiGLU (fp16 u -> fp16 fm) ----------------
__global__ void __launch_bounds__(256) swiglu_kernel(const __half* __restrict__ u,
                                                     __half* __restrict__ fmh) {
    int i = blockIdx.x * blockDim.x + threadIdx.x;   // over (2048*4096)/8
    int e = i * 8;
    int row = e >> 12;
    int col = e & 4095;
    uint4 xp4 = *reinterpret_cast<const uint4*>(u + (size_t)row * FUSEDW + col);
    uint4 g4  = *reinterpret_cast<const uint4*>(u + (size_t)row * FUSEDW + FF_IN + col);
    uint4 o4;
    const __half2* xp = reinterpret_cast<const __half2*>(&xp4);
    const __half2* gg = reinterpret_cast<const __half2*>(&g4);
    __half2* oo = reinterpret_cast<__half2*>(&o4);
    #pragma unroll
    for (int j = 0; j < 4; j++) {
        float2 xf = __half22float2(xp[j]);
        float2 gf = __half22float2(gg[j]);
        float a = (gf.x / (1.f + __expf(-gf.x))) * xf.x;
        float b = (gf.y / (1.f + __expf(-gf.y))) * xf.y;
        oo[j] = __floats2half2_rn(a, b);
    }
    *reinterpret_cast<uint4*>(fmh + (size_t)row * FF_IN + col) = o4;
}

// ---------------- launch ----------------
extern "C" void kernel_launch(void* const* d_in, const int* in_sizes, int n_in,
                              void* d_out, int out_size) {
    const float* h_states = (const float*)d_in[0];
    const float* Wq  = (const float*)d_in[1];
    const float* Wk  = (const float*)d_in[2];
    const float* Wv  = (const float*)d_in[3];
    const float* Wqb = (const float*)d_in[4];
    const float* Wkb = (const float*)d_in[5];
    const float* Wo  = (const float*)d_in[6];
    const float* bo  = (const float*)d_in[7];
    const float* W1  = (const float*)d_in[8];
    const float* b1  = (const float*)d_in[9];
    const float* W2  = (const float*)d_in[10];
    const float* b2  = (const float*)d_in[11];
    const float* lam = (const float*)d_in[12];
    const float* l2s = (const float*)d_in[13];
    float* out = (float*)d_out;

    float *q, *k, *v, *qb, *kb, *pkb, *cs, *sbv, *ao;
    __half *uh, *xh, *yh, *fmh, *wqh, *wkh, *wvh, *wqbh, *wkbh, *woh, *w1h, *w2h;
    cudaGetSymbolAddress((void**)&q,  g_q);
    cudaGetSymbolAddress((void**)&k,  g_k);
    cudaGetSymbolAddress((void**)&v,  g_v);
    cudaGetSymbolAddress((void**)&qb, g_qb);
    cudaGetSymbolAddress((void**)&kb, g_kb);
    cudaGetSymbolAddress((void**)&pkb, g_pkb);
    cudaGetSymbolAddress((void**)&cs, g_cs);
    cudaGetSymbolAddress((void**)&sbv, g_sb);
    cudaGetSymbolAddress((void**)&ao, g_ao);
    cudaGetSymbolAddress((void**)&uh, g_uh);
    cudaGetSymbolAddress((void**)&xh,  g_xh);
    cudaGetSymbolAddress((void**)&yh,  g_yh);
    cudaGetSymbolAddress((void**)&fmh, g_fmh);
    cudaGetSymbolAddress((void**)&wqh,  g_wqh);
    cudaGetSymbolAddress((void**)&wkh,  g_wkh);
    cudaGetSymbolAddress((void**)&wvh,  g_wvh);
    cudaGetSymbolAddress((void**)&wqbh, g_wqbh);
    cudaGetSymbolAddress((void**)&wkbh, g_wkbh);
    cudaGetSymbolAddress((void**)&woh,  g_woh);
    cudaGetSymbolAddress((void**)&w1h,  g_w1h);
    cudaGetSymbolAddress((void**)&w2h,  g_w2h);

    cudaFuncSetAttribute(attn_mma_kernel,
                         cudaFuncAttributeMaxDynamicSharedMemorySize, ATT_SMEM);
    cudaFuncSetAttribute(gemm_f16_kernel,
                         cudaFuncAttributeMaxDynamicSharedMemorySize, GEMM_SMEM);

    // 0. convert + transpose weights to fp16 [N][K]
    cvtT6_kernel<<<dim3(32, 32, 6), 256>>>(Wq, Wk, Wv, Wqb, Wkb, Wo,
                                           wqh, wkh, wvh, wqbh, wkbh, woh);
    cvtT_kernel<<<dim3(FUSEDW / 32, 32), 256>>>(W1, w1h, D_DIM, FUSEDW);
    cvtT_kernel<<<dim3(32, FF_IN / 32), 256>>>(W2, w2h, FF_IN, D_DIM);

    // 1. RMSNorm -> fp16 x
    rmsnorm_kernel<<<S_LEN, 256>>>(h_states, xh);

    // 2. five projections
    gemm_f16_kernel<<<dim3(D_DIM / 128, S_LEN / 128, 5), 256, GEMM_SMEM>>>(
        xh, wqh, wkh, wvh, wqbh, wkbh, q, k, v, qb, kb, nullptr,
        S_LEN, D_DIM, D_DIM, nullptr, nullptr, nullptr, nullptr);

    // 3. l2norm + RoPE
    ropenorm_kernel<<<dim3(S_LEN, 8), 256>>>(q, k, qb, kb);

    // 4. prefix of kb; 5. sb values
    prefix_p1<<<dim3(64, 4), 256>>>(kb, cs);
    prefix_p2<<<1, 1024>>>(cs);
    prefix_p3<<<dim3(64, 4), 256>>>(kb, cs, pkb);
    sb_kernel<<<S_LEN, 512>>>(qb, pkb, sbv);

    // 6. attention -> fp16 y
    attn_mma_kernel<<<dim3(S_LEN / 64, H_N), 256, ATT_SMEM>>>(q, k, v, sbv, l2s, yh);

    // 7. attn_out = y @ Wo + bo
    gemm_f16_kernel<<<dim3(D_DIM / 128, S_LEN / 128, 1), 256, GEMM_SMEM>>>(
        yh, woh, nullptr, nullptr, nullptr, nullptr,
        ao, nullptr, nullptr, nullptr, nullptr, nullptr,
        S_LEN, D_DIM, D_DIM, bo, nullptr, nullptr, nullptr);

    // 8. u = x @ W1 + b1 -> fp16
    gemm_f16_kernel<<<dim3(FUSEDW / 128, S_LEN / 128, 1), 256, GEMM_SMEM>>>(
        xh, w1h, nullptr, nullptr, nullptr, nullptr,
        nullptr, nullptr, nullptr, nullptr, nullptr, uh,
        S_LEN, FUSEDW, D_DIM, b1, nullptr, nullptr, nullptr);

    // 9. SwiGLU -> fp16 fm
    swiglu_kernel<<<(S_LEN * FF_IN / 8) / 256, 256>>>(uh, fmh);

    // 10. out = fm @ W2 + b2 + attn_out + lambda * h_states
    gemm_f16_kernel<<<dim3(D_DIM / 128, S_LEN / 128, 1), 256, GEMM_SMEM>>>(
        fmh, w2h, nullptr, nullptr, nullptr, nullptr,
        out, nullptr, nullptr, nullptr, nullptr, nullptr,
        S_LEN, D_DIM, FF_IN, b2, ao, h_states, lam);
}

// round 10
// speedup vs baseline: 8.3108x; 1.0809x over previous
#include <cuda_runtime.h>
#include <cuda_bf16.h>
#include <cuda_fp16.h>
#include <cstdint>

#define S_LEN 2048
#define D_DIM 1024
#define H_N 16
#define DHALF 32
#define FF_IN 4096
#define FUSEDW 8192

// ---------------- scratch ----------------
__device__ float  g_q  [S_LEN * D_DIM];
__device__ float  g_k  [S_LEN * D_DIM];
__device__ float  g_v  [S_LEN * D_DIM];
__device__ float  g_qb [S_LEN * D_DIM];
__device__ float  g_kb [S_LEN * D_DIM];
__device__ float  g_pkb[S_LEN * D_DIM];
__device__ float  g_cs [64 * D_DIM];
__device__ float  g_sb [S_LEN * H_N];
__device__ float  g_ao [S_LEN * D_DIM];
__device__ __half g_uh [S_LEN * FUSEDW];
__device__ __half g_xh [S_LEN * D_DIM];
__device__ __half g_yh [S_LEN * D_DIM];
__device__ __half g_fmh[S_LEN * FF_IN];
__device__ __half g_qhh[S_LEN * D_DIM];
__device__ __half g_khh[S_LEN * D_DIM];
__device__ __half g_vhh[S_LEN * D_DIM];
__device__ __half g_wqh [D_DIM * D_DIM];
__device__ __half g_wkh [D_DIM * D_DIM];
__device__ __half g_wvh [D_DIM * D_DIM];
__device__ __half g_wqbh[D_DIM * D_DIM];
__device__ __half g_wkbh[D_DIM * D_DIM];
__device__ __half g_woh [D_DIM * D_DIM];
__device__ __half g_w1h [FUSEDW * D_DIM];
__device__ __half g_w2h [D_DIM * FF_IN];

// ---------------- helpers ----------------
__device__ __forceinline__ uint32_t smem_u32(const void* p) {
    uint32_t a;
    asm("{ .reg .u64 t; cvta.to.shared.u64 t, %1; cvt.u32.u64 %0, t; }" : "=r"(a) : "l"(p));
    return a;
}

#define MMA_F16(d, a, b)                                                      \
    asm volatile(                                                             \
        "mma.sync.aligned.m16n8k16.row.col.f32.f16.f16.f32 "                  \
        "{%0,%1,%2,%3}, {%4,%5,%6,%7}, {%8,%9}, {%0,%1,%2,%3};"               \
        : "+f"(d[0]), "+f"(d[1]), "+f"(d[2]), "+f"(d[3])                      \
        : "r"(a[0]), "r"(a[1]), "r"(a[2]), "r"(a[3]), "r"(b[0]), "r"(b[1]))

#define LDSM_X4(r0, r1, r2, r3, a)                                            \
    asm volatile("ldmatrix.sync.aligned.m8n8.x4.shared.b16 {%0,%1,%2,%3}, [%4];" \
                 : "=r"(r0), "=r"(r1), "=r"(r2), "=r"(r3) : "r"(a))

#define LDSM_X4T(r0, r1, r2, r3, a)                                           \
    asm volatile("ldmatrix.sync.aligned.m8n8.x4.trans.shared.b16 {%0,%1,%2,%3}, [%4];" \
                 : "=r"(r0), "=r"(r1), "=r"(r2), "=r"(r3) : "r"(a))

#define EX2_F16X2(d, a)                                                       \
    asm volatile("ex2.approx.f16x2 %0, %1;" : "=r"(d) : "r"(a))

#define L2E 1.4426950408889634f

// ---------------- weight fp16 convert + transpose ----------------
__global__ void __launch_bounds__(256) cvtT6_kernel(
    const float* __restrict__ W0, const float* __restrict__ W1,
    const float* __restrict__ W2, const float* __restrict__ W3,
    const float* __restrict__ W4, const float* __restrict__ W5,
    __half* __restrict__ O0, __half* __restrict__ O1,
    __half* __restrict__ O2, __half* __restrict__ O3,
    __half* __restrict__ O4, __half* __restrict__ O5) {
    int z = blockIdx.z;
    const float* W = (z == 0) ? W0 : (z == 1) ? W1 : (z == 2) ? W2
                   : (z == 3) ? W3 : (z == 4) ? W4 : W5;
    __half* Wt = (z == 0) ? O0 : (z == 1) ? O1 : (z == 2) ? O2
               : (z == 3) ? O3 : (z == 4) ? O4 : O5;
    __shared__ float t[32][33];
    int n0 = blockIdx.x * 32, k0 = blockIdx.y * 32;
    int tx = threadIdx.x & 31, ty = threadIdx.x >> 5;
    #pragma unroll
    for (int i = 0; i < 32; i += 8)
        t[ty + i][tx] = W[(size_t)(k0 + ty + i) * D_DIM + n0 + tx];
    __syncthreads();
    #pragma unroll
    for (int i = 0; i < 32; i += 8)
        Wt[(size_t)(n0 + ty + i) * D_DIM + k0 + tx] = __float2half(t[tx][ty + i]);
}

__global__ void __launch_bounds__(256) cvtT_kernel(const float* __restrict__ W,
                                                   __half* __restrict__ Wt,
                                                   int K, int N) {
    __shared__ float t[32][33];
    int n0 = blockIdx.x * 32, k0 = blockIdx.y * 32;
    int tx = threadIdx.x & 31, ty = threadIdx.x >> 5;
    #pragma unroll
    for (int i = 0; i < 32; i += 8)
        t[ty + i][tx] = W[(size_t)(k0 + ty + i) * N + n0 + tx];
    __syncthreads();
    #pragma unroll
    for (int i = 0; i < 32; i += 8)
        Wt[(size_t)(n0 + ty + i) * K + k0 + tx] = __float2half(t[tx][ty + i]);
}

// ---------------- v -> fp16 ----------------
__global__ void __launch_bounds__(256) cvtV_kernel(const float* __restrict__ v,
                                                   __half* __restrict__ vh) {
    int i = blockIdx.x * 256 + threadIdx.x;   // over S*D/8
    size_t e = (size_t)i * 8;
    float4 a = *reinterpret_cast<const float4*>(v + e);
    float4 b = *reinterpret_cast<const float4*>(v + e + 4);
    __half2 h0 = __floats2half2_rn(a.x, a.y);
    __half2 h1 = __floats2half2_rn(a.z, a.w);
    __half2 h2 = __floats2half2_rn(b.x, b.y);
    __half2 h3 = __floats2half2_rn(b.z, b.w);
    uint4 o = make_uint4(*reinterpret_cast<uint32_t*>(&h0),
                         *reinterpret_cast<uint32_t*>(&h1),
                         *reinterpret_cast<uint32_t*>(&h2),
                         *reinterpret_cast<uint32_t*>(&h3));
    *reinterpret_cast<uint4*>(vh + e) = o;
}

// ---------------- RMSNorm -> fp16 x ----------------
__global__ void __launch_bounds__(256) rmsnorm_kernel(const float* __restrict__ h,
                                                      __half* __restrict__ xh) {
    int row = blockIdx.x;
    int t = threadIdx.x;
    const float4* hr = reinterpret_cast<const float4*>(h + (size_t)row * D_DIM);
    float4 a = hr[t];
    float ss = a.x * a.x + a.y * a.y + a.z * a.z + a.w * a.w;
    __shared__ float red[8];
    #pragma unroll
    for (int off = 16; off; off >>= 1) ss += __shfl_xor_sync(0xffffffffu, ss, off);
    if ((t & 31) == 0) red[t >> 5] = ss;
    __syncthreads();
    float tot = red[0] + red[1] + red[2] + red[3] + red[4] + red[5] + red[6] + red[7];
    float r = rsqrtf(tot * (1.0f / 1024.0f) + 1.1920929e-7f);
    __half2 h0 = __floats2half2_rn(a.x * r, a.y * r);
    __half2 h1 = __floats2half2_rn(a.z * r, a.w * r);
    uint2 packed = make_uint2(*reinterpret_cast<uint32_t*>(&h0),
                              *reinterpret_cast<uint32_t*>(&h1));
    *reinterpret_cast<uint2*>(xh + (size_t)row * D_DIM + t * 4) = packed;
}

// ---------------- fp16 cp.async GEMM (proven R8) ----------------
#define HSTR 40
#define GEMM_SMEM (4 * 128 * HSTR * 2)

__global__ void __launch_bounds__(256) gemm_f16_kernel(
    const __half* __restrict__ A,
    const __half* __restrict__ B0, const __half* __restrict__ B1,
    const __half* __restrict__ B2, const __half* __restrict__ B3,
    const __half* __restrict__ B4,
    float* __restrict__ C0, float* __restrict__ C1,
    float* __restrict__ C2, float* __restrict__ C3,
    float* __restrict__ C4,
    __half* __restrict__ Ch,
    int M, int N, int K,
    const float* __restrict__ bias,
    const float* __restrict__ add0,
    const float* __restrict__ add1,
    const float* __restrict__ lamPtr)
{
    int z = blockIdx.z;
    const __half* B = (z == 0) ? B0 : (z == 1) ? B1 : (z == 2) ? B2 : (z == 3) ? B3 : B4;
    float* C = (z == 0) ? C0 : (z == 1) ? C1 : (z == 2) ? C2 : (z == 3) ? C3 : C4;

    extern __shared__ __half smh[];
    __half (*As)[128][HSTR] = reinterpret_cast<__half(*)[128][HSTR]>(smh);
    __half (*Bs)[128][HSTR] = reinterpret_cast<__half(*)[128][HSTR]>(smh + 2 * 128 * HSTR);

    int tid = threadIdx.x;
    int lane = tid & 31;
    int warp = tid >> 5;
    int warpM = warp >> 1;
    int warpN = warp & 1;
    int lr = lane >> 2;
    int lc = lane & 3;
    int bm = blockIdx.y * 128;
    int bn = blockIdx.x * 128;

    int sr = tid >> 1;
    int sc = (tid & 1) * 16;
    const __half* Ap = A + (size_t)(bm + sr) * K + sc;
    const __half* Bp = B + (size_t)(bn + sr) * K + sc;

    int aRow = lane & 15, aCol = (lane >> 4) * 8;
    int bRow = ((lane & 16) ? 8 : 0) + (lane & 7);
    int bCol = ((lane & 8) ? 8 : 0);
    uint32_t aOff[2], bOff[4];
    #pragma unroll
    for (int mi = 0; mi < 2; mi++)
        aOff[mi] = ((warpM * 32 + mi * 16 + aRow) * HSTR + aCol) * 2;
    #pragma unroll
    for (int nip = 0; nip < 4; nip++)
        bOff[nip] = ((warpN * 64 + nip * 16 + bRow) * HSTR + bCol) * 2;

    float acc[2][8][4];
    #pragma unroll
    for (int mi = 0; mi < 2; mi++)
        #pragma unroll
        for (int ni = 0; ni < 8; ni++)
            #pragma unroll
            for (int r = 0; r < 4; r++) acc[mi][ni][r] = 0.f;

    int NT = K / 32;

    auto issue = [&](int buf, int t) {
        const __half* ga = Ap + t * 32;
        const __half* gb = Bp + t * 32;
        uint32_t da = smem_u32(&As[buf][sr][sc]);
        uint32_t db = smem_u32(&Bs[buf][sr][sc]);
        asm volatile("cp.async.ca.shared.global [%0], [%1], 16;" :: "r"(da), "l"(ga));
        asm volatile("cp.async.ca.shared.global [%0], [%1], 16;" :: "r"(da + 16), "l"(ga + 8));
        asm volatile("cp.async.ca.shared.global [%0], [%1], 16;" :: "r"(db), "l"(gb));
        asm volatile("cp.async.ca.shared.global [%0], [%1], 16;" :: "r"(db + 16), "l"(gb + 8));
        asm volatile("cp.async.commit_group;" ::: "memory");
    };

    issue(0, 0);
    for (int t = 0; t < NT; t++) {
        int buf = t & 1;
        if (t + 1 < NT) {
            issue(buf ^ 1, t + 1);
            asm volatile("cp.async.wait_group 1;" ::: "memory");
        } else {
            asm volatile("cp.async.wait_group 0;" ::: "memory");
        }
        __syncthreads();
        uint32_t aBase = smem_u32(&As[buf][0][0]);
        uint32_t bBase = smem_u32(&Bs[buf][0][0]);
        #pragma unroll
        for (int ks = 0; ks < 2; ks++) {
            uint32_t koff = ks * 32;
            uint32_t af[2][4], bf[8][2];
            #pragma unroll
            for (int mi = 0; mi < 2; mi++)
                LDSM_X4(af[mi][0], af[mi][1], af[mi][2], af[mi][3],
                        aBase + aOff[mi] + koff);
            #pragma unroll
            for (int nip = 0; nip < 4; nip++)
                LDSM_X4(bf[2 * nip][0], bf[2 * nip][1],
                        bf[2 * nip + 1][0], bf[2 * nip + 1][1],
                        bBase + bOff[nip] + koff);
            #pragma unroll
            for (int mi = 0; mi < 2; mi++)
                #pragma unroll
                for (int ni = 0; ni < 8; ni++)
                    MMA_F16(acc[mi][ni], af[mi], bf[ni]);
        }
        __syncthreads();
    }

    float lam = lamPtr ? lamPtr[0] : 0.f;
    #pragma unroll
    for (int mi = 0; mi < 2; mi++) {
        int r0 = bm + warpM * 32 + mi * 16 + lr;
        #pragma unroll
        for (int ni = 0; ni < 8; ni++) {
            int c0 = bn + warpN * 64 + ni * 8 + lc * 2;
            #pragma unroll
            for (int half_ = 0; half_ < 2; half_++) {
                int r = r0 + half_ * 8;
                float v0 = acc[mi][ni][half_ * 2 + 0];
                float v1 = acc[mi][ni][half_ * 2 + 1];
                if (bias) { v0 += bias[c0]; v1 += bias[c0 + 1]; }
                size_t idx = (size_t)r * N + c0;
                if (Ch) {
                    __half2 hv = __floats2half2_rn(v0, v1);
                    *reinterpret_cast<__half2*>(Ch + idx) = hv;
                } else {
                    if (add0) { v0 += add0[idx]; v1 += add0[idx + 1]; }
                    if (add1) { v0 += lam * add1[idx]; v1 += lam * add1[idx + 1]; }
                    C[idx]     = v0;
                    C[idx + 1] = v1;
                }
            }
        }
    }
}

// ---------------- l2norm + RoPE (q,k -> fp16; qb,kb in-place fp32) ----------
__global__ void __launch_bounds__(256) ropenorm_kernel(
    const float* __restrict__ q, const float* __restrict__ k,
    float* qb, float* kb, __half* __restrict__ qh, __half* __restrict__ kh) {
    int s = blockIdx.x;
    int warp = threadIdx.x >> 5;
    int lane = threadIdx.x & 31;
    int idx = blockIdx.y * 8 + warp;
    int h = idx & 15;
    int a = idx >> 4;
    const float* src = (a == 0) ? q : (a == 1) ? k : (a == 2) ? qb : kb;
    size_t off = (size_t)s * D_DIM + h * 64;
    const float* p = src + off;
    float x1 = p[lane];
    float x2 = p[lane + DHALF];
    float ss = x1 * x1 + x2 * x2;
    #pragma unroll
    for (int o = 16; o; o >>= 1) ss += __shfl_xor_sync(0xffffffffu, ss, o);
    float n = fmaxf(sqrtf(ss), 1e-12f);
    float inv = 1.f / n;
    x1 *= inv;
    x2 *= inv;
    float invfreq = powf(1000.0f, -(float)lane * (1.0f / 32.0f));
    float fr = (float)s * invfreq;
    float c  = __bfloat162float(__float2bfloat16(cosf(fr)));
    float sn = __bfloat162float(__float2bfloat16(sinf(fr)));
    float y1 = x1 * c + x2 * sn;
    float y2 = -x1 * sn + x2 * c;
    if (a < 2) {
        __half* dst = ((a == 0) ? qh : kh) + off;
        dst[lane]         = __float2half(y1);
        dst[lane + DHALF] = __float2half(y2);
    } else {
        float* dst = ((a == 2) ? qb : kb) + off;
        dst[lane]         = y1;
        dst[lane + DHALF] = y2;
    }
}

// ---------------- parallel prefix sum of kb ----------------
__global__ void __launch_bounds__(256) prefix_p1(const float* __restrict__ kb,
                                                 float* __restrict__ cs) {
    int ch = blockIdx.x;
    int col = blockIdx.y * 256 + threadIdx.x;
    const float* p = kb + (size_t)(ch * 32) * D_DIM + col;
    float acc = 0.f;
    #pragma unroll
    for (int r = 0; r < 32; r++) acc += p[(size_t)r * D_DIM];
    cs[(size_t)ch * D_DIM + col] = acc;
}
__global__ void __launch_bounds__(1024) prefix_p2(float* __restrict__ cs) {
    int col = threadIdx.x;
    float run = 0.f;
    #pragma unroll 8
    for (int ch = 0; ch < 64; ch++) {
        size_t i = (size_t)ch * D_DIM + col;
        float t = cs[i];
        cs[i] = run;
        run += t;
    }
}
__global__ void __launch_bounds__(256) prefix_p3(const float* __restrict__ kb,
                                                 const float* __restrict__ cs,
                                                 float* __restrict__ pkb) {
    int ch = blockIdx.x;
    int col = blockIdx.y * 256 + threadIdx.x;
    float acc = cs[(size_t)ch * D_DIM + col];
    const float* p = kb + (size_t)(ch * 32) * D_DIM + col;
    float* o = pkb + (size_t)(ch * 32) * D_DIM + col;
    #pragma unroll
    for (int r = 0; r < 32; r++) {
        acc += p[(size_t)r * D_DIM];
        o[(size_t)r * D_DIM] = acc;
    }
}

// ---------------- sb values ----------------
__global__ void __launch_bounds__(512) sb_kernel(const float* __restrict__ qb,
                                                 const float* __restrict__ pkb,
                                                 float* __restrict__ sbv) {
    int s = blockIdx.x;
    int h = threadIdx.x >> 5;
    int lane = threadIdx.x & 31;
    size_t off = (size_t)s * D_DIM + h * 64;
    float v = qb[off + lane] * pkb[off + lane] +
              qb[off + lane + DHALF] * pkb[off + lane + DHALF];
    #pragma unroll
    for (int o = 16; o; o >>= 1) v += __shfl_xor_sync(0xffffffffu, v, o);
    if (lane == 0) sbv[s * H_N + h] = 0.125f * v;
}

// ---------------- fp16 flash attention: fixed-max softmax + f16x2 ex2 ------
// scores s = q.k <= 1 (unit vectors), so p = exp(s-1): no running max, no
// rescaling; l accumulated in registers, one reduction at the end.
#define QSH 72
#define ATT_SMEM (4 * 64 * QSH * 2 + 128 * 4)

__global__ void __launch_bounds__(256) attn_mma_kernel(
    const __half* __restrict__ qh, const __half* __restrict__ kh,
    const __half* __restrict__ vh,
    const float* __restrict__ sbv, const float* __restrict__ l2sp,
    __half* __restrict__ yh)
{
    extern __shared__ __half smah[];
    __half (*Qs)[QSH] = reinterpret_cast<__half(*)[QSH]>(smah);
    __half (*Ks)[QSH] = reinterpret_cast<__half(*)[QSH]>(smah + 64 * QSH);
    __half (*Ps)[QSH] = reinterpret_cast<__half(*)[QSH]>(smah + 2 * 64 * QSH);
    __half (*Vs)[QSH] = reinterpret_cast<__half(*)[QSH]>(smah + 3 * 64 * QSH);
    float* red_l = reinterpret_cast<float*>(smah + 4 * 64 * QSH);  // [2][64]

    int h = blockIdx.y;
    int q0 = blockIdx.x * 64;
    int tid = threadIdx.x;
    int lane = tid & 31, warp = tid >> 5;
    int wm = warp >> 1;
    int wn = warp & 1;
    int lr = lane >> 2;
    int lc = lane & 3;

    int aRow = lane & 15, aCol = (lane >> 4) * 8;
    uint32_t qOff = ((wm * 16 + aRow) * QSH + aCol) * 2;
    int bRow = ((lane & 16) ? 8 : 0) + (lane & 7);
    int bCol = ((lane & 8) ? 8 : 0);
    uint32_t kOff[2];
    #pragma unroll
    for (int nip = 0; nip < 2; nip++)
        kOff[nip] = ((wn * 32 + nip * 16 + bRow) * QSH + bCol) * 2;
    int tRow = ((lane & 8) ? 8 : 0) + (lane & 7);
    int tCol = ((lane & 16) ? 8 : 0);
    uint32_t vOff[2];
    #pragma unroll
    for (int nip = 0; nip < 2; nip++)
        vOff[nip] = (tRow * QSH + wn * 32 + nip * 16 + tCol) * 2;

    uint32_t qBase = smem_u32(&Qs[0][0]);
    uint32_t kBase = smem_u32(&Ks[0][0]);
    uint32_t pBase = smem_u32(&Ps[0][0]);
    uint32_t vBase = smem_u32(&Vs[0][0]);

    // stage Q (fp16 source, raw copy)
    {
        int r = tid >> 2, c0 = (tid & 3) * 16;
        const __half* src = qh + (size_t)(q0 + r) * D_DIM + h * 64 + c0;
        *reinterpret_cast<uint4*>(&Qs[r][c0])     = *reinterpret_cast<const uint4*>(src);
        *reinterpret_cast<uint4*>(&Qs[r][c0 + 8]) = *reinterpret_cast<const uint4*>(src + 8);
    }

    float l0 = 0.f, l1 = 0.f;
    float o[4][4];
    #pragma unroll
    for (int ni = 0; ni < 4; ni++)
        #pragma unroll
        for (int j = 0; j < 4; j++) o[ni][j] = 0.f;

    int row0 = wm * 16 + lr;
    int row1 = row0 + 8;
    int nt = blockIdx.x + 1;

    for (int kt = 0; kt < nt; kt++) {
        int kbase = kt * 64;
        __syncthreads();   // prev PV reads done before restage
        {
            int r = tid >> 2, c0 = (tid & 3) * 16;
            const __half* ks = kh + (size_t)(kbase + r) * D_DIM + h * 64 + c0;
            const __half* vs = vh + (size_t)(kbase + r) * D_DIM + h * 64 + c0;
            *reinterpret_cast<uint4*>(&Ks[r][c0])     = *reinterpret_cast<const uint4*>(ks);
            *reinterpret_cast<uint4*>(&Ks[r][c0 + 8]) = *reinterpret_cast<const uint4*>(ks + 8);
            *reinterpret_cast<uint4*>(&Vs[r][c0])     = *reinterpret_cast<const uint4*>(vs);
            *reinterpret_cast<uint4*>(&Vs[r][c0 + 8]) = *reinterpret_cast<const uint4*>(vs + 8);
        }
        __syncthreads();

        // S = Q . K^T
        float s[4][4];
        #pragma unroll
        for (int ni = 0; ni < 4; ni++)
            #pragma unroll
            for (int j = 0; j < 4; j++) s[ni][j] = 0.f;
        #pragma unroll
        for (int ks = 0; ks < 4; ks++) {
            uint32_t kbyte = ks * 32;
            uint32_t af[4], bf[4][2];
            LDSM_X4(af[0], af[1], af[2], af[3], qBase + qOff + kbyte);
            #pragma unroll
            for (int nip = 0; nip < 2; nip++)
                LDSM_X4(bf[2 * nip][0], bf[2 * nip][1],
                        bf[2 * nip + 1][0], bf[2 * nip + 1][1],
                        kBase + kOff[nip] + kbyte);
            #pragma unroll
            for (int ni = 0; ni < 4; ni++)
                MMA_F16(s[ni], af, bf[ni]);
        }
        if (kt == nt - 1) {
            #pragma unroll
            for (int ni = 0; ni < 4; ni++) {
                int cbase = wn * 32 + ni * 8 + lc * 2;
                #pragma unroll
                for (int j = 0; j < 4; j++) {
                    int row = (j < 2) ? row0 : row1;
                    int col = cbase + (j & 1);
                    if (col > row) s[ni][j] = -1e4f;
                }
            }
        }
        // p = exp(s - 1) via ex2.approx.f16x2 ; accumulate l in registers
        #pragma unroll
        for (int ni = 0; ni < 4; ni++) {
            int cbase = wn * 32 + ni * 8 + lc * 2;
            float t0 = fmaf(s[ni][0], L2E, -L2E);
            float t1 = fmaf(s[ni][1], L2E, -L2E);
            float t2 = fmaf(s[ni][2], L2E, -L2E);
            float t3 = fmaf(s[ni][3], L2E, -L2E);
            __half2 ht0 = __floats2half2_rn(t0, t1);
            __half2 ht1 = __floats2half2_rn(t2, t3);
            uint32_t p0, p1;
            EX2_F16X2(p0, *reinterpret_cast<uint32_t*>(&ht0));
            EX2_F16X2(p1, *reinterpret_cast<uint32_t*>(&ht1));
            *reinterpret_cast<uint32_t*>(&Ps[row0][cbase]) = p0;
            *reinterpret_cast<uint32_t*>(&Ps[row1][cbase]) = p1;
            float2 f0 = __half22float2(*reinterpret_cast<__half2*>(&p0));
            float2 f1 = __half22float2(*reinterpret_cast<__half2*>(&p1));
            l0 += f0.x + f0.y;
            l1 += f1.x + f1.y;
        }
        __syncthreads();  // P visible to cross-warp PV reads
        // O += P . V (no rescale)
        #pragma unroll
        for (int ks = 0; ks < 4; ks++) {
            uint32_t af[4], bf[4][2];
            LDSM_X4(af[0], af[1], af[2], af[3], pBase + qOff + ks * 32);
            #pragma unroll
            for (int nip = 0; nip < 2; nip++)
                LDSM_X4T(bf[2 * nip][0], bf[2 * nip][1],
                         bf[2 * nip + 1][0], bf[2 * nip + 1][1],
                         vBase + vOff[nip] + ks * 16 * QSH * 2);
            #pragma unroll
            for (int ni = 0; ni < 4; ni++)
                MMA_F16(o[ni], af, bf[ni]);
        }
    }

    // final l reduction: over lc (shuffle), then across wn (smem)
    l0 += __shfl_xor_sync(0xffffffffu, l0, 1);
    l0 += __shfl_xor_sync(0xffffffffu, l0, 2);
    l1 += __shfl_xor_sync(0xffffffffu, l1, 1);
    l1 += __shfl_xor_sync(0xffffffffu, l1, 2);
    if (lc == 0) {
        red_l[wn * 64 + row0] = l0;
        red_l[wn * 64 + row1] = l1;
    }
    __syncthreads();
    float lt0 = red_l[row0] + red_l[64 + row0];
    float lt1 = red_l[row1] + red_l[64 + row1];

    float l2sv = l2sp[0];
    float inv0 = l2sv / lt0;
    float inv1 = l2sv / lt1;
    int g0 = q0 + row0, g1 = q0 + row1;
    float sb0 = sbv[g0 * H_N + h];
    float sb1 = sbv[g1 * H_N + h];
    #pragma unroll
    for (int ni = 0; ni < 4; ni++) {
        int col = h * 64 + wn * 32 + ni * 8 + lc * 2;
        __half2 r0v = __floats2half2_rn(o[ni][0] * inv0 + sb0, o[ni][1] * inv0 + sb0);
        __half2 r1v = __floats2half2_rn(o[ni][2] * inv1 + sb1, o[ni][3] * inv1 + sb1);
        *reinterpret_cast<__half2*>(&yh[(size_t)g0 * D_DIM + col]) = r0v;
        *reinterpret_cast<__half2*>(&yh[(size_t)g1 * D_DIM + col]) = r1v;
    }
}

// ---------------- SwiGLU (fp16 u -> fp16 fm) ----------------
__global__ void __launch_bounds__(256) swiglu_kernel(const __half* __restrict__ u,
                                                     __half* __restrict__ fmh) {
    int i = blockIdx.x * blockDim.x + threadIdx.x;
    int e = i * 8;
    int row = e >> 12;
    int col = e & 4095;
    uint4 xp4 = *reinterpret_cast<const uint4*>(u + (size_t)row * FUSEDW + col);
    uint4 g4  = *reinterpret_cast<const uint4*>(u + (size_t)row * FUSEDW + FF_IN + col);
    uint4 o4;
    const __half2* xp = reinterpret_cast<const __half2*>(&xp4);
    const __half2* gg = reinterpret_cast<const __half2*>(&g4);
    __half2* oo = reinterpret_cast<__half2*>(&o4);
    #pragma unroll
    for (int j = 0; j < 4; j++) {
        float2 xf = __half22float2(xp[j]);
        float2 gf = __half22float2(gg[j]);
        float a = (gf.x / (1.f + __expf(-gf.x))) * xf.x;
        float b = (gf.y / (1.f + __expf(-gf.y))) * xf.y;
        oo[j] = __floats2half2_rn(a, b);
    }
    *reinterpret_cast<uint4*>(fmh + (size_t)row * FF_IN + col) = o4;
}

// ---------------- launch ----------------
extern "C" void kernel_launch(void* const* d_in, const int* in_sizes, int n_in,
                              void* d_out, int out_size) {
    const float* h_states = (const float*)d_in[0];
    const float* Wq  = (const float*)d_in[1];
    const float* Wk  = (const float*)d_in[2];
    const float* Wv  = (const float*)d_in[3];
    const float* Wqb = (const float*)d_in[4];
    const float* Wkb = (const float*)d_in[5];
    const float* Wo  = (const float*)d_in[6];
    const float* bo  = (const float*)d_in[7];
    const float* W1  = (const float*)d_in[8];
    const float* b1  = (const float*)d_in[9];
    const float* W2  = (const float*)d_in[10];
    const float* b2  = (const float*)d_in[11];
    const float* lam = (const float*)d_in[12];
    const float* l2s = (const float*)d_in[13];
    float* out = (float*)d_out;

    float *q, *k, *v, *qb, *kb, *pkb, *cs, *sbv, *ao;
    __half *uh, *xh, *yh, *fmh, *qhh, *khh, *vhh;
    __half *wqh, *wkh, *wvh, *wqbh, *wkbh, *woh, *w1h, *w2h;
    cudaGetSymbolAddress((void**)&q,  g_q);
    cudaGetSymbolAddress((void**)&k,  g_k);
    cudaGetSymbolAddress((void**)&v,  g_v);
    cudaGetSymbolAddress((void**)&qb, g_qb);
    cudaGetSymbolAddress((void**)&kb, g_kb);
    cudaGetSymbolAddress((void**)&pkb, g_pkb);
    cudaGetSymbolAddress((void**)&cs, g_cs);
    cudaGetSymbolAddress((void**)&sbv, g_sb);
    cudaGetSymbolAddress((void**)&ao, g_ao);
    cudaGetSymbolAddress((void**)&uh, g_uh);
    cudaGetSymbolAddress((void**)&xh,  g_xh);
    cudaGetSymbolAddress((void**)&yh,  g_yh);
    cudaGetSymbolAddress((void**)&fmh, g_fmh);
    cudaGetSymbolAddress((void**)&qhh, g_qhh);
    cudaGetSymbolAddress((void**)&khh, g_khh);
    cudaGetSymbolAddress((void**)&vhh, g_vhh);
    cudaGetSymbolAddress((void**)&wqh,  g_wqh);
    cudaGetSymbolAddress((void**)&wkh,  g_wkh);
    cudaGetSymbolAddress((void**)&wvh,  g_wvh);
    cudaGetSymbolAddress((void**)&wqbh, g_wqbh);
    cudaGetSymbolAddress((void**)&wkbh, g_wkbh);
    cudaGetSymbolAddress((void**)&woh,  g_woh);
    cudaGetSymbolAddress((void**)&w1h,  g_w1h);
    cudaGetSymbolAddress((void**)&w2h,  g_w2h);

    cudaFuncSetAttribute(attn_mma_kernel,
                         cudaFuncAttributeMaxDynamicSharedMemorySize, ATT_SMEM);
    cudaFuncSetAttribute(gemm_f16_kernel,
                         cudaFuncAttributeMaxDynamicSharedMemorySize, GEMM_SMEM);

    // 0. convert + transpose weights
    cvtT6_kernel<<<dim3(32, 32, 6), 256>>>(Wq, Wk, Wv, Wqb, Wkb, Wo,
                                           wqh, wkh, wvh, wqbh, wkbh, woh);
    cvtT_kernel<<<dim3(FUSEDW / 32, 32), 256>>>(W1, w1h, D_DIM, FUSEDW);
    cvtT_kernel<<<dim3(32, FF_IN / 32), 256>>>(W2, w2h, FF_IN, D_DIM);

    // 1. RMSNorm -> fp16 x
    rmsnorm_kernel<<<S_LEN, 256>>>(h_states, xh);

    // 2. five projections
    gemm_f16_kernel<<<dim3(D_DIM / 128, S_LEN / 128, 5), 256, GEMM_SMEM>>>(
        xh, wqh, wkh, wvh, wqbh, wkbh, q, k, v, qb, kb, nullptr,
        S_LEN, D_DIM, D_DIM, nullptr, nullptr, nullptr, nullptr);

    // 3. l2norm + RoPE (q,k -> fp16; qb,kb fp32 in-place) ; v -> fp16
    ropenorm_kernel<<<dim3(S_LEN, 8), 256>>>(q, k, qb, kb, qhh, khh);
    cvtV_kernel<<<S_LEN * D_DIM / 8 / 256, 256>>>(v, vhh);

    // 4. prefix of kb; 5. sb values
    prefix_p1<<<dim3(64, 4), 256>>>(kb, cs);
    prefix_p2<<<1, 1024>>>(cs);
    prefix_p3<<<dim3(64, 4), 256>>>(kb, cs, pkb);
    sb_kernel<<<S_LEN, 512>>>(qb, pkb, sbv);

    // 6. attention -> fp16 y
    attn_mma_kernel<<<dim3(S_LEN / 64, H_N), 256, ATT_SMEM>>>(qhh, khh, vhh, sbv, l2s, yh);

    // 7. attn_out = y @ Wo + bo
    gemm_f16_kernel<<<dim3(D_DIM / 128, S_LEN / 128, 1), 256, GEMM_SMEM>>>(
        yh, woh, nullptr, nullptr, nullptr, nullptr,
        ao, nullptr, nullptr, nullptr, nullptr, nullptr,
        S_LEN, D_DIM, D_DIM, bo, nullptr, nullptr, nullptr);

    // 8. u = x @ W1 + b1 -> fp16
    gemm_f16_kernel<<<dim3(FUSEDW / 128, S_LEN / 128, 1), 256, GEMM_SMEM>>>(
        xh, w1h, nullptr, nullptr, nullptr, nullptr,
        nullptr, nullptr, nullptr, nullptr, nullptr, uh,
        S_LEN, FUSEDW, D_DIM, b1, nullptr, nullptr, nullptr);

    // 9. SwiGLU -> fp16 fm
    swiglu_kernel<<<(S_LEN * FF_IN / 8) / 256, 256>>>(uh, fmh);

    // 10. out = fm @ W2 + b2 + attn_out + lambda * h_states
    gemm_f16_kernel<<<dim3(D_DIM / 128, S_LEN / 128, 1), 256, GEMM_SMEM>>>(
        fmh, w2h, nullptr, nullptr, nullptr, nullptr,
        out, nullptr, nullptr, nullptr, nullptr, nullptr,
        S_LEN, D_DIM, FF_IN, b2, ao, h_states, lam);
}

// round 11
// speedup vs baseline: 9.1035x; 1.0954x over previous
#include <cuda_runtime.h>
#include <cuda_bf16.h>
#include <cuda_fp16.h>
#include <cstdint>

#define S_LEN 2048
#define D_DIM 1024
#define H_N 16
#define DHALF 32
#define FF_IN 4096
#define FUSEDW 8192

// ---------------- scratch ----------------
__device__ float  g_q  [S_LEN * D_DIM];
__device__ float  g_k  [S_LEN * D_DIM];
__device__ float  g_qb [S_LEN * D_DIM];
__device__ float  g_kb [S_LEN * D_DIM];
__device__ float  g_pkb[S_LEN * D_DIM];
__device__ float  g_cs [64 * D_DIM];
__device__ float  g_sb [S_LEN * H_N];
__device__ float  g_ao [S_LEN * D_DIM];
__device__ __half g_uh [S_LEN * FUSEDW];
__device__ __half g_xh [S_LEN * D_DIM];
__device__ __half g_yh [S_LEN * D_DIM];
__device__ __half g_fmh[S_LEN * FF_IN];
__device__ __half g_qhh[S_LEN * D_DIM];
__device__ __half g_khh[S_LEN * D_DIM];
__device__ __half g_vhh[S_LEN * D_DIM];
__device__ __half g_wqh [D_DIM * D_DIM];
__device__ __half g_wkh [D_DIM * D_DIM];
__device__ __half g_wvh [D_DIM * D_DIM];
__device__ __half g_wqbh[D_DIM * D_DIM];
__device__ __half g_wkbh[D_DIM * D_DIM];
__device__ __half g_woh [D_DIM * D_DIM];
__device__ __half g_w1h [FUSEDW * D_DIM];
__device__ __half g_w2h [D_DIM * FF_IN];

// ---------------- helpers ----------------
__device__ __forceinline__ uint32_t smem_u32(const void* p) {
    uint32_t a;
    asm("{ .reg .u64 t; cvta.to.shared.u64 t, %1; cvt.u32.u64 %0, t; }" : "=r"(a) : "l"(p));
    return a;
}

#define MMA_F16(d, a, b)                                                      \
    asm volatile(                                                             \
        "mma.sync.aligned.m16n8k16.row.col.f32.f16.f16.f32 "                  \
        "{%0,%1,%2,%3}, {%4,%5,%6,%7}, {%8,%9}, {%0,%1,%2,%3};"               \
        : "+f"(d[0]), "+f"(d[1]), "+f"(d[2]), "+f"(d[3])                      \
        : "r"(a[0]), "r"(a[1]), "r"(a[2]), "r"(a[3]), "r"(b[0]), "r"(b[1]))

#define LDSM_X4(r0, r1, r2, r3, a)                                            \
    asm volatile("ldmatrix.sync.aligned.m8n8.x4.shared.b16 {%0,%1,%2,%3}, [%4];" \
                 : "=r"(r0), "=r"(r1), "=r"(r2), "=r"(r3) : "r"(a))

#define LDSM_X4T(r0, r1, r2, r3, a)                                           \
    asm volatile("ldmatrix.sync.aligned.m8n8.x4.trans.shared.b16 {%0,%1,%2,%3}, [%4];" \
                 : "=r"(r0), "=r"(r1), "=r"(r2), "=r"(r3) : "r"(a))

#define EX2_F16X2(d, a)                                                       \
    asm volatile("ex2.approx.f16x2 %0, %1;" : "=r"(d) : "r"(a))

#define L2E 1.4426950408889634f

// ---------------- weight fp16 convert + transpose ----------------
__global__ void __launch_bounds__(256) cvtT6_kernel(
    const float* __restrict__ W0, const float* __restrict__ W1,
    const float* __restrict__ W2, const float* __restrict__ W3,
    const float* __restrict__ W4, const float* __restrict__ W5,
    __half* __restrict__ O0, __half* __restrict__ O1,
    __half* __restrict__ O2, __half* __restrict__ O3,
    __half* __restrict__ O4, __half* __restrict__ O5) {
    int z = blockIdx.z;
    const float* W = (z == 0) ? W0 : (z == 1) ? W1 : (z == 2) ? W2
                   : (z == 3) ? W3 : (z == 4) ? W4 : W5;
    __half* Wt = (z == 0) ? O0 : (z == 1) ? O1 : (z == 2) ? O2
               : (z == 3) ? O3 : (z == 4) ? O4 : O5;
    __shared__ float t[32][33];
    int n0 = blockIdx.x * 32, k0 = blockIdx.y * 32;
    int tx = threadIdx.x & 31, ty = threadIdx.x >> 5;
    #pragma unroll
    for (int i = 0; i < 32; i += 8)
        t[ty + i][tx] = W[(size_t)(k0 + ty + i) * D_DIM + n0 + tx];
    __syncthreads();
    #pragma unroll
    for (int i = 0; i < 32; i += 8)
        Wt[(size_t)(n0 + ty + i) * D_DIM + k0 + tx] = __float2half(t[tx][ty + i]);
}

__global__ void __launch_bounds__(256) cvtT_kernel(const float* __restrict__ W,
                                                   __half* __restrict__ Wt,
                                                   int K, int N) {
    __shared__ float t[32][33];
    int n0 = blockIdx.x * 32, k0 = blockIdx.y * 32;
    int tx = threadIdx.x & 31, ty = threadIdx.x >> 5;
    #pragma unroll
    for (int i = 0; i < 32; i += 8)
        t[ty + i][tx] = W[(size_t)(k0 + ty + i) * N + n0 + tx];
    __syncthreads();
    #pragma unroll
    for (int i = 0; i < 32; i += 8)
        Wt[(size_t)(n0 + ty + i) * K + k0 + tx] = __float2half(t[tx][ty + i]);
}

// ---------------- RMSNorm -> fp16 x ----------------
__global__ void __launch_bounds__(256) rmsnorm_kernel(const float* __restrict__ h,
                                                      __half* __restrict__ xh) {
    int row = blockIdx.x;
    int t = threadIdx.x;
    const float4* hr = reinterpret_cast<const float4*>(h + (size_t)row * D_DIM);
    float4 a = hr[t];
    float ss = a.x * a.x + a.y * a.y + a.z * a.z + a.w * a.w;
    __shared__ float red[8];
    #pragma unroll
    for (int off = 16; off; off >>= 1) ss += __shfl_xor_sync(0xffffffffu, ss, off);
    if ((t & 31) == 0) red[t >> 5] = ss;
    __syncthreads();
    float tot = red[0] + red[1] + red[2] + red[3] + red[4] + red[5] + red[6] + red[7];
    float r = rsqrtf(tot * (1.0f / 1024.0f) + 1.1920929e-7f);
    __half2 h0 = __floats2half2_rn(a.x * r, a.y * r);
    __half2 h1 = __floats2half2_rn(a.z * r, a.w * r);
    uint2 packed = make_uint2(*reinterpret_cast<uint32_t*>(&h0),
                              *reinterpret_cast<uint32_t*>(&h1));
    *reinterpret_cast<uint2*>(xh + (size_t)row * D_DIM + t * 4) = packed;
}

// ---------------- fp16 cp.async GEMM ----------------
#define HSTR 40
#define GEMM_SMEM (4 * 128 * HSTR * 2)

__global__ void __launch_bounds__(256) gemm_f16_kernel(
    const __half* __restrict__ A,
    const __half* __restrict__ B0, const __half* __restrict__ B1,
    const __half* __restrict__ B2, const __half* __restrict__ B3,
    const __half* __restrict__ B4,
    float* __restrict__ C0, float* __restrict__ C1,
    float* __restrict__ C2, float* __restrict__ C3,
    float* __restrict__ C4,
    __half* __restrict__ Ch,     // all-z half output (W1 -> u)
    __half* __restrict__ ChV,    // z==2 half output (v projection)
    int M, int N, int K,
    const float* __restrict__ bias,
    const float* __restrict__ add0,
    const float* __restrict__ add1,
    const float* __restrict__ lamPtr)
{
    int z = blockIdx.z;
    const __half* B = (z == 0) ? B0 : (z == 1) ? B1 : (z == 2) ? B2 : (z == 3) ? B3 : B4;
    float* C = (z == 0) ? C0 : (z == 1) ? C1 : (z == 2) ? C2 : (z == 3) ? C3 : C4;
    __half* chDst = Ch ? Ch : ((z == 2) ? ChV : nullptr);

    extern __shared__ __half smh[];
    __half (*As)[128][HSTR] = reinterpret_cast<__half(*)[128][HSTR]>(smh);
    __half (*Bs)[128][HSTR] = reinterpret_cast<__half(*)[128][HSTR]>(smh + 2 * 128 * HSTR);

    int tid = threadIdx.x;
    int lane = tid & 31;
    int warp = tid >> 5;
    int warpM = warp >> 1;
    int warpN = warp & 1;
    int lr = lane >> 2;
    int lc = lane & 3;
    int bm = blockIdx.y * 128;
    int bn = blockIdx.x * 128;

    int sr = tid >> 1;
    int sc = (tid & 1) * 16;
    const __half* Ap = A + (size_t)(bm + sr) * K + sc;
    const __half* Bp = B + (size_t)(bn + sr) * K + sc;

    int aRow = lane & 15, aCol = (lane >> 4) * 8;
    int bRow = ((lane & 16) ? 8 : 0) + (lane & 7);
    int bCol = ((lane & 8) ? 8 : 0);
    uint32_t aOff[2], bOff[4];
    #pragma unroll
    for (int mi = 0; mi < 2; mi++)
        aOff[mi] = ((warpM * 32 + mi * 16 + aRow) * HSTR + aCol) * 2;
    #pragma unroll
    for (int nip = 0; nip < 4; nip++)
        bOff[nip] = ((warpN * 64 + nip * 16 + bRow) * HSTR + bCol) * 2;

    float acc[2][8][4];
    #pragma unroll
    for (int mi = 0; mi < 2; mi++)
        #pragma unroll
        for (int ni = 0; ni < 8; ni++)
            #pragma unroll
            for (int r = 0; r < 4; r++) acc[mi][ni][r] = 0.f;

    int NT = K / 32;

    auto issue = [&](int buf, int t) {
        const __half* ga = Ap + t * 32;
        const __half* gb = Bp + t * 32;
        uint32_t da = smem_u32(&As[buf][sr][sc]);
        uint32_t db = smem_u32(&Bs[buf][sr][sc]);
        asm volatile("cp.async.ca.shared.global [%0], [%1], 16;" :: "r"(da), "l"(ga));
        asm volatile("cp.async.ca.shared.global [%0], [%1], 16;" :: "r"(da + 16), "l"(ga + 8));
        asm volatile("cp.async.ca.shared.global [%0], [%1], 16;" :: "r"(db), "l"(gb));
        asm volatile("cp.async.ca.shared.global [%0], [%1], 16;" :: "r"(db + 16), "l"(gb + 8));
        asm volatile("cp.async.commit_group;" ::: "memory");
    };

    issue(0, 0);
    for (int t = 0; t < NT; t++) {
        int buf = t & 1;
        if (t + 1 < NT) {
            issue(buf ^ 1, t + 1);
            asm volatile("cp.async.wait_group 1;" ::: "memory");
        } else {
            asm volatile("cp.async.wait_group 0;" ::: "memory");
        }
        __syncthreads();
        uint32_t aBase = smem_u32(&As[buf][0][0]);
        uint32_t bBase = smem_u32(&Bs[buf][0][0]);
        #pragma unroll
        for (int ks = 0; ks < 2; ks++) {
            uint32_t koff = ks * 32;
            uint32_t af[2][4], bf[8][2];
            #pragma unroll
            for (int mi = 0; mi < 2; mi++)
                LDSM_X4(af[mi][0], af[mi][1], af[mi][2], af[mi][3],
                        aBase + aOff[mi] + koff);
            #pragma unroll
            for (int nip = 0; nip < 4; nip++)
                LDSM_X4(bf[2 * nip][0], bf[2 * nip][1],
                        bf[2 * nip + 1][0], bf[2 * nip + 1][1],
                        bBase + bOff[nip] + koff);
            #pragma unroll
            for (int mi = 0; mi < 2; mi++)
                #pragma unroll
                for (int ni = 0; ni < 8; ni++)
                    MMA_F16(acc[mi][ni], af[mi], bf[ni]);
        }
        __syncthreads();
    }

    float lam = lamPtr ? lamPtr[0] : 0.f;
    #pragma unroll
    for (int mi = 0; mi < 2; mi++) {
        int r0 = bm + warpM * 32 + mi * 16 + lr;
        #pragma unroll
        for (int ni = 0; ni < 8; ni++) {
            int c0 = bn + warpN * 64 + ni * 8 + lc * 2;
            #pragma unroll
            for (int half_ = 0; half_ < 2; half_++) {
                int r = r0 + half_ * 8;
                float v0 = acc[mi][ni][half_ * 2 + 0];
                float v1 = acc[mi][ni][half_ * 2 + 1];
                if (bias) { v0 += bias[c0]; v1 += bias[c0 + 1]; }
                size_t idx = (size_t)r * N + c0;
                if (chDst) {
                    __half2 hv = __floats2half2_rn(v0, v1);
                    *reinterpret_cast<__half2*>(chDst + idx) = hv;
                } else {
                    if (add0) { v0 += add0[idx]; v1 += add0[idx + 1]; }
                    if (add1) { v0 += lam * add1[idx]; v1 += lam * add1[idx + 1]; }
                    C[idx]     = v0;
                    C[idx + 1] = v1;
                }
            }
        }
    }
}

// ---------------- l2norm + RoPE (q,k -> fp16; qb,kb in-place fp32) ----------
__global__ void __launch_bounds__(256) ropenorm_kernel(
    const float* __restrict__ q, const float* __restrict__ k,
    float* qb, float* kb, __half* __restrict__ qh, __half* __restrict__ kh) {
    int s = blockIdx.x;
    int warp = threadIdx.x >> 5;
    int lane = threadIdx.x & 31;
    int idx = blockIdx.y * 8 + warp;
    int h = idx & 15;
    int a = idx >> 4;
    const float* src = (a == 0) ? q : (a == 1) ? k : (a == 2) ? qb : kb;
    size_t off = (size_t)s * D_DIM + h * 64;
    const float* p = src + off;
    float x1 = p[lane];
    float x2 = p[lane + DHALF];
    float ss = x1 * x1 + x2 * x2;
    #pragma unroll
    for (int o = 16; o; o >>= 1) ss += __shfl_xor_sync(0xffffffffu, ss, o);
    float n = fmaxf(sqrtf(ss), 1e-12f);
    float inv = 1.f / n;
    x1 *= inv;
    x2 *= inv;
    float invfreq = powf(1000.0f, -(float)lane * (1.0f / 32.0f));
    float fr = (float)s * invfreq;
    float c  = __bfloat162float(__float2bfloat16(cosf(fr)));
    float sn = __bfloat162float(__float2bfloat16(sinf(fr)));
    float y1 = x1 * c + x2 * sn;
    float y2 = -x1 * sn + x2 * c;
    if (a < 2) {
        __half* dst = ((a == 0) ? qh : kh) + off;
        dst[lane]         = __float2half(y1);
        dst[lane + DHALF] = __float2half(y2);
    } else {
        float* dst = ((a == 2) ? qb : kb) + off;
        dst[lane]         = y1;
        dst[lane + DHALF] = y2;
    }
}

// ---------------- parallel prefix sum of kb ----------------
__global__ void __launch_bounds__(256) prefix_p1(const float* __restrict__ kb,
                                                 float* __restrict__ cs) {
    int ch = blockIdx.x;
    int col = blockIdx.y * 256 + threadIdx.x;
    const float* p = kb + (size_t)(ch * 32) * D_DIM + col;
    float acc = 0.f;
    #pragma unroll
    for (int r = 0; r < 32; r++) acc += p[(size_t)r * D_DIM];
    cs[(size_t)ch * D_DIM + col] = acc;
}
__global__ void __launch_bounds__(1024) prefix_p2(float* __restrict__ cs) {
    int col = threadIdx.x;
    float run = 0.f;
    #pragma unroll 8
    for (int ch = 0; ch < 64; ch++) {
        size_t i = (size_t)ch * D_DIM + col;
        float t = cs[i];
        cs[i] = run;
        run += t;
    }
}
__global__ void __launch_bounds__(256) prefix_p3(const float* __restrict__ kb,
                                                 const float* __restrict__ cs,
                                                 float* __restrict__ pkb) {
    int ch = blockIdx.x;
    int col = blockIdx.y * 256 + threadIdx.x;
    float acc = cs[(size_t)ch * D_DIM + col];
    const float* p = kb + (size_t)(ch * 32) * D_DIM + col;
    float* o = pkb + (size_t)(ch * 32) * D_DIM + col;
    #pragma unroll
    for (int r = 0; r < 32; r++) {
        acc += p[(size_t)r * D_DIM];
        o[(size_t)r * D_DIM] = acc;
    }
}

// ---------------- sb values ----------------
__global__ void __launch_bounds__(512) sb_kernel(const float* __restrict__ qb,
                                                 const float* __restrict__ pkb,
                                                 float* __restrict__ sbv) {
    int s = blockIdx.x;
    int h = threadIdx.x >> 5;
    int lane = threadIdx.x & 31;
    size_t off = (size_t)s * D_DIM + h * 64;
    float v = qb[off + lane] * pkb[off + lane] +
              qb[off + lane + DHALF] * pkb[off + lane + DHALF];
    #pragma unroll
    for (int o = 16; o; o >>= 1) v += __shfl_xor_sync(0xffffffffu, v, o);
    if (lane == 0) sbv[s * H_N + h] = 0.125f * v;
}

// ---------------- fp16 flash attention: 128-row q tiles ----------------
// 8 warps: wm=warp>>1 (32-row slice, 2 mi of 16), wn=warp&1 (32-col slice).
// Fixed-max softmax p = exp(s-1); l in registers; Q staged once per CTA.
#define QSH 72
#define ATT_SMEM (384 * QSH * 2 + 256 * 4)

__global__ void __launch_bounds__(256) attn_mma_kernel(
    const __half* __restrict__ qh, const __half* __restrict__ kh,
    const __half* __restrict__ vh,
    const float* __restrict__ sbv, const float* __restrict__ l2sp,
    __half* __restrict__ yh)
{
    extern __shared__ __half smah[];
    __half (*Qs)[QSH] = reinterpret_cast<__half(*)[QSH]>(smah);            // 128 rows
    __half (*Ks)[QSH] = reinterpret_cast<__half(*)[QSH]>(smah + 128 * QSH); // 64
    __half (*Ps)[QSH] = reinterpret_cast<__half(*)[QSH]>(smah + 192 * QSH); // 128
    __half (*Vs)[QSH] = reinterpret_cast<__half(*)[QSH]>(smah + 320 * QSH); // 64
    float* red_l = reinterpret_cast<float*>(smah + 384 * QSH);             // [2][128]

    int h = blockIdx.y;
    int q0 = blockIdx.x * 128;
    int tid = threadIdx.x;
    int lane = tid & 31, warp = tid >> 5;
    int wm = warp >> 1;
    int wn = warp & 1;
    int lr = lane >> 2;
    int lc = lane & 3;

    int aRow = lane & 15, aCol = (lane >> 4) * 8;
    uint32_t qOff[2];
    #pragma unroll
    for (int mi = 0; mi < 2; mi++)
        qOff[mi] = ((wm * 32 + mi * 16 + aRow) * QSH + aCol) * 2;
    int bRow = ((lane & 16) ? 8 : 0) + (lane & 7);
    int bCol = ((lane & 8) ? 8 : 0);
    uint32_t kOff[2];
    #pragma unroll
    for (int nip = 0; nip < 2; nip++)
        kOff[nip] = ((wn * 32 + nip * 16 + bRow) * QSH + bCol) * 2;
    int tRow = ((lane & 8) ? 8 : 0) + (lane & 7);
    int tCol = ((lane & 16) ? 8 : 0);
    uint32_t vOff[2];
    #pragma unroll
    for (int nip = 0; nip < 2; nip++)
        vOff[nip] = (tRow * QSH + wn * 32 + nip * 16 + tCol) * 2;

    uint32_t qBase = smem_u32(&Qs[0][0]);
    uint32_t kBase = smem_u32(&Ks[0][0]);
    uint32_t pBase = smem_u32(&Ps[0][0]);
    uint32_t vBase = smem_u32(&Vs[0][0]);

    // stage Q: 2 threads per row, 32 halfs each
    {
        int r = tid >> 1, c0 = (tid & 1) * 32;
        const __half* src = qh + (size_t)(q0 + r) * D_DIM + h * 64 + c0;
        #pragma unroll
        for (int j = 0; j < 4; j++)
            *reinterpret_cast<uint4*>(&Qs[r][c0 + j * 8]) =
                *reinterpret_cast<const uint4*>(src + j * 8);
    }

    float l[4] = {0.f, 0.f, 0.f, 0.f};
    float o[2][4][4];
    #pragma unroll
    for (int mi = 0; mi < 2; mi++)
        #pragma unroll
        for (int ni = 0; ni < 4; ni++)
            #pragma unroll
            for (int j = 0; j < 4; j++) o[mi][ni][j] = 0.f;

    int nt = 2 * blockIdx.x + 2;

    for (int kt = 0; kt < nt; kt++) {
        int kbase = kt * 64;
        __syncthreads();
        {
            int r = tid >> 2, c0 = (tid & 3) * 16;
            const __half* ks = kh + (size_t)(kbase + r) * D_DIM + h * 64 + c0;
            const __half* vs = vh + (size_t)(kbase + r) * D_DIM + h * 64 + c0;
            *reinterpret_cast<uint4*>(&Ks[r][c0])     = *reinterpret_cast<const uint4*>(ks);
            *reinterpret_cast<uint4*>(&Ks[r][c0 + 8]) = *reinterpret_cast<const uint4*>(ks + 8);
            *reinterpret_cast<uint4*>(&Vs[r][c0])     = *reinterpret_cast<const uint4*>(vs);
            *reinterpret_cast<uint4*>(&Vs[r][c0 + 8]) = *reinterpret_cast<const uint4*>(vs + 8);
        }
        __syncthreads();

        // S = Q . K^T
        float s[2][4][4];
        #pragma unroll
        for (int mi = 0; mi < 2; mi++)
            #pragma unroll
            for (int ni = 0; ni < 4; ni++)
                #pragma unroll
                for (int j = 0; j < 4; j++) s[mi][ni][j] = 0.f;
        #pragma unroll
        for (int ks = 0; ks < 4; ks++) {
            uint32_t kbyte = ks * 32;
            uint32_t af[2][4], bf[4][2];
            #pragma unroll
            for (int mi = 0; mi < 2; mi++)
                LDSM_X4(af[mi][0], af[mi][1], af[mi][2], af[mi][3],
                        qBase + qOff[mi] + kbyte);
            #pragma unroll
            for (int nip = 0; nip < 2; nip++)
                LDSM_X4(bf[2 * nip][0], bf[2 * nip][1],
                        bf[2 * nip + 1][0], bf[2 * nip + 1][1],
                        kBase + kOff[nip] + kbyte);
            #pragma unroll
            for (int mi = 0; mi < 2; mi++)
                #pragma unroll
                for (int ni = 0; ni < 4; ni++)
                    MMA_F16(s[mi][ni], af[mi], bf[ni]);
        }
        // causal mask: only the last two k-tiles intersect the diagonal
        if (kt >= nt - 2) {
            #pragma unroll
            for (int mi = 0; mi < 2; mi++) {
                int rg0 = q0 + wm * 32 + mi * 16 + lr;
                #pragma unroll
                for (int ni = 0; ni < 4; ni++) {
                    int cgb = kbase + wn * 32 + ni * 8 + lc * 2;
                    #pragma unroll
                    for (int j = 0; j < 4; j++) {
                        int rg = rg0 + ((j >= 2) ? 8 : 0);
                        int cg = cgb + (j & 1);
                        if (cg > rg) s[mi][ni][j] = -1e4f;
                    }
                }
            }
        }
        // p = exp(s - 1) via ex2.approx.f16x2
        #pragma unroll
        for (int mi = 0; mi < 2; mi++) {
            int r0m = wm * 32 + mi * 16 + lr;
            int r1m = r0m + 8;
            #pragma unroll
            for (int ni = 0; ni < 4; ni++) {
                int cbase = wn * 32 + ni * 8 + lc * 2;
                float t0 = fmaf(s[mi][ni][0], L2E, -L2E);
                float t1 = fmaf(s[mi][ni][1], L2E, -L2E);
                float t2 = fmaf(s[mi][ni][2], L2E, -L2E);
                float t3 = fmaf(s[mi][ni][3], L2E, -L2E);
                __half2 ht0 = __floats2half2_rn(t0, t1);
                __half2 ht1 = __floats2half2_rn(t2, t3);
                uint32_t p0, p1;
                EX2_F16X2(p0, *reinterpret_cast<uint32_t*>(&ht0));
                EX2_F16X2(p1, *reinterpret_cast<uint32_t*>(&ht1));
                *reinterpret_cast<uint32_t*>(&Ps[r0m][cbase]) = p0;
                *reinterpret_cast<uint32_t*>(&Ps[r1m][cbase]) = p1;
                float2 f0 = __half22float2(*reinterpret_cast<__half2*>(&p0));
                float2 f1 = __half22float2(*reinterpret_cast<__half2*>(&p1));
                l[mi * 2]     += f0.x + f0.y;
                l[mi * 2 + 1] += f1.x + f1.y;
            }
        }
        __syncthreads();
        // O += P . V
        #pragma unroll
        for (int ks = 0; ks < 4; ks++) {
            uint32_t af[2][4], bf[4][2];
            #pragma unroll
            for (int mi = 0; mi < 2; mi++)
                LDSM_X4(af[mi][0], af[mi][1], af[mi][2], af[mi][3],
                        pBase + qOff[mi] + ks * 32);
            #pragma unroll
            for (int nip = 0; nip < 2; nip++)
                LDSM_X4T(bf[2 * nip][0], bf[2 * nip][1],
                         bf[2 * nip + 1][0], bf[2 * nip + 1][1],
                         vBase + vOff[nip] + ks * 16 * QSH * 2);
            #pragma unroll
            for (int mi = 0; mi < 2; mi++)
                #pragma unroll
                for (int ni = 0; ni < 4; ni++)
                    MMA_F16(o[mi][ni], af[mi], bf[ni]);
        }
    }

    // l reduction
    #pragma unroll
    for (int i = 0; i < 4; i++) {
        l[i] += __shfl_xor_sync(0xffffffffu, l[i], 1);
        l[i] += __shfl_xor_sync(0xffffffffu, l[i], 2);
    }
    if (lc == 0) {
        #pragma unroll
        for (int mi = 0; mi < 2; mi++) {
            int r0m = wm * 32 + mi * 16 + lr;
            red_l[wn * 128 + r0m]     = l[mi * 2];
            red_l[wn * 128 + r0m + 8] = l[mi * 2 + 1];
        }
    }
    __syncthreads();

    float l2sv = l2sp[0];
    #pragma unroll
    for (int mi = 0; mi < 2; mi++) {
        int r0m = wm * 32 + mi * 16 + lr;
        int r1m = r0m + 8;
        float lt0 = red_l[r0m] + red_l[128 + r0m];
        float lt1 = red_l[r1m] + red_l[128 + r1m];
        float inv0 = l2sv / lt0;
        float inv1 = l2sv / lt1;
        int g0 = q0 + r0m, g1 = q0 + r1m;
        float sb0 = sbv[g0 * H_N + h];
        float sb1 = sbv[g1 * H_N + h];
        #pragma unroll
        for (int ni = 0; ni < 4; ni++) {
            int col = h * 64 + wn * 32 + ni * 8 + lc * 2;
            __half2 r0v = __floats2half2_rn(o[mi][ni][0] * inv0 + sb0,
                                            o[mi][ni][1] * inv0 + sb0);
            __half2 r1v = __floats2half2_rn(o[mi][ni][2] * inv1 + sb1,
                                            o[mi][ni][3] * inv1 + sb1);
            *reinterpret_cast<__half2*>(&yh[(size_t)g0 * D_DIM + col]) = r0v;
            *reinterpret_cast<__half2*>(&yh[(size_t)g1 * D_DIM + col]) = r1v;
        }
    }
}

// ---------------- SwiGLU (fp16 u -> fp16 fm) ----------------
__global__ void __launch_bounds__(256) swiglu_kernel(const __half* __restrict__ u,
                                                     __half* __restrict__ fmh) {
    int i = blockIdx.x * blockDim.x + threadIdx.x;
    int e = i * 8;
    int row = e >> 12;
    int col = e & 4095;
    uint4 xp4 = *reinterpret_cast<const uint4*>(u + (size_t)row * FUSEDW + col);
    uint4 g4  = *reinterpret_cast<const uint4*>(u + (size_t)row * FUSEDW + FF_IN + col);
    uint4 o4;
    const __half2* xp = reinterpret_cast<const __half2*>(&xp4);
    const __half2* gg = reinterpret_cast<const __half2*>(&g4);
    __half2* oo = reinterpret_cast<__half2*>(&o4);
    #pragma unroll
    for (int j = 0; j < 4; j++) {
        float2 xf = __half22float2(xp[j]);
        float2 gf = __half22float2(gg[j]);
        float a = (gf.x / (1.f + __expf(-gf.x))) * xf.x;
        float b = (gf.y / (1.f + __expf(-gf.y))) * xf.y;
        oo[j] = __floats2half2_rn(a, b);
    }
    *reinterpret_cast<uint4*>(fmh + (size_t)row * FF_IN + col) = o4;
}

// ---------------- launch ----------------
extern "C" void kernel_launch(void* const* d_in, const int* in_sizes, int n_in,
                              void* d_out, int out_size) {
    const float* h_states = (const float*)d_in[0];
    const float* Wq  = (const float*)d_in[1];
    const float* Wk  = (const float*)d_in[2];
    const float* Wv  = (const float*)d_in[3];
    const float* Wqb = (const float*)d_in[4];
    const float* Wkb = (const float*)d_in[5];
    const float* Wo  = (const float*)d_in[6];
    const float* bo  = (const float*)d_in[7];
    const float* W1  = (const float*)d_in[8];
    const float* b1  = (const float*)d_in[9];
    const float* W2  = (const float*)d_in[10];
    const float* b2  = (const float*)d_in[11];
    const float* lam = (const float*)d_in[12];
    const float* l2s = (const float*)d_in[13];
    float* out = (float*)d_out;

    float *q, *k, *qb, *kb, *pkb, *cs, *sbv, *ao;
    __half *uh, *xh, *yh, *fmh, *qhh, *khh, *vhh;
    __half *wqh, *wkh, *wvh, *wqbh, *wkbh, *woh, *w1h, *w2h;
    cudaGetSymbolAddress((void**)&q,  g_q);
    cudaGetSymbolAddress((void**)&k,  g_k);
    cudaGetSymbolAddress((void**)&qb, g_qb);
    cudaGetSymbolAddress((void**)&kb, g_kb);
    cudaGetSymbolAddress((void**)&pkb, g_pkb);
    cudaGetSymbolAddress((void**)&cs, g_cs);
    cudaGetSymbolAddress((void**)&sbv, g_sb);
    cudaGetSymbolAddress((void**)&ao, g_ao);
    cudaGetSymbolAddress((void**)&uh, g_uh);
    cudaGetSymbolAddress((void**)&xh,  g_xh);
    cudaGetSymbolAddress((void**)&yh,  g_yh);
    cudaGetSymbolAddress((void**)&fmh, g_fmh);
    cudaGetSymbolAddress((void**)&qhh, g_qhh);
    cudaGetSymbolAddress((void**)&khh, g_khh);
    cudaGetSymbolAddress((void**)&vhh, g_vhh);
    cudaGetSymbolAddress((void**)&wqh,  g_wqh);
    cudaGetSymbolAddress((void**)&wkh,  g_wkh);
    cudaGetSymbolAddress((void**)&wvh,  g_wvh);
    cudaGetSymbolAddress((void**)&wqbh, g_wqbh);
    cudaGetSymbolAddress((void**)&wkbh, g_wkbh);
    cudaGetSymbolAddress((void**)&woh,  g_woh);
    cudaGetSymbolAddress((void**)&w1h,  g_w1h);
    cudaGetSymbolAddress((void**)&w2h,  g_w2h);

    cudaFuncSetAttribute(attn_mma_kernel,
                         cudaFuncAttributeMaxDynamicSharedMemorySize, ATT_SMEM);
    cudaFuncSetAttribute(gemm_f16_kernel,
                         cudaFuncAttributeMaxDynamicSharedMemorySize, GEMM_SMEM);

    // one-time stream/event creation (host-side resources, created outside capture)
    static cudaStream_t s1 = nullptr;
    static cudaEvent_t evX = nullptr, evFFN = nullptr;
    if (!s1) {
        cudaStreamCreateWithFlags(&s1, cudaStreamNonBlocking);
        cudaEventCreateWithFlags(&evX, cudaEventDisableTiming);
        cudaEventCreateWithFlags(&evFFN, cudaEventDisableTiming);
    }

    // ---- main stream: shared prologue ----
    cvtT6_kernel<<<dim3(32, 32, 6), 256>>>(Wq, Wk, Wv, Wqb, Wkb, Wo,
                                           wqh, wkh, wvh, wqbh, wkbh, woh);
    rmsnorm_kernel<<<S_LEN, 256>>>(h_states, xh);
    cudaEventRecord(evX, 0);

    // ---- side stream: FFN branch (W1 convert/gemm/swiglu) ----
    cvtT_kernel<<<dim3(FUSEDW / 32, 32), 256, 0, s1>>>(W1, w1h, D_DIM, FUSEDW);
    cvtT_kernel<<<dim3(32, FF_IN / 32), 256, 0, s1>>>(W2, w2h, FF_IN, D_DIM);
    cudaStreamWaitEvent(s1, evX, 0);
    gemm_f16_kernel<<<dim3(FUSEDW / 128, S_LEN / 128, 1), 256, GEMM_SMEM, s1>>>(
        xh, w1h, nullptr, nullptr, nullptr, nullptr,
        nullptr, nullptr, nullptr, nullptr, nullptr, uh, nullptr,
        S_LEN, FUSEDW, D_DIM, b1, nullptr, nullptr, nullptr);
    swiglu_kernel<<<(S_LEN * FF_IN / 8) / 256, 256, 0, s1>>>(uh, fmh);
    cudaEventRecord(evFFN, s1);

    // ---- main stream: attention branch ----
    gemm_f16_kernel<<<dim3(D_DIM / 128, S_LEN / 128, 5), 256, GEMM_SMEM>>>(
        xh, wqh, wkh, wvh, wqbh, wkbh, q, k, nullptr, qb, kb, nullptr, vhh,
        S_LEN, D_DIM, D_DIM, nullptr, nullptr, nullptr, nullptr);

    ropenorm_kernel<<<dim3(S_LEN, 8), 256>>>(q, k, qb, kb, qhh, khh);

    prefix_p1<<<dim3(64, 4), 256>>>(kb, cs);
    prefix_p2<<<1, 1024>>>(cs);
    prefix_p3<<<dim3(64, 4), 256>>>(kb, cs, pkb);
    sb_kernel<<<S_LEN, 512>>>(qb, pkb, sbv);

    attn_mma_kernel<<<dim3(S_LEN / 128, H_N), 256, ATT_SMEM>>>(qhh, khh, vhh, sbv, l2s, yh);

    gemm_f16_kernel<<<dim3(D_DIM / 128, S_LEN / 128, 1), 256, GEMM_SMEM>>>(
        yh, woh, nullptr, nullptr, nullptr, nullptr,
        ao, nullptr, nullptr, nullptr, nullptr, nullptr, nullptr,
        S_LEN, D_DIM, D_DIM, bo, nullptr, nullptr, nullptr);

    // ---- join: final GEMM needs fm (s1) and ao (main) ----
    cudaStreamWaitEvent(0, evFFN, 0);
    gemm_f16_kernel<<<dim3(D_DIM / 128, S_LEN / 128, 1), 256, GEMM_SMEM>>>(
        fmh, w2h, nullptr, nullptr, nullptr, nullptr,
        out, nullptr, nullptr, nullptr, nullptr, nullptr, nullptr,
        S_LEN, D_DIM, FF_IN, b2, ao, h_states, lam);
}

// round 12
// speedup vs baseline: 9.2148x; 1.0122x over previous
#include <cuda_runtime.h>
#include <cuda_bf16.h>
#include <cuda_fp16.h>
#include <cstdint>

#define S_LEN 2048
#define D_DIM 1024
#define H_N 16
#define DHALF 32
#define FF_IN 4096
#define FUSEDW 8192

// ---------------- scratch ----------------
__device__ float  g_q  [S_LEN * D_DIM];
__device__ float  g_k  [S_LEN * D_DIM];
__device__ float  g_qb [S_LEN * D_DIM];
__device__ float  g_kb [S_LEN * D_DIM];
__device__ float  g_pkb[S_LEN * D_DIM];
__device__ float  g_cs [64 * D_DIM];
__device__ float  g_sb [S_LEN * H_N];
__device__ float  g_ao [S_LEN * D_DIM];
__device__ __half g_xh [S_LEN * D_DIM];
__device__ __half g_yh [S_LEN * D_DIM];
__device__ __half g_fmh[S_LEN * FF_IN];
__device__ __half g_qhh[S_LEN * D_DIM];
__device__ __half g_khh[S_LEN * D_DIM];
__device__ __half g_vhh[S_LEN * D_DIM];
__device__ __half g_wqh [D_DIM * D_DIM];
__device__ __half g_wkh [D_DIM * D_DIM];
__device__ __half g_wvh [D_DIM * D_DIM];
__device__ __half g_wqbh[D_DIM * D_DIM];
__device__ __half g_wkbh[D_DIM * D_DIM];
__device__ __half g_woh [D_DIM * D_DIM];
__device__ __half g_w1h [FUSEDW * D_DIM];
__device__ __half g_w2h [D_DIM * FF_IN];

// ---------------- helpers ----------------
__device__ __forceinline__ uint32_t smem_u32(const void* p) {
    uint32_t a;
    asm("{ .reg .u64 t; cvta.to.shared.u64 t, %1; cvt.u32.u64 %0, t; }" : "=r"(a) : "l"(p));
    return a;
}

#define MMA_F16(d, a, b)                                                      \
    asm volatile(                                                             \
        "mma.sync.aligned.m16n8k16.row.col.f32.f16.f16.f32 "                  \
        "{%0,%1,%2,%3}, {%4,%5,%6,%7}, {%8,%9}, {%0,%1,%2,%3};"               \
        : "+f"(d[0]), "+f"(d[1]), "+f"(d[2]), "+f"(d[3])                      \
        : "r"(a[0]), "r"(a[1]), "r"(a[2]), "r"(a[3]), "r"(b[0]), "r"(b[1]))

#define LDSM_X4(r0, r1, r2, r3, a)                                            \
    asm volatile("ldmatrix.sync.aligned.m8n8.x4.shared.b16 {%0,%1,%2,%3}, [%4];" \
                 : "=r"(r0), "=r"(r1), "=r"(r2), "=r"(r3) : "r"(a))

#define LDSM_X4T(r0, r1, r2, r3, a)                                           \
    asm volatile("ldmatrix.sync.aligned.m8n8.x4.trans.shared.b16 {%0,%1,%2,%3}, [%4];" \
                 : "=r"(r0), "=r"(r1), "=r"(r2), "=r"(r3) : "r"(a))

#define EX2_F16X2(d, a)                                                       \
    asm volatile("ex2.approx.f16x2 %0, %1;" : "=r"(d) : "r"(a))

#define CP16(dst, src)                                                        \
    asm volatile("cp.async.ca.shared.global [%0], [%1], 16;" :: "r"(dst), "l"(src))

#define L2E 1.4426950408889634f

// ---------------- weight fp16 convert + transpose ----------------
__global__ void __launch_bounds__(256) cvtT6_kernel(
    const float* __restrict__ W0, const float* __restrict__ W1,
    const float* __restrict__ W2, const float* __restrict__ W3,
    const float* __restrict__ W4, const float* __restrict__ W5,
    __half* __restrict__ O0, __half* __restrict__ O1,
    __half* __restrict__ O2, __half* __restrict__ O3,
    __half* __restrict__ O4, __half* __restrict__ O5) {
    int z = blockIdx.z;
    const float* W = (z == 0) ? W0 : (z == 1) ? W1 : (z == 2) ? W2
                   : (z == 3) ? W3 : (z == 4) ? W4 : W5;
    __half* Wt = (z == 0) ? O0 : (z == 1) ? O1 : (z == 2) ? O2
               : (z == 3) ? O3 : (z == 4) ? O4 : O5;
    __shared__ float t[32][33];
    int n0 = blockIdx.x * 32, k0 = blockIdx.y * 32;
    int tx = threadIdx.x & 31, ty = threadIdx.x >> 5;
    #pragma unroll
    for (int i = 0; i < 32; i += 8)
        t[ty + i][tx] = W[(size_t)(k0 + ty + i) * D_DIM + n0 + tx];
    __syncthreads();
    #pragma unroll
    for (int i = 0; i < 32; i += 8)
        Wt[(size_t)(n0 + ty + i) * D_DIM + k0 + tx] = __float2half(t[tx][ty + i]);
}

__global__ void __launch_bounds__(256) cvtT_kernel(const float* __restrict__ W,
                                                   __half* __restrict__ Wt,
                                                   int K, int N) {
    __shared__ float t[32][33];
    int n0 = blockIdx.x * 32, k0 = blockIdx.y * 32;
    int tx = threadIdx.x & 31, ty = threadIdx.x >> 5;
    #pragma unroll
    for (int i = 0; i < 32; i += 8)
        t[ty + i][tx] = W[(size_t)(k0 + ty + i) * N + n0 + tx];
    __syncthreads();
    #pragma unroll
    for (int i = 0; i < 32; i += 8)
        Wt[(size_t)(n0 + ty + i) * K + k0 + tx] = __float2half(t[tx][ty + i]);
}

// ---------------- RMSNorm -> fp16 x ----------------
__global__ void __launch_bounds__(256) rmsnorm_kernel(const float* __restrict__ h,
                                                      __half* __restrict__ xh) {
    int row = blockIdx.x;
    int t = threadIdx.x;
    const float4* hr = reinterpret_cast<const float4*>(h + (size_t)row * D_DIM);
    float4 a = hr[t];
    float ss = a.x * a.x + a.y * a.y + a.z * a.z + a.w * a.w;
    __shared__ float red[8];
    #pragma unroll
    for (int off = 16; off; off >>= 1) ss += __shfl_xor_sync(0xffffffffu, ss, off);
    if ((t & 31) == 0) red[t >> 5] = ss;
    __syncthreads();
    float tot = red[0] + red[1] + red[2] + red[3] + red[4] + red[5] + red[6] + red[7];
    float r = rsqrtf(tot * (1.0f / 1024.0f) + 1.1920929e-7f);
    __half2 h0 = __floats2half2_rn(a.x * r, a.y * r);
    __half2 h1 = __floats2half2_rn(a.z * r, a.w * r);
    uint2 packed = make_uint2(*reinterpret_cast<uint32_t*>(&h0),
                              *reinterpret_cast<uint32_t*>(&h1));
    *reinterpret_cast<uint2*>(xh + (size_t)row * D_DIM + t * 4) = packed;
}

// ---------------- fp16 cp.async GEMM (proj / Wo / W2) ----------------
#define HSTR 40
#define GEMM_SMEM (4 * 128 * HSTR * 2)

__global__ void __launch_bounds__(256) gemm_f16_kernel(
    const __half* __restrict__ A,
    const __half* __restrict__ B0, const __half* __restrict__ B1,
    const __half* __restrict__ B2, const __half* __restrict__ B3,
    const __half* __restrict__ B4,
    float* __restrict__ C0, float* __restrict__ C1,
    float* __restrict__ C2, float* __restrict__ C3,
    float* __restrict__ C4,
    __half* __restrict__ ChV,    // z==2 half output (v projection)
    int M, int N, int K,
    const float* __restrict__ bias,
    const float* __restrict__ add0,
    const float* __restrict__ add1,
    const float* __restrict__ lamPtr)
{
    int z = blockIdx.z;
    const __half* B = (z == 0) ? B0 : (z == 1) ? B1 : (z == 2) ? B2 : (z == 3) ? B3 : B4;
    float* C = (z == 0) ? C0 : (z == 1) ? C1 : (z == 2) ? C2 : (z == 3) ? C3 : C4;
    __half* chDst = (z == 2) ? ChV : nullptr;

    extern __shared__ __half smh[];
    __half (*As)[128][HSTR] = reinterpret_cast<__half(*)[128][HSTR]>(smh);
    __half (*Bs)[128][HSTR] = reinterpret_cast<__half(*)[128][HSTR]>(smh + 2 * 128 * HSTR);

    int tid = threadIdx.x;
    int lane = tid & 31;
    int warp = tid >> 5;
    int warpM = warp >> 1;
    int warpN = warp & 1;
    int lr = lane >> 2;
    int lc = lane & 3;
    int bm = blockIdx.y * 128;
    int bn = blockIdx.x * 128;

    int sr = tid >> 1;
    int sc = (tid & 1) * 16;
    const __half* Ap = A + (size_t)(bm + sr) * K + sc;
    const __half* Bp = B + (size_t)(bn + sr) * K + sc;

    int aRow = lane & 15, aCol = (lane >> 4) * 8;
    int bRow = ((lane & 16) ? 8 : 0) + (lane & 7);
    int bCol = ((lane & 8) ? 8 : 0);
    uint32_t aOff[2], bOff[4];
    #pragma unroll
    for (int mi = 0; mi < 2; mi++)
        aOff[mi] = ((warpM * 32 + mi * 16 + aRow) * HSTR + aCol) * 2;
    #pragma unroll
    for (int nip = 0; nip < 4; nip++)
        bOff[nip] = ((warpN * 64 + nip * 16 + bRow) * HSTR + bCol) * 2;

    float acc[2][8][4];
    #pragma unroll
    for (int mi = 0; mi < 2; mi++)
        #pragma unroll
        for (int ni = 0; ni < 8; ni++)
            #pragma unroll
            for (int r = 0; r < 4; r++) acc[mi][ni][r] = 0.f;

    int NT = K / 32;

    auto issue = [&](int buf, int t) {
        const __half* ga = Ap + t * 32;
        const __half* gb = Bp + t * 32;
        uint32_t da = smem_u32(&As[buf][sr][sc]);
        uint32_t db = smem_u32(&Bs[buf][sr][sc]);
        CP16(da, ga);
        CP16(da + 16, ga + 8);
        CP16(db, gb);
        CP16(db + 16, gb + 8);
        asm volatile("cp.async.commit_group;" ::: "memory");
    };

    issue(0, 0);
    for (int t = 0; t < NT; t++) {
        int buf = t & 1;
        if (t + 1 < NT) {
            issue(buf ^ 1, t + 1);
            asm volatile("cp.async.wait_group 1;" ::: "memory");
        } else {
            asm volatile("cp.async.wait_group 0;" ::: "memory");
        }
        __syncthreads();
        uint32_t aBase = smem_u32(&As[buf][0][0]);
        uint32_t bBase = smem_u32(&Bs[buf][0][0]);
        #pragma unroll
        for (int ks = 0; ks < 2; ks++) {
            uint32_t koff = ks * 32;
            uint32_t af[2][4], bf[8][2];
            #pragma unroll
            for (int mi = 0; mi < 2; mi++)
                LDSM_X4(af[mi][0], af[mi][1], af[mi][2], af[mi][3],
                        aBase + aOff[mi] + koff);
            #pragma unroll
            for (int nip = 0; nip < 4; nip++)
                LDSM_X4(bf[2 * nip][0], bf[2 * nip][1],
                        bf[2 * nip + 1][0], bf[2 * nip + 1][1],
                        bBase + bOff[nip] + koff);
            #pragma unroll
            for (int mi = 0; mi < 2; mi++)
                #pragma unroll
                for (int ni = 0; ni < 8; ni++)
                    MMA_F16(acc[mi][ni], af[mi], bf[ni]);
        }
        __syncthreads();
    }

    float lam = lamPtr ? lamPtr[0] : 0.f;
    #pragma unroll
    for (int mi = 0; mi < 2; mi++) {
        int r0 = bm + warpM * 32 + mi * 16 + lr;
        #pragma unroll
        for (int ni = 0; ni < 8; ni++) {
            int c0 = bn + warpN * 64 + ni * 8 + lc * 2;
            #pragma unroll
            for (int half_ = 0; half_ < 2; half_++) {
                int r = r0 + half_ * 8;
                float v0 = acc[mi][ni][half_ * 2 + 0];
                float v1 = acc[mi][ni][half_ * 2 + 1];
                if (bias) { v0 += bias[c0]; v1 += bias[c0 + 1]; }
                size_t idx = (size_t)r * N + c0;
                if (chDst) {
                    __half2 hv = __floats2half2_rn(v0, v1);
                    *reinterpret_cast<__half2*>(chDst + idx) = hv;
                } else {
                    if (add0) { v0 += add0[idx]; v1 += add0[idx + 1]; }
                    if (add1) { v0 += lam * add1[idx]; v1 += lam * add1[idx + 1]; }
                    C[idx]     = v0;
                    C[idx + 1] = v1;
                }
            }
        }
    }
}

// ---------------- fused W1 GEMM + SwiGLU -> fm (fp16) ----------------
// Computes xp = x@W1[:,c]+b1[c], gate = x@W1[:,4096+c]+b1[4096+c],
// fm[r][c] = silu(gate)*xp. Two B tiles (xp cols / gate cols), one A tile.
#define W1_SMEM (6 * 128 * HSTR * 2)

__global__ void __launch_bounds__(256) gemm_w1_swiglu_kernel(
    const __half* __restrict__ A, const __half* __restrict__ W1t,
    __half* __restrict__ fmh, const float* __restrict__ b1)
{
    extern __shared__ __half smh[];
    __half (*As)[128][HSTR]  = reinterpret_cast<__half(*)[128][HSTR]>(smh);
    __half (*Bx)[128][HSTR]  = reinterpret_cast<__half(*)[128][HSTR]>(smh + 2 * 128 * HSTR);
    __half (*Bg)[128][HSTR]  = reinterpret_cast<__half(*)[128][HSTR]>(smh + 4 * 128 * HSTR);

    const int K = D_DIM, N = FF_IN;
    int tid = threadIdx.x;
    int lane = tid & 31;
    int warp = tid >> 5;
    int warpM = warp >> 1;
    int warpN = warp & 1;
    int lr = lane >> 2;
    int lc = lane & 3;
    int bm = blockIdx.y * 128;
    int bn = blockIdx.x * 128;

    int sr = tid >> 1;
    int sc = (tid & 1) * 16;
    const __half* Ap  = A   + (size_t)(bm + sr) * K + sc;
    const __half* Bxp = W1t + (size_t)(bn + sr) * K + sc;
    const __half* Bgp = W1t + (size_t)(FF_IN + bn + sr) * K + sc;

    int aRow = lane & 15, aCol = (lane >> 4) * 8;
    int bRow = ((lane & 16) ? 8 : 0) + (lane & 7);
    int bCol = ((lane & 8) ? 8 : 0);
    uint32_t aOff[2], bOff[4];
    #pragma unroll
    for (int mi = 0; mi < 2; mi++)
        aOff[mi] = ((warpM * 32 + mi * 16 + aRow) * HSTR + aCol) * 2;
    #pragma unroll
    for (int nip = 0; nip < 4; nip++)
        bOff[nip] = ((warpN * 64 + nip * 16 + bRow) * HSTR + bCol) * 2;

    float accX[2][8][4], accG[2][8][4];
    #pragma unroll
    for (int mi = 0; mi < 2; mi++)
        #pragma unroll
        for (int ni = 0; ni < 8; ni++)
            #pragma unroll
            for (int r = 0; r < 4; r++) { accX[mi][ni][r] = 0.f; accG[mi][ni][r] = 0.f; }

    const int NT = K / 32;

    auto issue = [&](int buf, int t) {
        uint32_t da = smem_u32(&As[buf][sr][sc]);
        uint32_t dx = smem_u32(&Bx[buf][sr][sc]);
        uint32_t dg = smem_u32(&Bg[buf][sr][sc]);
        CP16(da, Ap + t * 32);
        CP16(da + 16, Ap + t * 32 + 8);
        CP16(dx, Bxp + t * 32);
        CP16(dx + 16, Bxp + t * 32 + 8);
        CP16(dg, Bgp + t * 32);
        CP16(dg + 16, Bgp + t * 32 + 8);
        asm volatile("cp.async.commit_group;" ::: "memory");
    };

    issue(0, 0);
    for (int t = 0; t < NT; t++) {
        int buf = t & 1;
        if (t + 1 < NT) {
            issue(buf ^ 1, t + 1);
            asm volatile("cp.async.wait_group 1;" ::: "memory");
        } else {
            asm volatile("cp.async.wait_group 0;" ::: "memory");
        }
        __syncthreads();
        uint32_t aBase = smem_u32(&As[buf][0][0]);
        uint32_t xBase = smem_u32(&Bx[buf][0][0]);
        uint32_t gBase = smem_u32(&Bg[buf][0][0]);
        #pragma unroll
        for (int ks = 0; ks < 2; ks++) {
            uint32_t koff = ks * 32;
            uint32_t af[2][4], bx[8][2], bg[8][2];
            #pragma unroll
            for (int mi = 0; mi < 2; mi++)
                LDSM_X4(af[mi][0], af[mi][1], af[mi][2], af[mi][3],
                        aBase + aOff[mi] + koff);
            #pragma unroll
            for (int nip = 0; nip < 4; nip++) {
                LDSM_X4(bx[2 * nip][0], bx[2 * nip][1],
                        bx[2 * nip + 1][0], bx[2 * nip + 1][1],
                        xBase + bOff[nip] + koff);
                LDSM_X4(bg[2 * nip][0], bg[2 * nip][1],
                        bg[2 * nip + 1][0], bg[2 * nip + 1][1],
                        gBase + bOff[nip] + koff);
            }
            #pragma unroll
            for (int mi = 0; mi < 2; mi++)
                #pragma unroll
                for (int ni = 0; ni < 8; ni++) {
                    MMA_F16(accX[mi][ni], af[mi], bx[ni]);
                    MMA_F16(accG[mi][ni], af[mi], bg[ni]);
                }
        }
        __syncthreads();
    }

    #pragma unroll
    for (int mi = 0; mi < 2; mi++) {
        int r0 = bm + warpM * 32 + mi * 16 + lr;
        #pragma unroll
        for (int ni = 0; ni < 8; ni++) {
            int c0 = bn + warpN * 64 + ni * 8 + lc * 2;
            float bx0 = b1[c0], bx1 = b1[c0 + 1];
            float bg0 = b1[FF_IN + c0], bg1 = b1[FF_IN + c0 + 1];
            #pragma unroll
            for (int half_ = 0; half_ < 2; half_++) {
                int r = r0 + half_ * 8;
                float xp0 = accX[mi][ni][half_ * 2 + 0] + bx0;
                float xp1 = accX[mi][ni][half_ * 2 + 1] + bx1;
                float g0 = accG[mi][ni][half_ * 2 + 0] + bg0;
                float g1 = accG[mi][ni][half_ * 2 + 1] + bg1;
                float f0 = (g0 / (1.f + __expf(-g0))) * xp0;
                float f1 = (g1 / (1.f + __expf(-g1))) * xp1;
                __half2 hv = __floats2half2_rn(f0, f1);
                *reinterpret_cast<__half2*>(fmh + (size_t)r * N + c0) = hv;
            }
        }
    }
}

// ---------------- l2norm + RoPE (q,k -> fp16; qb,kb in-place fp32) ----------
__global__ void __launch_bounds__(256) ropenorm_kernel(
    const float* __restrict__ q, const float* __restrict__ k,
    float* qb, float* kb, __half* __restrict__ qh, __half* __restrict__ kh) {
    int s = blockIdx.x;
    int warp = threadIdx.x >> 5;
    int lane = threadIdx.x & 31;
    int idx = blockIdx.y * 8 + warp;
    int h = idx & 15;
    int a = idx >> 4;
    const float* src = (a == 0) ? q : (a == 1) ? k : (a == 2) ? qb : kb;
    size_t off = (size_t)s * D_DIM + h * 64;
    const float* p = src + off;
    float x1 = p[lane];
    float x2 = p[lane + DHALF];
    float ss = x1 * x1 + x2 * x2;
    #pragma unroll
    for (int o = 16; o; o >>= 1) ss += __shfl_xor_sync(0xffffffffu, ss, o);
    float n = fmaxf(sqrtf(ss), 1e-12f);
    float inv = 1.f / n;
    x1 *= inv;
    x2 *= inv;
    float invfreq = powf(1000.0f, -(float)lane * (1.0f / 32.0f));
    float fr = (float)s * invfreq;
    float c  = __bfloat162float(__float2bfloat16(cosf(fr)));
    float sn = __bfloat162float(__float2bfloat16(sinf(fr)));
    float y1 = x1 * c + x2 * sn;
    float y2 = -x1 * sn + x2 * c;
    if (a < 2) {
        __half* dst = ((a == 0) ? qh : kh) + off;
        dst[lane]         = __float2half(y1);
        dst[lane + DHALF] = __float2half(y2);
    } else {
        float* dst = ((a == 2) ? qb : kb) + off;
        dst[lane]         = y1;
        dst[lane + DHALF] = y2;
    }
}

// ---------------- parallel prefix sum of kb ----------------
__global__ void __launch_bounds__(256) prefix_p1(const float* __restrict__ kb,
                                                 float* __restrict__ cs) {
    int ch = blockIdx.x;
    int col = blockIdx.y * 256 + threadIdx.x;
    const float* p = kb + (size_t)(ch * 32) * D_DIM + col;
    float acc = 0.f;
    #pragma unroll
    for (int r = 0; r < 32; r++) acc += p[(size_t)r * D_DIM];
    cs[(size_t)ch * D_DIM + col] = acc;
}
__global__ void __launch_bounds__(1024) prefix_p2(float* __restrict__ cs) {
    int col = threadIdx.x;
    float run = 0.f;
    #pragma unroll 8
    for (int ch = 0; ch < 64; ch++) {
        size_t i = (size_t)ch * D_DIM + col;
        float t = cs[i];
        cs[i] = run;
        run += t;
    }
}
__global__ void __launch_bounds__(256) prefix_p3(const float* __restrict__ kb,
                                                 const float* __restrict__ cs,
                                                 float* __restrict__ pkb) {
    int ch = blockIdx.x;
    int col = blockIdx.y * 256 + threadIdx.x;
    float acc = cs[(size_t)ch * D_DIM + col];
    const float* p = kb + (size_t)(ch * 32) * D_DIM + col;
    float* o = pkb + (size_t)(ch * 32) * D_DIM + col;
    #pragma unroll
    for (int r = 0; r < 32; r++) {
        acc += p[(size_t)r * D_DIM];
        o[(size_t)r * D_DIM] = acc;
    }
}

// ---------------- sb values ----------------
__global__ void __launch_bounds__(512) sb_kernel(const float* __restrict__ qb,
                                                 const float* __restrict__ pkb,
                                                 float* __restrict__ sbv) {
    int s = blockIdx.x;
    int h = threadIdx.x >> 5;
    int lane = threadIdx.x & 31;
    size_t off = (size_t)s * D_DIM + h * 64;
    float v = qb[off + lane] * pkb[off + lane] +
              qb[off + lane + DHALF] * pkb[off + lane + DHALF];
    #pragma unroll
    for (int o = 16; o; o >>= 1) v += __shfl_xor_sync(0xffffffffu, v, o);
    if (lane == 0) sbv[s * H_N + h] = 0.125f * v;
}

// ---------------- fp16 flash attention: 128-row q tiles, cp.async K/V ------
#define QSH 72
// Qs 128 + Ps 128 + Ks 2x64 + Vs 2x64 = 512 rows
#define ATT_SMEM (512 * QSH * 2 + 256 * 4)

__global__ void __launch_bounds__(256) attn_mma_kernel(
    const __half* __restrict__ qh, const __half* __restrict__ kh,
    const __half* __restrict__ vh,
    const float* __restrict__ sbv, const float* __restrict__ l2sp,
    __half* __restrict__ yh)
{
    extern __shared__ __half smah[];
    __half (*Qs)[QSH] = reinterpret_cast<__half(*)[QSH]>(smah);             // 128
    __half (*Ps)[QSH] = reinterpret_cast<__half(*)[QSH]>(smah + 128 * QSH); // 128
    __half (*Ks)[64][QSH] = reinterpret_cast<__half(*)[64][QSH]>(smah + 256 * QSH); // 2x64
    __half (*Vs)[64][QSH] = reinterpret_cast<__half(*)[64][QSH]>(smah + 384 * QSH); // 2x64
    float* red_l = reinterpret_cast<float*>(smah + 512 * QSH);              // [2][128]

    int h = blockIdx.y;
    int q0 = blockIdx.x * 128;
    int tid = threadIdx.x;
    int lane = tid & 31, warp = tid >> 5;
    int wm = warp >> 1;
    int wn = warp & 1;
    int lr = lane >> 2;
    int lc = lane & 3;

    int aRow = lane & 15, aCol = (lane >> 4) * 8;
    uint32_t qOff[2];
    #pragma unroll
    for (int mi = 0; mi < 2; mi++)
        qOff[mi] = ((wm * 32 + mi * 16 + aRow) * QSH + aCol) * 2;
    int bRow = ((lane & 16) ? 8 : 0) + (lane & 7);
    int bCol = ((lane & 8) ? 8 : 0);
    uint32_t kOff[2];
    #pragma unroll
    for (int nip = 0; nip < 2; nip++)
        kOff[nip] = ((wn * 32 + nip * 16 + bRow) * QSH + bCol) * 2;
    int tRow = ((lane & 8) ? 8 : 0) + (lane & 7);
    int tCol = ((lane & 16) ? 8 : 0);
    uint32_t vOff[2];
    #pragma unroll
    for (int nip = 0; nip < 2; nip++)
        vOff[nip] = (tRow * QSH + wn * 32 + nip * 16 + tCol) * 2;

    uint32_t qBase = smem_u32(&Qs[0][0]);
    uint32_t pBase = smem_u32(&Ps[0][0]);

    // staging indices for K/V: one quarter-row per thread
    int stR = tid >> 2, stC = (tid & 3) * 16;

    auto issueKV = [&](int buf, int kt) {
        int kbase = kt * 64;
        const __half* ks = kh + (size_t)(kbase + stR) * D_DIM + h * 64 + stC;
        const __half* vs = vh + (size_t)(kbase + stR) * D_DIM + h * 64 + stC;
        uint32_t dk = smem_u32(&Ks[buf][stR][stC]);
        uint32_t dv = smem_u32(&Vs[buf][stR][stC]);
        CP16(dk, ks);
        CP16(dk + 16, ks + 8);
        CP16(dv, vs);
        CP16(dv + 16, vs + 8);
        asm volatile("cp.async.commit_group;" ::: "memory");
    };

    // stage Q (sync; covered by first S1)
    {
        int r = tid >> 1, c0 = (tid & 1) * 32;
        const __half* src = qh + (size_t)(q0 + r) * D_DIM + h * 64 + c0;
        #pragma unroll
        for (int j = 0; j < 4; j++)
            *reinterpret_cast<uint4*>(&Qs[r][c0 + j * 8]) =
                *reinterpret_cast<const uint4*>(src + j * 8);
    }

    float l[4] = {0.f, 0.f, 0.f, 0.f};
    float o[2][4][4];
    #pragma unroll
    for (int mi = 0; mi < 2; mi++)
        #pragma unroll
        for (int ni = 0; ni < 4; ni++)
            #pragma unroll
            for (int j = 0; j < 4; j++) o[mi][ni][j] = 0.f;

    int nt = 2 * blockIdx.x + 2;
    issueKV(0, 0);

    for (int kt = 0; kt < nt; kt++) {
        int buf = kt & 1;
        int kbase = kt * 64;
        __syncthreads();            // S1: drains prev PV reads of Ks/Vs[buf^1]
        if (kt + 1 < nt) {
            issueKV(buf ^ 1, kt + 1);
            asm volatile("cp.async.wait_group 1;" ::: "memory");
        } else {
            asm volatile("cp.async.wait_group 0;" ::: "memory");
        }
        __syncthreads();            // S2: tile kt staged, visible CTA-wide

        uint32_t kBase = smem_u32(&Ks[buf][0][0]);
        uint32_t vBase = smem_u32(&Vs[buf][0][0]);

        // S = Q . K^T
        float s[2][4][4];
        #pragma unroll
        for (int mi = 0; mi < 2; mi++)
            #pragma unroll
            for (int ni = 0; ni < 4; ni++)
                #pragma unroll
                for (int j = 0; j < 4; j++) s[mi][ni][j] = 0.f;
        #pragma unroll
        for (int ks = 0; ks < 4; ks++) {
            uint32_t kbyte = ks * 32;
            uint32_t af[2][4], bf[4][2];
            #pragma unroll
            for (int mi = 0; mi < 2; mi++)
                LDSM_X4(af[mi][0], af[mi][1], af[mi][2], af[mi][3],
                        qBase + qOff[mi] + kbyte);
            #pragma unroll
            for (int nip = 0; nip < 2; nip++)
                LDSM_X4(bf[2 * nip][0], bf[2 * nip][1],
                        bf[2 * nip + 1][0], bf[2 * nip + 1][1],
                        kBase + kOff[nip] + kbyte);
            #pragma unroll
            for (int mi = 0; mi < 2; mi++)
                #pragma unroll
                for (int ni = 0; ni < 4; ni++)
                    MMA_F16(s[mi][ni], af[mi], bf[ni]);
        }
        if (kt >= nt - 2) {
            #pragma unroll
            for (int mi = 0; mi < 2; mi++) {
                int rg0 = q0 + wm * 32 + mi * 16 + lr;
                #pragma unroll
                for (int ni = 0; ni < 4; ni++) {
                    int cgb = kbase + wn * 32 + ni * 8 + lc * 2;
                    #pragma unroll
                    for (int j = 0; j < 4; j++) {
                        int rg = rg0 + ((j >= 2) ? 8 : 0);
                        int cg = cgb + (j & 1);
                        if (cg > rg) s[mi][ni][j] = -1e4f;
                    }
                }
            }
        }
        // p = exp(s - 1) via ex2.approx.f16x2
        #pragma unroll
        for (int mi = 0; mi < 2; mi++) {
            int r0m = wm * 32 + mi * 16 + lr;
            int r1m = r0m + 8;
            #pragma unroll
            for (int ni = 0; ni < 4; ni++) {
                int cbase = wn * 32 + ni * 8 + lc * 2;
                float t0 = fmaf(s[mi][ni][0], L2E, -L2E);
                float t1 = fmaf(s[mi][ni][1], L2E, -L2E);
                float t2 = fmaf(s[mi][ni][2], L2E, -L2E);
                float t3 = fmaf(s[mi][ni][3], L2E, -L2E);
                __half2 ht0 = __floats2half2_rn(t0, t1);
                __half2 ht1 = __floats2half2_rn(t2, t3);
                uint32_t p0, p1;
                EX2_F16X2(p0, *reinterpret_cast<uint32_t*>(&ht0));
                EX2_F16X2(p1, *reinterpret_cast<uint32_t*>(&ht1));
                *reinterpret_cast<uint32_t*>(&Ps[r0m][cbase]) = p0;
                *reinterpret_cast<uint32_t*>(&Ps[r1m][cbase]) = p1;
                float2 f0 = __half22float2(*reinterpret_cast<__half2*>(&p0));
                float2 f1 = __half22float2(*reinterpret_cast<__half2*>(&p1));
                l[mi * 2]     += f0.x + f0.y;
                l[mi * 2 + 1] += f1.x + f1.y;
            }
        }
        __syncthreads();            // S3: P visible
        // O += P . V
        #pragma unroll
        for (int ks = 0; ks < 4; ks++) {
            uint32_t af[2][4], bf[4][2];
            #pragma unroll
            for (int mi = 0; mi < 2; mi++)
                LDSM_X4(af[mi][0], af[mi][1], af[mi][2], af[mi][3],
                        pBase + qOff[mi] + ks * 32);
            #pragma unroll
            for (int nip = 0; nip < 2; nip++)
                LDSM_X4T(bf[2 * nip][0], bf[2 * nip][1],
                         bf[2 * nip + 1][0], bf[2 * nip + 1][1],
                         vBase + vOff[nip] + ks * 16 * QSH * 2);
            #pragma unroll
            for (int mi = 0; mi < 2; mi++)
                #pragma unroll
                for (int ni = 0; ni < 4; ni++)
                    MMA_F16(o[mi][ni], af[mi], bf[ni]);
        }
    }

    #pragma unroll
    for (int i = 0; i < 4; i++) {
        l[i] += __shfl_xor_sync(0xffffffffu, l[i], 1);
        l[i] += __shfl_xor_sync(0xffffffffu, l[i], 2);
    }
    if (lc == 0) {
        #pragma unroll
        for (int mi = 0; mi < 2; mi++) {
            int r0m = wm * 32 + mi * 16 + lr;
            red_l[wn * 128 + r0m]     = l[mi * 2];
            red_l[wn * 128 + r0m + 8] = l[mi * 2 + 1];
        }
    }
    __syncthreads();

    float l2sv = l2sp[0];
    #pragma unroll
    for (int mi = 0; mi < 2; mi++) {
        int r0m = wm * 32 + mi * 16 + lr;
        int r1m = r0m + 8;
        float lt0 = red_l[r0m] + red_l[128 + r0m];
        float lt1 = red_l[r1m] + red_l[128 + r1m];
        float inv0 = l2sv / lt0;
        float inv1 = l2sv / lt1;
        int g0 = q0 + r0m, g1 = q0 + r1m;
        float sb0 = sbv[g0 * H_N + h];
        float sb1 = sbv[g1 * H_N + h];
        #pragma unroll
        for (int ni = 0; ni < 4; ni++) {
            int col = h * 64 + wn * 32 + ni * 8 + lc * 2;
            __half2 r0v = __floats2half2_rn(o[mi][ni][0] * inv0 + sb0,
                                            o[mi][ni][1] * inv0 + sb0);
            __half2 r1v = __floats2half2_rn(o[mi][ni][2] * inv1 + sb1,
                                            o[mi][ni][3] * inv1 + sb1);
            *reinterpret_cast<__half2*>(&yh[(size_t)g0 * D_DIM + col]) = r0v;
            *reinterpret_cast<__half2*>(&yh[(size_t)g1 * D_DIM + col]) = r1v;
        }
    }
}

// ---------------- launch ----------------
extern "C" void kernel_launch(void* const* d_in, const int* in_sizes, int n_in,
                              void* d_out, int out_size) {
    const float* h_states = (const float*)d_in[0];
    const float* Wq  = (const float*)d_in[1];
    const float* Wk  = (const float*)d_in[2];
    const float* Wv  = (const float*)d_in[3];
    const float* Wqb = (const float*)d_in[4];
    const float* Wkb = (const float*)d_in[5];
    const float* Wo  = (const float*)d_in[6];
    const float* bo  = (const float*)d_in[7];
    const float* W1  = (const float*)d_in[8];
    const float* b1  = (const float*)d_in[9];
    const float* W2  = (const float*)d_in[10];
    const float* b2  = (const float*)d_in[11];
    const float* lam = (const float*)d_in[12];
    const float* l2s = (const float*)d_in[13];
    float* out = (float*)d_out;

    float *q, *k, *qb, *kb, *pkb, *cs, *sbv, *ao;
    __half *xh, *yh, *fmh, *qhh, *khh, *vhh;
    __half *wqh, *wkh, *wvh, *wqbh, *wkbh, *woh, *w1h, *w2h;
    cudaGetSymbolAddress((void**)&q,  g_q);
    cudaGetSymbolAddress((void**)&k,  g_k);
    cudaGetSymbolAddress((void**)&qb, g_qb);
    cudaGetSymbolAddress((void**)&kb, g_kb);
    cudaGetSymbolAddress((void**)&pkb, g_pkb);
    cudaGetSymbolAddress((void**)&cs, g_cs);
    cudaGetSymbolAddress((void**)&sbv, g_sb);
    cudaGetSymbolAddress((void**)&ao, g_ao);
    cudaGetSymbolAddress((void**)&xh,  g_xh);
    cudaGetSymbolAddress((void**)&yh,  g_yh);
    cudaGetSymbolAddress((void**)&fmh, g_fmh);
    cudaGetSymbolAddress((void**)&qhh, g_qhh);
    cudaGetSymbolAddress((void**)&khh, g_khh);
    cudaGetSymbolAddress((void**)&vhh, g_vhh);
    cudaGetSymbolAddress((void**)&wqh,  g_wqh);
    cudaGetSymbolAddress((void**)&wkh,  g_wkh);
    cudaGetSymbolAddress((void**)&wvh,  g_wvh);
    cudaGetSymbolAddress((void**)&wqbh, g_wqbh);
    cudaGetSymbolAddress((void**)&wkbh, g_wkbh);
    cudaGetSymbolAddress((void**)&woh,  g_woh);
    cudaGetSymbolAddress((void**)&w1h,  g_w1h);
    cudaGetSymbolAddress((void**)&w2h,  g_w2h);

    cudaFuncSetAttribute(attn_mma_kernel,
                         cudaFuncAttributeMaxDynamicSharedMemorySize, ATT_SMEM);
    cudaFuncSetAttribute(gemm_f16_kernel,
                         cudaFuncAttributeMaxDynamicSharedMemorySize, GEMM_SMEM);
    cudaFuncSetAttribute(gemm_w1_swiglu_kernel,
                         cudaFuncAttributeMaxDynamicSharedMemorySize, W1_SMEM);

    static cudaStream_t s1 = nullptr;
    static cudaEvent_t evX = nullptr, evFFN = nullptr;
    if (!s1) {
        cudaStreamCreateWithFlags(&s1, cudaStreamNonBlocking);
        cudaEventCreateWithFlags(&evX, cudaEventDisableTiming);
        cudaEventCreateWithFlags(&evFFN, cudaEventDisableTiming);
    }

    // ---- main stream: shared prologue ----
    cvtT6_kernel<<<dim3(32, 32, 6), 256>>>(Wq, Wk, Wv, Wqb, Wkb, Wo,
                                           wqh, wkh, wvh, wqbh, wkbh, woh);
    rmsnorm_kernel<<<S_LEN, 256>>>(h_states, xh);
    cudaEventRecord(evX, 0);

    // ---- side stream: FFN branch ----
    cvtT_kernel<<<dim3(FUSEDW / 32, 32), 256, 0, s1>>>(W1, w1h, D_DIM, FUSEDW);
    cvtT_kernel<<<dim3(32, FF_IN / 32), 256, 0, s1>>>(W2, w2h, FF_IN, D_DIM);
    cudaStreamWaitEvent(s1, evX, 0);
    gemm_w1_swiglu_kernel<<<dim3(FF_IN / 128, S_LEN / 128), 256, W1_SMEM, s1>>>(
        xh, w1h, fmh, b1);
    cudaEventRecord(evFFN, s1);

    // ---- main stream: attention branch ----
    gemm_f16_kernel<<<dim3(D_DIM / 128, S_LEN / 128, 5), 256, GEMM_SMEM>>>(
        xh, wqh, wkh, wvh, wqbh, wkbh, q, k, nullptr, qb, kb, vhh,
        S_LEN, D_DIM, D_DIM, nullptr, nullptr, nullptr, nullptr);

    ropenorm_kernel<<<dim3(S_LEN, 8), 256>>>(q, k, qb, kb, qhh, khh);

    prefix_p1<<<dim3(64, 4), 256>>>(kb, cs);
    prefix_p2<<<1, 1024>>>(cs);
    prefix_p3<<<dim3(64, 4), 256>>>(kb, cs, pkb);
    sb_kernel<<<S_LEN, 512>>>(qb, pkb, sbv);

    attn_mma_kernel<<<dim3(S_LEN / 128, H_N), 256, ATT_SMEM>>>(qhh, khh, vhh, sbv, l2s, yh);

    gemm_f16_kernel<<<dim3(D_DIM / 128, S_LEN / 128, 1), 256, GEMM_SMEM>>>(
        yh, woh, nullptr, nullptr, nullptr, nullptr,
        ao, nullptr, nullptr, nullptr, nullptr, nullptr,
        S_LEN, D_DIM, D_DIM, bo, nullptr, nullptr, nullptr);

    // ---- join ----
    cudaStreamWaitEvent(0, evFFN, 0);
    gemm_f16_kernel<<<dim3(D_DIM / 128, S_LEN / 128, 1), 256, GEMM_SMEM>>>(
        fmh, w2h, nullptr, nullptr, nullptr, nullptr,
        out, nullptr, nullptr, nullptr, nullptr, nullptr,
        S_LEN, D_DIM, FF_IN, b2, ao, h_states, lam);
}

// round 13
// speedup vs baseline: 9.5386x; 1.0351x over previous
#include <cuda_runtime.h>
#include <cuda_bf16.h>
#include <cuda_fp16.h>
#include <cstdint>

#define S_LEN 2048
#define D_DIM 1024
#define H_N 16
#define DHALF 32
#define FF_IN 4096
#define FUSEDW 8192

// ---------------- scratch ----------------
__device__ float  g_qb [S_LEN * D_DIM];
__device__ float  g_kb [S_LEN * D_DIM];
__device__ float  g_pkb[S_LEN * D_DIM];
__device__ float  g_cs [64 * D_DIM];
__device__ float  g_sb [S_LEN * H_N];
__device__ float  g_ao [S_LEN * D_DIM];
__device__ float  g_wos[H_N * D_DIM];      // WoSum[h][c]
__device__ float  g_cor[S_LEN * D_DIM];    // sb correction for ao
__device__ __half g_xh [S_LEN * D_DIM];
__device__ __half g_yh [S_LEN * D_DIM];
__device__ __half g_fmh[S_LEN * FF_IN];
__device__ __half g_qhh[S_LEN * D_DIM];
__device__ __half g_khh[S_LEN * D_DIM];
__device__ __half g_vhh[S_LEN * D_DIM];
__device__ __half g_wqh [D_DIM * D_DIM];
__device__ __half g_wkh [D_DIM * D_DIM];
__device__ __half g_wvh [D_DIM * D_DIM];
__device__ __half g_wqbh[D_DIM * D_DIM];
__device__ __half g_wkbh[D_DIM * D_DIM];
__device__ __half g_woh [D_DIM * D_DIM];
__device__ __half g_w1h [FUSEDW * D_DIM];
__device__ __half g_w2h [D_DIM * FF_IN];

// ---------------- helpers ----------------
__device__ __forceinline__ uint32_t smem_u32(const void* p) {
    uint32_t a;
    asm("{ .reg .u64 t; cvta.to.shared.u64 t, %1; cvt.u32.u64 %0, t; }" : "=r"(a) : "l"(p));
    return a;
}

#define MMA_F16(d, a, b)                                                      \
    asm volatile(                                                             \
        "mma.sync.aligned.m16n8k16.row.col.f32.f16.f16.f32 "                  \
        "{%0,%1,%2,%3}, {%4,%5,%6,%7}, {%8,%9}, {%0,%1,%2,%3};"               \
        : "+f"(d[0]), "+f"(d[1]), "+f"(d[2]), "+f"(d[3])                      \
        : "r"(a[0]), "r"(a[1]), "r"(a[2]), "r"(a[3]), "r"(b[0]), "r"(b[1]))

#define LDSM_X4(r0, r1, r2, r3, a)                                            \
    asm volatile("ldmatrix.sync.aligned.m8n8.x4.shared.b16 {%0,%1,%2,%3}, [%4];" \
                 : "=r"(r0), "=r"(r1), "=r"(r2), "=r"(r3) : "r"(a))

#define LDSM_X4T(r0, r1, r2, r3, a)                                           \
    asm volatile("ldmatrix.sync.aligned.m8n8.x4.trans.shared.b16 {%0,%1,%2,%3}, [%4];" \
                 : "=r"(r0), "=r"(r1), "=r"(r2), "=r"(r3) : "r"(a))

#define EX2_F16X2(d, a)                                                       \
    asm volatile("ex2.approx.f16x2 %0, %1;" : "=r"(d) : "r"(a))

#define CP16(dst, src)                                                        \
    asm volatile("cp.async.ca.shared.global [%0], [%1], 16;" :: "r"(dst), "l"(src))

#define L2E 1.4426950408889634f

// ---------------- weight fp16 convert + transpose ----------------
__global__ void __launch_bounds__(256) cvtT6_kernel(
    const float* __restrict__ W0, const float* __restrict__ W1,
    const float* __restrict__ W2, const float* __restrict__ W3,
    const float* __restrict__ W4, const float* __restrict__ W5,
    __half* __restrict__ O0, __half* __restrict__ O1,
    __half* __restrict__ O2, __half* __restrict__ O3,
    __half* __restrict__ O4, __half* __restrict__ O5) {
    int z = blockIdx.z;
    const float* W = (z == 0) ? W0 : (z == 1) ? W1 : (z == 2) ? W2
                   : (z == 3) ? W3 : (z == 4) ? W4 : W5;
    __half* Wt = (z == 0) ? O0 : (z == 1) ? O1 : (z == 2) ? O2
               : (z == 3) ? O3 : (z == 4) ? O4 : O5;
    __shared__ float t[32][33];
    int n0 = blockIdx.x * 32, k0 = blockIdx.y * 32;
    int tx = threadIdx.x & 31, ty = threadIdx.x >> 5;
    #pragma unroll
    for (int i = 0; i < 32; i += 8)
        t[ty + i][tx] = W[(size_t)(k0 + ty + i) * D_DIM + n0 + tx];
    __syncthreads();
    #pragma unroll
    for (int i = 0; i < 32; i += 8)
        Wt[(size_t)(n0 + ty + i) * D_DIM + k0 + tx] = __float2half(t[tx][ty + i]);
}

__global__ void __launch_bounds__(256) cvtT_kernel(const float* __restrict__ W,
                                                   __half* __restrict__ Wt,
                                                   int K, int N) {
    __shared__ float t[32][33];
    int n0 = blockIdx.x * 32, k0 = blockIdx.y * 32;
    int tx = threadIdx.x & 31, ty = threadIdx.x >> 5;
    #pragma unroll
    for (int i = 0; i < 32; i += 8)
        t[ty + i][tx] = W[(size_t)(k0 + ty + i) * N + n0 + tx];
    __syncthreads();
    #pragma unroll
    for (int i = 0; i < 32; i += 8)
        Wt[(size_t)(n0 + ty + i) * K + k0 + tx] = __float2half(t[tx][ty + i]);
}

// ---------------- WoSum[h][c] = sum_d Wo[h*64+d][c] ----------------
__global__ void __launch_bounds__(256) wosum_kernel(const float* __restrict__ Wo,
                                                    float* __restrict__ woSum) {
    int i = blockIdx.x * 256 + threadIdx.x;   // 16384
    int h = i >> 10, c = i & 1023;
    float acc = 0.f;
    #pragma unroll 8
    for (int d = 0; d < 64; d++)
        acc += Wo[(size_t)(h * 64 + d) * D_DIM + c];
    woSum[i] = acc;
}

// ---------------- corr[r][c] = sum_h sbv[r][h]*WoSum[h][c] ----------------
__global__ void __launch_bounds__(256) corr_kernel(const float* __restrict__ sbv,
                                                   const float* __restrict__ woSum,
                                                   float* __restrict__ corr) {
    int r = blockIdx.x;
    int c = threadIdx.x * 4;
    float sb[16];
    #pragma unroll
    for (int h = 0; h < 16; h++) sb[h] = sbv[r * H_N + h];
    float4 acc = make_float4(0.f, 0.f, 0.f, 0.f);
    #pragma unroll
    for (int h = 0; h < 16; h++) {
        float4 w = *reinterpret_cast<const float4*>(woSum + h * D_DIM + c);
        acc.x += sb[h] * w.x;
        acc.y += sb[h] * w.y;
        acc.z += sb[h] * w.z;
        acc.w += sb[h] * w.w;
    }
    *reinterpret_cast<float4*>(corr + (size_t)r * D_DIM + c) = acc;
}

// ---------------- RMSNorm -> fp16 x ----------------
__global__ void __launch_bounds__(256) rmsnorm_kernel(const float* __restrict__ h,
                                                      __half* __restrict__ xh) {
    int row = blockIdx.x;
    int t = threadIdx.x;
    const float4* hr = reinterpret_cast<const float4*>(h + (size_t)row * D_DIM);
    float4 a = hr[t];
    float ss = a.x * a.x + a.y * a.y + a.z * a.z + a.w * a.w;
    __shared__ float red[8];
    #pragma unroll
    for (int off = 16; off; off >>= 1) ss += __shfl_xor_sync(0xffffffffu, ss, off);
    if ((t & 31) == 0) red[t >> 5] = ss;
    __syncthreads();
    float tot = red[0] + red[1] + red[2] + red[3] + red[4] + red[5] + red[6] + red[7];
    float r = rsqrtf(tot * (1.0f / 1024.0f) + 1.1920929e-7f);
    __half2 h0 = __floats2half2_rn(a.x * r, a.y * r);
    __half2 h1 = __floats2half2_rn(a.z * r, a.w * r);
    uint2 packed = make_uint2(*reinterpret_cast<uint32_t*>(&h0),
                              *reinterpret_cast<uint32_t*>(&h1));
    *reinterpret_cast<uint2*>(xh + (size_t)row * D_DIM + t * 4) = packed;
}

// ---------------- fp16 cp.async GEMM ----------------
#define HSTR 40
#define GEMM_SMEM (4 * 128 * HSTR * 2)

__global__ void __launch_bounds__(256) gemm_f16_kernel(
    const __half* __restrict__ A,
    const __half* __restrict__ B0, const __half* __restrict__ B1,
    const __half* __restrict__ B2, const __half* __restrict__ B3,
    const __half* __restrict__ B4,
    float* __restrict__ C0, float* __restrict__ C3, float* __restrict__ C4,
    __half* __restrict__ ChQ, __half* __restrict__ ChK, __half* __restrict__ ChV,
    int M, int N, int K,
    const float* __restrict__ bias,
    const float* __restrict__ add0,
    const float* __restrict__ add1,
    const float* __restrict__ lamPtr)
{
    int z = blockIdx.z;
    const __half* B = (z == 0) ? B0 : (z == 1) ? B1 : (z == 2) ? B2 : (z == 3) ? B3 : B4;
    float* C = (z == 3) ? C3 : (z == 4) ? C4 : C0;
    __half* chDst = (z == 0) ? ChQ : (z == 1) ? ChK : (z == 2) ? ChV : nullptr;

    extern __shared__ __half smh[];
    __half (*As)[128][HSTR] = reinterpret_cast<__half(*)[128][HSTR]>(smh);
    __half (*Bs)[128][HSTR] = reinterpret_cast<__half(*)[128][HSTR]>(smh + 2 * 128 * HSTR);

    int tid = threadIdx.x;
    int lane = tid & 31;
    int warp = tid >> 5;
    int warpM = warp >> 1;
    int warpN = warp & 1;
    int lr = lane >> 2;
    int lc = lane & 3;
    int bm = blockIdx.y * 128;
    int bn = blockIdx.x * 128;

    int sr = tid >> 1;
    int sc = (tid & 1) * 16;
    const __half* Ap = A + (size_t)(bm + sr) * K + sc;
    const __half* Bp = B + (size_t)(bn + sr) * K + sc;

    int aRow = lane & 15, aCol = (lane >> 4) * 8;
    int bRow = ((lane & 16) ? 8 : 0) + (lane & 7);
    int bCol = ((lane & 8) ? 8 : 0);
    uint32_t aOff[2], bOff[4];
    #pragma unroll
    for (int mi = 0; mi < 2; mi++)
        aOff[mi] = ((warpM * 32 + mi * 16 + aRow) * HSTR + aCol) * 2;
    #pragma unroll
    for (int nip = 0; nip < 4; nip++)
        bOff[nip] = ((warpN * 64 + nip * 16 + bRow) * HSTR + bCol) * 2;

    float acc[2][8][4];
    #pragma unroll
    for (int mi = 0; mi < 2; mi++)
        #pragma unroll
        for (int ni = 0; ni < 8; ni++)
            #pragma unroll
            for (int r = 0; r < 4; r++) acc[mi][ni][r] = 0.f;

    int NT = K / 32;

    auto issue = [&](int buf, int t) {
        const __half* ga = Ap + t * 32;
        const __half* gb = Bp + t * 32;
        uint32_t da = smem_u32(&As[buf][sr][sc]);
        uint32_t db = smem_u32(&Bs[buf][sr][sc]);
        CP16(da, ga);
        CP16(da + 16, ga + 8);
        CP16(db, gb);
        CP16(db + 16, gb + 8);
        asm volatile("cp.async.commit_group;" ::: "memory");
    };

    issue(0, 0);
    for (int t = 0; t < NT; t++) {
        int buf = t & 1;
        if (t + 1 < NT) {
            issue(buf ^ 1, t + 1);
            asm volatile("cp.async.wait_group 1;" ::: "memory");
        } else {
            asm volatile("cp.async.wait_group 0;" ::: "memory");
        }
        __syncthreads();
        uint32_t aBase = smem_u32(&As[buf][0][0]);
        uint32_t bBase = smem_u32(&Bs[buf][0][0]);
        #pragma unroll
        for (int ks = 0; ks < 2; ks++) {
            uint32_t koff = ks * 32;
            uint32_t af[2][4], bf[8][2];
            #pragma unroll
            for (int mi = 0; mi < 2; mi++)
                LDSM_X4(af[mi][0], af[mi][1], af[mi][2], af[mi][3],
                        aBase + aOff[mi] + koff);
            #pragma unroll
            for (int nip = 0; nip < 4; nip++)
                LDSM_X4(bf[2 * nip][0], bf[2 * nip][1],
                        bf[2 * nip + 1][0], bf[2 * nip + 1][1],
                        bBase + bOff[nip] + koff);
            #pragma unroll
            for (int mi = 0; mi < 2; mi++)
                #pragma unroll
                for (int ni = 0; ni < 8; ni++)
                    MMA_F16(acc[mi][ni], af[mi], bf[ni]);
        }
        __syncthreads();
    }

    float lam = lamPtr ? lamPtr[0] : 0.f;
    #pragma unroll
    for (int mi = 0; mi < 2; mi++) {
        int r0 = bm + warpM * 32 + mi * 16 + lr;
        #pragma unroll
        for (int ni = 0; ni < 8; ni++) {
            int c0 = bn + warpN * 64 + ni * 8 + lc * 2;
            #pragma unroll
            for (int half_ = 0; half_ < 2; half_++) {
                int r = r0 + half_ * 8;
                float v0 = acc[mi][ni][half_ * 2 + 0];
                float v1 = acc[mi][ni][half_ * 2 + 1];
                if (bias) { v0 += bias[c0]; v1 += bias[c0 + 1]; }
                size_t idx = (size_t)r * N + c0;
                if (chDst) {
                    __half2 hv = __floats2half2_rn(v0, v1);
                    *reinterpret_cast<__half2*>(chDst + idx) = hv;
                } else {
                    if (add0) { v0 += add0[idx]; v1 += add0[idx + 1]; }
                    if (add1) { v0 += lam * add1[idx]; v1 += lam * add1[idx + 1]; }
                    C[idx]     = v0;
                    C[idx + 1] = v1;
                }
            }
        }
    }
}

// ---------------- fused W1 GEMM + SwiGLU -> fm (fp16) ----------------
#define W1_SMEM (6 * 128 * HSTR * 2)

__global__ void __launch_bounds__(256) gemm_w1_swiglu_kernel(
    const __half* __restrict__ A, const __half* __restrict__ W1t,
    __half* __restrict__ fmh, const float* __restrict__ b1)
{
    extern __shared__ __half smh[];
    __half (*As)[128][HSTR]  = reinterpret_cast<__half(*)[128][HSTR]>(smh);
    __half (*Bx)[128][HSTR]  = reinterpret_cast<__half(*)[128][HSTR]>(smh + 2 * 128 * HSTR);
    __half (*Bg)[128][HSTR]  = reinterpret_cast<__half(*)[128][HSTR]>(smh + 4 * 128 * HSTR);

    const int K = D_DIM, N = FF_IN;
    int tid = threadIdx.x;
    int lane = tid & 31;
    int warp = tid >> 5;
    int warpM = warp >> 1;
    int warpN = warp & 1;
    int lr = lane >> 2;
    int lc = lane & 3;
    int bm = blockIdx.y * 128;
    int bn = blockIdx.x * 128;

    int sr = tid >> 1;
    int sc = (tid & 1) * 16;
    const __half* Ap  = A   + (size_t)(bm + sr) * K + sc;
    const __half* Bxp = W1t + (size_t)(bn + sr) * K + sc;
    const __half* Bgp = W1t + (size_t)(FF_IN + bn + sr) * K + sc;

    int aRow = lane & 15, aCol = (lane >> 4) * 8;
    int bRow = ((lane & 16) ? 8 : 0) + (lane & 7);
    int bCol = ((lane & 8) ? 8 : 0);
    uint32_t aOff[2], bOff[4];
    #pragma unroll
    for (int mi = 0; mi < 2; mi++)
        aOff[mi] = ((warpM * 32 + mi * 16 + aRow) * HSTR + aCol) * 2;
    #pragma unroll
    for (int nip = 0; nip < 4; nip++)
        bOff[nip] = ((warpN * 64 + nip * 16 + bRow) * HSTR + bCol) * 2;

    float accX[2][8][4], accG[2][8][4];
    #pragma unroll
    for (int mi = 0; mi < 2; mi++)
        #pragma unroll
        for (int ni = 0; ni < 8; ni++)
            #pragma unroll
            for (int r = 0; r < 4; r++) { accX[mi][ni][r] = 0.f; accG[mi][ni][r] = 0.f; }

    const int NT = K / 32;

    auto issue = [&](int buf, int t) {
        uint32_t da = smem_u32(&As[buf][sr][sc]);
        uint32_t dx = smem_u32(&Bx[buf][sr][sc]);
        uint32_t dg = smem_u32(&Bg[buf][sr][sc]);
        CP16(da, Ap + t * 32);
        CP16(da + 16, Ap + t * 32 + 8);
        CP16(dx, Bxp + t * 32);
        CP16(dx + 16, Bxp + t * 32 + 8);
        CP16(dg, Bgp + t * 32);
        CP16(dg + 16, Bgp + t * 32 + 8);
        asm volatile("cp.async.commit_group;" ::: "memory");
    };

    issue(0, 0);
    for (int t = 0; t < NT; t++) {
        int buf = t & 1;
        if (t + 1 < NT) {
            issue(buf ^ 1, t + 1);
            asm volatile("cp.async.wait_group 1;" ::: "memory");
        } else {
            asm volatile("cp.async.wait_group 0;" ::: "memory");
        }
        __syncthreads();
        uint32_t aBase = smem_u32(&As[buf][0][0]);
        uint32_t xBase = smem_u32(&Bx[buf][0][0]);
        uint32_t gBase = smem_u32(&Bg[buf][0][0]);
        #pragma unroll
        for (int ks = 0; ks < 2; ks++) {
            uint32_t koff = ks * 32;
            uint32_t af[2][4], bx[8][2], bg[8][2];
            #pragma unroll
            for (int mi = 0; mi < 2; mi++)
                LDSM_X4(af[mi][0], af[mi][1], af[mi][2], af[mi][3],
                        aBase + aOff[mi] + koff);
            #pragma unroll
            for (int nip = 0; nip < 4; nip++) {
                LDSM_X4(bx[2 * nip][0], bx[2 * nip][1],
                        bx[2 * nip + 1][0], bx[2 * nip + 1][1],
                        xBase + bOff[nip] + koff);
                LDSM_X4(bg[2 * nip][0], bg[2 * nip][1],
                        bg[2 * nip + 1][0], bg[2 * nip + 1][1],
                        gBase + bOff[nip] + koff);
            }
            #pragma unroll
            for (int mi = 0; mi < 2; mi++)
                #pragma unroll
                for (int ni = 0; ni < 8; ni++) {
                    MMA_F16(accX[mi][ni], af[mi], bx[ni]);
                    MMA_F16(accG[mi][ni], af[mi], bg[ni]);
                }
        }
        __syncthreads();
    }

    #pragma unroll
    for (int mi = 0; mi < 2; mi++) {
        int r0 = bm + warpM * 32 + mi * 16 + lr;
        #pragma unroll
        for (int ni = 0; ni < 8; ni++) {
            int c0 = bn + warpN * 64 + ni * 8 + lc * 2;
            float bx0 = b1[c0], bx1 = b1[c0 + 1];
            float bg0 = b1[FF_IN + c0], bg1 = b1[FF_IN + c0 + 1];
            #pragma unroll
            for (int half_ = 0; half_ < 2; half_++) {
                int r = r0 + half_ * 8;
                float xp0 = accX[mi][ni][half_ * 2 + 0] + bx0;
                float xp1 = accX[mi][ni][half_ * 2 + 1] + bx1;
                float g0 = accG[mi][ni][half_ * 2 + 0] + bg0;
                float g1 = accG[mi][ni][half_ * 2 + 1] + bg1;
                float f0 = (g0 / (1.f + __expf(-g0))) * xp0;
                float f1 = (g1 / (1.f + __expf(-g1))) * xp1;
                __half2 hv = __floats2half2_rn(f0, f1);
                *reinterpret_cast<__half2*>(fmh + (size_t)r * N + c0) = hv;
            }
        }
    }
}

// ---------------- l2norm + RoPE (q,k fp16 in-place; qb,kb fp32 in-place) ----
__global__ void __launch_bounds__(256) ropenorm_kernel(
    __half* __restrict__ qh, __half* __restrict__ kh, float* qb, float* kb) {
    int s = blockIdx.x;
    int warp = threadIdx.x >> 5;
    int lane = threadIdx.x & 31;
    int idx = blockIdx.y * 8 + warp;
    int h = idx & 15;
    int a = idx >> 4;
    size_t off = (size_t)s * D_DIM + h * 64;
    float x1, x2;
    if (a < 2) {
        const __half* p = ((a == 0) ? qh : kh) + off;
        x1 = __half2float(p[lane]);
        x2 = __half2float(p[lane + DHALF]);
    } else {
        const float* p = ((a == 2) ? qb : kb) + off;
        x1 = p[lane];
        x2 = p[lane + DHALF];
    }
    float ss = x1 * x1 + x2 * x2;
    #pragma unroll
    for (int o = 16; o; o >>= 1) ss += __shfl_xor_sync(0xffffffffu, ss, o);
    float n = fmaxf(sqrtf(ss), 1e-12f);
    float inv = 1.f / n;
    x1 *= inv;
    x2 *= inv;
    float invfreq = powf(1000.0f, -(float)lane * (1.0f / 32.0f));
    float fr = (float)s * invfreq;
    float c  = __bfloat162float(__float2bfloat16(cosf(fr)));
    float sn = __bfloat162float(__float2bfloat16(sinf(fr)));
    float y1 = x1 * c + x2 * sn;
    float y2 = -x1 * sn + x2 * c;
    if (a < 2) {
        __half* dst = ((a == 0) ? qh : kh) + off;
        dst[lane]         = __float2half(y1);
        dst[lane + DHALF] = __float2half(y2);
    } else {
        float* dst = ((a == 2) ? qb : kb) + off;
        dst[lane]         = y1;
        dst[lane + DHALF] = y2;
    }
}

// ---------------- parallel prefix sum of kb ----------------
__global__ void __launch_bounds__(256) prefix_p1(const float* __restrict__ kb,
                                                 float* __restrict__ cs) {
    int ch = blockIdx.x;
    int col = blockIdx.y * 256 + threadIdx.x;
    const float* p = kb + (size_t)(ch * 32) * D_DIM + col;
    float acc = 0.f;
    #pragma unroll
    for (int r = 0; r < 32; r++) acc += p[(size_t)r * D_DIM];
    cs[(size_t)ch * D_DIM + col] = acc;
}
__global__ void __launch_bounds__(1024) prefix_p2(float* __restrict__ cs) {
    int col = threadIdx.x;
    float run = 0.f;
    #pragma unroll 8
    for (int ch = 0; ch < 64; ch++) {
        size_t i = (size_t)ch * D_DIM + col;
        float t = cs[i];
        cs[i] = run;
        run += t;
    }
}
__global__ void __launch_bounds__(256) prefix_p3(const float* __restrict__ kb,
                                                 const float* __restrict__ cs,
                                                 float* __restrict__ pkb) {
    int ch = blockIdx.x;
    int col = blockIdx.y * 256 + threadIdx.x;
    float acc = cs[(size_t)ch * D_DIM + col];
    const float* p = kb + (size_t)(ch * 32) * D_DIM + col;
    float* o = pkb + (size_t)(ch * 32) * D_DIM + col;
    #pragma unroll
    for (int r = 0; r < 32; r++) {
        acc += p[(size_t)r * D_DIM];
        o[(size_t)r * D_DIM] = acc;
    }
}

// ---------------- sb values ----------------
__global__ void __launch_bounds__(512) sb_kernel(const float* __restrict__ qb,
                                                 const float* __restrict__ pkb,
                                                 float* __restrict__ sbv) {
    int s = blockIdx.x;
    int h = threadIdx.x >> 5;
    int lane = threadIdx.x & 31;
    size_t off = (size_t)s * D_DIM + h * 64;
    float v = qb[off + lane] * pkb[off + lane] +
              qb[off + lane + DHALF] * pkb[off + lane + DHALF];
    #pragma unroll
    for (int o = 16; o; o >>= 1) v += __shfl_xor_sync(0xffffffffu, v, o);
    if (lane == 0) sbv[s * H_N + h] = 0.125f * v;
}

// ---------------- fp16 flash attention: 128-row q tiles, cp.async K/V ------
// Longest-first scheduling: qt = gridDim.x-1-blockIdx.x. No sb here (moved to Wo).
#define QSH 72
#define ATT_SMEM (512 * QSH * 2 + 256 * 4)

__global__ void __launch_bounds__(256) attn_mma_kernel(
    const __half* __restrict__ qh, const __half* __restrict__ kh,
    const __half* __restrict__ vh,
    const float* __restrict__ l2sp, __half* __restrict__ yh)
{
    extern __shared__ __half smah[];
    __half (*Qs)[QSH] = reinterpret_cast<__half(*)[QSH]>(smah);
    __half (*Ps)[QSH] = reinterpret_cast<__half(*)[QSH]>(smah + 128 * QSH);
    __half (*Ks)[64][QSH] = reinterpret_cast<__half(*)[64][QSH]>(smah + 256 * QSH);
    __half (*Vs)[64][QSH] = reinterpret_cast<__half(*)[64][QSH]>(smah + 384 * QSH);
    float* red_l = reinterpret_cast<float*>(smah + 512 * QSH);

    int h = blockIdx.y;
    int qt = gridDim.x - 1 - blockIdx.x;   // longest tiles first
    int q0 = qt * 128;
    int tid = threadIdx.x;
    int lane = tid & 31, warp = tid >> 5;
    int wm = warp >> 1;
    int wn = warp & 1;
    int lr = lane >> 2;
    int lc = lane & 3;

    int aRow = lane & 15, aCol = (lane >> 4) * 8;
    uint32_t qOff[2];
    #pragma unroll
    for (int mi = 0; mi < 2; mi++)
        qOff[mi] = ((wm * 32 + mi * 16 + aRow) * QSH + aCol) * 2;
    int bRow = ((lane & 16) ? 8 : 0) + (lane & 7);
    int bCol = ((lane & 8) ? 8 : 0);
    uint32_t kOff[2];
    #pragma unroll
    for (int nip = 0; nip < 2; nip++)
        kOff[nip] = ((wn * 32 + nip * 16 + bRow) * QSH + bCol) * 2;
    int tRow = ((lane & 8) ? 8 : 0) + (lane & 7);
    int tCol = ((lane & 16) ? 8 : 0);
    uint32_t vOff[2];
    #pragma unroll
    for (int nip = 0; nip < 2; nip++)
        vOff[nip] = (tRow * QSH + wn * 32 + nip * 16 + tCol) * 2;

    uint32_t qBase = smem_u32(&Qs[0][0]);
    uint32_t pBase = smem_u32(&Ps[0][0]);

    int stR = tid >> 2, stC = (tid & 3) * 16;

    auto issueKV = [&](int buf, int kt) {
        int kbase = kt * 64;
        const __half* ks = kh + (size_t)(kbase + stR) * D_DIM + h * 64 + stC;
        const __half* vs = vh + (size_t)(kbase + stR) * D_DIM + h * 64 + stC;
        uint32_t dk = smem_u32(&Ks[buf][stR][stC]);
        uint32_t dv = smem_u32(&Vs[buf][stR][stC]);
        CP16(dk, ks);
        CP16(dk + 16, ks + 8);
        CP16(dv, vs);
        CP16(dv + 16, vs + 8);
        asm volatile("cp.async.commit_group;" ::: "memory");
    };

    {
        int r = tid >> 1, c0 = (tid & 1) * 32;
        const __half* src = qh + (size_t)(q0 + r) * D_DIM + h * 64 + c0;
        #pragma unroll
        for (int j = 0; j < 4; j++)
            *reinterpret_cast<uint4*>(&Qs[r][c0 + j * 8]) =
                *reinterpret_cast<const uint4*>(src + j * 8);
    }

    float l[4] = {0.f, 0.f, 0.f, 0.f};
    float o[2][4][4];
    #pragma unroll
    for (int mi = 0; mi < 2; mi++)
        #pragma unroll
        for (int ni = 0; ni < 4; ni++)
            #pragma unroll
            for (int j = 0; j < 4; j++) o[mi][ni][j] = 0.f;

    int nt = 2 * qt + 2;
    issueKV(0, 0);

    for (int kt = 0; kt < nt; kt++) {
        int buf = kt & 1;
        int kbase = kt * 64;
        __syncthreads();
        if (kt + 1 < nt) {
            issueKV(buf ^ 1, kt + 1);
            asm volatile("cp.async.wait_group 1;" ::: "memory");
        } else {
            asm volatile("cp.async.wait_group 0;" ::: "memory");
        }
        __syncthreads();

        uint32_t kBase = smem_u32(&Ks[buf][0][0]);
        uint32_t vBase = smem_u32(&Vs[buf][0][0]);

        float s[2][4][4];
        #pragma unroll
        for (int mi = 0; mi < 2; mi++)
            #pragma unroll
            for (int ni = 0; ni < 4; ni++)
                #pragma unroll
                for (int j = 0; j < 4; j++) s[mi][ni][j] = 0.f;
        #pragma unroll
        for (int ks = 0; ks < 4; ks++) {
            uint32_t kbyte = ks * 32;
            uint32_t af[2][4], bf[4][2];
            #pragma unroll
            for (int mi = 0; mi < 2; mi++)
                LDSM_X4(af[mi][0], af[mi][1], af[mi][2], af[mi][3],
                        qBase + qOff[mi] + kbyte);
            #pragma unroll
            for (int nip = 0; nip < 2; nip++)
                LDSM_X4(bf[2 * nip][0], bf[2 * nip][1],
                        bf[2 * nip + 1][0], bf[2 * nip + 1][1],
                        kBase + kOff[nip] + kbyte);
            #pragma unroll
            for (int mi = 0; mi < 2; mi++)
                #pragma unroll
                for (int ni = 0; ni < 4; ni++)
                    MMA_F16(s[mi][ni], af[mi], bf[ni]);
        }
        if (kt >= nt - 2) {
            #pragma unroll
            for (int mi = 0; mi < 2; mi++) {
                int rg0 = q0 + wm * 32 + mi * 16 + lr;
                #pragma unroll
                for (int ni = 0; ni < 4; ni++) {
                    int cgb = kbase + wn * 32 + ni * 8 + lc * 2;
                    #pragma unroll
                    for (int j = 0; j < 4; j++) {
                        int rg = rg0 + ((j >= 2) ? 8 : 0);
                        int cg = cgb + (j & 1);
                        if (cg > rg) s[mi][ni][j] = -1e4f;
                    }
                }
            }
        }
        #pragma unroll
        for (int mi = 0; mi < 2; mi++) {
            int r0m = wm * 32 + mi * 16 + lr;
            int r1m = r0m + 8;
            #pragma unroll
            for (int ni = 0; ni < 4; ni++) {
                int cbase = wn * 32 + ni * 8 + lc * 2;
                float t0 = fmaf(s[mi][ni][0], L2E, -L2E);
                float t1 = fmaf(s[mi][ni][1], L2E, -L2E);
                float t2 = fmaf(s[mi][ni][2], L2E, -L2E);
                float t3 = fmaf(s[mi][ni][3], L2E, -L2E);
                __half2 ht0 = __floats2half2_rn(t0, t1);
                __half2 ht1 = __floats2half2_rn(t2, t3);
                uint32_t p0, p1;
                EX2_F16X2(p0, *reinterpret_cast<uint32_t*>(&ht0));
                EX2_F16X2(p1, *reinterpret_cast<uint32_t*>(&ht1));
                *reinterpret_cast<uint32_t*>(&Ps[r0m][cbase]) = p0;
                *reinterpret_cast<uint32_t*>(&Ps[r1m][cbase]) = p1;
                float2 f0 = __half22float2(*reinterpret_cast<__half2*>(&p0));
                float2 f1 = __half22float2(*reinterpret_cast<__half2*>(&p1));
                l[mi * 2]     += f0.x + f0.y;
                l[mi * 2 + 1] += f1.x + f1.y;
            }
        }
        __syncthreads();
        #pragma unroll
        for (int ks = 0; ks < 4; ks++) {
            uint32_t af[2][4], bf[4][2];
            #pragma unroll
            for (int mi = 0; mi < 2; mi++)
                LDSM_X4(af[mi][0], af[mi][1], af[mi][2], af[mi][3],
                        pBase + qOff[mi] + ks * 32);
            #pragma unroll
            for (int nip = 0; nip < 2; nip++)
                LDSM_X4T(bf[2 * nip][0], bf[2 * nip][1],
                         bf[2 * nip + 1][0], bf[2 * nip + 1][1],
                         vBase + vOff[nip] + ks * 16 * QSH * 2);
            #pragma unroll
            for (int mi = 0; mi < 2; mi++)
                #pragma unroll
                for (int ni = 0; ni < 4; ni++)
                    MMA_F16(o[mi][ni], af[mi], bf[ni]);
        }
    }

    #pragma unroll
    for (int i = 0; i < 4; i++) {
        l[i] += __shfl_xor_sync(0xffffffffu, l[i], 1);
        l[i] += __shfl_xor_sync(0xffffffffu, l[i], 2);
    }
    if (lc == 0) {
        #pragma unroll
        for (int mi = 0; mi < 2; mi++) {
            int r0m = wm * 32 + mi * 16 + lr;
            red_l[wn * 128 + r0m]     = l[mi * 2];
            red_l[wn * 128 + r0m + 8] = l[mi * 2 + 1];
        }
    }
    __syncthreads();

    float l2sv = l2sp[0];
    #pragma unroll
    for (int mi = 0; mi < 2; mi++) {
        int r0m = wm * 32 + mi * 16 + lr;
        int r1m = r0m + 8;
        float lt0 = red_l[r0m] + red_l[128 + r0m];
        float lt1 = red_l[r1m] + red_l[128 + r1m];
        float inv0 = l2sv / lt0;
        float inv1 = l2sv / lt1;
        int g0 = q0 + r0m, g1 = q0 + r1m;
        #pragma unroll
        for (int ni = 0; ni < 4; ni++) {
            int col = h * 64 + wn * 32 + ni * 8 + lc * 2;
            __half2 r0v = __floats2half2_rn(o[mi][ni][0] * inv0, o[mi][ni][1] * inv0);
            __half2 r1v = __floats2half2_rn(o[mi][ni][2] * inv1, o[mi][ni][3] * inv1);
            *reinterpret_cast<__half2*>(&yh[(size_t)g0 * D_DIM + col]) = r0v;
            *reinterpret_cast<__half2*>(&yh[(size_t)g1 * D_DIM + col]) = r1v;
        }
    }
}

// ---------------- launch ----------------
extern "C" void kernel_launch(void* const* d_in, const int* in_sizes, int n_in,
                              void* d_out, int out_size) {
    const float* h_states = (const float*)d_in[0];
    const float* Wq  = (const float*)d_in[1];
    const float* Wk  = (const float*)d_in[2];
    const float* Wv  = (const float*)d_in[3];
    const float* Wqb = (const float*)d_in[4];
    const float* Wkb = (const float*)d_in[5];
    const float* Wo  = (const float*)d_in[6];
    const float* bo  = (const float*)d_in[7];
    const float* W1  = (const float*)d_in[8];
    const float* b1  = (const float*)d_in[9];
    const float* W2  = (const float*)d_in[10];
    const float* b2  = (const float*)d_in[11];
    const float* lam = (const float*)d_in[12];
    const float* l2s = (const float*)d_in[13];
    float* out = (float*)d_out;

    float *qb, *kb, *pkb, *cs, *sbv, *ao, *wos, *cor;
    __half *xh, *yh, *fmh, *qhh, *khh, *vhh;
    __half *wqh, *wkh, *wvh, *wqbh, *wkbh, *woh, *w1h, *w2h;
    cudaGetSymbolAddress((void**)&qb, g_qb);
    cudaGetSymbolAddress((void**)&kb, g_kb);
    cudaGetSymbolAddress((void**)&pkb, g_pkb);
    cudaGetSymbolAddress((void**)&cs, g_cs);
    cudaGetSymbolAddress((void**)&sbv, g_sb);
    cudaGetSymbolAddress((void**)&ao, g_ao);
    cudaGetSymbolAddress((void**)&wos, g_wos);
    cudaGetSymbolAddress((void**)&cor, g_cor);
    cudaGetSymbolAddress((void**)&xh,  g_xh);
    cudaGetSymbolAddress((void**)&yh,  g_yh);
    cudaGetSymbolAddress((void**)&fmh, g_fmh);
    cudaGetSymbolAddress((void**)&qhh, g_qhh);
    cudaGetSymbolAddress((void**)&khh, g_khh);
    cudaGetSymbolAddress((void**)&vhh, g_vhh);
    cudaGetSymbolAddress((void**)&wqh,  g_wqh);
    cudaGetSymbolAddress((void**)&wkh,  g_wkh);
    cudaGetSymbolAddress((void**)&wvh,  g_wvh);
    cudaGetSymbolAddress((void**)&wqbh, g_wqbh);
    cudaGetSymbolAddress((void**)&wkbh, g_wkbh);
    cudaGetSymbolAddress((void**)&woh,  g_woh);
    cudaGetSymbolAddress((void**)&w1h,  g_w1h);
    cudaGetSymbolAddress((void**)&w2h,  g_w2h);

    cudaFuncSetAttribute(attn_mma_kernel,
                         cudaFuncAttributeMaxDynamicSharedMemorySize, ATT_SMEM);
    cudaFuncSetAttribute(gemm_f16_kernel,
                         cudaFuncAttributeMaxDynamicSharedMemorySize, GEMM_SMEM);
    cudaFuncSetAttribute(gemm_w1_swiglu_kernel,
                         cudaFuncAttributeMaxDynamicSharedMemorySize, W1_SMEM);

    static cudaStream_t s1 = nullptr, s2 = nullptr;
    static cudaEvent_t evX = nullptr, evFFN = nullptr, evRope = nullptr, evSB = nullptr;
    if (!s1) {
        cudaStreamCreateWithFlags(&s1, cudaStreamNonBlocking);
        cudaStreamCreateWithFlags(&s2, cudaStreamNonBlocking);
        cudaEventCreateWithFlags(&evX, cudaEventDisableTiming);
        cudaEventCreateWithFlags(&evFFN, cudaEventDisableTiming);
        cudaEventCreateWithFlags(&evRope, cudaEventDisableTiming);
        cudaEventCreateWithFlags(&evSB, cudaEventDisableTiming);
    }

    // ---- main: shared prologue ----
    cvtT6_kernel<<<dim3(32, 32, 6), 256>>>(Wq, Wk, Wv, Wqb, Wkb, Wo,
                                           wqh, wkh, wvh, wqbh, wkbh, woh);
    rmsnorm_kernel<<<S_LEN, 256>>>(h_states, xh);
    cudaEventRecord(evX, 0);

    // ---- s1: FFN branch ----
    cvtT_kernel<<<dim3(FUSEDW / 32, 32), 256, 0, s1>>>(W1, w1h, D_DIM, FUSEDW);
    cvtT_kernel<<<dim3(32, FF_IN / 32), 256, 0, s1>>>(W2, w2h, FF_IN, D_DIM);
    cudaStreamWaitEvent(s1, evX, 0);
    gemm_w1_swiglu_kernel<<<dim3(FF_IN / 128, S_LEN / 128), 256, W1_SMEM, s1>>>(
        xh, w1h, fmh, b1);
    cudaEventRecord(evFFN, s1);

    // ---- s2: WoSum (needs only Wo) ----
    wosum_kernel<<<H_N * D_DIM / 256, 256, 0, s2>>>(Wo, wos);

    // ---- main: attention branch ----
    gemm_f16_kernel<<<dim3(D_DIM / 128, S_LEN / 128, 5), 256, GEMM_SMEM>>>(
        xh, wqh, wkh, wvh, wqbh, wkbh, nullptr, qb, kb, qhh, khh, vhh,
        S_LEN, D_DIM, D_DIM, nullptr, nullptr, nullptr, nullptr);
    ropenorm_kernel<<<dim3(S_LEN, 8), 256>>>(qhh, khh, qb, kb);
    cudaEventRecord(evRope, 0);

    // ---- s2: sb/corr chain, overlapped with attention ----
    cudaStreamWaitEvent(s2, evRope, 0);
    prefix_p1<<<dim3(64, 4), 256, 0, s2>>>(kb, cs);
    prefix_p2<<<1, 1024, 0, s2>>>(cs);
    prefix_p3<<<dim3(64, 4), 256, 0, s2>>>(kb, cs, pkb);
    sb_kernel<<<S_LEN, 512, 0, s2>>>(qb, pkb, sbv);
    corr_kernel<<<S_LEN, 256, 0, s2>>>(sbv, wos, cor);
    cudaEventRecord(evSB, s2);

    // ---- main: attention (no sb) ----
    attn_mma_kernel<<<dim3(S_LEN / 128, H_N), 256, ATT_SMEM>>>(qhh, khh, vhh, l2s, yh);

    // ---- main: Wo GEMM with corr (join s2) ----
    cudaStreamWaitEvent(0, evSB, 0);
    gemm_f16_kernel<<<dim3(D_DIM / 128, S_LEN / 128, 1), 256, GEMM_SMEM>>>(
        yh, woh, nullptr, nullptr, nullptr, nullptr,
        ao, nullptr, nullptr, nullptr, nullptr, nullptr,
        S_LEN, D_DIM, D_DIM, bo, cor, nullptr, nullptr);

    // ---- join FFN, final GEMM ----
    cudaStreamWaitEvent(0, evFFN, 0);
    gemm_f16_kernel<<<dim3(D_DIM / 128, S_LEN / 128, 1), 256, GEMM_SMEM>>>(
        fmh, w2h, nullptr, nullptr, nullptr, nullptr,
        out, nullptr, nullptr, nullptr, nullptr, nullptr,
        S_LEN, D_DIM, FF_IN, b2, ao, h_states, lam);
}

// round 15
// speedup vs baseline: 9.6686x; 1.0136x over previous
#include <cuda_runtime.h>
#include <cuda_bf16.h>
#include <cuda_fp16.h>
#include <cstdint>

#define S_LEN 2048
#define D_DIM 1024
#define H_N 16
#define DHALF 32
#define FF_IN 4096
#define FUSEDW 8192

// ---------------- scratch ----------------
__device__ float  g_qb [S_LEN * D_DIM];
__device__ float  g_kb [S_LEN * D_DIM];
__device__ float  g_pkb[S_LEN * D_DIM];
__device__ float  g_cs [64 * D_DIM];
__device__ float  g_sb [S_LEN * H_N];
__device__ float  g_ao [S_LEN * D_DIM];
__device__ float  g_wos[H_N * D_DIM];
__device__ float  g_cor[S_LEN * D_DIM];
__device__ __half g_xh [S_LEN * D_DIM];
__device__ __half g_yh [S_LEN * D_DIM];
__device__ __half g_fmh[S_LEN * FF_IN];
__device__ __half g_qhh[S_LEN * D_DIM];
__device__ __half g_khh[S_LEN * D_DIM];
__device__ __half g_vhh[S_LEN * D_DIM];
__device__ __half g_wqh [D_DIM * D_DIM];
__device__ __half g_wkh [D_DIM * D_DIM];
__device__ __half g_wvh [D_DIM * D_DIM];
__device__ __half g_wqbh[D_DIM * D_DIM];
__device__ __half g_wkbh[D_DIM * D_DIM];
__device__ __half g_woh [D_DIM * D_DIM];
__device__ __half g_w1h [FUSEDW * D_DIM];
__device__ __half g_w2h [D_DIM * FF_IN];

// ---------------- helpers ----------------
__device__ __forceinline__ uint32_t smem_u32(const void* p) {
    uint32_t a;
    asm("{ .reg .u64 t; cvta.to.shared.u64 t, %1; cvt.u32.u64 %0, t; }" : "=r"(a) : "l"(p));
    return a;
}

#define MMA_F16(d, a, b)                                                      \
    asm volatile(                                                             \
        "mma.sync.aligned.m16n8k16.row.col.f32.f16.f16.f32 "                  \
        "{%0,%1,%2,%3}, {%4,%5,%6,%7}, {%8,%9}, {%0,%1,%2,%3};"               \
        : "+f"(d[0]), "+f"(d[1]), "+f"(d[2]), "+f"(d[3])                      \
        : "r"(a[0]), "r"(a[1]), "r"(a[2]), "r"(a[3]), "r"(b[0]), "r"(b[1]))

#define LDSM_X4(r0, r1, r2, r3, a)                                            \
    asm volatile("ldmatrix.sync.aligned.m8n8.x4.shared.b16 {%0,%1,%2,%3}, [%4];" \
                 : "=r"(r0), "=r"(r1), "=r"(r2), "=r"(r3) : "r"(a))

#define LDSM_X4T(r0, r1, r2, r3, a)                                           \
    asm volatile("ldmatrix.sync.aligned.m8n8.x4.trans.shared.b16 {%0,%1,%2,%3}, [%4];" \
                 : "=r"(r0), "=r"(r1), "=r"(r2), "=r"(r3) : "r"(a))

#define EX2_F16X2(d, a)                                                       \
    asm volatile("ex2.approx.f16x2 %0, %1;" : "=r"(d) : "r"(a))

#define CP16(dst, src)                                                        \
    asm volatile("cp.async.ca.shared.global [%0], [%1], 16;" :: "r"(dst), "l"(src))

#define L2E 1.4426950408889634f

// ---------------- weight fp16 convert + transpose ----------------
__global__ void __launch_bounds__(256) cvtT6_kernel(
    const float* __restrict__ W0, const float* __restrict__ W1,
    const float* __restrict__ W2, const float* __restrict__ W3,
    const float* __restrict__ W4, const float* __restrict__ W5,
    __half* __restrict__ O0, __half* __restrict__ O1,
    __half* __restrict__ O2, __half* __restrict__ O3,
    __half* __restrict__ O4, __half* __restrict__ O5) {
    int z = blockIdx.z;
    const float* W = (z == 0) ? W0 : (z == 1) ? W1 : (z == 2) ? W2
                   : (z == 3) ? W3 : (z == 4) ? W4 : W5;
    __half* Wt = (z == 0) ? O0 : (z == 1) ? O1 : (z == 2) ? O2
               : (z == 3) ? O3 : (z == 4) ? O4 : O5;
    __shared__ float t[32][33];
    int n0 = blockIdx.x * 32, k0 = blockIdx.y * 32;
    int tx = threadIdx.x & 31, ty = threadIdx.x >> 5;
    #pragma unroll
    for (int i = 0; i < 32; i += 8)
        t[ty + i][tx] = W[(size_t)(k0 + ty + i) * D_DIM + n0 + tx];
    __syncthreads();
    #pragma unroll
    for (int i = 0; i < 32; i += 8)
        Wt[(size_t)(n0 + ty + i) * D_DIM + k0 + tx] = __float2half(t[tx][ty + i]);
}

__global__ void __launch_bounds__(256) cvtT_kernel(const float* __restrict__ W,
                                                   __half* __restrict__ Wt,
                                                   int K, int N) {
    __shared__ float t[32][33];
    int n0 = blockIdx.x * 32, k0 = blockIdx.y * 32;
    int tx = threadIdx.x & 31, ty = threadIdx.x >> 5;
    #pragma unroll
    for (int i = 0; i < 32; i += 8)
        t[ty + i][tx] = W[(size_t)(k0 + ty + i) * N + n0 + tx];
    __syncthreads();
    #pragma unroll
    for (int i = 0; i < 32; i += 8)
        Wt[(size_t)(n0 + ty + i) * K + k0 + tx] = __float2half(t[tx][ty + i]);
}

// ---------------- WoSum[h][c] = sum_d Wo[h*64+d][c] ----------------
__global__ void __launch_bounds__(256) wosum_kernel(const float* __restrict__ Wo,
                                                    float* __restrict__ woSum) {
    int i = blockIdx.x * 256 + threadIdx.x;
    int h = i >> 10, c = i & 1023;
    float acc = 0.f;
    #pragma unroll 8
    for (int d = 0; d < 64; d++)
        acc += Wo[(size_t)(h * 64 + d) * D_DIM + c];
    woSum[i] = acc;
}

// ---------------- corr[r][c] = sum_h sbv[r][h]*WoSum[h][c] ----------------
__global__ void __launch_bounds__(256) corr_kernel(const float* __restrict__ sbv,
                                                   const float* __restrict__ woSum,
                                                   float* __restrict__ corr) {
    int r = blockIdx.x;
    int c = threadIdx.x * 4;
    float sb[16];
    #pragma unroll
    for (int h = 0; h < 16; h++) sb[h] = sbv[r * H_N + h];
    float4 acc = make_float4(0.f, 0.f, 0.f, 0.f);
    #pragma unroll
    for (int h = 0; h < 16; h++) {
        float4 w = *reinterpret_cast<const float4*>(woSum + h * D_DIM + c);
        acc.x += sb[h] * w.x;
        acc.y += sb[h] * w.y;
        acc.z += sb[h] * w.z;
        acc.w += sb[h] * w.w;
    }
    *reinterpret_cast<float4*>(corr + (size_t)r * D_DIM + c) = acc;
}

// ---------------- RMSNorm -> fp16 x ----------------
__global__ void __launch_bounds__(256) rmsnorm_kernel(const float* __restrict__ h,
                                                      __half* __restrict__ xh) {
    int row = blockIdx.x;
    int t = threadIdx.x;
    const float4* hr = reinterpret_cast<const float4*>(h + (size_t)row * D_DIM);
    float4 a = hr[t];
    float ss = a.x * a.x + a.y * a.y + a.z * a.z + a.w * a.w;
    __shared__ float red[8];
    #pragma unroll
    for (int off = 16; off; off >>= 1) ss += __shfl_xor_sync(0xffffffffu, ss, off);
    if ((t & 31) == 0) red[t >> 5] = ss;
    __syncthreads();
    float tot = red[0] + red[1] + red[2] + red[3] + red[4] + red[5] + red[6] + red[7];
    float r = rsqrtf(tot * (1.0f / 1024.0f) + 1.1920929e-7f);
    __half2 h0 = __floats2half2_rn(a.x * r, a.y * r);
    __half2 h1 = __floats2half2_rn(a.z * r, a.w * r);
    uint2 packed = make_uint2(*reinterpret_cast<uint32_t*>(&h0),
                              *reinterpret_cast<uint32_t*>(&h1));
    *reinterpret_cast<uint2*>(xh + (size_t)row * D_DIM + t * 4) = packed;
}

// ---------------- fp16 cp.async GEMM, 3-stage (1 barrier / K-step) ----------
#define HSTR 40
#define GEMM_SMEM (6 * 128 * HSTR * 2)   // 3 stages x (A+B)

__global__ void __launch_bounds__(256) gemm_f16_kernel(
    const __half* __restrict__ A,
    const __half* __restrict__ B0, const __half* __restrict__ B1,
    const __half* __restrict__ B2, const __half* __restrict__ B3,
    const __half* __restrict__ B4,
    float* __restrict__ C0, float* __restrict__ C3, float* __restrict__ C4,
    __half* __restrict__ ChQ, __half* __restrict__ ChK, __half* __restrict__ ChV,
    int M, int N, int K,
    const float* __restrict__ bias,
    const float* __restrict__ add0,
    const float* __restrict__ add1,
    const float* __restrict__ lamPtr)
{
    int z = blockIdx.z;
    const __half* B = (z == 0) ? B0 : (z == 1) ? B1 : (z == 2) ? B2 : (z == 3) ? B3 : B4;
    float* C = (z == 3) ? C3 : (z == 4) ? C4 : C0;
    __half* chDst = (z == 0) ? ChQ : (z == 1) ? ChK : (z == 2) ? ChV : nullptr;

    extern __shared__ __half smh[];
    __half (*As)[128][HSTR] = reinterpret_cast<__half(*)[128][HSTR]>(smh);
    __half (*Bs)[128][HSTR] = reinterpret_cast<__half(*)[128][HSTR]>(smh + 3 * 128 * HSTR);

    int tid = threadIdx.x;
    int lane = tid & 31;
    int warp = tid >> 5;
    int warpM = warp >> 1;
    int warpN = warp & 1;
    int lr = lane >> 2;
    int lc = lane & 3;
    int bm = blockIdx.y * 128;
    int bn = blockIdx.x * 128;

    int sr = tid >> 1;
    int sc = (tid & 1) * 16;
    const __half* Ap = A + (size_t)(bm + sr) * K + sc;
    const __half* Bp = B + (size_t)(bn + sr) * K + sc;

    int aRow = lane & 15, aCol = (lane >> 4) * 8;
    int bRow = ((lane & 16) ? 8 : 0) + (lane & 7);
    int bCol = ((lane & 8) ? 8 : 0);
    uint32_t aOff[2], bOff[4];
    #pragma unroll
    for (int mi = 0; mi < 2; mi++)
        aOff[mi] = ((warpM * 32 + mi * 16 + aRow) * HSTR + aCol) * 2;
    #pragma unroll
    for (int nip = 0; nip < 4; nip++)
        bOff[nip] = ((warpN * 64 + nip * 16 + bRow) * HSTR + bCol) * 2;

    float acc[2][8][4];
    #pragma unroll
    for (int mi = 0; mi < 2; mi++)
        #pragma unroll
        for (int ni = 0; ni < 8; ni++)
            #pragma unroll
            for (int r = 0; r < 4; r++) acc[mi][ni][r] = 0.f;

    int NT = K / 32;

    auto issue = [&](int buf, int t) {
        const __half* ga = Ap + t * 32;
        const __half* gb = Bp + t * 32;
        uint32_t da = smem_u32(&As[buf][sr][sc]);
        uint32_t db = smem_u32(&Bs[buf][sr][sc]);
        CP16(da, ga);
        CP16(da + 16, ga + 8);
        CP16(db, gb);
        CP16(db + 16, gb + 8);
        asm volatile("cp.async.commit_group;" ::: "memory");
    };

    issue(0, 0);
    issue(1, 1);
    int buf = 0;
    for (int t = 0; t < NT; t++) {
        if (t + 1 < NT) {
            asm volatile("cp.async.wait_group 1;" ::: "memory");
        } else {
            asm volatile("cp.async.wait_group 0;" ::: "memory");
        }
        __syncthreads();   // tile t visible; all threads done reading tile t-1's buffer
        if (t + 2 < NT) {
            int nb = buf + 2;
            if (nb >= 3) nb -= 3;
            issue(nb, t + 2);
        }
        uint32_t aBase = smem_u32(&As[buf][0][0]);
        uint32_t bBase = smem_u32(&Bs[buf][0][0]);
        #pragma unroll
        for (int ks = 0; ks < 2; ks++) {
            uint32_t koff = ks * 32;
            uint32_t af[2][4], bf[8][2];
            #pragma unroll
            for (int mi = 0; mi < 2; mi++)
                LDSM_X4(af[mi][0], af[mi][1], af[mi][2], af[mi][3],
                        aBase + aOff[mi] + koff);
            #pragma unroll
            for (int nip = 0; nip < 4; nip++)
                LDSM_X4(bf[2 * nip][0], bf[2 * nip][1],
                        bf[2 * nip + 1][0], bf[2 * nip + 1][1],
                        bBase + bOff[nip] + koff);
            #pragma unroll
            for (int mi = 0; mi < 2; mi++)
                #pragma unroll
                for (int ni = 0; ni < 8; ni++)
                    MMA_F16(acc[mi][ni], af[mi], bf[ni]);
        }
        if (++buf == 3) buf = 0;
    }

    float lam = lamPtr ? lamPtr[0] : 0.f;
    #pragma unroll
    for (int mi = 0; mi < 2; mi++) {
        int r0 = bm + warpM * 32 + mi * 16 + lr;
        #pragma unroll
        for (int ni = 0; ni < 8; ni++) {
            int c0 = bn + warpN * 64 + ni * 8 + lc * 2;
            #pragma unroll
            for (int half_ = 0; half_ < 2; half_++) {
                int r = r0 + half_ * 8;
                float v0 = acc[mi][ni][half_ * 2 + 0];
                float v1 = acc[mi][ni][half_ * 2 + 1];
                if (bias) { v0 += bias[c0]; v1 += bias[c0 + 1]; }
                size_t idx = (size_t)r * N + c0;
                if (chDst) {
                    __half2 hv = __floats2half2_rn(v0, v1);
                    *reinterpret_cast<__half2*>(chDst + idx) = hv;
                } else {
                    if (add0) { v0 += add0[idx]; v1 += add0[idx + 1]; }
                    if (add1) { v0 += lam * add1[idx]; v1 += lam * add1[idx + 1]; }
                    C[idx]     = v0;
                    C[idx + 1] = v1;
                }
            }
        }
    }
}

// ---------------- fused W1 GEMM + SwiGLU, 3-stage ----------------
#define W1_SMEM (9 * 128 * HSTR * 2)

__global__ void __launch_bounds__(256) gemm_w1_swiglu_kernel(
    const __half* __restrict__ A, const __half* __restrict__ W1t,
    __half* __restrict__ fmh, const float* __restrict__ b1)
{
    extern __shared__ __half smh[];
    __half (*As)[128][HSTR]  = reinterpret_cast<__half(*)[128][HSTR]>(smh);
    __half (*Bx)[128][HSTR]  = reinterpret_cast<__half(*)[128][HSTR]>(smh + 3 * 128 * HSTR);
    __half (*Bg)[128][HSTR]  = reinterpret_cast<__half(*)[128][HSTR]>(smh + 6 * 128 * HSTR);

    const int K = D_DIM, N = FF_IN;
    int tid = threadIdx.x;
    int lane = tid & 31;
    int warp = tid >> 5;
    int warpM = warp >> 1;
    int warpN = warp & 1;
    int lr = lane >> 2;
    int lc = lane & 3;
    int bm = blockIdx.y * 128;
    int bn = blockIdx.x * 128;

    int sr = tid >> 1;
    int sc = (tid & 1) * 16;
    const __half* Ap  = A   + (size_t)(bm + sr) * K + sc;
    const __half* Bxp = W1t + (size_t)(bn + sr) * K + sc;
    const __half* Bgp = W1t + (size_t)(FF_IN + bn + sr) * K + sc;

    int aRow = lane & 15, aCol = (lane >> 4) * 8;
    int bRow = ((lane & 16) ? 8 : 0) + (lane & 7);
    int bCol = ((lane & 8) ? 8 : 0);
    uint32_t aOff[2], bOff[4];
    #pragma unroll
    for (int mi = 0; mi < 2; mi++)
        aOff[mi] = ((warpM * 32 + mi * 16 + aRow) * HSTR + aCol) * 2;
    #pragma unroll
    for (int nip = 0; nip < 4; nip++)
        bOff[nip] = ((warpN * 64 + nip * 16 + bRow) * HSTR + bCol) * 2;

    float accX[2][8][4], accG[2][8][4];
    #pragma unroll
    for (int mi = 0; mi < 2; mi++)
        #pragma unroll
        for (int ni = 0; ni < 8; ni++)
            #pragma unroll
            for (int r = 0; r < 4; r++) { accX[mi][ni][r] = 0.f; accG[mi][ni][r] = 0.f; }

    const int NT = K / 32;

    auto issue = [&](int buf, int t) {
        uint32_t da = smem_u32(&As[buf][sr][sc]);
        uint32_t dx = smem_u32(&Bx[buf][sr][sc]);
        uint32_t dg = smem_u32(&Bg[buf][sr][sc]);
        CP16(da, Ap + t * 32);
        CP16(da + 16, Ap + t * 32 + 8);
        CP16(dx, Bxp + t * 32);
        CP16(dx + 16, Bxp + t * 32 + 8);
        CP16(dg, Bgp + t * 32);
        CP16(dg + 16, Bgp + t * 32 + 8);
        asm volatile("cp.async.commit_group;" ::: "memory");
    };

    issue(0, 0);
    issue(1, 1);
    int buf = 0;
    for (int t = 0; t < NT; t++) {
        if (t + 1 < NT) {
            asm volatile("cp.async.wait_group 1;" ::: "memory");
        } else {
            asm volatile("cp.async.wait_group 0;" ::: "memory");
        }
        __syncthreads();
        if (t + 2 < NT) {
            int nb = buf + 2;
            if (nb >= 3) nb -= 3;
            issue(nb, t + 2);
        }
        uint32_t aBase = smem_u32(&As[buf][0][0]);
        uint32_t xBase = smem_u32(&Bx[buf][0][0]);
        uint32_t gBase = smem_u32(&Bg[buf][0][0]);
        #pragma unroll
        for (int ks = 0; ks < 2; ks++) {
            uint32_t koff = ks * 32;
            uint32_t af[2][4], bx[8][2], bg[8][2];
            #pragma unroll
            for (int mi = 0; mi < 2; mi++)
                LDSM_X4(af[mi][0], af[mi][1], af[mi][2], af[mi][3],
                        aBase + aOff[mi] + koff);
            #pragma unroll
            for (int nip = 0; nip < 4; nip++) {
                LDSM_X4(bx[2 * nip][0], bx[2 * nip][1],
                        bx[2 * nip + 1][0], bx[2 * nip + 1][1],
                        xBase + bOff[nip] + koff);
                LDSM_X4(bg[2 * nip][0], bg[2 * nip][1],
                        bg[2 * nip + 1][0], bg[2 * nip + 1][1],
                        gBase + bOff[nip] + koff);
            }
            #pragma unroll
            for (int mi = 0; mi < 2; mi++)
                #pragma unroll
                for (int ni = 0; ni < 8; ni++) {
                    MMA_F16(accX[mi][ni], af[mi], bx[ni]);
                    MMA_F16(accG[mi][ni], af[mi], bg[ni]);
                }
        }
        if (++buf == 3) buf = 0;
    }

    #pragma unroll
    for (int mi = 0; mi < 2; mi++) {
        int r0 = bm + warpM * 32 + mi * 16 + lr;
        #pragma unroll
        for (int ni = 0; ni < 8; ni++) {
            int c0 = bn + warpN * 64 + ni * 8 + lc * 2;
            float bx0 = b1[c0], bx1 = b1[c0 + 1];
            float bg0 = b1[FF_IN + c0], bg1 = b1[FF_IN + c0 + 1];
            #pragma unroll
            for (int half_ = 0; half_ < 2; half_++) {
                int r = r0 + half_ * 8;
                float xp0 = accX[mi][ni][half_ * 2 + 0] + bx0;
                float xp1 = accX[mi][ni][half_ * 2 + 1] + bx1;
                float g0 = accG[mi][ni][half_ * 2 + 0] + bg0;
                float g1 = accG[mi][ni][half_ * 2 + 1] + bg1;
                float f0 = (g0 / (1.f + __expf(-g0))) * xp0;
                float f1 = (g1 / (1.f + __expf(-g1))) * xp1;
                __half2 hv = __floats2half2_rn(f0, f1);
                *reinterpret_cast<__half2*>(fmh + (size_t)r * N + c0) = hv;
            }
        }
    }
}

// ---------------- l2norm + RoPE ----------------
__global__ void __launch_bounds__(256) ropenorm_kernel(
    __half* __restrict__ qh, __half* __restrict__ kh, float* qb, float* kb) {
    int s = blockIdx.x;
    int warp = threadIdx.x >> 5;
    int lane = threadIdx.x & 31;
    int idx = blockIdx.y * 8 + warp;
    int h = idx & 15;
    int a = idx >> 4;
    size_t off = (size_t)s * D_DIM + h * 64;
    float x1, x2;
    if (a < 2) {
        const __half* p = ((a == 0) ? qh : kh) + off;
        x1 = __half2float(p[lane]);
        x2 = __half2float(p[lane + DHALF]);
    } else {
        const float* p = ((a == 2) ? qb : kb) + off;
        x1 = p[lane];
        x2 = p[lane + DHALF];
    }
    float ss = x1 * x1 + x2 * x2;
    #pragma unroll
    for (int o = 16; o; o >>= 1) ss += __shfl_xor_sync(0xffffffffu, ss, o);
    float n = fmaxf(sqrtf(ss), 1e-12f);
    float inv = 1.f / n;
    x1 *= inv;
    x2 *= inv;
    float invfreq = powf(1000.0f, -(float)lane * (1.0f / 32.0f));
    float fr = (float)s * invfreq;
    float c  = __bfloat162float(__float2bfloat16(cosf(fr)));
    float sn = __bfloat162float(__float2bfloat16(sinf(fr)));
    float y1 = x1 * c + x2 * sn;
    float y2 = -x1 * sn + x2 * c;
    if (a < 2) {
        __half* dst = ((a == 0) ? qh : kh) + off;
        dst[lane]         = __float2half(y1);
        dst[lane + DHALF] = __float2half(y2);
    } else {
        float* dst = ((a == 2) ? qb : kb) + off;
        dst[lane]         = y1;
        dst[lane + DHALF] = y2;
    }
}

// ---------------- parallel prefix sum of kb ----------------
__global__ void __launch_bounds__(256) prefix_p1(const float* __restrict__ kb,
                                                 float* __restrict__ cs) {
    int ch = blockIdx.x;
    int col = blockIdx.y * 256 + threadIdx.x;
    const float* p = kb + (size_t)(ch * 32) * D_DIM + col;
    float acc = 0.f;
    #pragma unroll
    for (int r = 0; r < 32; r++) acc += p[(size_t)r * D_DIM];
    cs[(size_t)ch * D_DIM + col] = acc;
}
__global__ void __launch_bounds__(1024) prefix_p2(float* __restrict__ cs) {
    int col = threadIdx.x;
    float run = 0.f;
    #pragma unroll 8
    for (int ch = 0; ch < 64; ch++) {
        size_t i = (size_t)ch * D_DIM + col;
        float t = cs[i];
        cs[i] = run;
        run += t;
    }
}
__global__ void __launch_bounds__(256) prefix_p3(const float* __restrict__ kb,
                                                 const float* __restrict__ cs,
                                                 float* __restrict__ pkb) {
    int ch = blockIdx.x;
    int col = blockIdx.y * 256 + threadIdx.x;
    float acc = cs[(size_t)ch * D_DIM + col];
    const float* p = kb + (size_t)(ch * 32) * D_DIM + col;
    float* o = pkb + (size_t)(ch * 32) * D_DIM + col;
    #pragma unroll
    for (int r = 0; r < 32; r++) {
        acc += p[(size_t)r * D_DIM];
        o[(size_t)r * D_DIM] = acc;
    }
}

// ---------------- sb values ----------------
__global__ void __launch_bounds__(512) sb_kernel(const float* __restrict__ qb,
                                                 const float* __restrict__ pkb,
                                                 float* __restrict__ sbv) {
    int s = blockIdx.x;
    int h = threadIdx.x >> 5;
    int lane = threadIdx.x & 31;
    size_t off = (size_t)s * D_DIM + h * 64;
    float v = qb[off + lane] * pkb[off + lane] +
              qb[off + lane + DHALF] * pkb[off + lane + DHALF];
    #pragma unroll
    for (int o = 16; o; o >>= 1) v += __shfl_xor_sync(0xffffffffu, v, o);
    if (lane == 0) sbv[s * H_N + h] = 0.125f * v;
}

// ---------------- fp16 flash attention (proven R12/R13) ----------------
#define QSH 72
#define ATT_SMEM (512 * QSH * 2 + 256 * 4)

__global__ void __launch_bounds__(256) attn_mma_kernel(
    const __half* __restrict__ qh, const __half* __restrict__ kh,
    const __half* __restrict__ vh,
    const float* __restrict__ l2sp, __half* __restrict__ yh)
{
    extern __shared__ __half smah[];
    __half (*Qs)[QSH] = reinterpret_cast<__half(*)[QSH]>(smah);
    __half (*Ps)[QSH] = reinterpret_cast<__half(*)[QSH]>(smah + 128 * QSH);
    __half (*Ks)[64][QSH] = reinterpret_cast<__half(*)[64][QSH]>(smah + 256 * QSH);
    __half (*Vs)[64][QSH] = reinterpret_cast<__half(*)[64][QSH]>(smah + 384 * QSH);
    float* red_l = reinterpret_cast<float*>(smah + 512 * QSH);

    int h = blockIdx.y;
    int qt = gridDim.x - 1 - blockIdx.x;
    int q0 = qt * 128;
    int tid = threadIdx.x;
    int lane = tid & 31, warp = tid >> 5;
    int wm = warp >> 1;
    int wn = warp & 1;
    int lr = lane >> 2;
    int lc = lane & 3;

    int aRow = lane & 15, aCol = (lane >> 4) * 8;
    uint32_t qOff[2];
    #pragma unroll
    for (int mi = 0; mi < 2; mi++)
        qOff[mi] = ((wm * 32 + mi * 16 + aRow) * QSH + aCol) * 2;
    int bRow = ((lane & 16) ? 8 : 0) + (lane & 7);
    int bCol = ((lane & 8) ? 8 : 0);
    uint32_t kOff[2];
    #pragma unroll
    for (int nip = 0; nip < 2; nip++)
        kOff[nip] = ((wn * 32 + nip * 16 + bRow) * QSH + bCol) * 2;
    int tRow = ((lane & 8) ? 8 : 0) + (lane & 7);
    int tCol = ((lane & 16) ? 8 : 0);
    uint32_t vOff[2];
    #pragma unroll
    for (int nip = 0; nip < 2; nip++)
        vOff[nip] = (tRow * QSH + wn * 32 + nip * 16 + tCol) * 2;

    uint32_t qBase = smem_u32(&Qs[0][0]);
    uint32_t pBase = smem_u32(&Ps[0][0]);

    int stR = tid >> 2, stC = (tid & 3) * 16;

    auto issueKV = [&](int buf, int kt) {
        int kbase = kt * 64;
        const __half* ks = kh + (size_t)(kbase + stR) * D_DIM + h * 64 + stC;
        const __half* vs = vh + (size_t)(kbase + stR) * D_DIM + h * 64 + stC;
        uint32_t dk = smem_u32(&Ks[buf][stR][stC]);
        uint32_t dv = smem_u32(&Vs[buf][stR][stC]);
        CP16(dk, ks);
        CP16(dk + 16, ks + 8);
        CP16(dv, vs);
        CP16(dv + 16, vs + 8);
        asm volatile("cp.async.commit_group;" ::: "memory");
    };

    {
        int r = tid >> 1, c0 = (tid & 1) * 32;
        const __half* src = qh + (size_t)(q0 + r) * D_DIM + h * 64 + c0;
        #pragma unroll
        for (int j = 0; j < 4; j++)
            *reinterpret_cast<uint4*>(&Qs[r][c0 + j * 8]) =
                *reinterpret_cast<const uint4*>(src + j * 8);
    }

    float l[4] = {0.f, 0.f, 0.f, 0.f};
    float o[2][4][4];
    #pragma unroll
    for (int mi = 0; mi < 2; mi++)
        #pragma unroll
        for (int ni = 0; ni < 4; ni++)
            #pragma unroll
            for (int j = 0; j < 4; j++) o[mi][ni][j] = 0.f;

    int nt = 2 * qt + 2;
    issueKV(0, 0);

    for (int kt = 0; kt < nt; kt++) {
        int buf = kt & 1;
        int kbase = kt * 64;
        __syncthreads();
        if (kt + 1 < nt) {
            issueKV(buf ^ 1, kt + 1);
            asm volatile("cp.async.wait_group 1;" ::: "memory");
        } else {
            asm volatile("cp.async.wait_group 0;" ::: "memory");
        }
        __syncthreads();

        uint32_t kBase = smem_u32(&Ks[buf][0][0]);
        uint32_t vBase = smem_u32(&Vs[buf][0][0]);

        float s[2][4][4];
        #pragma unroll
        for (int mi = 0; mi < 2; mi++)
            #pragma unroll
            for (int ni = 0; ni < 4; ni++)
                #pragma unroll
                for (int j = 0; j < 4; j++) s[mi][ni][j] = 0.f;
        #pragma unroll
        for (int ks = 0; ks < 4; ks++) {
            uint32_t kbyte = ks * 32;
            uint32_t af[2][4], bf[4][2];
            #pragma unroll
            for (int mi = 0; mi < 2; mi++)
                LDSM_X4(af[mi][0], af[mi][1], af[mi][2], af[mi][3],
                        qBase + qOff[mi] + kbyte);
            #pragma unroll
            for (int nip = 0; nip < 2; nip++)
                LDSM_X4(bf[2 * nip][0], bf[2 * nip][1],
                        bf[2 * nip + 1][0], bf[2 * nip + 1][1],
                        kBase + kOff[nip] + kbyte);
            #pragma unroll
            for (int mi = 0; mi < 2; mi++)
                #pragma unroll
                for (int ni = 0; ni < 4; ni++)
                    MMA_F16(s[mi][ni], af[mi], bf[ni]);
        }
        if (kt >= nt - 2) {
            #pragma unroll
            for (int mi = 0; mi < 2; mi++) {
                int rg0 = q0 + wm * 32 + mi * 16 + lr;
                #pragma unroll
                for (int ni = 0; ni < 4; ni++) {
                    int cgb = kbase + wn * 32 + ni * 8 + lc * 2;
                    #pragma unroll
                    for (int j = 0; j < 4; j++) {
                        int rg = rg0 + ((j >= 2) ? 8 : 0);
                        int cg = cgb + (j & 1);
                        if (cg > rg) s[mi][ni][j] = -1e4f;
                    }
                }
            }
        }
        #pragma unroll
        for (int mi = 0; mi < 2; mi++) {
            int r0m = wm * 32 + mi * 16 + lr;
            int r1m = r0m + 8;
            #pragma unroll
            for (int ni = 0; ni < 4; ni++) {
                int cbase = wn * 32 + ni * 8 + lc * 2;
                float t0 = fmaf(s[mi][ni][0], L2E, -L2E);
                float t1 = fmaf(s[mi][ni][1], L2E, -L2E);
                float t2 = fmaf(s[mi][ni][2], L2E, -L2E);
                float t3 = fmaf(s[mi][ni][3], L2E, -L2E);
                __half2 ht0 = __floats2half2_rn(t0, t1);
                __half2 ht1 = __floats2half2_rn(t2, t3);
                uint32_t p0, p1;
                EX2_F16X2(p0, *reinterpret_cast<uint32_t*>(&ht0));
                EX2_F16X2(p1, *reinterpret_cast<uint32_t*>(&ht1));
                *reinterpret_cast<uint32_t*>(&Ps[r0m][cbase]) = p0;
                *reinterpret_cast<uint32_t*>(&Ps[r1m][cbase]) = p1;
                float2 f0 = __half22float2(*reinterpret_cast<__half2*>(&p0));
                float2 f1 = __half22float2(*reinterpret_cast<__half2*>(&p1));
                l[mi * 2]     += f0.x + f0.y;
                l[mi * 2 + 1] += f1.x + f1.y;
            }
        }
        __syncthreads();
        #pragma unroll
        for (int ks = 0; ks < 4; ks++) {
            uint32_t af[2][4], bf[4][2];
            #pragma unroll
            for (int mi = 0; mi < 2; mi++)
                LDSM_X4(af[mi][0], af[mi][1], af[mi][2], af[mi][3],
                        pBase + qOff[mi] + ks * 32);
            #pragma unroll
            for (int nip = 0; nip < 2; nip++)
                LDSM_X4T(bf[2 * nip][0], bf[2 * nip][1],
                         bf[2 * nip + 1][0], bf[2 * nip + 1][1],
                         vBase + vOff[nip] + ks * 16 * QSH * 2);
            #pragma unroll
            for (int mi = 0; mi < 2; mi++)
                #pragma unroll
                for (int ni = 0; ni < 4; ni++)
                    MMA_F16(o[mi][ni], af[mi], bf[ni]);
        }
    }

    #pragma unroll
    for (int i = 0; i < 4; i++) {
        l[i] += __shfl_xor_sync(0xffffffffu, l[i], 1);
        l[i] += __shfl_xor_sync(0xffffffffu, l[i], 2);
    }
    if (lc == 0) {
        #pragma unroll
        for (int mi = 0; mi < 2; mi++) {
            int r0m = wm * 32 + mi * 16 + lr;
            red_l[wn * 128 + r0m]     = l[mi * 2];
            red_l[wn * 128 + r0m + 8] = l[mi * 2 + 1];
        }
    }
    __syncthreads();

    float l2sv = l2sp[0];
    #pragma unroll
    for (int mi = 0; mi < 2; mi++) {
        int r0m = wm * 32 + mi * 16 + lr;
        int r1m = r0m + 8;
        float lt0 = red_l[r0m] + red_l[128 + r0m];
        float lt1 = red_l[r1m] + red_l[128 + r1m];
        float inv0 = l2sv / lt0;
        float inv1 = l2sv / lt1;
        int g0 = q0 + r0m, g1 = q0 + r1m;
        #pragma unroll
        for (int ni = 0; ni < 4; ni++) {
            int col = h * 64 + wn * 32 + ni * 8 + lc * 2;
            __half2 r0v = __floats2half2_rn(o[mi][ni][0] * inv0, o[mi][ni][1] * inv0);
            __half2 r1v = __floats2half2_rn(o[mi][ni][2] * inv1, o[mi][ni][3] * inv1);
            *reinterpret_cast<__half2*>(&yh[(size_t)g0 * D_DIM + col]) = r0v;
            *reinterpret_cast<__half2*>(&yh[(size_t)g1 * D_DIM + col]) = r1v;
        }
    }
}

// ---------------- launch ----------------
extern "C" void kernel_launch(void* const* d_in, const int* in_sizes, int n_in,
                              void* d_out, int out_size) {
    const float* h_states = (const float*)d_in[0];
    const float* Wq  = (const float*)d_in[1];
    const float* Wk  = (const float*)d_in[2];
    const float* Wv  = (const float*)d_in[3];
    const float* Wqb = (const float*)d_in[4];
    const float* Wkb = (const float*)d_in[5];
    const float* Wo  = (const float*)d_in[6];
    const float* bo  = (const float*)d_in[7];
    const float* W1  = (const float*)d_in[8];
    const float* b1  = (const float*)d_in[9];
    const float* W2  = (const float*)d_in[10];
    const float* b2  = (const float*)d_in[11];
    const float* lam = (const float*)d_in[12];
    const float* l2s = (const float*)d_in[13];
    float* out = (float*)d_out;

    float *qb, *kb, *pkb, *cs, *sbv, *ao, *wos, *cor;
    __half *xh, *yh, *fmh, *qhh, *khh, *vhh;
    __half *wqh, *wkh, *wvh, *wqbh, *wkbh, *woh, *w1h, *w2h;
    cudaGetSymbolAddress((void**)&qb, g_qb);
    cudaGetSymbolAddress((void**)&kb, g_kb);
    cudaGetSymbolAddress((void**)&pkb, g_pkb);
    cudaGetSymbolAddress((void**)&cs, g_cs);
    cudaGetSymbolAddress((void**)&sbv, g_sb);
    cudaGetSymbolAddress((void**)&ao, g_ao);
    cudaGetSymbolAddress((void**)&wos, g_wos);
    cudaGetSymbolAddress((void**)&cor, g_cor);
    cudaGetSymbolAddress((void**)&xh,  g_xh);
    cudaGetSymbolAddress((void**)&yh,  g_yh);
    cudaGetSymbolAddress((void**)&fmh, g_fmh);
    cudaGetSymbolAddress((void**)&qhh, g_qhh);
    cudaGetSymbolAddress((void**)&khh, g_khh);
    cudaGetSymbolAddress((void**)&vhh, g_vhh);
    cudaGetSymbolAddress((void**)&wqh,  g_wqh);
    cudaGetSymbolAddress((void**)&wkh,  g_wkh);
    cudaGetSymbolAddress((void**)&wvh,  g_wvh);
    cudaGetSymbolAddress((void**)&wqbh, g_wqbh);
    cudaGetSymbolAddress((void**)&wkbh, g_wkbh);
    cudaGetSymbolAddress((void**)&woh,  g_woh);
    cudaGetSymbolAddress((void**)&w1h,  g_w1h);
    cudaGetSymbolAddress((void**)&w2h,  g_w2h);

    cudaFuncSetAttribute(attn_mma_kernel,
                         cudaFuncAttributeMaxDynamicSharedMemorySize, ATT_SMEM);
    cudaFuncSetAttribute(gemm_f16_kernel,
                         cudaFuncAttributeMaxDynamicSharedMemorySize, GEMM_SMEM);
    cudaFuncSetAttribute(gemm_w1_swiglu_kernel,
                         cudaFuncAttributeMaxDynamicSharedMemorySize, W1_SMEM);

    static cudaStream_t s1 = nullptr, s2 = nullptr;
    static cudaEvent_t evX = nullptr, evFFN = nullptr, evRope = nullptr,
                       evSB = nullptr, evW = nullptr;
    if (!s1) {
        cudaStreamCreateWithFlags(&s1, cudaStreamNonBlocking);
        cudaStreamCreateWithFlags(&s2, cudaStreamNonBlocking);
        cudaEventCreateWithFlags(&evX, cudaEventDisableTiming);
        cudaEventCreateWithFlags(&evFFN, cudaEventDisableTiming);
        cudaEventCreateWithFlags(&evRope, cudaEventDisableTiming);
        cudaEventCreateWithFlags(&evSB, cudaEventDisableTiming);
        cudaEventCreateWithFlags(&evW, cudaEventDisableTiming);
    }

    // ---- main: rmsnorm first; evX is the capture-fork point for s1/s2 ----
    rmsnorm_kernel<<<S_LEN, 256>>>(h_states, xh);
    cudaEventRecord(evX, 0);

    // ---- s2 (forked via evX): attention-weight converts + WoSum ----
    cudaStreamWaitEvent(s2, evX, 0);
    cvtT6_kernel<<<dim3(32, 32, 6), 256, 0, s2>>>(Wq, Wk, Wv, Wqb, Wkb, Wo,
                                                  wqh, wkh, wvh, wqbh, wkbh, woh);
    wosum_kernel<<<H_N * D_DIM / 256, 256, 0, s2>>>(Wo, wos);
    cudaEventRecord(evW, s2);

    // ---- s1 (forked via evX): FFN branch ----
    cudaStreamWaitEvent(s1, evX, 0);
    cvtT_kernel<<<dim3(FUSEDW / 32, 32), 256, 0, s1>>>(W1, w1h, D_DIM, FUSEDW);
    cvtT_kernel<<<dim3(32, FF_IN / 32), 256, 0, s1>>>(W2, w2h, FF_IN, D_DIM);
    gemm_w1_swiglu_kernel<<<dim3(FF_IN / 128, S_LEN / 128), 256, W1_SMEM, s1>>>(
        xh, w1h, fmh, b1);
    cudaEventRecord(evFFN, s1);

    // ---- main: attention branch (waits on s2 weight converts) ----
    cudaStreamWaitEvent(0, evW, 0);
    gemm_f16_kernel<<<dim3(D_DIM / 128, S_LEN / 128, 5), 256, GEMM_SMEM>>>(
        xh, wqh, wkh, wvh, wqbh, wkbh, nullptr, qb, kb, qhh, khh, vhh,
        S_LEN, D_DIM, D_DIM, nullptr, nullptr, nullptr, nullptr);
    ropenorm_kernel<<<dim3(S_LEN, 8), 256>>>(qhh, khh, qb, kb);
    cudaEventRecord(evRope, 0);

    // ---- s2: sb/corr chain, overlapped with attention ----
    cudaStreamWaitEvent(s2, evRope, 0);
    prefix_p1<<<dim3(64, 4), 256, 0, s2>>>(kb, cs);
    prefix_p2<<<1, 1024, 0, s2>>>(cs);
    prefix_p3<<<dim3(64, 4), 256, 0, s2>>>(kb, cs, pkb);
    sb_kernel<<<S_LEN, 512, 0, s2>>>(qb, pkb, sbv);
    corr_kernel<<<S_LEN, 256, 0, s2>>>(sbv, wos, cor);
    cudaEventRecord(evSB, s2);

    // ---- main: attention ----
    attn_mma_kernel<<<dim3(S_LEN / 128, H_N), 256, ATT_SMEM>>>(qhh, khh, vhh, l2s, yh);

    // ---- main: Wo GEMM with corr (join s2) ----
    cudaStreamWaitEvent(0, evSB, 0);
    gemm_f16_kernel<<<dim3(D_DIM / 128, S_LEN / 128, 1), 256, GEMM_SMEM>>>(
        yh, woh, nullptr, nullptr, nullptr, nullptr,
        ao, nullptr, nullptr, nullptr, nullptr, nullptr,
        S_LEN, D_DIM, D_DIM, bo, cor, nullptr, nullptr);

    // ---- join FFN, final GEMM ----
    cudaStreamWaitEvent(0, evFFN, 0);
    gemm_f16_kernel<<<dim3(D_DIM / 128, S_LEN / 128, 1), 256, GEMM_SMEM>>>(
        fmh, w2h, nullptr, nullptr, nullptr, nullptr,
        out, nullptr, nullptr, nullptr, nullptr, nullptr,
        S_LEN, D_DIM, FF_IN, b2, ao, h_states, lam);
}

// round 16
// speedup vs baseline: 9.6889x; 1.0021x over previous
#include <cuda_runtime.h>
#include <cuda_bf16.h>
#include <cuda_fp16.h>
#include <cstdint>

#define S_LEN 2048
#define D_DIM 1024
#define H_N 16
#define DHALF 32
#define FF_IN 4096
#define FUSEDW 8192

// ---------------- scratch ----------------
__device__ float  g_qb [S_LEN * D_DIM];
__device__ float  g_kb [S_LEN * D_DIM];
__device__ float  g_pkb[S_LEN * D_DIM];
__device__ float  g_cs [64 * D_DIM];
__device__ float  g_sb [S_LEN * H_N];
__device__ float  g_wos[H_N * D_DIM];
__device__ float  g_cor[S_LEN * D_DIM];   // sb·WoSum + bo + b2
__device__ float  g_ct [S_LEN * DHALF];   // rope cos (bf16-quantized, stored fp32)
__device__ float  g_st [S_LEN * DHALF];   // rope sin
__device__ __half g_xh [S_LEN * D_DIM];
__device__ __half g_yh [S_LEN * D_DIM];
__device__ __half g_fmh[S_LEN * FF_IN];
__device__ __half g_qhh[S_LEN * D_DIM];
__device__ __half g_khh[S_LEN * D_DIM];
__device__ __half g_vhh[S_LEN * D_DIM];
__device__ __half g_wqh [D_DIM * D_DIM];
__device__ __half g_wkh [D_DIM * D_DIM];
__device__ __half g_wvh [D_DIM * D_DIM];
__device__ __half g_wqbh[D_DIM * D_DIM];
__device__ __half g_wkbh[D_DIM * D_DIM];
__device__ __half g_woh [D_DIM * D_DIM];
__device__ __half g_w1h [FUSEDW * D_DIM];
__device__ __half g_w2h [D_DIM * FF_IN];

// ---------------- helpers ----------------
__device__ __forceinline__ uint32_t smem_u32(const void* p) {
    uint32_t a;
    asm("{ .reg .u64 t; cvta.to.shared.u64 t, %1; cvt.u32.u64 %0, t; }" : "=r"(a) : "l"(p));
    return a;
}

#define MMA_F16(d, a, b)                                                      \
    asm volatile(                                                             \
        "mma.sync.aligned.m16n8k16.row.col.f32.f16.f16.f32 "                  \
        "{%0,%1,%2,%3}, {%4,%5,%6,%7}, {%8,%9}, {%0,%1,%2,%3};"               \
        : "+f"(d[0]), "+f"(d[1]), "+f"(d[2]), "+f"(d[3])                      \
        : "r"(a[0]), "r"(a[1]), "r"(a[2]), "r"(a[3]), "r"(b[0]), "r"(b[1]))

#define LDSM_X4(r0, r1, r2, r3, a)                                            \
    asm volatile("ldmatrix.sync.aligned.m8n8.x4.shared.b16 {%0,%1,%2,%3}, [%4];" \
                 : "=r"(r0), "=r"(r1), "=r"(r2), "=r"(r3) : "r"(a))

#define LDSM_X4T(r0, r1, r2, r3, a)                                           \
    asm volatile("ldmatrix.sync.aligned.m8n8.x4.trans.shared.b16 {%0,%1,%2,%3}, [%4];" \
                 : "=r"(r0), "=r"(r1), "=r"(r2), "=r"(r3) : "r"(a))

#define EX2_F16X2(d, a)                                                       \
    asm volatile("ex2.approx.f16x2 %0, %1;" : "=r"(d) : "r"(a))

#define CP16(dst, src)                                                        \
    asm volatile("cp.async.ca.shared.global [%0], [%1], 16;" :: "r"(dst), "l"(src))

#define L2E 1.4426950408889634f

// ---------------- weight fp16 convert + transpose ----------------
__global__ void __launch_bounds__(256) cvtT6_kernel(
    const float* __restrict__ W0, const float* __restrict__ W1,
    const float* __restrict__ W2, const float* __restrict__ W3,
    const float* __restrict__ W4, const float* __restrict__ W5,
    __half* __restrict__ O0, __half* __restrict__ O1,
    __half* __restrict__ O2, __half* __restrict__ O3,
    __half* __restrict__ O4, __half* __restrict__ O5) {
    int z = blockIdx.z;
    const float* W = (z == 0) ? W0 : (z == 1) ? W1 : (z == 2) ? W2
                   : (z == 3) ? W3 : (z == 4) ? W4 : W5;
    __half* Wt = (z == 0) ? O0 : (z == 1) ? O1 : (z == 2) ? O2
               : (z == 3) ? O3 : (z == 4) ? O4 : O5;
    __shared__ float t[32][33];
    int n0 = blockIdx.x * 32, k0 = blockIdx.y * 32;
    int tx = threadIdx.x & 31, ty = threadIdx.x >> 5;
    #pragma unroll
    for (int i = 0; i < 32; i += 8)
        t[ty + i][tx] = W[(size_t)(k0 + ty + i) * D_DIM + n0 + tx];
    __syncthreads();
    #pragma unroll
    for (int i = 0; i < 32; i += 8)
        Wt[(size_t)(n0 + ty + i) * D_DIM + k0 + tx] = __float2half(t[tx][ty + i]);
}

__global__ void __launch_bounds__(256) cvtT_kernel(const float* __restrict__ W,
                                                   __half* __restrict__ Wt,
                                                   int K, int N) {
    __shared__ float t[32][33];
    int n0 = blockIdx.x * 32, k0 = blockIdx.y * 32;
    int tx = threadIdx.x & 31, ty = threadIdx.x >> 5;
    #pragma unroll
    for (int i = 0; i < 32; i += 8)
        t[ty + i][tx] = W[(size_t)(k0 + ty + i) * N + n0 + tx];
    __syncthreads();
    #pragma unroll
    for (int i = 0; i < 32; i += 8)
        Wt[(size_t)(n0 + ty + i) * K + k0 + tx] = __float2half(t[tx][ty + i]);
}

// ---------------- rope tables (bf16-quantized like reference) ----------------
__global__ void __launch_bounds__(256) ropetab_kernel(float* __restrict__ ct,
                                                      float* __restrict__ st) {
    int i = blockIdx.x * 256 + threadIdx.x;   // S_LEN*32
    int s = i >> 5, lane = i & 31;
    float invfreq = powf(1000.0f, -(float)lane * (1.0f / 32.0f));
    float fr = (float)s * invfreq;
    ct[i] = __bfloat162float(__float2bfloat16(cosf(fr)));
    st[i] = __bfloat162float(__float2bfloat16(sinf(fr)));
}

// ---------------- WoSum[h][c] = sum_d Wo[h*64+d][c] ----------------
__global__ void __launch_bounds__(256) wosum_kernel(const float* __restrict__ Wo,
                                                    float* __restrict__ woSum) {
    int i = blockIdx.x * 256 + threadIdx.x;
    int h = i >> 10, c = i & 1023;
    float acc = 0.f;
    #pragma unroll 8
    for (int d = 0; d < 64; d++)
        acc += Wo[(size_t)(h * 64 + d) * D_DIM + c];
    woSum[i] = acc;
}

// ---------------- corr[r][c] = sum_h sbv[r][h]*WoSum[h][c] + bo[c] + b2[c] ---
__global__ void __launch_bounds__(256) corr_kernel(const float* __restrict__ sbv,
                                                   const float* __restrict__ woSum,
                                                   const float* __restrict__ bo,
                                                   const float* __restrict__ b2,
                                                   float* __restrict__ corr) {
    int r = blockIdx.x;
    int c = threadIdx.x * 4;
    float sb[16];
    #pragma unroll
    for (int h = 0; h < 16; h++) sb[h] = sbv[r * H_N + h];
    float4 b = *reinterpret_cast<const float4*>(bo + c);
    float4 b2v = *reinterpret_cast<const float4*>(b2 + c);
    float4 acc = make_float4(b.x + b2v.x, b.y + b2v.y, b.z + b2v.z, b.w + b2v.w);
    #pragma unroll
    for (int h = 0; h < 16; h++) {
        float4 w = *reinterpret_cast<const float4*>(woSum + h * D_DIM + c);
        acc.x += sb[h] * w.x;
        acc.y += sb[h] * w.y;
        acc.z += sb[h] * w.z;
        acc.w += sb[h] * w.w;
    }
    *reinterpret_cast<float4*>(corr + (size_t)r * D_DIM + c) = acc;
}

// ---------------- RMSNorm -> fp16 x ----------------
__global__ void __launch_bounds__(256) rmsnorm_kernel(const float* __restrict__ h,
                                                      __half* __restrict__ xh) {
    int row = blockIdx.x;
    int t = threadIdx.x;
    const float4* hr = reinterpret_cast<const float4*>(h + (size_t)row * D_DIM);
    float4 a = hr[t];
    float ss = a.x * a.x + a.y * a.y + a.z * a.z + a.w * a.w;
    __shared__ float red[8];
    #pragma unroll
    for (int off = 16; off; off >>= 1) ss += __shfl_xor_sync(0xffffffffu, ss, off);
    if ((t & 31) == 0) red[t >> 5] = ss;
    __syncthreads();
    float tot = red[0] + red[1] + red[2] + red[3] + red[4] + red[5] + red[6] + red[7];
    float r = rsqrtf(tot * (1.0f / 1024.0f) + 1.1920929e-7f);
    __half2 h0 = __floats2half2_rn(a.x * r, a.y * r);
    __half2 h1 = __floats2half2_rn(a.z * r, a.w * r);
    uint2 packed = make_uint2(*reinterpret_cast<uint32_t*>(&h0),
                              *reinterpret_cast<uint32_t*>(&h1));
    *reinterpret_cast<uint2*>(xh + (size_t)row * D_DIM + t * 4) = packed;
}

// ---------------- fp16 cp.async GEMM, 3-stage (projections) ----------------
#define HSTR 40
#define GEMM_SMEM (6 * 128 * HSTR * 2)

__global__ void __launch_bounds__(256) gemm_f16_kernel(
    const __half* __restrict__ A,
    const __half* __restrict__ B0, const __half* __restrict__ B1,
    const __half* __restrict__ B2, const __half* __restrict__ B3,
    const __half* __restrict__ B4,
    float* __restrict__ C3, float* __restrict__ C4,
    __half* __restrict__ ChQ, __half* __restrict__ ChK, __half* __restrict__ ChV,
    int M, int N, int K)
{
    int z = blockIdx.z;
    const __half* B = (z == 0) ? B0 : (z == 1) ? B1 : (z == 2) ? B2 : (z == 3) ? B3 : B4;
    float* C = (z == 3) ? C3 : C4;
    __half* chDst = (z == 0) ? ChQ : (z == 1) ? ChK : (z == 2) ? ChV : nullptr;

    extern __shared__ __half smh[];
    __half (*As)[128][HSTR] = reinterpret_cast<__half(*)[128][HSTR]>(smh);
    __half (*Bs)[128][HSTR] = reinterpret_cast<__half(*)[128][HSTR]>(smh + 3 * 128 * HSTR);

    int tid = threadIdx.x;
    int lane = tid & 31;
    int warp = tid >> 5;
    int warpM = warp >> 1;
    int warpN = warp & 1;
    int lr = lane >> 2;
    int lc = lane & 3;
    int bm = blockIdx.y * 128;
    int bn = blockIdx.x * 128;

    int sr = tid >> 1;
    int sc = (tid & 1) * 16;
    const __half* Ap = A + (size_t)(bm + sr) * K + sc;
    const __half* Bp = B + (size_t)(bn + sr) * K + sc;

    int aRow = lane & 15, aCol = (lane >> 4) * 8;
    int bRow = ((lane & 16) ? 8 : 0) + (lane & 7);
    int bCol = ((lane & 8) ? 8 : 0);
    uint32_t aOff[2], bOff[4];
    #pragma unroll
    for (int mi = 0; mi < 2; mi++)
        aOff[mi] = ((warpM * 32 + mi * 16 + aRow) * HSTR + aCol) * 2;
    #pragma unroll
    for (int nip = 0; nip < 4; nip++)
        bOff[nip] = ((warpN * 64 + nip * 16 + bRow) * HSTR + bCol) * 2;

    float acc[2][8][4];
    #pragma unroll
    for (int mi = 0; mi < 2; mi++)
        #pragma unroll
        for (int ni = 0; ni < 8; ni++)
            #pragma unroll
            for (int r = 0; r < 4; r++) acc[mi][ni][r] = 0.f;

    int NT = K / 32;

    auto issue = [&](int buf, int t) {
        const __half* ga = Ap + t * 32;
        const __half* gb = Bp + t * 32;
        uint32_t da = smem_u32(&As[buf][sr][sc]);
        uint32_t db = smem_u32(&Bs[buf][sr][sc]);
        CP16(da, ga);
        CP16(da + 16, ga + 8);
        CP16(db, gb);
        CP16(db + 16, gb + 8);
        asm volatile("cp.async.commit_group;" ::: "memory");
    };

    issue(0, 0);
    issue(1, 1);
    int buf = 0;
    for (int t = 0; t < NT; t++) {
        if (t + 1 < NT) {
            asm volatile("cp.async.wait_group 1;" ::: "memory");
        } else {
            asm volatile("cp.async.wait_group 0;" ::: "memory");
        }
        __syncthreads();
        if (t + 2 < NT) {
            int nb = buf + 2;
            if (nb >= 3) nb -= 3;
            issue(nb, t + 2);
        }
        uint32_t aBase = smem_u32(&As[buf][0][0]);
        uint32_t bBase = smem_u32(&Bs[buf][0][0]);
        #pragma unroll
        for (int ks = 0; ks < 2; ks++) {
            uint32_t koff = ks * 32;
            uint32_t af[2][4], bf[8][2];
            #pragma unroll
            for (int mi = 0; mi < 2; mi++)
                LDSM_X4(af[mi][0], af[mi][1], af[mi][2], af[mi][3],
                        aBase + aOff[mi] + koff);
            #pragma unroll
            for (int nip = 0; nip < 4; nip++)
                LDSM_X4(bf[2 * nip][0], bf[2 * nip][1],
                        bf[2 * nip + 1][0], bf[2 * nip + 1][1],
                        bBase + bOff[nip] + koff);
            #pragma unroll
            for (int mi = 0; mi < 2; mi++)
                #pragma unroll
                for (int ni = 0; ni < 8; ni++)
                    MMA_F16(acc[mi][ni], af[mi], bf[ni]);
        }
        if (++buf == 3) buf = 0;
    }

    #pragma unroll
    for (int mi = 0; mi < 2; mi++) {
        int r0 = bm + warpM * 32 + mi * 16 + lr;
        #pragma unroll
        for (int ni = 0; ni < 8; ni++) {
            int c0 = bn + warpN * 64 + ni * 8 + lc * 2;
            #pragma unroll
            for (int half_ = 0; half_ < 2; half_++) {
                int r = r0 + half_ * 8;
                float v0 = acc[mi][ni][half_ * 2 + 0];
                float v1 = acc[mi][ni][half_ * 2 + 1];
                size_t idx = (size_t)r * N + c0;
                if (chDst) {
                    __half2 hv = __floats2half2_rn(v0, v1);
                    *reinterpret_cast<__half2*>(chDst + idx) = hv;
                } else {
                    C[idx]     = v0;
                    C[idx + 1] = v1;
                }
            }
        }
    }
}

// ---------------- fused output GEMM: out = y@Wo + fm@W2 + cor + lam*h -------
// K = 1024 (y/Wo) + 4096 (fm/W2) = 5120, pointer switch per K-tile.
__global__ void __launch_bounds__(256) gemm_out_kernel(
    const __half* __restrict__ Ay, const __half* __restrict__ Af,
    const __half* __restrict__ Bw, const __half* __restrict__ B2,
    float* __restrict__ out,
    const float* __restrict__ cor, const float* __restrict__ hst,
    const float* __restrict__ lamPtr)
{
    extern __shared__ __half smh[];
    __half (*As)[128][HSTR] = reinterpret_cast<__half(*)[128][HSTR]>(smh);
    __half (*Bs)[128][HSTR] = reinterpret_cast<__half(*)[128][HSTR]>(smh + 3 * 128 * HSTR);

    const int N = D_DIM;
    int tid = threadIdx.x;
    int lane = tid & 31;
    int warp = tid >> 5;
    int warpM = warp >> 1;
    int warpN = warp & 1;
    int lr = lane >> 2;
    int lc = lane & 3;
    int bm = blockIdx.y * 128;
    int bn = blockIdx.x * 128;

    int sr = tid >> 1;
    int sc = (tid & 1) * 16;

    int aRow = lane & 15, aCol = (lane >> 4) * 8;
    int bRow = ((lane & 16) ? 8 : 0) + (lane & 7);
    int bCol = ((lane & 8) ? 8 : 0);
    uint32_t aOff[2], bOff[4];
    #pragma unroll
    for (int mi = 0; mi < 2; mi++)
        aOff[mi] = ((warpM * 32 + mi * 16 + aRow) * HSTR + aCol) * 2;
    #pragma unroll
    for (int nip = 0; nip < 4; nip++)
        bOff[nip] = ((warpN * 64 + nip * 16 + bRow) * HSTR + bCol) * 2;

    float acc[2][8][4];
    #pragma unroll
    for (int mi = 0; mi < 2; mi++)
        #pragma unroll
        for (int ni = 0; ni < 8; ni++)
            #pragma unroll
            for (int r = 0; r < 4; r++) acc[mi][ni][r] = 0.f;

    const int NT = (D_DIM + FF_IN) / 32;   // 160

    auto issue = [&](int buf, int t) {
        int kk = t * 32;
        const __half* ga;
        const __half* gb;
        if (kk < D_DIM) {
            ga = Ay + (size_t)(bm + sr) * D_DIM + kk + sc;
            gb = Bw + (size_t)(bn + sr) * D_DIM + kk + sc;
        } else {
            ga = Af + (size_t)(bm + sr) * FF_IN + (kk - D_DIM) + sc;
            gb = B2 + (size_t)(bn + sr) * FF_IN + (kk - D_DIM) + sc;
        }
        uint32_t da = smem_u32(&As[buf][sr][sc]);
        uint32_t db = smem_u32(&Bs[buf][sr][sc]);
        CP16(da, ga);
        CP16(da + 16, ga + 8);
        CP16(db, gb);
        CP16(db + 16, gb + 8);
        asm volatile("cp.async.commit_group;" ::: "memory");
    };

    issue(0, 0);
    issue(1, 1);
    int buf = 0;
    for (int t = 0; t < NT; t++) {
        if (t + 1 < NT) {
            asm volatile("cp.async.wait_group 1;" ::: "memory");
        } else {
            asm volatile("cp.async.wait_group 0;" ::: "memory");
        }
        __syncthreads();
        if (t + 2 < NT) {
            int nb = buf + 2;
            if (nb >= 3) nb -= 3;
            issue(nb, t + 2);
        }
        uint32_t aBase = smem_u32(&As[buf][0][0]);
        uint32_t bBase = smem_u32(&Bs[buf][0][0]);
        #pragma unroll
        for (int ks = 0; ks < 2; ks++) {
            uint32_t koff = ks * 32;
            uint32_t af[2][4], bf[8][2];
            #pragma unroll
            for (int mi = 0; mi < 2; mi++)
                LDSM_X4(af[mi][0], af[mi][1], af[mi][2], af[mi][3],
                        aBase + aOff[mi] + koff);
            #pragma unroll
            for (int nip = 0; nip < 4; nip++)
                LDSM_X4(bf[2 * nip][0], bf[2 * nip][1],
                        bf[2 * nip + 1][0], bf[2 * nip + 1][1],
                        bBase + bOff[nip] + koff);
            #pragma unroll
            for (int mi = 0; mi < 2; mi++)
                #pragma unroll
                for (int ni = 0; ni < 8; ni++)
                    MMA_F16(acc[mi][ni], af[mi], bf[ni]);
        }
        if (++buf == 3) buf = 0;
    }

    float lam = lamPtr[0];
    #pragma unroll
    for (int mi = 0; mi < 2; mi++) {
        int r0 = bm + warpM * 32 + mi * 16 + lr;
        #pragma unroll
        for (int ni = 0; ni < 8; ni++) {
            int c0 = bn + warpN * 64 + ni * 8 + lc * 2;
            #pragma unroll
            for (int half_ = 0; half_ < 2; half_++) {
                int r = r0 + half_ * 8;
                size_t idx = (size_t)r * N + c0;
                float2 cv = *reinterpret_cast<const float2*>(cor + idx);
                float2 hv = *reinterpret_cast<const float2*>(hst + idx);
                float v0 = acc[mi][ni][half_ * 2 + 0] + cv.x + lam * hv.x;
                float v1 = acc[mi][ni][half_ * 2 + 1] + cv.y + lam * hv.y;
                out[idx]     = v0;
                out[idx + 1] = v1;
            }
        }
    }
}

// ---------------- fused W1 GEMM + SwiGLU, 3-stage ----------------
#define W1_SMEM (9 * 128 * HSTR * 2)

__global__ void __launch_bounds__(256) gemm_w1_swiglu_kernel(
    const __half* __restrict__ A, const __half* __restrict__ W1t,
    __half* __restrict__ fmh, const float* __restrict__ b1)
{
    extern __shared__ __half smh[];
    __half (*As)[128][HSTR]  = reinterpret_cast<__half(*)[128][HSTR]>(smh);
    __half (*Bx)[128][HSTR]  = reinterpret_cast<__half(*)[128][HSTR]>(smh + 3 * 128 * HSTR);
    __half (*Bg)[128][HSTR]  = reinterpret_cast<__half(*)[128][HSTR]>(smh + 6 * 128 * HSTR);

    const int K = D_DIM, N = FF_IN;
    int tid = threadIdx.x;
    int lane = tid & 31;
    int warp = tid >> 5;
    int warpM = warp >> 1;
    int warpN = warp & 1;
    int lr = lane >> 2;
    int lc = lane & 3;
    int bm = blockIdx.y * 128;
    int bn = blockIdx.x * 128;

    int sr = tid >> 1;
    int sc = (tid & 1) * 16;
    const __half* Ap  = A   + (size_t)(bm + sr) * K + sc;
    const __half* Bxp = W1t + (size_t)(bn + sr) * K + sc;
    const __half* Bgp = W1t + (size_t)(FF_IN + bn + sr) * K + sc;

    int aRow = lane & 15, aCol = (lane >> 4) * 8;
    int bRow = ((lane & 16) ? 8 : 0) + (lane & 7);
    int bCol = ((lane & 8) ? 8 : 0);
    uint32_t aOff[2], bOff[4];
    #pragma unroll
    for (int mi = 0; mi < 2; mi++)
        aOff[mi] = ((warpM * 32 + mi * 16 + aRow) * HSTR + aCol) * 2;
    #pragma unroll
    for (int nip = 0; nip < 4; nip++)
        bOff[nip] = ((warpN * 64 + nip * 16 + bRow) * HSTR + bCol) * 2;

    float accX[2][8][4], accG[2][8][4];
    #pragma unroll
    for (int mi = 0; mi < 2; mi++)
        #pragma unroll
        for (int ni = 0; ni < 8; ni++)
            #pragma unroll
            for (int r = 0; r < 4; r++) { accX[mi][ni][r] = 0.f; accG[mi][ni][r] = 0.f; }

    const int NT = K / 32;

    auto issue = [&](int buf, int t) {
        uint32_t da = smem_u32(&As[buf][sr][sc]);
        uint32_t dx = smem_u32(&Bx[buf][sr][sc]);
        uint32_t dg = smem_u32(&Bg[buf][sr][sc]);
        CP16(da, Ap + t * 32);
        CP16(da + 16, Ap + t * 32 + 8);
        CP16(dx, Bxp + t * 32);
        CP16(dx + 16, Bxp + t * 32 + 8);
        CP16(dg, Bgp + t * 32);
        CP16(dg + 16, Bgp + t * 32 + 8);
        asm volatile("cp.async.commit_group;" ::: "memory");
    };

    issue(0, 0);
    issue(1, 1);
    int buf = 0;
    for (int t = 0; t < NT; t++) {
        if (t + 1 < NT) {
            asm volatile("cp.async.wait_group 1;" ::: "memory");
        } else {
            asm volatile("cp.async.wait_group 0;" ::: "memory");
        }
        __syncthreads();
        if (t + 2 < NT) {
            int nb = buf + 2;
            if (nb >= 3) nb -= 3;
            issue(nb, t + 2);
        }
        uint32_t aBase = smem_u32(&As[buf][0][0]);
        uint32_t xBase = smem_u32(&Bx[buf][0][0]);
        uint32_t gBase = smem_u32(&Bg[buf][0][0]);
        #pragma unroll
        for (int ks = 0; ks < 2; ks++) {
            uint32_t koff = ks * 32;
            uint32_t af[2][4], bx[8][2], bg[8][2];
            #pragma unroll
            for (int mi = 0; mi < 2; mi++)
                LDSM_X4(af[mi][0], af[mi][1], af[mi][2], af[mi][3],
                        aBase + aOff[mi] + koff);
            #pragma unroll
            for (int nip = 0; nip < 4; nip++) {
                LDSM_X4(bx[2 * nip][0], bx[2 * nip][1],
                        bx[2 * nip + 1][0], bx[2 * nip + 1][1],
                        xBase + bOff[nip] + koff);
                LDSM_X4(bg[2 * nip][0], bg[2 * nip][1],
                        bg[2 * nip + 1][0], bg[2 * nip + 1][1],
                        gBase + bOff[nip] + koff);
            }
            #pragma unroll
            for (int mi = 0; mi < 2; mi++)
                #pragma unroll
                for (int ni = 0; ni < 8; ni++) {
                    MMA_F16(accX[mi][ni], af[mi], bx[ni]);
                    MMA_F16(accG[mi][ni], af[mi], bg[ni]);
                }
        }
        if (++buf == 3) buf = 0;
    }

    #pragma unroll
    for (int mi = 0; mi < 2; mi++) {
        int r0 = bm + warpM * 32 + mi * 16 + lr;
        #pragma unroll
        for (int ni = 0; ni < 8; ni++) {
            int c0 = bn + warpN * 64 + ni * 8 + lc * 2;
            float bx0 = b1[c0], bx1 = b1[c0 + 1];
            float bg0 = b1[FF_IN + c0], bg1 = b1[FF_IN + c0 + 1];
            #pragma unroll
            for (int half_ = 0; half_ < 2; half_++) {
                int r = r0 + half_ * 8;
                float xp0 = accX[mi][ni][half_ * 2 + 0] + bx0;
                float xp1 = accX[mi][ni][half_ * 2 + 1] + bx1;
                float g0 = accG[mi][ni][half_ * 2 + 0] + bg0;
                float g1 = accG[mi][ni][half_ * 2 + 1] + bg1;
                float f0 = (g0 / (1.f + __expf(-g0))) * xp0;
                float f1 = (g1 / (1.f + __expf(-g1))) * xp1;
                __half2 hv = __floats2half2_rn(f0, f1);
                *reinterpret_cast<__half2*>(fmh + (size_t)r * N + c0) = hv;
            }
        }
    }
}

// ---------------- l2norm + RoPE (table-driven) ----------------
__global__ void __launch_bounds__(256) ropenorm_kernel(
    __half* __restrict__ qh, __half* __restrict__ kh, float* qb, float* kb,
    const float* __restrict__ ct, const float* __restrict__ st) {
    int s = blockIdx.x;
    int warp = threadIdx.x >> 5;
    int lane = threadIdx.x & 31;
    int idx = blockIdx.y * 8 + warp;
    int h = idx & 15;
    int a = idx >> 4;
    size_t off = (size_t)s * D_DIM + h * 64;
    float x1, x2;
    if (a < 2) {
        const __half* p = ((a == 0) ? qh : kh) + off;
        x1 = __half2float(p[lane]);
        x2 = __half2float(p[lane + DHALF]);
    } else {
        const float* p = ((a == 2) ? qb : kb) + off;
        x1 = p[lane];
        x2 = p[lane + DHALF];
    }
    float ss = x1 * x1 + x2 * x2;
    #pragma unroll
    for (int o = 16; o; o >>= 1) ss += __shfl_xor_sync(0xffffffffu, ss, o);
    float n = fmaxf(sqrtf(ss), 1e-12f);
    float inv = 1.f / n;
    x1 *= inv;
    x2 *= inv;
    float c  = ct[s * DHALF + lane];
    float sn = st[s * DHALF + lane];
    float y1 = x1 * c + x2 * sn;
    float y2 = -x1 * sn + x2 * c;
    if (a < 2) {
        __half* dst = ((a == 0) ? qh : kh) + off;
        dst[lane]         = __float2half(y1);
        dst[lane + DHALF] = __float2half(y2);
    } else {
        float* dst = ((a == 2) ? qb : kb) + off;
        dst[lane]         = y1;
        dst[lane + DHALF] = y2;
    }
}

// ---------------- parallel prefix sum of kb ----------------
__global__ void __launch_bounds__(256) prefix_p1(const float* __restrict__ kb,
                                                 float* __restrict__ cs) {
    int ch = blockIdx.x;
    int col = blockIdx.y * 256 + threadIdx.x;
    const float* p = kb + (size_t)(ch * 32) * D_DIM + col;
    float acc = 0.f;
    #pragma unroll
    for (int r = 0; r < 32; r++) acc += p[(size_t)r * D_DIM];
    cs[(size_t)ch * D_DIM + col] = acc;
}
__global__ void __launch_bounds__(1024) prefix_p2(float* __restrict__ cs) {
    int col = threadIdx.x;
    float run = 0.f;
    #pragma unroll 8
    for (int ch = 0; ch < 64; ch++) {
        size_t i = (size_t)ch * D_DIM + col;
        float t = cs[i];
        cs[i] = run;
        run += t;
    }
}
__global__ void __launch_bounds__(256) prefix_p3(const float* __restrict__ kb,
                                                 const float* __restrict__ cs,
                                                 float* __restrict__ pkb) {
    int ch = blockIdx.x;
    int col = blockIdx.y * 256 + threadIdx.x;
    float acc = cs[(size_t)ch * D_DIM + col];
    const float* p = kb + (size_t)(ch * 32) * D_DIM + col;
    float* o = pkb + (size_t)(ch * 32) * D_DIM + col;
    #pragma unroll
    for (int r = 0; r < 32; r++) {
        acc += p[(size_t)r * D_DIM];
        o[(size_t)r * D_DIM] = acc;
    }
}

// ---------------- sb values ----------------
__global__ void __launch_bounds__(512) sb_kernel(const float* __restrict__ qb,
                                                 const float* __restrict__ pkb,
                                                 float* __restrict__ sbv) {
    int s = blockIdx.x;
    int h = threadIdx.x >> 5;
    int lane = threadIdx.x & 31;
    size_t off = (size_t)s * D_DIM + h * 64;
    float v = qb[off + lane] * pkb[off + lane] +
              qb[off + lane + DHALF] * pkb[off + lane + DHALF];
    #pragma unroll
    for (int o = 16; o; o >>= 1) v += __shfl_xor_sync(0xffffffffu, v, o);
    if (lane == 0) sbv[s * H_N + h] = 0.125f * v;
}

// ---------------- fp16 flash attention (proven) ----------------
#define QSH 72
#define ATT_SMEM (512 * QSH * 2 + 256 * 4)

__global__ void __launch_bounds__(256) attn_mma_kernel(
    const __half* __restrict__ qh, const __half* __restrict__ kh,
    const __half* __restrict__ vh,
    const float* __restrict__ l2sp, __half* __restrict__ yh)
{
    extern __shared__ __half smah[];
    __half (*Qs)[QSH] = reinterpret_cast<__half(*)[QSH]>(smah);
    __half (*Ps)[QSH] = reinterpret_cast<__half(*)[QSH]>(smah + 128 * QSH);
    __half (*Ks)[64][QSH] = reinterpret_cast<__half(*)[64][QSH]>(smah + 256 * QSH);
    __half (*Vs)[64][QSH] = reinterpret_cast<__half(*)[64][QSH]>(smah + 384 * QSH);
    float* red_l = reinterpret_cast<float*>(smah + 512 * QSH);

    int h = blockIdx.y;
    int qt = gridDim.x - 1 - blockIdx.x;
    int q0 = qt * 128;
    int tid = threadIdx.x;
    int lane = tid & 31, warp = tid >> 5;
    int wm = warp >> 1;
    int wn = warp & 1;
    int lr = lane >> 2;
    int lc = lane & 3;

    int aRow = lane & 15, aCol = (lane >> 4) * 8;
    uint32_t qOff[2];
    #pragma unroll
    for (int mi = 0; mi < 2; mi++)
        qOff[mi] = ((wm * 32 + mi * 16 + aRow) * QSH + aCol) * 2;
    int bRow = ((lane & 16) ? 8 : 0) + (lane & 7);
    int bCol = ((lane & 8) ? 8 : 0);
    uint32_t kOff[2];
    #pragma unroll
    for (int nip = 0; nip < 2; nip++)
        kOff[nip] = ((wn * 32 + nip * 16 + bRow) * QSH + bCol) * 2;
    int tRow = ((lane & 8) ? 8 : 0) + (lane & 7);
    int tCol = ((lane & 16) ? 8 : 0);
    uint32_t vOff[2];
    #pragma unroll
    for (int nip = 0; nip < 2; nip++)
        vOff[nip] = (tRow * QSH + wn * 32 + nip * 16 + tCol) * 2;

    uint32_t qBase = smem_u32(&Qs[0][0]);
    uint32_t pBase = smem_u32(&Ps[0][0]);

    int stR = tid >> 2, stC = (tid & 3) * 16;

    auto issueKV = [&](int buf, int kt) {
        int kbase = kt * 64;
        const __half* ks = kh + (size_t)(kbase + stR) * D_DIM + h * 64 + stC;
        const __half* vs = vh + (size_t)(kbase + stR) * D_DIM + h * 64 + stC;
        uint32_t dk = smem_u32(&Ks[buf][stR][stC]);
        uint32_t dv = smem_u32(&Vs[buf][stR][stC]);
        CP16(dk, ks);
        CP16(dk + 16, ks + 8);
        CP16(dv, vs);
        CP16(dv + 16, vs + 8);
        asm volatile("cp.async.commit_group;" ::: "memory");
    };

    {
        int r = tid >> 1, c0 = (tid & 1) * 32;
        const __half* src = qh + (size_t)(q0 + r) * D_DIM + h * 64 + c0;
        #pragma unroll
        for (int j = 0; j < 4; j++)
            *reinterpret_cast<uint4*>(&Qs[r][c0 + j * 8]) =
                *reinterpret_cast<const uint4*>(src + j * 8);
    }

    float l[4] = {0.f, 0.f, 0.f, 0.f};
    float o[2][4][4];
    #pragma unroll
    for (int mi = 0; mi < 2; mi++)
        #pragma unroll
        for (int ni = 0; ni < 4; ni++)
            #pragma unroll
            for (int j = 0; j < 4; j++) o[mi][ni][j] = 0.f;

    int nt = 2 * qt + 2;
    issueKV(0, 0);

    for (int kt = 0; kt < nt; kt++) {
        int buf = kt & 1;
        int kbase = kt * 64;
        __syncthreads();
        if (kt + 1 < nt) {
            issueKV(buf ^ 1, kt + 1);
            asm volatile("cp.async.wait_group 1;" ::: "memory");
        } else {
            asm volatile("cp.async.wait_group 0;" ::: "memory");
        }
        __syncthreads();

        uint32_t kBase = smem_u32(&Ks[buf][0][0]);
        uint32_t vBase = smem_u32(&Vs[buf][0][0]);

        float s[2][4][4];
        #pragma unroll
        for (int mi = 0; mi < 2; mi++)
            #pragma unroll
            for (int ni = 0; ni < 4; ni++)
                #pragma unroll
                for (int j = 0; j < 4; j++) s[mi][ni][j] = 0.f;
        #pragma unroll
        for (int ks = 0; ks < 4; ks++) {
            uint32_t kbyte = ks * 32;
            uint32_t af[2][4], bf[4][2];
            #pragma unroll
            for (int mi = 0; mi < 2; mi++)
                LDSM_X4(af[mi][0], af[mi][1], af[mi][2], af[mi][3],
                        qBase + qOff[mi] + kbyte);
            #pragma unroll
            for (int nip = 0; nip < 2; nip++)
                LDSM_X4(bf[2 * nip][0], bf[2 * nip][1],
                        bf[2 * nip + 1][0], bf[2 * nip + 1][1],
                        kBase + kOff[nip] + kbyte);
            #pragma unroll
            for (int mi = 0; mi < 2; mi++)
                #pragma unroll
                for (int ni = 0; ni < 4; ni++)
                    MMA_F16(s[mi][ni], af[mi], bf[ni]);
        }
        if (kt >= nt - 2) {
            #pragma unroll
            for (int mi = 0; mi < 2; mi++) {
                int rg0 = q0 + wm * 32 + mi * 16 + lr;
                #pragma unroll
                for (int ni = 0; ni < 4; ni++) {
                    int cgb = kbase + wn * 32 + ni * 8 + lc * 2;
                    #pragma unroll
                    for (int j = 0; j < 4; j++) {
                        int rg = rg0 + ((j >= 2) ? 8 : 0);
                        int cg = cgb + (j & 1);
                        if (cg > rg) s[mi][ni][j] = -1e4f;
                    }
                }
            }
        }
        #pragma unroll
        for (int mi = 0; mi < 2; mi++) {
            int r0m = wm * 32 + mi * 16 + lr;
            int r1m = r0m + 8;
            #pragma unroll
            for (int ni = 0; ni < 4; ni++) {
                int cbase = wn * 32 + ni * 8 + lc * 2;
                float t0 = fmaf(s[mi][ni][0], L2E, -L2E);
                float t1 = fmaf(s[mi][ni][1], L2E, -L2E);
                float t2 = fmaf(s[mi][ni][2], L2E, -L2E);
                float t3 = fmaf(s[mi][ni][3], L2E, -L2E);
                __half2 ht0 = __floats2half2_rn(t0, t1);
                __half2 ht1 = __floats2half2_rn(t2, t3);
                uint32_t p0, p1;
                EX2_F16X2(p0, *reinterpret_cast<uint32_t*>(&ht0));
                EX2_F16X2(p1, *reinterpret_cast<uint32_t*>(&ht1));
                *reinterpret_cast<uint32_t*>(&Ps[r0m][cbase]) = p0;
                *reinterpret_cast<uint32_t*>(&Ps[r1m][cbase]) = p1;
                float2 f0 = __half22float2(*reinterpret_cast<__half2*>(&p0));
                float2 f1 = __half22float2(*reinterpret_cast<__half2*>(&p1));
                l[mi * 2]     += f0.x + f0.y;
                l[mi * 2 + 1] += f1.x + f1.y;
            }
        }
        __syncthreads();
        #pragma unroll
        for (int ks = 0; ks < 4; ks++) {
            uint32_t af[2][4], bf[4][2];
            #pragma unroll
            for (int mi = 0; mi < 2; mi++)
                LDSM_X4(af[mi][0], af[mi][1], af[mi][2], af[mi][3],
                        pBase + qOff[mi] + ks * 32);
            #pragma unroll
            for (int nip = 0; nip < 2; nip++)
                LDSM_X4T(bf[2 * nip][0], bf[2 * nip][1],
                         bf[2 * nip + 1][0], bf[2 * nip + 1][1],
                         vBase + vOff[nip] + ks * 16 * QSH * 2);
            #pragma unroll
            for (int mi = 0; mi < 2; mi++)
                #pragma unroll
                for (int ni = 0; ni < 4; ni++)
                    MMA_F16(o[mi][ni], af[mi], bf[ni]);
        }
    }

    #pragma unroll
    for (int i = 0; i < 4; i++) {
        l[i] += __shfl_xor_sync(0xffffffffu, l[i], 1);
        l[i] += __shfl_xor_sync(0xffffffffu, l[i], 2);
    }
    if (lc == 0) {
        #pragma unroll
        for (int mi = 0; mi < 2; mi++) {
            int r0m = wm * 32 + mi * 16 + lr;
            red_l[wn * 128 + r0m]     = l[mi * 2];
            red_l[wn * 128 + r0m + 8] = l[mi * 2 + 1];
        }
    }
    __syncthreads();

    float l2sv = l2sp[0];
    #pragma unroll
    for (int mi = 0; mi < 2; mi++) {
        int r0m = wm * 32 + mi * 16 + lr;
        int r1m = r0m + 8;
        float lt0 = red_l[r0m] + red_l[128 + r0m];
        float lt1 = red_l[r1m] + red_l[128 + r1m];
        float inv0 = l2sv / lt0;
        float inv1 = l2sv / lt1;
        int g0 = q0 + r0m, g1 = q0 + r1m;
        #pragma unroll
        for (int ni = 0; ni < 4; ni++) {
            int col = h * 64 + wn * 32 + ni * 8 + lc * 2;
            __half2 r0v = __floats2half2_rn(o[mi][ni][0] * inv0, o[mi][ni][1] * inv0);
            __half2 r1v = __floats2half2_rn(o[mi][ni][2] * inv1, o[mi][ni][3] * inv1);
            *reinterpret_cast<__half2*>(&yh[(size_t)g0 * D_DIM + col]) = r0v;
            *reinterpret_cast<__half2*>(&yh[(size_t)g1 * D_DIM + col]) = r1v;
        }
    }
}

// ---------------- launch ----------------
extern "C" void kernel_launch(void* const* d_in, const int* in_sizes, int n_in,
                              void* d_out, int out_size) {
    const float* h_states = (const float*)d_in[0];
    const float* Wq  = (const float*)d_in[1];
    const float* Wk  = (const float*)d_in[2];
    const float* Wv  = (const float*)d_in[3];
    const float* Wqb = (const float*)d_in[4];
    const float* Wkb = (const float*)d_in[5];
    const float* Wo  = (const float*)d_in[6];
    const float* bo  = (const float*)d_in[7];
    const float* W1  = (const float*)d_in[8];
    const float* b1  = (const float*)d_in[9];
    const float* W2  = (const float*)d_in[10];
    const float* b2  = (const float*)d_in[11];
    const float* lam = (const float*)d_in[12];
    const float* l2s = (const float*)d_in[13];
    float* out = (float*)d_out;

    float *qb, *kb, *pkb, *cs, *sbv, *wos, *cor, *ct, *st;
    __half *xh, *yh, *fmh, *qhh, *khh, *vhh;
    __half *wqh, *wkh, *wvh, *wqbh, *wkbh, *woh, *w1h, *w2h;
    cudaGetSymbolAddress((void**)&qb, g_qb);
    cudaGetSymbolAddress((void**)&kb, g_kb);
    cudaGetSymbolAddress((void**)&pkb, g_pkb);
    cudaGetSymbolAddress((void**)&cs, g_cs);
    cudaGetSymbolAddress((void**)&sbv, g_sb);
    cudaGetSymbolAddress((void**)&wos, g_wos);
    cudaGetSymbolAddress((void**)&cor, g_cor);
    cudaGetSymbolAddress((void**)&ct, g_ct);
    cudaGetSymbolAddress((void**)&st, g_st);
    cudaGetSymbolAddress((void**)&xh,  g_xh);
    cudaGetSymbolAddress((void**)&yh,  g_yh);
    cudaGetSymbolAddress((void**)&fmh, g_fmh);
    cudaGetSymbolAddress((void**)&qhh, g_qhh);
    cudaGetSymbolAddress((void**)&khh, g_khh);
    cudaGetSymbolAddress((void**)&vhh, g_vhh);
    cudaGetSymbolAddress((void**)&wqh,  g_wqh);
    cudaGetSymbolAddress((void**)&wkh,  g_wkh);
    cudaGetSymbolAddress((void**)&wvh,  g_wvh);
    cudaGetSymbolAddress((void**)&wqbh, g_wqbh);
    cudaGetSymbolAddress((void**)&wkbh, g_wkbh);
    cudaGetSymbolAddress((void**)&woh,  g_woh);
    cudaGetSymbolAddress((void**)&w1h,  g_w1h);
    cudaGetSymbolAddress((void**)&w2h,  g_w2h);

    cudaFuncSetAttribute(attn_mma_kernel,
                         cudaFuncAttributeMaxDynamicSharedMemorySize, ATT_SMEM);
    cudaFuncSetAttribute(gemm_f16_kernel,
                         cudaFuncAttributeMaxDynamicSharedMemorySize, GEMM_SMEM);
    cudaFuncSetAttribute(gemm_out_kernel,
                         cudaFuncAttributeMaxDynamicSharedMemorySize, GEMM_SMEM);
    cudaFuncSetAttribute(gemm_w1_swiglu_kernel,
                         cudaFuncAttributeMaxDynamicSharedMemorySize, W1_SMEM);

    static cudaStream_t s1 = nullptr, s2 = nullptr;
    static cudaEvent_t evX = nullptr, evFFN = nullptr, evRope = nullptr,
                       evSB = nullptr, evW = nullptr;
    if (!s1) {
        cudaStreamCreateWithFlags(&s1, cudaStreamNonBlocking);
        cudaStreamCreateWithFlags(&s2, cudaStreamNonBlocking);
        cudaEventCreateWithFlags(&evX, cudaEventDisableTiming);
        cudaEventCreateWithFlags(&evFFN, cudaEventDisableTiming);
        cudaEventCreateWithFlags(&evRope, cudaEventDisableTiming);
        cudaEventCreateWithFlags(&evSB, cudaEventDisableTiming);
        cudaEventCreateWithFlags(&evW, cudaEventDisableTiming);
    }

    // ---- main: rmsnorm first; evX is the capture-fork point ----
    rmsnorm_kernel<<<S_LEN, 256>>>(h_states, xh);
    cudaEventRecord(evX, 0);

    // ---- s2 (fork): weight converts + WoSum + rope tables ----
    cudaStreamWaitEvent(s2, evX, 0);
    cvtT6_kernel<<<dim3(32, 32, 6), 256, 0, s2>>>(Wq, Wk, Wv, Wqb, Wkb, Wo,
                                                  wqh, wkh, wvh, wqbh, wkbh, woh);
    ropetab_kernel<<<S_LEN * DHALF / 256, 256, 0, s2>>>(ct, st);
    wosum_kernel<<<H_N * D_DIM / 256, 256, 0, s2>>>(Wo, wos);
    cudaEventRecord(evW, s2);

    // ---- s1 (fork): FFN branch ----
    cudaStreamWaitEvent(s1, evX, 0);
    cvtT_kernel<<<dim3(FUSEDW / 32, 32), 256, 0, s1>>>(W1, w1h, D_DIM, FUSEDW);
    cvtT_kernel<<<dim3(32, FF_IN / 32), 256, 0, s1>>>(W2, w2h, FF_IN, D_DIM);
    gemm_w1_swiglu_kernel<<<dim3(FF_IN / 128, S_LEN / 128), 256, W1_SMEM, s1>>>(
        xh, w1h, fmh, b1);
    cudaEventRecord(evFFN, s1);

    // ---- main: attention branch ----
    cudaStreamWaitEvent(0, evW, 0);
    gemm_f16_kernel<<<dim3(D_DIM / 128, S_LEN / 128, 5), 256, GEMM_SMEM>>>(
        xh, wqh, wkh, wvh, wqbh, wkbh, qb, kb, qhh, khh, vhh,
        S_LEN, D_DIM, D_DIM);
    ropenorm_kernel<<<dim3(S_LEN, 8), 256>>>(qhh, khh, qb, kb, ct, st);
    cudaEventRecord(evRope, 0);

    // ---- s2: sb/corr chain, overlapped with attention ----
    cudaStreamWaitEvent(s2, evRope, 0);
    prefix_p1<<<dim3(64, 4), 256, 0, s2>>>(kb, cs);
    prefix_p2<<<1, 1024, 0, s2>>>(cs);
    prefix_p3<<<dim3(64, 4), 256, 0, s2>>>(kb, cs, pkb);
    sb_kernel<<<S_LEN, 512, 0, s2>>>(qb, pkb, sbv);
    corr_kernel<<<S_LEN, 256, 0, s2>>>(sbv, wos, bo, b2, cor);
    cudaEventRecord(evSB, s2);

    // ---- main: attention ----
    attn_mma_kernel<<<dim3(S_LEN / 128, H_N), 256, ATT_SMEM>>>(qhh, khh, vhh, l2s, yh);

    // ---- join everything: fused output GEMM (y@Wo + fm@W2 + cor + lam*h) ----
    cudaStreamWaitEvent(0, evSB, 0);
    cudaStreamWaitEvent(0, evFFN, 0);
    gemm_out_kernel<<<dim3(D_DIM / 128, S_LEN / 128), 256, GEMM_SMEM>>>(
        yh, fmh, woh, w2h, out, cor, h_states, lam);
}

// round 17
// speedup vs baseline: 9.8817x; 1.0199x over previous
#include <cuda_runtime.h>
#include <cuda_bf16.h>
#include <cuda_fp16.h>
#include <cstdint>

#define S_LEN 2048
#define D_DIM 1024
#define H_N 16
#define DHALF 32
#define FF_IN 4096
#define FUSEDW 8192

// ---------------- scratch ----------------
__device__ float  g_qb [S_LEN * D_DIM];
__device__ float  g_kb [S_LEN * D_DIM];
__device__ float  g_pkb[S_LEN * D_DIM];
__device__ float  g_cs [64 * D_DIM];
__device__ float  g_sb [S_LEN * H_N];
__device__ float  g_wos[H_N * D_DIM];
__device__ float  g_cor[S_LEN * D_DIM];
__device__ float  g_ct [S_LEN * DHALF];
__device__ float  g_st [S_LEN * DHALF];
__device__ __half g_xh [S_LEN * D_DIM];
__device__ __half g_yh [S_LEN * D_DIM];
__device__ __half g_fmh[S_LEN * FF_IN];
__device__ __half g_qhh[S_LEN * D_DIM];
__device__ __half g_khh[S_LEN * D_DIM];
__device__ __half g_vhh[S_LEN * D_DIM];
__device__ __half g_wqh [D_DIM * D_DIM];
__device__ __half g_wkh [D_DIM * D_DIM];
__device__ __half g_wvh [D_DIM * D_DIM];
__device__ __half g_wqbh[D_DIM * D_DIM];
__device__ __half g_wkbh[D_DIM * D_DIM];
__device__ __half g_woh [D_DIM * D_DIM];
__device__ __half g_w1h [FUSEDW * D_DIM];
__device__ __half g_w2h [D_DIM * FF_IN];

// ---------------- helpers ----------------
__device__ __forceinline__ uint32_t smem_u32(const void* p) {
    uint32_t a;
    asm("{ .reg .u64 t; cvta.to.shared.u64 t, %1; cvt.u32.u64 %0, t; }" : "=r"(a) : "l"(p));
    return a;
}

#define MMA_F16(d, a, b)                                                      \
    asm volatile(                                                             \
        "mma.sync.aligned.m16n8k16.row.col.f32.f16.f16.f32 "                  \
        "{%0,%1,%2,%3}, {%4,%5,%6,%7}, {%8,%9}, {%0,%1,%2,%3};"               \
        : "+f"(d[0]), "+f"(d[1]), "+f"(d[2]), "+f"(d[3])                      \
        : "r"(a[0]), "r"(a[1]), "r"(a[2]), "r"(a[3]), "r"(b[0]), "r"(b[1]))

#define LDSM_X4(r0, r1, r2, r3, a)                                            \
    asm volatile("ldmatrix.sync.aligned.m8n8.x4.shared.b16 {%0,%1,%2,%3}, [%4];" \
                 : "=r"(r0), "=r"(r1), "=r"(r2), "=r"(r3) : "r"(a))

#define LDSM_X4T(r0, r1, r2, r3, a)                                           \
    asm volatile("ldmatrix.sync.aligned.m8n8.x4.trans.shared.b16 {%0,%1,%2,%3}, [%4];" \
                 : "=r"(r0), "=r"(r1), "=r"(r2), "=r"(r3) : "r"(a))

#define EX2_F16X2(d, a)                                                       \
    asm volatile("ex2.approx.f16x2 %0, %1;" : "=r"(d) : "r"(a))

#define CP16(dst, src)                                                        \
    asm volatile("cp.async.ca.shared.global [%0], [%1], 16;" :: "r"(dst), "l"(src))

#define L2E 1.4426950408889634f

// ---------------- tiny no-op (graph fork anchor) ----------------
__global__ void noop_kernel() {}

// ---------------- weight fp16 convert + transpose ----------------
__global__ void __launch_bounds__(256) cvtT6_kernel(
    const float* __restrict__ W0, const float* __restrict__ W1,
    const float* __restrict__ W2, const float* __restrict__ W3,
    const float* __restrict__ W4, const float* __restrict__ W5,
    __half* __restrict__ O0, __half* __restrict__ O1,
    __half* __restrict__ O2, __half* __restrict__ O3,
    __half* __restrict__ O4, __half* __restrict__ O5) {
    int z = blockIdx.z;
    const float* W = (z == 0) ? W0 : (z == 1) ? W1 : (z == 2) ? W2
                   : (z == 3) ? W3 : (z == 4) ? W4 : W5;
    __half* Wt = (z == 0) ? O0 : (z == 1) ? O1 : (z == 2) ? O2
               : (z == 3) ? O3 : (z == 4) ? O4 : O5;
    __shared__ float t[32][33];
    int n0 = blockIdx.x * 32, k0 = blockIdx.y * 32;
    int tx = threadIdx.x & 31, ty = threadIdx.x >> 5;
    #pragma unroll
    for (int i = 0; i < 32; i += 8)
        t[ty + i][tx] = W[(size_t)(k0 + ty + i) * D_DIM + n0 + tx];
    __syncthreads();
    #pragma unroll
    for (int i = 0; i < 32; i += 8)
        Wt[(size_t)(n0 + ty + i) * D_DIM + k0 + tx] = __float2half(t[tx][ty + i]);
}

__global__ void __launch_bounds__(256) cvtT_kernel(const float* __restrict__ W,
                                                   __half* __restrict__ Wt,
                                                   int K, int N) {
    __shared__ float t[32][33];
    int n0 = blockIdx.x * 32, k0 = blockIdx.y * 32;
    int tx = threadIdx.x & 31, ty = threadIdx.x >> 5;
    #pragma unroll
    for (int i = 0; i < 32; i += 8)
        t[ty + i][tx] = W[(size_t)(k0 + ty + i) * N + n0 + tx];
    __syncthreads();
    #pragma unroll
    for (int i = 0; i < 32; i += 8)
        Wt[(size_t)(n0 + ty + i) * K + k0 + tx] = __float2half(t[tx][ty + i]);
}

// ---------------- rope tables ----------------
__global__ void __launch_bounds__(256) ropetab_kernel(float* __restrict__ ct,
                                                      float* __restrict__ st) {
    int i = blockIdx.x * 256 + threadIdx.x;
    int s = i >> 5, lane = i & 31;
    float invfreq = powf(1000.0f, -(float)lane * (1.0f / 32.0f));
    float fr = (float)s * invfreq;
    ct[i] = __bfloat162float(__float2bfloat16(cosf(fr)));
    st[i] = __bfloat162float(__float2bfloat16(sinf(fr)));
}

// ---------------- WoSum ----------------
__global__ void __launch_bounds__(256) wosum_kernel(const float* __restrict__ Wo,
                                                    float* __restrict__ woSum) {
    int i = blockIdx.x * 256 + threadIdx.x;
    int h = i >> 10, c = i & 1023;
    float acc = 0.f;
    #pragma unroll 8
    for (int d = 0; d < 64; d++)
        acc += Wo[(size_t)(h * 64 + d) * D_DIM + c];
    woSum[i] = acc;
}

// ---------------- corr ----------------
__global__ void __launch_bounds__(256) corr_kernel(const float* __restrict__ sbv,
                                                   const float* __restrict__ woSum,
                                                   const float* __restrict__ bo,
                                                   const float* __restrict__ b2,
                                                   float* __restrict__ corr) {
    int r = blockIdx.x;
    int c = threadIdx.x * 4;
    float sb[16];
    #pragma unroll
    for (int h = 0; h < 16; h++) sb[h] = sbv[r * H_N + h];
    float4 b = *reinterpret_cast<const float4*>(bo + c);
    float4 b2v = *reinterpret_cast<const float4*>(b2 + c);
    float4 acc = make_float4(b.x + b2v.x, b.y + b2v.y, b.z + b2v.z, b.w + b2v.w);
    #pragma unroll
    for (int h = 0; h < 16; h++) {
        float4 w = *reinterpret_cast<const float4*>(woSum + h * D_DIM + c);
        acc.x += sb[h] * w.x;
        acc.y += sb[h] * w.y;
        acc.z += sb[h] * w.z;
        acc.w += sb[h] * w.w;
    }
    *reinterpret_cast<float4*>(corr + (size_t)r * D_DIM + c) = acc;
}

// ---------------- RMSNorm -> fp16 x ----------------
__global__ void __launch_bounds__(256) rmsnorm_kernel(const float* __restrict__ h,
                                                      __half* __restrict__ xh) {
    int row = blockIdx.x;
    int t = threadIdx.x;
    const float4* hr = reinterpret_cast<const float4*>(h + (size_t)row * D_DIM);
    float4 a = hr[t];
    float ss = a.x * a.x + a.y * a.y + a.z * a.z + a.w * a.w;
    __shared__ float red[8];
    #pragma unroll
    for (int off = 16; off; off >>= 1) ss += __shfl_xor_sync(0xffffffffu, ss, off);
    if ((t & 31) == 0) red[t >> 5] = ss;
    __syncthreads();
    float tot = red[0] + red[1] + red[2] + red[3] + red[4] + red[5] + red[6] + red[7];
    float r = rsqrtf(tot * (1.0f / 1024.0f) + 1.1920929e-7f);
    __half2 h0 = __floats2half2_rn(a.x * r, a.y * r);
    __half2 h1 = __floats2half2_rn(a.z * r, a.w * r);
    uint2 packed = make_uint2(*reinterpret_cast<uint32_t*>(&h0),
                              *reinterpret_cast<uint32_t*>(&h1));
    *reinterpret_cast<uint2*>(xh + (size_t)row * D_DIM + t * 4) = packed;
}

// ---------------- fp16 cp.async GEMM, 3-stage (projections) ----------------
#define HSTR 40
#define GEMM_SMEM (6 * 128 * HSTR * 2)

__global__ void __launch_bounds__(256) gemm_f16_kernel(
    const __half* __restrict__ A,
    const __half* __restrict__ B0, const __half* __restrict__ B1,
    const __half* __restrict__ B2, const __half* __restrict__ B3,
    const __half* __restrict__ B4,
    float* __restrict__ C3, float* __restrict__ C4,
    __half* __restrict__ ChQ, __half* __restrict__ ChK, __half* __restrict__ ChV,
    int M, int N, int K)
{
    int z = blockIdx.z;
    const __half* B = (z == 0) ? B0 : (z == 1) ? B1 : (z == 2) ? B2 : (z == 3) ? B3 : B4;
    float* C = (z == 3) ? C3 : C4;
    __half* chDst = (z == 0) ? ChQ : (z == 1) ? ChK : (z == 2) ? ChV : nullptr;

    extern __shared__ __half smh[];
    __half (*As)[128][HSTR] = reinterpret_cast<__half(*)[128][HSTR]>(smh);
    __half (*Bs)[128][HSTR] = reinterpret_cast<__half(*)[128][HSTR]>(smh + 3 * 128 * HSTR);

    int tid = threadIdx.x;
    int lane = tid & 31;
    int warp = tid >> 5;
    int warpM = warp >> 1;
    int warpN = warp & 1;
    int lr = lane >> 2;
    int lc = lane & 3;
    int bm = blockIdx.y * 128;
    int bn = blockIdx.x * 128;

    int sr = tid >> 1;
    int sc = (tid & 1) * 16;
    const __half* Ap = A + (size_t)(bm + sr) * K + sc;
    const __half* Bp = B + (size_t)(bn + sr) * K + sc;

    int aRow = lane & 15, aCol = (lane >> 4) * 8;
    int bRow = ((lane & 16) ? 8 : 0) + (lane & 7);
    int bCol = ((lane & 8) ? 8 : 0);
    uint32_t aOff[2], bOff[4];
    #pragma unroll
    for (int mi = 0; mi < 2; mi++)
        aOff[mi] = ((warpM * 32 + mi * 16 + aRow) * HSTR + aCol) * 2;
    #pragma unroll
    for (int nip = 0; nip < 4; nip++)
        bOff[nip] = ((warpN * 64 + nip * 16 + bRow) * HSTR + bCol) * 2;

    float acc[2][8][4];
    #pragma unroll
    for (int mi = 0; mi < 2; mi++)
        #pragma unroll
        for (int ni = 0; ni < 8; ni++)
            #pragma unroll
            for (int r = 0; r < 4; r++) acc[mi][ni][r] = 0.f;

    int NT = K / 32;

    auto issue = [&](int buf, int t) {
        const __half* ga = Ap + t * 32;
        const __half* gb = Bp + t * 32;
        uint32_t da = smem_u32(&As[buf][sr][sc]);
        uint32_t db = smem_u32(&Bs[buf][sr][sc]);
        CP16(da, ga);
        CP16(da + 16, ga + 8);
        CP16(db, gb);
        CP16(db + 16, gb + 8);
        asm volatile("cp.async.commit_group;" ::: "memory");
    };

    issue(0, 0);
    issue(1, 1);
    int buf = 0;
    for (int t = 0; t < NT; t++) {
        if (t + 1 < NT) {
            asm volatile("cp.async.wait_group 1;" ::: "memory");
        } else {
            asm volatile("cp.async.wait_group 0;" ::: "memory");
        }
        __syncthreads();
        if (t + 2 < NT) {
            int nb = buf + 2;
            if (nb >= 3) nb -= 3;
            issue(nb, t + 2);
        }
        uint32_t aBase = smem_u32(&As[buf][0][0]);
        uint32_t bBase = smem_u32(&Bs[buf][0][0]);
        #pragma unroll
        for (int ks = 0; ks < 2; ks++) {
            uint32_t koff = ks * 32;
            uint32_t af[2][4], bf[8][2];
            #pragma unroll
            for (int mi = 0; mi < 2; mi++)
                LDSM_X4(af[mi][0], af[mi][1], af[mi][2], af[mi][3],
                        aBase + aOff[mi] + koff);
            #pragma unroll
            for (int nip = 0; nip < 4; nip++)
                LDSM_X4(bf[2 * nip][0], bf[2 * nip][1],
                        bf[2 * nip + 1][0], bf[2 * nip + 1][1],
                        bBase + bOff[nip] + koff);
            #pragma unroll
            for (int mi = 0; mi < 2; mi++)
                #pragma unroll
                for (int ni = 0; ni < 8; ni++)
                    MMA_F16(acc[mi][ni], af[mi], bf[ni]);
        }
        if (++buf == 3) buf = 0;
    }

    #pragma unroll
    for (int mi = 0; mi < 2; mi++) {
        int r0 = bm + warpM * 32 + mi * 16 + lr;
        #pragma unroll
        for (int ni = 0; ni < 8; ni++) {
            int c0 = bn + warpN * 64 + ni * 8 + lc * 2;
            #pragma unroll
            for (int half_ = 0; half_ < 2; half_++) {
                int r = r0 + half_ * 8;
                float v0 = acc[mi][ni][half_ * 2 + 0];
                float v1 = acc[mi][ni][half_ * 2 + 1];
                size_t idx = (size_t)r * N + c0;
                if (chDst) {
                    __half2 hv = __floats2half2_rn(v0, v1);
                    *reinterpret_cast<__half2*>(chDst + idx) = hv;
                } else {
                    C[idx]     = v0;
                    C[idx + 1] = v1;
                }
            }
        }
    }
}

// ---------------- fused output GEMM ----------------
__global__ void __launch_bounds__(256) gemm_out_kernel(
    const __half* __restrict__ Ay, const __half* __restrict__ Af,
    const __half* __restrict__ Bw, const __half* __restrict__ B2,
    float* __restrict__ out,
    const float* __restrict__ cor, const float* __restrict__ hst,
    const float* __restrict__ lamPtr)
{
    extern __shared__ __half smh[];
    __half (*As)[128][HSTR] = reinterpret_cast<__half(*)[128][HSTR]>(smh);
    __half (*Bs)[128][HSTR] = reinterpret_cast<__half(*)[128][HSTR]>(smh + 3 * 128 * HSTR);

    const int N = D_DIM;
    int tid = threadIdx.x;
    int lane = tid & 31;
    int warp = tid >> 5;
    int warpM = warp >> 1;
    int warpN = warp & 1;
    int lr = lane >> 2;
    int lc = lane & 3;
    int bm = blockIdx.y * 128;
    int bn = blockIdx.x * 128;

    int sr = tid >> 1;
    int sc = (tid & 1) * 16;

    int aRow = lane & 15, aCol = (lane >> 4) * 8;
    int bRow = ((lane & 16) ? 8 : 0) + (lane & 7);
    int bCol = ((lane & 8) ? 8 : 0);
    uint32_t aOff[2], bOff[4];
    #pragma unroll
    for (int mi = 0; mi < 2; mi++)
        aOff[mi] = ((warpM * 32 + mi * 16 + aRow) * HSTR + aCol) * 2;
    #pragma unroll
    for (int nip = 0; nip < 4; nip++)
        bOff[nip] = ((warpN * 64 + nip * 16 + bRow) * HSTR + bCol) * 2;

    float acc[2][8][4];
    #pragma unroll
    for (int mi = 0; mi < 2; mi++)
        #pragma unroll
        for (int ni = 0; ni < 8; ni++)
            #pragma unroll
            for (int r = 0; r < 4; r++) acc[mi][ni][r] = 0.f;

    const int NT = (D_DIM + FF_IN) / 32;

    auto issue = [&](int buf, int t) {
        int kk = t * 32;
        const __half* ga;
        const __half* gb;
        if (kk < D_DIM) {
            ga = Ay + (size_t)(bm + sr) * D_DIM + kk + sc;
            gb = Bw + (size_t)(bn + sr) * D_DIM + kk + sc;
        } else {
            ga = Af + (size_t)(bm + sr) * FF_IN + (kk - D_DIM) + sc;
            gb = B2 + (size_t)(bn + sr) * FF_IN + (kk - D_DIM) + sc;
        }
        uint32_t da = smem_u32(&As[buf][sr][sc]);
        uint32_t db = smem_u32(&Bs[buf][sr][sc]);
        CP16(da, ga);
        CP16(da + 16, ga + 8);
        CP16(db, gb);
        CP16(db + 16, gb + 8);
        asm volatile("cp.async.commit_group;" ::: "memory");
    };

    issue(0, 0);
    issue(1, 1);
    int buf = 0;
    for (int t = 0; t < NT; t++) {
        if (t + 1 < NT) {
            asm volatile("cp.async.wait_group 1;" ::: "memory");
        } else {
            asm volatile("cp.async.wait_group 0;" ::: "memory");
        }
        __syncthreads();
        if (t + 2 < NT) {
            int nb = buf + 2;
            if (nb >= 3) nb -= 3;
            issue(nb, t + 2);
        }
        uint32_t aBase = smem_u32(&As[buf][0][0]);
        uint32_t bBase = smem_u32(&Bs[buf][0][0]);
        #pragma unroll
        for (int ks = 0; ks < 2; ks++) {
            uint32_t koff = ks * 32;
            uint32_t af[2][4], bf[8][2];
            #pragma unroll
            for (int mi = 0; mi < 2; mi++)
                LDSM_X4(af[mi][0], af[mi][1], af[mi][2], af[mi][3],
                        aBase + aOff[mi] + koff);
            #pragma unroll
            for (int nip = 0; nip < 4; nip++)
                LDSM_X4(bf[2 * nip][0], bf[2 * nip][1],
                        bf[2 * nip + 1][0], bf[2 * nip + 1][1],
                        bBase + bOff[nip] + koff);
            #pragma unroll
            for (int mi = 0; mi < 2; mi++)
                #pragma unroll
                for (int ni = 0; ni < 8; ni++)
                    MMA_F16(acc[mi][ni], af[mi], bf[ni]);
        }
        if (++buf == 3) buf = 0;
    }

    float lam = lamPtr[0];
    #pragma unroll
    for (int mi = 0; mi < 2; mi++) {
        int r0 = bm + warpM * 32 + mi * 16 + lr;
        #pragma unroll
        for (int ni = 0; ni < 8; ni++) {
            int c0 = bn + warpN * 64 + ni * 8 + lc * 2;
            #pragma unroll
            for (int half_ = 0; half_ < 2; half_++) {
                int r = r0 + half_ * 8;
                size_t idx = (size_t)r * N + c0;
                float2 cv = *reinterpret_cast<const float2*>(cor + idx);
                float2 hv = *reinterpret_cast<const float2*>(hst + idx);
                float v0 = acc[mi][ni][half_ * 2 + 0] + cv.x + lam * hv.x;
                float v1 = acc[mi][ni][half_ * 2 + 1] + cv.y + lam * hv.y;
                out[idx]     = v0;
                out[idx + 1] = v1;
            }
        }
    }
}

// ---------------- fused W1 GEMM + SwiGLU ----------------
#define W1_SMEM (9 * 128 * HSTR * 2)

__global__ void __launch_bounds__(256) gemm_w1_swiglu_kernel(
    const __half* __restrict__ A, const __half* __restrict__ W1t,
    __half* __restrict__ fmh, const float* __restrict__ b1)
{
    extern __shared__ __half smh[];
    __half (*As)[128][HSTR]  = reinterpret_cast<__half(*)[128][HSTR]>(smh);
    __half (*Bx)[128][HSTR]  = reinterpret_cast<__half(*)[128][HSTR]>(smh + 3 * 128 * HSTR);
    __half (*Bg)[128][HSTR]  = reinterpret_cast<__half(*)[128][HSTR]>(smh + 6 * 128 * HSTR);

    const int K = D_DIM, N = FF_IN;
    int tid = threadIdx.x;
    int lane = tid & 31;
    int warp = tid >> 5;
    int warpM = warp >> 1;
    int warpN = warp & 1;
    int lr = lane >> 2;
    int lc = lane & 3;
    int bm = blockIdx.y * 128;
    int bn = blockIdx.x * 128;

    int sr = tid >> 1;
    int sc = (tid & 1) * 16;
    const __half* Ap  = A   + (size_t)(bm + sr) * K + sc;
    const __half* Bxp = W1t + (size_t)(bn + sr) * K + sc;
    const __half* Bgp = W1t + (size_t)(FF_IN + bn + sr) * K + sc;

    int aRow = lane & 15, aCol = (lane >> 4) * 8;
    int bRow = ((lane & 16) ? 8 : 0) + (lane & 7);
    int bCol = ((lane & 8) ? 8 : 0);
    uint32_t aOff[2], bOff[4];
    #pragma unroll
    for (int mi = 0; mi < 2; mi++)
        aOff[mi] = ((warpM * 32 + mi * 16 + aRow) * HSTR + aCol) * 2;
    #pragma unroll
    for (int nip = 0; nip < 4; nip++)
        bOff[nip] = ((warpN * 64 + nip * 16 + bRow) * HSTR + bCol) * 2;

    float accX[2][8][4], accG[2][8][4];
    #pragma unroll
    for (int mi = 0; mi < 2; mi++)
        #pragma unroll
        for (int ni = 0; ni < 8; ni++)
            #pragma unroll
            for (int r = 0; r < 4; r++) { accX[mi][ni][r] = 0.f; accG[mi][ni][r] = 0.f; }

    const int NT = K / 32;

    auto issue = [&](int buf, int t) {
        uint32_t da = smem_u32(&As[buf][sr][sc]);
        uint32_t dx = smem_u32(&Bx[buf][sr][sc]);
        uint32_t dg = smem_u32(&Bg[buf][sr][sc]);
        CP16(da, Ap + t * 32);
        CP16(da + 16, Ap + t * 32 + 8);
        CP16(dx, Bxp + t * 32);
        CP16(dx + 16, Bxp + t * 32 + 8);
        CP16(dg, Bgp + t * 32);
        CP16(dg + 16, Bgp + t * 32 + 8);
        asm volatile("cp.async.commit_group;" ::: "memory");
    };

    issue(0, 0);
    issue(1, 1);
    int buf = 0;
    for (int t = 0; t < NT; t++) {
        if (t + 1 < NT) {
            asm volatile("cp.async.wait_group 1;" ::: "memory");
        } else {
            asm volatile("cp.async.wait_group 0;" ::: "memory");
        }
        __syncthreads();
        if (t + 2 < NT) {
            int nb = buf + 2;
            if (nb >= 3) nb -= 3;
            issue(nb, t + 2);
        }
        uint32_t aBase = smem_u32(&As[buf][0][0]);
        uint32_t xBase = smem_u32(&Bx[buf][0][0]);
        uint32_t gBase = smem_u32(&Bg[buf][0][0]);
        #pragma unroll
        for (int ks = 0; ks < 2; ks++) {
            uint32_t koff = ks * 32;
            uint32_t af[2][4], bx[8][2], bg[8][2];
            #pragma unroll
            for (int mi = 0; mi < 2; mi++)
                LDSM_X4(af[mi][0], af[mi][1], af[mi][2], af[mi][3],
                        aBase + aOff[mi] + koff);
            #pragma unroll
            for (int nip = 0; nip < 4; nip++) {
                LDSM_X4(bx[2 * nip][0], bx[2 * nip][1],
                        bx[2 * nip + 1][0], bx[2 * nip + 1][1],
                        xBase + bOff[nip] + koff);
                LDSM_X4(bg[2 * nip][0], bg[2 * nip][1],
                        bg[2 * nip + 1][0], bg[2 * nip + 1][1],
                        gBase + bOff[nip] + koff);
            }
            #pragma unroll
            for (int mi = 0; mi < 2; mi++)
                #pragma unroll
                for (int ni = 0; ni < 8; ni++) {
                    MMA_F16(accX[mi][ni], af[mi], bx[ni]);
                    MMA_F16(accG[mi][ni], af[mi], bg[ni]);
                }
        }
        if (++buf == 3) buf = 0;
    }

    #pragma unroll
    for (int mi = 0; mi < 2; mi++) {
        int r0 = bm + warpM * 32 + mi * 16 + lr;
        #pragma unroll
        for (int ni = 0; ni < 8; ni++) {
            int c0 = bn + warpN * 64 + ni * 8 + lc * 2;
            float bx0 = b1[c0], bx1 = b1[c0 + 1];
            float bg0 = b1[FF_IN + c0], bg1 = b1[FF_IN + c0 + 1];
            #pragma unroll
            for (int half_ = 0; half_ < 2; half_++) {
                int r = r0 + half_ * 8;
                float xp0 = accX[mi][ni][half_ * 2 + 0] + bx0;
                float xp1 = accX[mi][ni][half_ * 2 + 1] + bx1;
                float g0 = accG[mi][ni][half_ * 2 + 0] + bg0;
                float g1 = accG[mi][ni][half_ * 2 + 1] + bg1;
                float f0 = (g0 / (1.f + __expf(-g0))) * xp0;
                float f1 = (g1 / (1.f + __expf(-g1))) * xp1;
                __half2 hv = __floats2half2_rn(f0, f1);
                *reinterpret_cast<__half2*>(fmh + (size_t)r * N + c0) = hv;
            }
        }
    }
}

// ---------------- l2norm + RoPE (table-driven) ----------------
__global__ void __launch_bounds__(256) ropenorm_kernel(
    __half* __restrict__ qh, __half* __restrict__ kh, float* qb, float* kb,
    const float* __restrict__ ct, const float* __restrict__ st) {
    int s = blockIdx.x;
    int warp = threadIdx.x >> 5;
    int lane = threadIdx.x & 31;
    int idx = blockIdx.y * 8 + warp;
    int h = idx & 15;
    int a = idx >> 4;
    size_t off = (size_t)s * D_DIM + h * 64;
    float x1, x2;
    if (a < 2) {
        const __half* p = ((a == 0) ? qh : kh) + off;
        x1 = __half2float(p[lane]);
        x2 = __half2float(p[lane + DHALF]);
    } else {
        const float* p = ((a == 2) ? qb : kb) + off;
        x1 = p[lane];
        x2 = p[lane + DHALF];
    }
    float ss = x1 * x1 + x2 * x2;
    #pragma unroll
    for (int o = 16; o; o >>= 1) ss += __shfl_xor_sync(0xffffffffu, ss, o);
    float n = fmaxf(sqrtf(ss), 1e-12f);
    float inv = 1.f / n;
    x1 *= inv;
    x2 *= inv;
    float c  = ct[s * DHALF + lane];
    float sn = st[s * DHALF + lane];
    float y1 = x1 * c + x2 * sn;
    float y2 = -x1 * sn + x2 * c;
    if (a < 2) {
        __half* dst = ((a == 0) ? qh : kh) + off;
        dst[lane]         = __float2half(y1);
        dst[lane + DHALF] = __float2half(y2);
    } else {
        float* dst = ((a == 2) ? qb : kb) + off;
        dst[lane]         = y1;
        dst[lane + DHALF] = y2;
    }
}

// ---------------- parallel prefix sum of kb ----------------
__global__ void __launch_bounds__(256) prefix_p1(const float* __restrict__ kb,
                                                 float* __restrict__ cs) {
    int ch = blockIdx.x;
    int col = blockIdx.y * 256 + threadIdx.x;
    const float* p = kb + (size_t)(ch * 32) * D_DIM + col;
    float acc = 0.f;
    #pragma unroll
    for (int r = 0; r < 32; r++) acc += p[(size_t)r * D_DIM];
    cs[(size_t)ch * D_DIM + col] = acc;
}
__global__ void __launch_bounds__(1024) prefix_p2(float* __restrict__ cs) {
    int col = threadIdx.x;
    float run = 0.f;
    #pragma unroll 8
    for (int ch = 0; ch < 64; ch++) {
        size_t i = (size_t)ch * D_DIM + col;
        float t = cs[i];
        cs[i] = run;
        run += t;
    }
}
__global__ void __launch_bounds__(256) prefix_p3(const float* __restrict__ kb,
                                                 const float* __restrict__ cs,
                                                 float* __restrict__ pkb) {
    int ch = blockIdx.x;
    int col = blockIdx.y * 256 + threadIdx.x;
    float acc = cs[(size_t)ch * D_DIM + col];
    const float* p = kb + (size_t)(ch * 32) * D_DIM + col;
    float* o = pkb + (size_t)(ch * 32) * D_DIM + col;
    #pragma unroll
    for (int r = 0; r < 32; r++) {
        acc += p[(size_t)r * D_DIM];
        o[(size_t)r * D_DIM] = acc;
    }
}

// ---------------- sb values ----------------
__global__ void __launch_bounds__(512) sb_kernel(const float* __restrict__ qb,
                                                 const float* __restrict__ pkb,
                                                 float* __restrict__ sbv) {
    int s = blockIdx.x;
    int h = threadIdx.x >> 5;
    int lane = threadIdx.x & 31;
    size_t off = (size_t)s * D_DIM + h * 64;
    float v = qb[off + lane] * pkb[off + lane] +
              qb[off + lane + DHALF] * pkb[off + lane + DHALF];
    #pragma unroll
    for (int o = 16; o; o >>= 1) v += __shfl_xor_sync(0xffffffffu, v, o);
    if (lane == 0) sbv[s * H_N + h] = 0.125f * v;
}

// ---------------- fp16 flash attention (proven) ----------------
#define QSH 72
#define ATT_SMEM (512 * QSH * 2 + 256 * 4)

__global__ void __launch_bounds__(256) attn_mma_kernel(
    const __half* __restrict__ qh, const __half* __restrict__ kh,
    const __half* __restrict__ vh,
    const float* __restrict__ l2sp, __half* __restrict__ yh)
{
    extern __shared__ __half smah[];
    __half (*Qs)[QSH] = reinterpret_cast<__half(*)[QSH]>(smah);
    __half (*Ps)[QSH] = reinterpret_cast<__half(*)[QSH]>(smah + 128 * QSH);
    __half (*Ks)[64][QSH] = reinterpret_cast<__half(*)[64][QSH]>(smah + 256 * QSH);
    __half (*Vs)[64][QSH] = reinterpret_cast<__half(*)[64][QSH]>(smah + 384 * QSH);
    float* red_l = reinterpret_cast<float*>(smah + 512 * QSH);

    int h = blockIdx.y;
    int qt = gridDim.x - 1 - blockIdx.x;
    int q0 = qt * 128;
    int tid = threadIdx.x;
    int lane = tid & 31, warp = tid >> 5;
    int wm = warp >> 1;
    int wn = warp & 1;
    int lr = lane >> 2;
    int lc = lane & 3;

    int aRow = lane & 15, aCol = (lane >> 4) * 8;
    uint32_t qOff[2];
    #pragma unroll
    for (int mi = 0; mi < 2; mi++)
        qOff[mi] = ((wm * 32 + mi * 16 + aRow) * QSH + aCol) * 2;
    int bRow = ((lane & 16) ? 8 : 0) + (lane & 7);
    int bCol = ((lane & 8) ? 8 : 0);
    uint32_t kOff[2];
    #pragma unroll
    for (int nip = 0; nip < 2; nip++)
        kOff[nip] = ((wn * 32 + nip * 16 + bRow) * QSH + bCol) * 2;
    int tRow = ((lane & 8) ? 8 : 0) + (lane & 7);
    int tCol = ((lane & 16) ? 8 : 0);
    uint32_t vOff[2];
    #pragma unroll
    for (int nip = 0; nip < 2; nip++)
        vOff[nip] = (tRow * QSH + wn * 32 + nip * 16 + tCol) * 2;

    uint32_t qBase = smem_u32(&Qs[0][0]);
    uint32_t pBase = smem_u32(&Ps[0][0]);

    int stR = tid >> 2, stC = (tid & 3) * 16;

    auto issueKV = [&](int buf, int kt) {
        int kbase = kt * 64;
        const __half* ks = kh + (size_t)(kbase + stR) * D_DIM + h * 64 + stC;
        const __half* vs = vh + (size_t)(kbase + stR) * D_DIM + h * 64 + stC;
        uint32_t dk = smem_u32(&Ks[buf][stR][stC]);
        uint32_t dv = smem_u32(&Vs[buf][stR][stC]);
        CP16(dk, ks);
        CP16(dk + 16, ks + 8);
        CP16(dv, vs);
        CP16(dv + 16, vs + 8);
        asm volatile("cp.async.commit_group;" ::: "memory");
    };

    {
        int r = tid >> 1, c0 = (tid & 1) * 32;
        const __half* src = qh + (size_t)(q0 + r) * D_DIM + h * 64 + c0;
        #pragma unroll
        for (int j = 0; j < 4; j++)
            *reinterpret_cast<uint4*>(&Qs[r][c0 + j * 8]) =
                *reinterpret_cast<const uint4*>(src + j * 8);
    }

    float l[4] = {0.f, 0.f, 0.f, 0.f};
    float o[2][4][4];
    #pragma unroll
    for (int mi = 0; mi < 2; mi++)
        #pragma unroll
        for (int ni = 0; ni < 4; ni++)
            #pragma unroll
            for (int j = 0; j < 4; j++) o[mi][ni][j] = 0.f;

    int nt = 2 * qt + 2;
    issueKV(0, 0);

    for (int kt = 0; kt < nt; kt++) {
        int buf = kt & 1;
        int kbase = kt * 64;
        __syncthreads();
        if (kt + 1 < nt) {
            issueKV(buf ^ 1, kt + 1);
            asm volatile("cp.async.wait_group 1;" ::: "memory");
        } else {
            asm volatile("cp.async.wait_group 0;" ::: "memory");
        }
        __syncthreads();

        uint32_t kBase = smem_u32(&Ks[buf][0][0]);
        uint32_t vBase = smem_u32(&Vs[buf][0][0]);

        float s[2][4][4];
        #pragma unroll
        for (int mi = 0; mi < 2; mi++)
            #pragma unroll
            for (int ni = 0; ni < 4; ni++)
                #pragma unroll
                for (int j = 0; j < 4; j++) s[mi][ni][j] = 0.f;
        #pragma unroll
        for (int ks = 0; ks < 4; ks++) {
            uint32_t kbyte = ks * 32;
            uint32_t af[2][4], bf[4][2];
            #pragma unroll
            for (int mi = 0; mi < 2; mi++)
                LDSM_X4(af[mi][0], af[mi][1], af[mi][2], af[mi][3],
                        qBase + qOff[mi] + kbyte);
            #pragma unroll
            for (int nip = 0; nip < 2; nip++)
                LDSM_X4(bf[2 * nip][0], bf[2 * nip][1],
                        bf[2 * nip + 1][0], bf[2 * nip + 1][1],
                        kBase + kOff[nip] + kbyte);
            #pragma unroll
            for (int mi = 0; mi < 2; mi++)
                #pragma unroll
                for (int ni = 0; ni < 4; ni++)
                    MMA_F16(s[mi][ni], af[mi], bf[ni]);
        }
        if (kt >= nt - 2) {
            #pragma unroll
            for (int mi = 0; mi < 2; mi++) {
                int rg0 = q0 + wm * 32 + mi * 16 + lr;
                #pragma unroll
                for (int ni = 0; ni < 4; ni++) {
                    int cgb = kbase + wn * 32 + ni * 8 + lc * 2;
                    #pragma unroll
                    for (int j = 0; j < 4; j++) {
                        int rg = rg0 + ((j >= 2) ? 8 : 0);
                        int cg = cgb + (j & 1);
                        if (cg > rg) s[mi][ni][j] = -1e4f;
                    }
                }
            }
        }
        #pragma unroll
        for (int mi = 0; mi < 2; mi++) {
            int r0m = wm * 32 + mi * 16 + lr;
            int r1m = r0m + 8;
            #pragma unroll
            for (int ni = 0; ni < 4; ni++) {
                int cbase = wn * 32 + ni * 8 + lc * 2;
                float t0 = fmaf(s[mi][ni][0], L2E, -L2E);
                float t1 = fmaf(s[mi][ni][1], L2E, -L2E);
                float t2 = fmaf(s[mi][ni][2], L2E, -L2E);
                float t3 = fmaf(s[mi][ni][3], L2E, -L2E);
                __half2 ht0 = __floats2half2_rn(t0, t1);
                __half2 ht1 = __floats2half2_rn(t2, t3);
                uint32_t p0, p1;
                EX2_F16X2(p0, *reinterpret_cast<uint32_t*>(&ht0));
                EX2_F16X2(p1, *reinterpret_cast<uint32_t*>(&ht1));
                *reinterpret_cast<uint32_t*>(&Ps[r0m][cbase]) = p0;
                *reinterpret_cast<uint32_t*>(&Ps[r1m][cbase]) = p1;
                float2 f0 = __half22float2(*reinterpret_cast<__half2*>(&p0));
                float2 f1 = __half22float2(*reinterpret_cast<__half2*>(&p1));
                l[mi * 2]     += f0.x + f0.y;
                l[mi * 2 + 1] += f1.x + f1.y;
            }
        }
        __syncthreads();
        #pragma unroll
        for (int ks = 0; ks < 4; ks++) {
            uint32_t af[2][4], bf[4][2];
            #pragma unroll
            for (int mi = 0; mi < 2; mi++)
                LDSM_X4(af[mi][0], af[mi][1], af[mi][2], af[mi][3],
                        pBase + qOff[mi] + ks * 32);
            #pragma unroll
            for (int nip = 0; nip < 2; nip++)
                LDSM_X4T(bf[2 * nip][0], bf[2 * nip][1],
                         bf[2 * nip + 1][0], bf[2 * nip + 1][1],
                         vBase + vOff[nip] + ks * 16 * QSH * 2);
            #pragma unroll
            for (int mi = 0; mi < 2; mi++)
                #pragma unroll
                for (int ni = 0; ni < 4; ni++)
                    MMA_F16(o[mi][ni], af[mi], bf[ni]);
        }
    }

    #pragma unroll
    for (int i = 0; i < 4; i++) {
        l[i] += __shfl_xor_sync(0xffffffffu, l[i], 1);
        l[i] += __shfl_xor_sync(0xffffffffu, l[i], 2);
    }
    if (lc == 0) {
        #pragma unroll
        for (int mi = 0; mi < 2; mi++) {
            int r0m = wm * 32 + mi * 16 + lr;
            red_l[wn * 128 + r0m]     = l[mi * 2];
            red_l[wn * 128 + r0m + 8] = l[mi * 2 + 1];
        }
    }
    __syncthreads();

    float l2sv = l2sp[0];
    #pragma unroll
    for (int mi = 0; mi < 2; mi++) {
        int r0m = wm * 32 + mi * 16 + lr;
        int r1m = r0m + 8;
        float lt0 = red_l[r0m] + red_l[128 + r0m];
        float lt1 = red_l[r1m] + red_l[128 + r1m];
        float inv0 = l2sv / lt0;
        float inv1 = l2sv / lt1;
        int g0 = q0 + r0m, g1 = q0 + r1m;
        #pragma unroll
        for (int ni = 0; ni < 4; ni++) {
            int col = h * 64 + wn * 32 + ni * 8 + lc * 2;
            __half2 r0v = __floats2half2_rn(o[mi][ni][0] * inv0, o[mi][ni][1] * inv0);
            __half2 r1v = __floats2half2_rn(o[mi][ni][2] * inv1, o[mi][ni][3] * inv1);
            *reinterpret_cast<__half2*>(&yh[(size_t)g0 * D_DIM + col]) = r0v;
            *reinterpret_cast<__half2*>(&yh[(size_t)g1 * D_DIM + col]) = r1v;
        }
    }
}

// ---------------- launch ----------------
extern "C" void kernel_launch(void* const* d_in, const int* in_sizes, int n_in,
                              void* d_out, int out_size) {
    const float* h_states = (const float*)d_in[0];
    const float* Wq  = (const float*)d_in[1];
    const float* Wk  = (const float*)d_in[2];
    const float* Wv  = (const float*)d_in[3];
    const float* Wqb = (const float*)d_in[4];
    const float* Wkb = (const float*)d_in[5];
    const float* Wo  = (const float*)d_in[6];
    const float* bo  = (const float*)d_in[7];
    const float* W1  = (const float*)d_in[8];
    const float* b1  = (const float*)d_in[9];
    const float* W2  = (const float*)d_in[10];
    const float* b2  = (const float*)d_in[11];
    const float* lam = (const float*)d_in[12];
    const float* l2s = (const float*)d_in[13];
    float* out = (float*)d_out;

    float *qb, *kb, *pkb, *cs, *sbv, *wos, *cor, *ct, *st;
    __half *xh, *yh, *fmh, *qhh, *khh, *vhh;
    __half *wqh, *wkh, *wvh, *wqbh, *wkbh, *woh, *w1h, *w2h;
    cudaGetSymbolAddress((void**)&qb, g_qb);
    cudaGetSymbolAddress((void**)&kb, g_kb);
    cudaGetSymbolAddress((void**)&pkb, g_pkb);
    cudaGetSymbolAddress((void**)&cs, g_cs);
    cudaGetSymbolAddress((void**)&sbv, g_sb);
    cudaGetSymbolAddress((void**)&wos, g_wos);
    cudaGetSymbolAddress((void**)&cor, g_cor);
    cudaGetSymbolAddress((void**)&ct, g_ct);
    cudaGetSymbolAddress((void**)&st, g_st);
    cudaGetSymbolAddress((void**)&xh,  g_xh);
    cudaGetSymbolAddress((void**)&yh,  g_yh);
    cudaGetSymbolAddress((void**)&fmh, g_fmh);
    cudaGetSymbolAddress((void**)&qhh, g_qhh);
    cudaGetSymbolAddress((void**)&khh, g_khh);
    cudaGetSymbolAddress((void**)&vhh, g_vhh);
    cudaGetSymbolAddress((void**)&wqh,  g_wqh);
    cudaGetSymbolAddress((void**)&wkh,  g_wkh);
    cudaGetSymbolAddress((void**)&wvh,  g_wvh);
    cudaGetSymbolAddress((void**)&wqbh, g_wqbh);
    cudaGetSymbolAddress((void**)&wkbh, g_wkbh);
    cudaGetSymbolAddress((void**)&woh,  g_woh);
    cudaGetSymbolAddress((void**)&w1h,  g_w1h);
    cudaGetSymbolAddress((void**)&w2h,  g_w2h);

    cudaFuncSetAttribute(attn_mma_kernel,
                         cudaFuncAttributeMaxDynamicSharedMemorySize, ATT_SMEM);
    cudaFuncSetAttribute(gemm_f16_kernel,
                         cudaFuncAttributeMaxDynamicSharedMemorySize, GEMM_SMEM);
    cudaFuncSetAttribute(gemm_out_kernel,
                         cudaFuncAttributeMaxDynamicSharedMemorySize, GEMM_SMEM);
    cudaFuncSetAttribute(gemm_w1_swiglu_kernel,
                         cudaFuncAttributeMaxDynamicSharedMemorySize, W1_SMEM);

    static cudaStream_t s1 = nullptr, s2 = nullptr;
    static cudaEvent_t ev0 = nullptr, evFFN = nullptr, evRope = nullptr,
                       evSB = nullptr, evW = nullptr, evT = nullptr;
    if (!s1) {
        cudaStreamCreateWithFlags(&s1, cudaStreamNonBlocking);
        cudaStreamCreateWithFlags(&s2, cudaStreamNonBlocking);
        cudaEventCreateWithFlags(&ev0, cudaEventDisableTiming);
        cudaEventCreateWithFlags(&evFFN, cudaEventDisableTiming);
        cudaEventCreateWithFlags(&evRope, cudaEventDisableTiming);
        cudaEventCreateWithFlags(&evSB, cudaEventDisableTiming);
        cudaEventCreateWithFlags(&evW, cudaEventDisableTiming);
        cudaEventCreateWithFlags(&evT, cudaEventDisableTiming);
    }

    // ---- main: noop fork anchor, then rmsnorm (parallel with weight converts)
    noop_kernel<<<1, 32>>>();
    cudaEventRecord(ev0, 0);
    rmsnorm_kernel<<<S_LEN, 256>>>(h_states, xh);

    // ---- s2 (fork at ev0): weight converts -> evW; then ropetab -> evT; wosum
    cudaStreamWaitEvent(s2, ev0, 0);
    cvtT6_kernel<<<dim3(32, 32, 6), 256, 0, s2>>>(Wq, Wk, Wv, Wqb, Wkb, Wo,
                                                  wqh, wkh, wvh, wqbh, wkbh, woh);
    cudaEventRecord(evW, s2);
    ropetab_kernel<<<S_LEN * DHALF / 256, 256, 0, s2>>>(ct, st);
    cudaEventRecord(evT, s2);
    wosum_kernel<<<H_N * D_DIM / 256, 256, 0, s2>>>(Wo, wos);

    // ---- s1 (fork at ev0): FFN branch (W1 gemm waits for rmsnorm via main record)
    cudaStreamWaitEvent(s1, ev0, 0);
    cvtT_kernel<<<dim3(FUSEDW / 32, 32), 256, 0, s1>>>(W1, w1h, D_DIM, FUSEDW);
    cvtT_kernel<<<dim3(32, FF_IN / 32), 256, 0, s1>>>(W2, w2h, FF_IN, D_DIM);
    cudaEventRecord(evRope, 0);   // reuse as "rmsnorm done" marker for s1
    cudaStreamWaitEvent(s1, evRope, 0);
    gemm_w1_swiglu_kernel<<<dim3(FF_IN / 128, S_LEN / 128), 256, W1_SMEM, s1>>>(
        xh, w1h, fmh, b1);
    cudaEventRecord(evFFN, s1);

    // ---- main: attention branch (waits on s2 weight converts only) ----
    cudaStreamWaitEvent(0, evW, 0);
    gemm_f16_kernel<<<dim3(D_DIM / 128, S_LEN / 128, 5), 256, GEMM_SMEM>>>(
        xh, wqh, wkh, wvh, wqbh, wkbh, qb, kb, qhh, khh, vhh,
        S_LEN, D_DIM, D_DIM);
    cudaStreamWaitEvent(0, evT, 0);
    ropenorm_kernel<<<dim3(S_LEN, 8), 256>>>(qhh, khh, qb, kb, ct, st);
    cudaEventRecord(evRope, 0);

    // ---- s2: sb/corr chain, overlapped with attention ----
    cudaStreamWaitEvent(s2, evRope, 0);
    prefix_p1<<<dim3(64, 4), 256, 0, s2>>>(kb, cs);
    prefix_p2<<<1, 1024, 0, s2>>>(cs);
    prefix_p3<<<dim3(64, 4), 256, 0, s2>>>(kb, cs, pkb);
    sb_kernel<<<S_LEN, 512, 0, s2>>>(qb, pkb, sbv);
    corr_kernel<<<S_LEN, 256, 0, s2>>>(sbv, wos, bo, b2, cor);
    cudaEventRecord(evSB, s2);

    // ---- main: attention ----
    attn_mma_kernel<<<dim3(S_LEN / 128, H_N), 256, ATT_SMEM>>>(qhh, khh, vhh, l2s, yh);

    // ---- join everything: fused output GEMM ----
    cudaStreamWaitEvent(0, evSB, 0);
    cudaStreamWaitEvent(0, evFFN, 0);
    gemm_out_kernel<<<dim3(D_DIM / 128, S_LEN / 128), 256, GEMM_SMEM>>>(
        yh, fmh, woh, w2h, out, cor, h_states, lam);
}